// round 4
// baseline (speedup 1.0000x reference)
#include <cuda_runtime.h>
#include <math.h>
#include <stddef.h>

// Problem constants (fixed by the reference)
#define B_   32
#define N_   8192
#define E_   1048576
#define H_   128
#define BN_  (B_ * N_)          // 262144
#define L_   2

// ---------------------------------------------------------------------------
// Scratch (static device globals; allocation-free per harness rules)
// ---------------------------------------------------------------------------
static __device__ float g_h  [(size_t)BN_ * 128];   // node hidden state
static __device__ float g_b1 [(size_t)BN_ * 128];   // msg_all / node_features / h_hidden
static __device__ float g_b2 [(size_t)BN_ * 128];   // agg / s_hidden
static __device__ float g_tmp[(size_t)BN_ * 256];   // concat inputs (max lda 256)

// ---------------------------------------------------------------------------
// Zero fill (float4 granularity; n4 = number of float4s)
// ---------------------------------------------------------------------------
__global__ void k_zero4(float4* __restrict__ p, int n4) {
    int i = blockIdx.x * blockDim.x + threadIdx.x;
    int stride = gridDim.x * blockDim.x;
    for (; i < n4; i += stride) p[i] = make_float4(0.f, 0.f, 0.f, 0.f);
}

// ---------------------------------------------------------------------------
// Build A0 = [embed[atom_types] | coordinates]  -> g_tmp, lda = 67
// ---------------------------------------------------------------------------
__global__ void k_buildA0(float* __restrict__ out,
                          const float* __restrict__ emb,
                          const int* __restrict__ types,
                          const float* __restrict__ coords) {
    const int total = BN_ * 67;
    for (int idx = blockIdx.x * blockDim.x + threadIdx.x; idx < total;
         idx += gridDim.x * blockDim.x) {
        int row = idx / 67;
        int c   = idx - row * 67;
        float v;
        if (c < 64) v = emb[types[row] * 64 + c];
        else        v = coords[row * 3 + (c - 64)];
        out[idx] = v;
    }
}

// ---------------------------------------------------------------------------
// Build concat [h | agg] -> g_tmp, lda = 256 (float4 granularity)
// ---------------------------------------------------------------------------
__global__ void k_concat2(float4* __restrict__ out,
                          const float4* __restrict__ a,
                          const float4* __restrict__ b) {
    const int total = BN_ * 64;   // 64 float4 per row of 256 floats
    for (int idx = blockIdx.x * blockDim.x + threadIdx.x; idx < total;
         idx += gridDim.x * blockDim.x) {
        int row = idx >> 6;
        int c4  = idx & 63;
        out[idx] = (c4 < 32) ? a[row * 32 + c4] : b[row * 32 + (c4 - 32)];
    }
}

// ---------------------------------------------------------------------------
// Build feat = [node_features | cond_coords] -> g_tmp, lda = 131
// cond_coords = coords * !coupling_mask; coupling_mask = (n even) && valid
// ---------------------------------------------------------------------------
__global__ void k_buildFeat(float* __restrict__ out,
                            const float* __restrict__ nf,
                            const float* __restrict__ coords,
                            const unsigned char* __restrict__ maskB) {
    const int total = BN_ * 131;
    for (int idx = blockIdx.x * blockDim.x + threadIdx.x; idx < total;
         idx += gridDim.x * blockDim.x) {
        int row = idx / 131;
        int c   = idx - row * 131;
        float v;
        if (c < 128) {
            v = nf[(size_t)row * 128 + c];
        } else {
            bool valid = (maskB[row] == 0);
            bool cm    = ((row & 1) == 0) && valid;   // PHASE = 0, N even
            v = cm ? 0.f : coords[row * 3 + (c - 128)];
        }
        out[idx] = v;
    }
}

// ---------------------------------------------------------------------------
// Edge scatter: agg[dst] += msg_all[src]. 32 lanes per edge, float4 each.
// ---------------------------------------------------------------------------
__global__ void k_scatter(const float* __restrict__ msg,
                          const int* __restrict__ adj,
                          const int* __restrict__ ebi,
                          float* __restrict__ agg) {
    long gid = (long)blockIdx.x * blockDim.x + threadIdx.x;
    int e    = (int)(gid >> 5);
    int lane = (int)(gid & 31);
    if (e >= E_) return;
    int b   = ebi[e];
    int src = b * N_ + adj[2 * e];
    int dst = b * N_ + adj[2 * e + 1];
    float4 v = *(const float4*)(msg + (size_t)src * 128 + lane * 4);
    float* p = agg + (size_t)dst * 128 + lane * 4;
    atomicAdd(p + 0, v.x);
    atomicAdd(p + 1, v.y);
    atomicAdd(p + 2, v.z);
    atomicAdd(p + 3, v.w);
}

// ---------------------------------------------------------------------------
// Generic tiled GEMM: C[BN_,128] = act(A[BN_,K] @ W[K,128] + bias)
// TM=64, TN=128, TK=16; 256 threads; thread micro-tile 4 rows x 8 cols.
// Optional relu; optional row mask (zero masked rows, i.e. "* vf").
// ---------------------------------------------------------------------------
__global__ void __launch_bounds__(256)
k_gemm(const float* __restrict__ A, int lda,
       const float* __restrict__ W,
       const float* __restrict__ bias,
       float* __restrict__ C,
       int K, int do_relu,
       const unsigned char* __restrict__ maskB) {
    __shared__ float As[16][64];
    __shared__ float Ws[16][128];

    const int block_row = blockIdx.x * 64;
    const int tid = threadIdx.x;
    const int tx  = tid & 15;   // column group: cols = tx + 16*j
    const int ty  = tid >> 4;   // row group:    rows = ty*4 + i

    float acc[4][8];
#pragma unroll
    for (int i = 0; i < 4; i++)
#pragma unroll
        for (int j = 0; j < 8; j++) acc[i][j] = 0.f;

    for (int k0 = 0; k0 < K; k0 += 16) {
        // load A tile (64 x 16), stored transposed As[k][row]
#pragma unroll
        for (int t = 0; t < 4; t++) {
            int idx = tid + t * 256;          // 0..1023
            int r   = idx >> 4;
            int kk  = idx & 15;
            int k   = k0 + kk;
            As[kk][r] = (k < K) ? A[(size_t)(block_row + r) * lda + k] : 0.f;
        }
        // load W tile (16 x 128)
#pragma unroll
        for (int t = 0; t < 8; t++) {
            int idx = tid + t * 256;          // 0..2047
            int col = idx & 127;
            int kk  = idx >> 7;
            int k   = k0 + kk;
            Ws[kk][col] = (k < K) ? W[(size_t)k * 128 + col] : 0.f;
        }
        __syncthreads();

#pragma unroll
        for (int kk = 0; kk < 16; kk++) {
            float a[4], w[8];
#pragma unroll
            for (int i = 0; i < 4; i++) a[i] = As[kk][ty * 4 + i];
#pragma unroll
            for (int j = 0; j < 8; j++) w[j] = Ws[kk][tx + 16 * j];
#pragma unroll
            for (int i = 0; i < 4; i++)
#pragma unroll
                for (int j = 0; j < 8; j++) acc[i][j] = fmaf(a[i], w[j], acc[i][j]);
        }
        __syncthreads();
    }

    // epilogue
#pragma unroll
    for (int j = 0; j < 8; j++) {
        int col  = tx + 16 * j;
        float bv = bias[col];
#pragma unroll
        for (int i = 0; i < 4; i++) {
            int row = block_row + ty * 4 + i;
            float v = acc[i][j] + bv;
            if (do_relu) v = fmaxf(v, 0.f);
            if (maskB && maskB[row]) v = 0.f;
            C[(size_t)row * 128 + col] = v;
        }
    }
}

// ---------------------------------------------------------------------------
// Final coupling kernel: one warp per node.
// raw_scales = s_hidden @ Ws2 + bs2 ; shifts = h_hidden @ Wh2 + bh2  (3 cols)
// log_scales = tanh(raw)*2*cmask ; out = where(cmask, exp(ls)*coord+shift, coord)
// log_det accumulated per batch via atomicAdd into d_out[BN_*3 + b].
// ---------------------------------------------------------------------------
__global__ void k_final(const float* __restrict__ sH,
                        const float* __restrict__ hH,
                        const float* __restrict__ Ws2, const float* __restrict__ bs2,
                        const float* __restrict__ Wh2, const float* __restrict__ bh2,
                        const float* __restrict__ coords,
                        const unsigned char* __restrict__ maskB,
                        float* __restrict__ out,
                        float* __restrict__ logdet) {
    int warp = (blockIdx.x * blockDim.x + threadIdx.x) >> 5;
    int lane = threadIdx.x & 31;
    if (warp >= BN_) return;
    const int node = warp;

    float s[4], h[4];
#pragma unroll
    for (int i = 0; i < 4; i++) {
        int k = lane + 32 * i;
        s[i] = sH[(size_t)node * 128 + k];
        h[i] = hH[(size_t)node * 128 + k];
    }

    float raw[3], sh[3];
#pragma unroll
    for (int c = 0; c < 3; c++) {
        float ps = 0.f, ph = 0.f;
#pragma unroll
        for (int i = 0; i < 4; i++) {
            int k = lane + 32 * i;
            ps = fmaf(s[i], Ws2[k * 3 + c], ps);
            ph = fmaf(h[i], Wh2[k * 3 + c], ph);
        }
#pragma unroll
        for (int off = 16; off > 0; off >>= 1) {
            ps += __shfl_xor_sync(0xFFFFFFFFu, ps, off);
            ph += __shfl_xor_sync(0xFFFFFFFFu, ph, off);
        }
        raw[c] = ps + bs2[c];
        sh[c]  = ph + bh2[c];
    }

    if (lane == 0) {
        bool valid = (maskB[node] == 0);
        bool cm    = ((node & 1) == 0) && valid;   // PHASE = 0
        float ld = 0.f;
#pragma unroll
        for (int c = 0; c < 3; c++) {
            float ls = cm ? tanhf(raw[c]) * 2.f : 0.f;
            ld += ls;
            float coord = coords[node * 3 + c];
            float o = cm ? (expf(ls) * coord + sh[c]) : coord;
            out[node * 3 + c] = o;
        }
        atomicAdd(&logdet[node >> 13], ld);        // node / N_
    }
}

__global__ void k_zero_logdet(float* __restrict__ logdet) {
    if (threadIdx.x < B_) logdet[threadIdx.x] = 0.f;
}

// ---------------------------------------------------------------------------
// Host launcher
// ---------------------------------------------------------------------------
extern "C" void kernel_launch(void* const* d_in, const int* in_sizes, int n_in,
                              void* d_out, int out_size) {
    const float*         coords = (const float*)d_in[0];
    const int*           types  = (const int*)  d_in[1];
    const int*           adj    = (const int*)  d_in[2];
    const int*           ebi    = (const int*)  d_in[3];
    const unsigned char* maskB  = (const unsigned char*)d_in[4];
    const float* emb   = (const float*)d_in[5];
    const float* W_in  = (const float*)d_in[6];
    const float* b_in  = (const float*)d_in[7];
    const float* msg_W = (const float*)d_in[8];
    const float* msg_b = (const float*)d_in[9];
    const float* upd_W = (const float*)d_in[10];
    const float* upd_b = (const float*)d_in[11];
    const float* W_out = (const float*)d_in[12];
    const float* b_out = (const float*)d_in[13];
    const float* Ws1   = (const float*)d_in[14];
    const float* bs1   = (const float*)d_in[15];
    const float* Ws2   = (const float*)d_in[16];
    const float* bs2   = (const float*)d_in[17];
    const float* Wh1   = (const float*)d_in[18];
    const float* bh1   = (const float*)d_in[19];
    const float* Wh2   = (const float*)d_in[20];
    const float* bh2   = (const float*)d_in[21];

    float* out    = (float*)d_out;
    float* logdet = out + (size_t)BN_ * 3;

    float *h, *b1, *b2, *tmp;
    cudaGetSymbolAddress((void**)&h,   g_h);
    cudaGetSymbolAddress((void**)&b1,  g_b1);
    cudaGetSymbolAddress((void**)&b2,  g_b2);
    cudaGetSymbolAddress((void**)&tmp, g_tmp);

    const int GEMM_BLOCKS = BN_ / 64;   // 4096
    const int BT = 256;

    // --- input layer: h = relu([emb|coords] @ W_in + b_in) * vf ---
    k_buildA0<<<8192, BT>>>(tmp, emb, types, coords);
    k_gemm<<<GEMM_BLOCKS, BT>>>(tmp, 67, W_in, b_in, h, 67, 1, maskB);

    // --- message-passing layers ---
    for (int l = 0; l < L_; l++) {
        const float* mW = msg_W + (size_t)l * 128 * 128;
        const float* mb = msg_b + (size_t)l * 128;
        const float* uW = upd_W + (size_t)l * 256 * 128;
        const float* ub = upd_b + (size_t)l * 128;

        // per-node message precompute: msg_all = relu(h @ msg_W + msg_b)
        k_gemm<<<GEMM_BLOCKS, BT>>>(h, 128, mW, mb, b1, 128, 1, (const unsigned char*)0);
        // agg = segment_sum over edges
        k_zero4<<<16384, BT>>>((float4*)b2, BN_ * 32);
        k_scatter<<<(E_ * 32) / BT, BT>>>(b1, adj, ebi, b2);
        // h = relu([h | agg] @ upd_W + upd_b) * vf
        k_concat2<<<16384, BT>>>((float4*)tmp, (const float4*)h, (const float4*)b2);
        k_gemm<<<GEMM_BLOCKS, BT>>>(tmp, 256, uW, ub, h, 256, 1, maskB);
    }

    // --- output projection (no relu, no mask) ---
    k_gemm<<<GEMM_BLOCKS, BT>>>(h, 128, W_out, b_out, b1, 128, 0, (const unsigned char*)0);

    // --- coupling networks ---
    k_buildFeat<<<16384, BT>>>(tmp, b1, coords, maskB);
    k_gemm<<<GEMM_BLOCKS, BT>>>(tmp, 131, Ws1, bs1, b2, 131, 1, (const unsigned char*)0); // s_hidden
    k_gemm<<<GEMM_BLOCKS, BT>>>(tmp, 131, Wh1, bh1, b1, 131, 1, (const unsigned char*)0); // h_hidden

    // --- final: small projections + tanh/exp + log_det ---
    k_zero_logdet<<<1, 32>>>(logdet);
    k_final<<<BN_ / 8, BT>>>(b2, b1, Ws2, bs2, Wh2, bh2, coords, maskB, out, logdet);
}

// round 6
// speedup vs baseline: 1.8606x; 1.8606x over previous
#include <cuda_runtime.h>
#include <cstdint>
#include <math.h>
#include <stddef.h>

// Problem constants
#define B_   32
#define N_   8192
#define E_   1048576
#define BN_  (B_ * N_)          // 262144
#define L_   2

// ---------------------------------------------------------------------------
// Arch-feature gate: tcgen05 exists only on sm_100a/sm_103a compilation passes.
// The harness also compiles a plain compute_103 PTX pass which must still
// compile; it gets a scalar fallback (never selected on real GB300 hardware,
// which loads the sm_103a SASS).
// ---------------------------------------------------------------------------
#if defined(__CUDA_ARCH_FEAT_SM103_ALL) || defined(__CUDA_ARCH_FEAT_SM100_ALL)
#  define TC_AVAIL 1
#endif
#ifndef TC_AVAIL
#  ifdef __CUDA_ARCH_HAS_FEATURE__
#    if __CUDA_ARCH_HAS_FEATURE__(SM103_ALL) || __CUDA_ARCH_HAS_FEATURE__(SM100_ALL)
#      define TC_AVAIL 1
#    endif
#  endif
#endif
#ifndef TC_AVAIL
#  define TC_AVAIL 0
#endif

// ---------------------------------------------------------------------------
// Scratch (static device globals; allocation-free per harness rules)
// ---------------------------------------------------------------------------
static __device__ float g_h [(size_t)BN_ * 128];
static __device__ float g_b1[(size_t)BN_ * 128];
static __device__ float g_b2[(size_t)BN_ * 128];
static __device__ float g_wt[167936];             // transposed+padded weights

// ---------------------------------------------------------------------------
// Helpers
// ---------------------------------------------------------------------------
__device__ __forceinline__ uint32_t smem_u32(const void* p) {
    uint32_t a;
    asm("{ .reg .u64 t; cvta.to.shared.u64 t, %1; cvt.u32.u64 %0, t; }"
        : "=r"(a) : "l"(p));
    return a;
}

#define SW128(o) ((o) ^ (((o) >> 3) & 0x70))

#if TC_AVAIL
__device__ __forceinline__ uint64_t mk_desc(uint32_t addr) {
    // SW128, version=1 (Blackwell), LBO=1, SBO=64  (K-major)
    const uint64_t BASE = (2ULL << 61) | (1ULL << 46) | (64ULL << 32) | (1ULL << 16);
    return BASE | ((uint64_t)(addr >> 4) & 0x3FFF);
}

// idesc: acc=F32(1<<4), atype=TF32(2<<7), btype=TF32(2<<10), N=128, M=128
#define IDESC_TF32 ((1u << 4) | (2u << 7) | (2u << 10) | ((128u/8u) << 17) | ((128u/16u) << 24))

__device__ __forceinline__ void mma_tf32_ss(uint32_t d, uint64_t a, uint64_t b,
                                            uint32_t en) {
    asm volatile(
        "{\n\t.reg .pred p;\n\t"
        "setp.ne.u32 p, %4, 0;\n\t"
        "tcgen05.mma.cta_group::1.kind::tf32 [%0], %1, %2, %3, p;\n\t}"
        :: "r"(d), "l"(a), "l"(b), "r"(IDESC_TF32), "r"(en) : "memory");
}

__device__ __forceinline__ void tc_commit(uint32_t mbar) {
    asm volatile(
        "tcgen05.commit.cta_group::1.mbarrier::arrive::one.shared::cluster.b64 [%0];"
        :: "r"(mbar) : "memory");
}

#define TC_LD_X32(r, addr)                                                     \
    asm volatile(                                                              \
        "tcgen05.ld.sync.aligned.32x32b.x32.b32 "                              \
        "{%0, %1, %2, %3, %4, %5, %6, %7, "                                    \
        " %8, %9, %10, %11, %12, %13, %14, %15, "                              \
        " %16, %17, %18, %19, %20, %21, %22, %23, "                            \
        " %24, %25, %26, %27, %28, %29, %30, %31}, [%32];"                     \
        : "=r"((r)[0]),  "=r"((r)[1]),  "=r"((r)[2]),  "=r"((r)[3]),           \
          "=r"((r)[4]),  "=r"((r)[5]),  "=r"((r)[6]),  "=r"((r)[7]),           \
          "=r"((r)[8]),  "=r"((r)[9]),  "=r"((r)[10]), "=r"((r)[11]),          \
          "=r"((r)[12]), "=r"((r)[13]), "=r"((r)[14]), "=r"((r)[15]),          \
          "=r"((r)[16]), "=r"((r)[17]), "=r"((r)[18]), "=r"((r)[19]),          \
          "=r"((r)[20]), "=r"((r)[21]), "=r"((r)[22]), "=r"((r)[23]),          \
          "=r"((r)[24]), "=r"((r)[25]), "=r"((r)[26]), "=r"((r)[27]),          \
          "=r"((r)[28]), "=r"((r)[29]), "=r"((r)[30]), "=r"((r)[31])           \
        : "r"(addr))
#endif  // TC_AVAIL

__device__ __forceinline__ void mbar_init(uint32_t a, uint32_t cnt) {
    asm volatile("mbarrier.init.shared.b64 [%0], %1;" :: "r"(a), "r"(cnt) : "memory");
}
__device__ __forceinline__ void mbar_wait(uint32_t a, uint32_t parity) {
    asm volatile(
        "{\n\t.reg .pred P;\n"
        "WL%=:\n\t"
        "mbarrier.try_wait.parity.acquire.cta.shared::cta.b64 P, [%0], %1, 0x989680;\n\t"
        "@P bra WD%=;\n\t"
        "bra WL%=;\n"
        "WD%=:\n\t}"
        :: "r"(a), "r"(parity) : "memory");
}

// ---------------------------------------------------------------------------
// GEMM:  C[BN,128] = act(A[BN,K] @ Wt^T + bias)
// Wt pre-transposed [128 n-rows, Kpad k-cols], zero-padded (Kpad mult of 32).
// tcgen05 path: M-tile 128/CTA, N=128, K tiles of 32, 2-stage smem ring.
// MODE: 0=direct(lda128) 1=concat(h|agg) 2=embed-gather 3=feat(nf|masked coords)
// ---------------------------------------------------------------------------
#define NSTAGE       2
#define STAGE_BYTES  32768            // 16KB A + 16KB W
#define SMEM_GEMM    (1024 + NSTAGE * STAGE_BYTES)

struct GP {
    const float* A1; const float* A2;
    const float* emb; const int* types; const float* coords;
    const float* Wt; const float* bias;
    const unsigned char* maskB;
    float* C;
    int K; int Kpad; int relu; int use_mask;
};

template<int MODE>
__device__ __forceinline__ float4 loadA4(const GP& g, int gr, int k) {
    if (MODE == 0) {                       // direct, K = 128
        return *(const float4*)(g.A1 + (size_t)gr * 128 + k);
    } else if (MODE == 1) {                // concat [h | agg], K = 256
        if (k < 128) return *(const float4*)(g.A1 + (size_t)gr * 128 + k);
        return *(const float4*)(g.A2 + (size_t)gr * 128 + (k - 128));
    } else if (MODE == 2) {                // [embed[types] | coords], K = 67
        int t = g.types[gr];
        if (k + 3 < 64) return *(const float4*)(g.emb + t * 64 + k);
        float4 v; float* vp = &v.x;
#pragma unroll
        for (int i = 0; i < 4; i++) {
            int kk = k + i; float x;
            if (kk < 64)      x = g.emb[t * 64 + kk];
            else if (kk < 67) x = g.coords[gr * 3 + (kk - 64)];
            else              x = 0.f;
            vp[i] = x;
        }
        return v;
    } else {                               // [nf | cond_coords], K = 131
        if (k + 3 < 128) return *(const float4*)(g.A1 + (size_t)gr * 128 + k);
        bool cm = ((gr & 1) == 0) && (g.maskB[gr] == 0);   // PHASE=0
        float4 v; float* vp = &v.x;
#pragma unroll
        for (int i = 0; i < 4; i++) {
            int kk = k + i; float x;
            if (kk < 128)      x = g.A1[(size_t)gr * 128 + kk];
            else if (kk < 131) x = cm ? 0.f : g.coords[gr * 3 + (kk - 128)];
            else               x = 0.f;
            vp[i] = x;
        }
        return v;
    }
}

template<int MODE>
__global__ void __launch_bounds__(128) k_gemm_tc(GP g) {
#if TC_AVAIL
    extern __shared__ __align__(1024) char smem[];
    const uint32_t sb = smem_u32(smem);
    const int tid = threadIdx.x;
    const int wid = tid >> 5;
    const int lid = tid & 31;
    const int block_row = blockIdx.x * 128;

    if (wid == 0) {
        asm volatile(
            "tcgen05.alloc.cta_group::1.sync.aligned.shared::cta.b32 [%0], %1;"
            :: "r"(sb), "r"(128u) : "memory");
        asm volatile("tcgen05.relinquish_alloc_permit.cta_group::1.sync.aligned;");
    }
    if (tid == 0) {
#pragma unroll
        for (int s = 0; s < NSTAGE; s++) mbar_init(sb + 8 + s * 8, 1);
    }
    __syncthreads();
    uint32_t tmem;
    asm volatile("ld.shared.b32 %0, [%1];" : "=r"(tmem) : "r"(sb));

    const int nt = g.Kpad / 32;

    for (int t = 0; t < nt; t++) {
        const int b = t & (NSTAGE - 1);
        if (t >= NSTAGE) mbar_wait(sb + 8 + b * 8, ((t >> 1) - 1) & 1);

        // stage fill: A tile [128 rows x 32 k] + W tile [128 n x 32 k], SW128
        char* bufA = smem + 1024 + b * STAGE_BYTES;
        char* bufW = bufA + 16384;
#pragma unroll
        for (int it = 0; it < 8; it++) {
            int idx = tid + it * 128;         // 0..1023
            int r   = idx >> 3;               // row / n
            int c4  = idx & 7;
            int k   = t * 32 + c4 * 4;
            float4 av = (k < g.K) ? loadA4<MODE>(g, block_row + r, k)
                                  : make_float4(0.f, 0.f, 0.f, 0.f);
            float4 wv = *(const float4*)(g.Wt + (size_t)r * g.Kpad + k);
            uint32_t off = SW128((uint32_t)(r * 128 + c4 * 16));
            *(float4*)(bufA + off) = av;
            *(float4*)(bufW + off) = wv;
        }
        __syncthreads();

        if (tid == 0) {
            asm volatile("fence.proxy.async.shared::cta;" ::: "memory");
            uint64_t ad = mk_desc(sb + 1024 + b * STAGE_BYTES);
            uint64_t bd = mk_desc(sb + 1024 + b * STAGE_BYTES + 16384);
#pragma unroll
            for (int j = 0; j < 4; j++)   // 4 x K=8 tf32 steps = K 32
                mma_tf32_ss(tmem, ad + j * 2, bd + j * 2,
                            (t > 0 || j > 0) ? 1u : 0u);
            tc_commit(sb + 8 + b * 8);
        }
    }

    // wait for last commit (MMAs issue in order => all done)
    mbar_wait(sb + 8 + ((nt - 1) & (NSTAGE - 1)) * 8, ((nt - 1) >> 1) & 1);
    asm volatile("tcgen05.fence::after_thread_sync;" ::: "memory");

    // epilogue: each warp reads its own 32-lane TMEM subpartition => rows
    const int m = block_row + wid * 32 + lid;
    const bool masked = g.use_mask && (g.maskB[m] != 0);
#pragma unroll
    for (int cb = 0; cb < 128; cb += 32) {
        uint32_t r32[32];
        TC_LD_X32(r32, tmem + cb);
        asm volatile("tcgen05.wait::ld.sync.aligned;" ::: "memory");
#pragma unroll
        for (int j = 0; j < 32; j += 4) {
            float4 o;
            float* op = &o.x;
#pragma unroll
            for (int i = 0; i < 4; i++) {
                float v = __uint_as_float(r32[j + i]) + g.bias[cb + j + i];
                if (g.relu) v = fmaxf(v, 0.f);
                if (masked) v = 0.f;
                op[i] = v;
            }
            *(float4*)(g.C + (size_t)m * 128 + cb + j) = o;
        }
    }

    __syncthreads();
    if (wid == 0) {
        asm volatile("tcgen05.dealloc.cta_group::1.sync.aligned.b32 %0, %1;"
                     :: "r"(tmem), "r"(128u));
    }
#else
    // Scalar fallback for non-sm_103a compilation passes (correct, slow;
    // never selected on GB300 where the sm_103a SASS is loaded).
    const int row = blockIdx.x * 128 + threadIdx.x;
    const bool masked = g.use_mask && (g.maskB[row] != 0);
#pragma unroll 1
    for (int cb = 0; cb < 128; cb += 4) {
        float acc[4] = {0.f, 0.f, 0.f, 0.f};
        for (int k = 0; k < g.K; k += 4) {
            float4 a = loadA4<MODE>(g, row, k);
            const float* ap = &a.x;
#pragma unroll
            for (int c = 0; c < 4; c++) {
                const float* wr = g.Wt + (size_t)(cb + c) * g.Kpad + k;
#pragma unroll
                for (int i = 0; i < 4; i++)
                    acc[c] = fmaf(ap[i], wr[i], acc[c]);
            }
        }
#pragma unroll
        for (int c = 0; c < 4; c++) {
            float v = acc[c] + g.bias[cb + c];
            if (g.relu) v = fmaxf(v, 0.f);
            if (masked) v = 0.f;
            g.C[(size_t)row * 128 + cb + c] = v;
        }
    }
#endif
}

// ---------------------------------------------------------------------------
// Weight transpose+pad: Wt[n*Kpad + k] = (k<K) ? W[k*128+n] : 0
// ---------------------------------------------------------------------------
__global__ void k_tw(float* __restrict__ dst, const float* __restrict__ src,
                     int K, int Kpad) {
    int total = 128 * Kpad;
    for (int idx = blockIdx.x * blockDim.x + threadIdx.x; idx < total;
         idx += gridDim.x * blockDim.x) {
        int n = idx / Kpad;
        int k = idx - n * Kpad;
        dst[idx] = (k < K) ? src[k * 128 + n] : 0.f;
    }
}

// ---------------------------------------------------------------------------
// Zero fill
// ---------------------------------------------------------------------------
__global__ void k_zero4(float4* __restrict__ p, int n4) {
    int i = blockIdx.x * blockDim.x + threadIdx.x;
    int stride = gridDim.x * blockDim.x;
    for (; i < n4; i += stride) p[i] = make_float4(0.f, 0.f, 0.f, 0.f);
}

// ---------------------------------------------------------------------------
// Edge scatter: agg[dst] += msg[src], vector red (1 RED.128 per 16B)
// ---------------------------------------------------------------------------
__global__ void k_scatter(const float* __restrict__ msg,
                          const int* __restrict__ adj,
                          const int* __restrict__ ebi,
                          float* __restrict__ agg) {
    long gid = (long)blockIdx.x * blockDim.x + threadIdx.x;
    int e    = (int)(gid >> 5);
    int lane = (int)(gid & 31);
    if (e >= E_) return;
    int b   = ebi[e];
    int src = b * N_ + adj[2 * e];
    int dst = b * N_ + adj[2 * e + 1];
    float4 v = *(const float4*)(msg + (size_t)src * 128 + lane * 4);
    float* p = agg + (size_t)dst * 128 + lane * 4;
    asm volatile("red.global.add.v4.f32 [%0], {%1, %2, %3, %4};"
                 :: "l"(p), "f"(v.x), "f"(v.y), "f"(v.z), "f"(v.w) : "memory");
}

// ---------------------------------------------------------------------------
// Final coupling: one warp per node
// ---------------------------------------------------------------------------
__global__ void k_final(const float* __restrict__ sH,
                        const float* __restrict__ hH,
                        const float* __restrict__ Ws2, const float* __restrict__ bs2,
                        const float* __restrict__ Wh2, const float* __restrict__ bh2,
                        const float* __restrict__ coords,
                        const unsigned char* __restrict__ maskB,
                        float* __restrict__ out,
                        float* __restrict__ logdet) {
    int warp = (blockIdx.x * blockDim.x + threadIdx.x) >> 5;
    int lane = threadIdx.x & 31;
    if (warp >= BN_) return;
    const int node = warp;

    float s[4], h[4];
#pragma unroll
    for (int i = 0; i < 4; i++) {
        int k = lane + 32 * i;
        s[i] = sH[(size_t)node * 128 + k];
        h[i] = hH[(size_t)node * 128 + k];
    }
    float raw[3], sh[3];
#pragma unroll
    for (int c = 0; c < 3; c++) {
        float ps = 0.f, ph = 0.f;
#pragma unroll
        for (int i = 0; i < 4; i++) {
            int k = lane + 32 * i;
            ps = fmaf(s[i], Ws2[k * 3 + c], ps);
            ph = fmaf(h[i], Wh2[k * 3 + c], ph);
        }
#pragma unroll
        for (int off = 16; off > 0; off >>= 1) {
            ps += __shfl_xor_sync(0xFFFFFFFFu, ps, off);
            ph += __shfl_xor_sync(0xFFFFFFFFu, ph, off);
        }
        raw[c] = ps + bs2[c];
        sh[c]  = ph + bh2[c];
    }
    if (lane == 0) {
        bool valid = (maskB[node] == 0);
        bool cm    = ((node & 1) == 0) && valid;   // PHASE = 0
        float ld = 0.f;
#pragma unroll
        for (int c = 0; c < 3; c++) {
            float ls = cm ? tanhf(raw[c]) * 2.f : 0.f;
            ld += ls;
            float coord = coords[node * 3 + c];
            out[node * 3 + c] = cm ? (expf(ls) * coord + sh[c]) : coord;
        }
        atomicAdd(&logdet[node >> 13], ld);
    }
}

__global__ void k_zero_logdet(float* __restrict__ logdet) {
    if (threadIdx.x < B_) logdet[threadIdx.x] = 0.f;
}

// ---------------------------------------------------------------------------
// Host launcher
// ---------------------------------------------------------------------------
extern "C" void kernel_launch(void* const* d_in, const int* in_sizes, int n_in,
                              void* d_out, int out_size) {
    const float*         coords = (const float*)d_in[0];
    const int*           types  = (const int*)  d_in[1];
    const int*           adj    = (const int*)  d_in[2];
    const int*           ebi    = (const int*)  d_in[3];
    const unsigned char* maskB  = (const unsigned char*)d_in[4];
    const float* emb   = (const float*)d_in[5];
    const float* W_in  = (const float*)d_in[6];
    const float* b_in  = (const float*)d_in[7];
    const float* msg_W = (const float*)d_in[8];
    const float* msg_b = (const float*)d_in[9];
    const float* upd_W = (const float*)d_in[10];
    const float* upd_b = (const float*)d_in[11];
    const float* W_out = (const float*)d_in[12];
    const float* b_out = (const float*)d_in[13];
    const float* Ws1   = (const float*)d_in[14];
    const float* bs1   = (const float*)d_in[15];
    const float* Ws2   = (const float*)d_in[16];
    const float* bs2   = (const float*)d_in[17];
    const float* Wh1   = (const float*)d_in[18];
    const float* bh1   = (const float*)d_in[19];
    const float* Wh2   = (const float*)d_in[20];
    const float* bh2   = (const float*)d_in[21];

    float* out    = (float*)d_out;
    float* logdet = out + (size_t)BN_ * 3;

    float *h, *b1, *b2, *wt;
    cudaGetSymbolAddress((void**)&h,  g_h);
    cudaGetSymbolAddress((void**)&b1, g_b1);
    cudaGetSymbolAddress((void**)&b2, g_b2);
    cudaGetSymbolAddress((void**)&wt, g_wt);

    cudaFuncSetAttribute(k_gemm_tc<0>, cudaFuncAttributeMaxDynamicSharedMemorySize, SMEM_GEMM);
    cudaFuncSetAttribute(k_gemm_tc<1>, cudaFuncAttributeMaxDynamicSharedMemorySize, SMEM_GEMM);
    cudaFuncSetAttribute(k_gemm_tc<2>, cudaFuncAttributeMaxDynamicSharedMemorySize, SMEM_GEMM);
    cudaFuncSetAttribute(k_gemm_tc<3>, cudaFuncAttributeMaxDynamicSharedMemorySize, SMEM_GEMM);

    // transposed-weight scratch offsets (floats)
    const int o_Win  = 0;        // Kpad  96
    const int o_msg0 = 12288;    // Kpad 128
    const int o_msg1 = 28672;
    const int o_upd0 = 45056;    // Kpad 256
    const int o_upd1 = 77824;
    const int o_Wout = 110592;   // Kpad 128
    const int o_Ws1  = 126976;   // Kpad 160
    const int o_Wh1  = 147456;

    const int BT = 256;
    auto tw = [&](float* dst, const float* src, int K, int Kpad) {
        k_tw<<<(128 * Kpad + BT - 1) / BT, BT>>>(dst, src, K, Kpad);
    };
    tw(wt + o_Win,  W_in,                   67, 96);
    tw(wt + o_msg0, msg_W,                 128, 128);
    tw(wt + o_msg1, msg_W + 128 * 128,     128, 128);
    tw(wt + o_upd0, upd_W,                 256, 256);
    tw(wt + o_upd1, upd_W + 256 * 128,     256, 256);
    tw(wt + o_Wout, W_out,                 128, 128);
    tw(wt + o_Ws1,  Ws1,                   131, 160);
    tw(wt + o_Wh1,  Wh1,                   131, 160);

    const int GB = BN_ / 128;   // 2048 CTAs per GEMM

    GP g{};
    g.emb = emb; g.types = types; g.coords = coords; g.maskB = maskB;

    // input layer: h = relu([emb|coords] @ W_in + b_in) * vf
    g.A1 = 0; g.A2 = 0; g.Wt = wt + o_Win; g.bias = b_in; g.C = h;
    g.K = 67; g.Kpad = 96; g.relu = 1; g.use_mask = 1;
    k_gemm_tc<2><<<GB, 128, SMEM_GEMM>>>(g);

    const float* mWt[2] = {wt + o_msg0, wt + o_msg1};
    const float* uWt[2] = {wt + o_upd0, wt + o_upd1};
    for (int l = 0; l < L_; l++) {
        // msg_all = relu(h @ msg_W + msg_b)
        g.A1 = h; g.A2 = 0; g.Wt = mWt[l]; g.bias = msg_b + l * 128; g.C = b1;
        g.K = 128; g.Kpad = 128; g.relu = 1; g.use_mask = 0;
        k_gemm_tc<0><<<GB, 128, SMEM_GEMM>>>(g);
        // agg = segment_sum
        k_zero4<<<16384, BT>>>((float4*)b2, BN_ * 32);
        k_scatter<<<(E_ * 32) / BT, BT>>>(b1, adj, ebi, b2);
        // h = relu([h|agg] @ upd_W + upd_b) * vf   (in-place: own rows only)
        g.A1 = h; g.A2 = b2; g.Wt = uWt[l]; g.bias = upd_b + l * 128; g.C = h;
        g.K = 256; g.Kpad = 256; g.relu = 1; g.use_mask = 1;
        k_gemm_tc<1><<<GB, 128, SMEM_GEMM>>>(g);
    }

    // node_features = h @ W_out + b_out
    g.A1 = h; g.A2 = 0; g.Wt = wt + o_Wout; g.bias = b_out; g.C = b1;
    g.K = 128; g.Kpad = 128; g.relu = 0; g.use_mask = 0;
    k_gemm_tc<0><<<GB, 128, SMEM_GEMM>>>(g);

    // coupling hidden layers: feat = [nf | cond_coords]
    g.A1 = b1; g.A2 = 0; g.Wt = wt + o_Ws1; g.bias = bs1; g.C = b2;
    g.K = 131; g.Kpad = 160; g.relu = 1; g.use_mask = 0;
    k_gemm_tc<3><<<GB, 128, SMEM_GEMM>>>(g);   // s_hidden -> b2

    g.Wt = wt + o_Wh1; g.bias = bh1; g.C = h;
    k_gemm_tc<3><<<GB, 128, SMEM_GEMM>>>(g);   // h_hidden -> h

    k_zero_logdet<<<1, 32>>>(logdet);
    k_final<<<BN_ / 8, BT>>>(b2, h, Ws2, bs2, Wh2, bh2, coords, maskB, out, logdet);
}

// round 7
// speedup vs baseline: 3.0984x; 1.6653x over previous
#include <cuda_runtime.h>
#include <cstdint>
#include <math.h>
#include <stddef.h>

// Problem constants
#define B_   32
#define N_   8192
#define E_   1048576
#define BN_  (B_ * N_)          // 262144
#define L_   2

// ---------------------------------------------------------------------------
// Arch-feature gate (tcgen05 only exists on sm_100a/sm_103a passes)
// ---------------------------------------------------------------------------
#if defined(__CUDA_ARCH_FEAT_SM103_ALL) || defined(__CUDA_ARCH_FEAT_SM100_ALL)
#  define TC_AVAIL 1
#endif
#ifndef TC_AVAIL
#  ifdef __CUDA_ARCH_HAS_FEATURE__
#    if __CUDA_ARCH_HAS_FEATURE__(SM103_ALL) || __CUDA_ARCH_HAS_FEATURE__(SM100_ALL)
#      define TC_AVAIL 1
#    endif
#  endif
#endif
#ifndef TC_AVAIL
#  define TC_AVAIL 0
#endif

// ---------------------------------------------------------------------------
// Scratch (static device globals)
// ---------------------------------------------------------------------------
static __device__ float g_h   [(size_t)BN_ * 128];
static __device__ float g_b1  [(size_t)BN_ * 128];   // msg_all
static __device__ float g_b2  [(size_t)BN_ * 128];   // agg
static __device__ float g_wt  [167936];              // packed weights (see offsets)
static __device__ int   g_off [BN_ + 1];             // CSR offsets (also deg/hist)
static __device__ int   g_part[512];                 // scan partials
static __device__ int   g_cur [BN_];                 // placement cursors
static __device__ int   g_srcl[E_];                  // CSR src list

// g_wt float offsets
#define O_WIN   0        // Kpad 96   (12288)
#define O_MSG0  12288    // 128x128
#define O_MSG1  28672
#define O_UPD0  45056    // 128x256
#define O_UPD1  77824
#define O_WSE   110592   // 128x160 fused coupling (scale)
#define O_WHE   131072   // 128x160 fused coupling (shift)
#define O_BSE   151552   // 128
#define O_BHE   151680   // 128

// ---------------------------------------------------------------------------
// Helpers
// ---------------------------------------------------------------------------
__device__ __forceinline__ uint32_t smem_u32(const void* p) {
    uint32_t a;
    asm("{ .reg .u64 t; cvta.to.shared.u64 t, %1; cvt.u32.u64 %0, t; }"
        : "=r"(a) : "l"(p));
    return a;
}

#define SW128(o) ((o) ^ (((o) >> 3) & 0x70))

#if TC_AVAIL
__device__ __forceinline__ uint64_t mk_desc(uint32_t addr) {
    // SW128, version=1 (Blackwell), LBO=1, SBO=64 (K-major)
    const uint64_t BASE = (2ULL << 61) | (1ULL << 46) | (64ULL << 32) | (1ULL << 16);
    return BASE | ((uint64_t)(addr >> 4) & 0x3FFF);
}

// idesc: acc=F32(1<<4), atype=TF32(2<<7), btype=TF32(2<<10), N=128, M=128
#define IDESC_TF32 ((1u << 4) | (2u << 7) | (2u << 10) | ((128u/8u) << 17) | ((128u/16u) << 24))

__device__ __forceinline__ void mma_tf32_ss(uint32_t d, uint64_t a, uint64_t b,
                                            uint32_t en) {
    asm volatile(
        "{\n\t.reg .pred p;\n\t"
        "setp.ne.u32 p, %4, 0;\n\t"
        "tcgen05.mma.cta_group::1.kind::tf32 [%0], %1, %2, %3, p;\n\t}"
        :: "r"(d), "l"(a), "l"(b), "r"(IDESC_TF32), "r"(en) : "memory");
}

__device__ __forceinline__ void tc_commit(uint32_t mbar) {
    asm volatile(
        "tcgen05.commit.cta_group::1.mbarrier::arrive::one.shared::cluster.b64 [%0];"
        :: "r"(mbar) : "memory");
}

#define TC_LD_X32(r, addr)                                                     \
    asm volatile(                                                              \
        "tcgen05.ld.sync.aligned.32x32b.x32.b32 "                              \
        "{%0, %1, %2, %3, %4, %5, %6, %7, "                                    \
        " %8, %9, %10, %11, %12, %13, %14, %15, "                              \
        " %16, %17, %18, %19, %20, %21, %22, %23, "                            \
        " %24, %25, %26, %27, %28, %29, %30, %31}, [%32];"                     \
        : "=r"((r)[0]),  "=r"((r)[1]),  "=r"((r)[2]),  "=r"((r)[3]),           \
          "=r"((r)[4]),  "=r"((r)[5]),  "=r"((r)[6]),  "=r"((r)[7]),           \
          "=r"((r)[8]),  "=r"((r)[9]),  "=r"((r)[10]), "=r"((r)[11]),          \
          "=r"((r)[12]), "=r"((r)[13]), "=r"((r)[14]), "=r"((r)[15]),          \
          "=r"((r)[16]), "=r"((r)[17]), "=r"((r)[18]), "=r"((r)[19]),          \
          "=r"((r)[20]), "=r"((r)[21]), "=r"((r)[22]), "=r"((r)[23]),          \
          "=r"((r)[24]), "=r"((r)[25]), "=r"((r)[26]), "=r"((r)[27]),          \
          "=r"((r)[28]), "=r"((r)[29]), "=r"((r)[30]), "=r"((r)[31])           \
        : "r"(addr))
#endif  // TC_AVAIL

__device__ __forceinline__ void mbar_init(uint32_t a, uint32_t cnt) {
    asm volatile("mbarrier.init.shared.b64 [%0], %1;" :: "r"(a), "r"(cnt) : "memory");
}
__device__ __forceinline__ void mbar_wait(uint32_t a, uint32_t parity) {
    asm volatile(
        "{\n\t.reg .pred P;\n"
        "WL%=:\n\t"
        "mbarrier.try_wait.parity.acquire.cta.shared::cta.b64 P, [%0], %1, 0x989680;\n\t"
        "@P bra WD%=;\n\t"
        "bra WL%=;\n"
        "WD%=:\n\t}"
        :: "r"(a), "r"(parity) : "memory");
}

// ---------------------------------------------------------------------------
// k_prep: weight transposes, fused coupling weight products, zeros.
//   Wse_t[n*160+k] = sum_q W_out[k][q]*Ws1[q][n]  (k<128) ; Ws1[k][n] (128..130)
//   bse[n] = bs1[n] + sum_q b_out[q]*Ws1[q][n]
// ---------------------------------------------------------------------------
__global__ void k_prep(const float* __restrict__ W_in,
                       const float* __restrict__ msg_W,
                       const float* __restrict__ upd_W,
                       const float* __restrict__ W_out,
                       const float* __restrict__ Ws1,
                       const float* __restrict__ Wh1,
                       const float* __restrict__ bs1,
                       const float* __restrict__ bh1,
                       const float* __restrict__ b_out,
                       float* __restrict__ wt,
                       int* __restrict__ off,
                       float* __restrict__ logdet) {
    const int TOTAL = 151808 + (BN_ + 1) + 32;
    for (int idx = blockIdx.x * blockDim.x + threadIdx.x; idx < TOTAL;
         idx += gridDim.x * blockDim.x) {
        if (idx < 12288) {                       // W_in^T, K=67 pad 96
            int n = idx / 96, k = idx - n * 96;
            wt[idx] = (k < 67) ? W_in[k * 128 + n] : 0.f;
        } else if (idx < 45056) {                // msg_W^T x2
            int j = idx - 12288;
            int l = j >> 14, r = j & 16383;
            int n = r >> 7, k = r & 127;
            wt[idx] = msg_W[l * 16384 + k * 128 + n];
        } else if (idx < 110592) {               // upd_W^T x2 (K=256)
            int j = idx - 45056;
            int l = j >> 15, r = j & 32767;
            int n = r >> 8, k = r & 255;
            wt[idx] = upd_W[l * 32768 + k * 128 + n];
        } else if (idx < 131072) {               // Wse_t
            int j = idx - 110592;
            int n = j / 160, k = j - n * 160;
            float v = 0.f;
            if (k < 128) {
                for (int q = 0; q < 128; q++)
                    v = fmaf(W_out[k * 128 + q], Ws1[q * 128 + n], v);
            } else if (k < 131) {
                v = Ws1[k * 128 + n];
            }
            wt[idx] = v;
        } else if (idx < 151552) {               // Whe_t
            int j = idx - 131072;
            int n = j / 160, k = j - n * 160;
            float v = 0.f;
            if (k < 128) {
                for (int q = 0; q < 128; q++)
                    v = fmaf(W_out[k * 128 + q], Wh1[q * 128 + n], v);
            } else if (k < 131) {
                v = Wh1[k * 128 + n];
            }
            wt[idx] = v;
        } else if (idx < 151680) {               // bse
            int n = idx - 151552;
            float v = bs1[n];
            for (int q = 0; q < 128; q++)
                v = fmaf(b_out[q], Ws1[q * 128 + n], v);
            wt[idx] = v;
        } else if (idx < 151808) {               // bhe
            int n = idx - 151680;
            float v = bh1[n];
            for (int q = 0; q < 128; q++)
                v = fmaf(b_out[q], Wh1[q * 128 + n], v);
            wt[idx] = v;
        } else if (idx < 151808 + BN_ + 1) {     // zero deg/offsets
            off[idx - 151808] = 0;
        } else {                                 // zero logdet
            logdet[idx - (151808 + BN_ + 1)] = 0.f;
        }
    }
}

// ---------------------------------------------------------------------------
// CSR build: hist -> scanA -> scanB -> place
// ---------------------------------------------------------------------------
__global__ void k_hist(const int* __restrict__ adj, const int* __restrict__ ebi,
                       int* __restrict__ deg) {
    int e = blockIdx.x * blockDim.x + threadIdx.x;
    if (e >= E_) return;
    int dst = ebi[e] * N_ + adj[2 * e + 1];
    atomicAdd(&deg[dst], 1);
}

__global__ void k_scanA(int* __restrict__ off, int* __restrict__ part) {
    __shared__ int s[512];
    int t = threadIdx.x;
    int i = blockIdx.x * 512 + t;
    int v = off[i];
    s[t] = v; __syncthreads();
    for (int d = 1; d < 512; d <<= 1) {
        int x = (t >= d) ? s[t - d] : 0;
        __syncthreads();
        s[t] += x;
        __syncthreads();
    }
    off[i] = s[t] - v;                 // exclusive within chunk
    if (t == 511) part[blockIdx.x] = s[t];
}

__global__ void k_scanB(int* __restrict__ off, const int* __restrict__ part,
                        int* __restrict__ cur) {
    __shared__ int s[512];
    int t = threadIdx.x, b = blockIdx.x;
    s[t] = part[t]; __syncthreads();
    for (int d = 1; d < 512; d <<= 1) {
        int x = (t >= d) ? s[t - d] : 0;
        __syncthreads();
        s[t] += x;
        __syncthreads();
    }
    int prefix = (b == 0) ? 0 : s[b - 1];
    int i = b * 512 + t;
    int v = off[i] + prefix;
    off[i] = v;
    cur[i] = v;
    if (b == 0 && t == 0) off[BN_] = E_;
}

__global__ void k_place(const int* __restrict__ adj, const int* __restrict__ ebi,
                        int* __restrict__ cur, int* __restrict__ srcl) {
    int e = blockIdx.x * blockDim.x + threadIdx.x;
    if (e >= E_) return;
    int b = ebi[e];
    int src = b * N_ + adj[2 * e];
    int dst = b * N_ + adj[2 * e + 1];
    int pos = atomicAdd(&cur[dst], 1);
    srcl[pos] = src;
}

// ---------------------------------------------------------------------------
// Gather: agg[d] = sum over incident edges of msg[src]. One warp per node.
// ---------------------------------------------------------------------------
__global__ void k_gather(const float* __restrict__ msg,
                         const int* __restrict__ off,
                         const int* __restrict__ srcl,
                         float* __restrict__ agg) {
    int warp = (blockIdx.x * blockDim.x + threadIdx.x) >> 5;
    int lane = threadIdx.x & 31;
    int s0 = off[warp], s1 = off[warp + 1];
    float4 acc = make_float4(0.f, 0.f, 0.f, 0.f);
    for (int j = s0; j < s1; j++) {
        int s = srcl[j];
        float4 v = *((const float4*)(msg + (size_t)s * 128) + lane);
        acc.x += v.x; acc.y += v.y; acc.z += v.z; acc.w += v.w;
    }
    *((float4*)(agg + (size_t)warp * 128) + lane) = acc;
}

// ---------------------------------------------------------------------------
// GEMM core (shared by standard + coupling kernels)
// ---------------------------------------------------------------------------
#define NSTAGE       2
#define STAGE_BYTES  32768            // 16KB A + 16KB W
#define SMEM_GEMM    (1024 + NSTAGE * STAGE_BYTES)

struct GP {
    const float* A1; const float* A2;
    const float* emb; const int* types; const float* coords;
    const float* Wt; const float* bias;
    const unsigned char* maskB;
    float* C;
    int K; int Kpad; int relu; int use_mask;
};

template<int MODE>
__device__ __forceinline__ float4 loadA4(const GP& g, int gr, int k) {
    if (MODE == 0) {                       // direct, K = 128
        return *(const float4*)(g.A1 + (size_t)gr * 128 + k);
    } else if (MODE == 1) {                // concat [h | agg], K = 256
        if (k < 128) return *(const float4*)(g.A1 + (size_t)gr * 128 + k);
        return *(const float4*)(g.A2 + (size_t)gr * 128 + (k - 128));
    } else if (MODE == 2) {                // [embed[types] | coords], K = 67
        int t = g.types[gr];
        if (k + 3 < 64) return *(const float4*)(g.emb + t * 64 + k);
        float4 v; float* vp = &v.x;
#pragma unroll
        for (int i = 0; i < 4; i++) {
            int kk = k + i; float x;
            if (kk < 64)      x = g.emb[t * 64 + kk];
            else if (kk < 67) x = g.coords[gr * 3 + (kk - 64)];
            else              x = 0.f;
            vp[i] = x;
        }
        return v;
    } else {                               // [h | cond_coords], K = 131
        if (k + 3 < 128) return *(const float4*)(g.A1 + (size_t)gr * 128 + k);
        bool cm = ((gr & 1) == 0) && (g.maskB[gr] == 0);   // PHASE=0
        float4 v; float* vp = &v.x;
#pragma unroll
        for (int i = 0; i < 4; i++) {
            int kk = k + i; float x;
            if (kk < 128)      x = g.A1[(size_t)gr * 128 + kk];
            else if (kk < 131) x = cm ? 0.f : g.coords[gr * 3 + (kk - 128)];
            else               x = 0.f;
            vp[i] = x;
        }
        return v;
    }
}

template<int MODE>
__global__ void __launch_bounds__(128) k_gemm_tc(GP g) {
#if TC_AVAIL
    extern __shared__ __align__(1024) char smem[];
    const uint32_t sb = smem_u32(smem);
    const int tid = threadIdx.x;
    const int wid = tid >> 5;
    const int lid = tid & 31;
    const int block_row = blockIdx.x * 128;

    if (wid == 0) {
        asm volatile(
            "tcgen05.alloc.cta_group::1.sync.aligned.shared::cta.b32 [%0], %1;"
            :: "r"(sb), "r"(128u) : "memory");
        asm volatile("tcgen05.relinquish_alloc_permit.cta_group::1.sync.aligned;");
    }
    if (tid == 0) {
#pragma unroll
        for (int s = 0; s < NSTAGE; s++) mbar_init(sb + 8 + s * 8, 1);
    }
    __syncthreads();
    uint32_t tmem;
    asm volatile("ld.shared.b32 %0, [%1];" : "=r"(tmem) : "r"(sb));

    const int nt = g.Kpad / 32;

    for (int t = 0; t < nt; t++) {
        const int b = t & (NSTAGE - 1);
        if (t >= NSTAGE) mbar_wait(sb + 8 + b * 8, ((t >> 1) - 1) & 1);

        char* bufA = smem + 1024 + b * STAGE_BYTES;
        char* bufW = bufA + 16384;
#pragma unroll
        for (int it = 0; it < 8; it++) {
            int idx = tid + it * 128;
            int r   = idx >> 3;
            int c4  = idx & 7;
            int k   = t * 32 + c4 * 4;
            float4 av = (k < g.K) ? loadA4<MODE>(g, block_row + r, k)
                                  : make_float4(0.f, 0.f, 0.f, 0.f);
            float4 wv = *(const float4*)(g.Wt + (size_t)r * g.Kpad + k);
            uint32_t off = SW128((uint32_t)(r * 128 + c4 * 16));
            *(float4*)(bufA + off) = av;
            *(float4*)(bufW + off) = wv;
        }
        __syncthreads();

        if (tid == 0) {
            asm volatile("fence.proxy.async.shared::cta;" ::: "memory");
            uint64_t ad = mk_desc(sb + 1024 + b * STAGE_BYTES);
            uint64_t bd = mk_desc(sb + 1024 + b * STAGE_BYTES + 16384);
#pragma unroll
            for (int j = 0; j < 4; j++)
                mma_tf32_ss(tmem, ad + j * 2, bd + j * 2,
                            (t > 0 || j > 0) ? 1u : 0u);
            tc_commit(sb + 8 + b * 8);
        }
    }

    mbar_wait(sb + 8 + ((nt - 1) & (NSTAGE - 1)) * 8, ((nt - 1) >> 1) & 1);
    asm volatile("tcgen05.fence::after_thread_sync;" ::: "memory");

    const int m = block_row + wid * 32 + lid;
    const bool masked = g.use_mask && (g.maskB[m] != 0);
#pragma unroll
    for (int cb = 0; cb < 128; cb += 32) {
        uint32_t r32[32];
        TC_LD_X32(r32, tmem + cb);
        asm volatile("tcgen05.wait::ld.sync.aligned;" ::: "memory");
#pragma unroll
        for (int j = 0; j < 32; j += 4) {
            float4 o;
            float* op = &o.x;
#pragma unroll
            for (int i = 0; i < 4; i++) {
                float v = __uint_as_float(r32[j + i]) + g.bias[cb + j + i];
                if (g.relu) v = fmaxf(v, 0.f);
                if (masked) v = 0.f;
                op[i] = v;
            }
            *(float4*)(g.C + (size_t)m * 128 + cb + j) = o;
        }
    }

    __syncthreads();
    if (wid == 0) {
        asm volatile("tcgen05.dealloc.cta_group::1.sync.aligned.b32 %0, %1;"
                     :: "r"(tmem), "r"(128u));
    }
#else
    // Scalar fallback for non-sm_103a passes (never runs on GB300).
    const int row = blockIdx.x * 128 + threadIdx.x;
    const bool masked = g.use_mask && (g.maskB[row] != 0);
#pragma unroll 1
    for (int cb = 0; cb < 128; cb += 4) {
        float acc[4] = {0.f, 0.f, 0.f, 0.f};
        for (int k = 0; k < g.K; k += 4) {
            float4 a = loadA4<MODE>(g, row, k);
            const float* ap = &a.x;
#pragma unroll
            for (int c = 0; c < 4; c++) {
                const float* wr = g.Wt + (size_t)(cb + c) * g.Kpad + k;
#pragma unroll
                for (int i = 0; i < 4; i++)
                    acc[c] = fmaf(ap[i], wr[i], acc[c]);
            }
        }
#pragma unroll
        for (int c = 0; c < 4; c++) {
            float v = acc[c] + g.bias[cb + c];
            if (g.relu) v = fmaxf(v, 0.f);
            if (masked) v = 0.f;
            g.C[(size_t)row * 128 + cb + c] = v;
        }
    }
#endif
}

// ---------------------------------------------------------------------------
// Coupling dual GEMM + fused final epilogue.
// A = [h | cond_coords] (K=131, Kpad=160). Two MMA chains:
//   s_pre = A @ Wse^T   (TMEM cols   0..127)
//   h_pre = A @ Whe^T   (TMEM cols 128..255)
// Epilogue per row m: sv = relu(s_pre + bse), hv = relu(h_pre + bhe),
//   raw[c] = sv . Ws2[:,c] + bs2[c];  sh[c] = hv . Wh2[:,c] + bh2[c]
//   ls = cm ? 2*tanh(raw) : 0 ; out = cm ? exp(ls)*coord + sh : coord
//   logdet[b] += sum ls  (warp-reduced, 1 atomic per warp)
// ---------------------------------------------------------------------------
#define CPL_HDR      8192
#define CPL_STAGE    49152           // 16KB A + 16KB Ws + 16KB Wh
#define SMEM_CPL     (CPL_HDR + NSTAGE * CPL_STAGE)
// header layout: 0 tmem ptr; 8,16 mbars; 64 Ws2s[384]; 1600 Wh2s[384];
//                3136 bse[128]; 3648 bhe[128]

struct CP {
    const float* A1; const float* coords;
    const float* Wse; const float* Whe;        // g_wt + O_WSE / O_WHE
    const float* bse; const float* bhe;        // g_wt + O_BSE / O_BHE
    const float* Ws2; const float* bs2;
    const float* Wh2; const float* bh2;
    const unsigned char* maskB;
    float* out; float* logdet;
};

__global__ void __launch_bounds__(128) k_gemm_cpl(CP g) {
#if TC_AVAIL
    extern __shared__ __align__(1024) char smem[];
    const uint32_t sb = smem_u32(smem);
    float* smf = (float*)smem;
    const int tid = threadIdx.x;
    const int wid = tid >> 5;
    const int lid = tid & 31;
    const int block_row = blockIdx.x * 128;

    if (wid == 0) {
        asm volatile(
            "tcgen05.alloc.cta_group::1.sync.aligned.shared::cta.b32 [%0], %1;"
            :: "r"(sb), "r"(256u) : "memory");
        asm volatile("tcgen05.relinquish_alloc_permit.cta_group::1.sync.aligned;");
    }
    if (tid == 0) {
#pragma unroll
        for (int s = 0; s < NSTAGE; s++) mbar_init(sb + 8 + s * 8, 1);
    }
    // preload epilogue tables: Ws2/Wh2 (384 each), bse/bhe (128 each)
    for (int i = tid; i < 384; i += 128) {
        smf[16 + i]  = g.Ws2[i];        // byte 64
        smf[400 + i] = g.Wh2[i];        // byte 1600
    }
    smf[784 + tid] = g.bse[tid];        // byte 3136
    smf[912 + tid] = g.bhe[tid];        // byte 3648
    __syncthreads();
    uint32_t tmem;
    asm volatile("ld.shared.b32 %0, [%1];" : "=r"(tmem) : "r"(sb));

    const int nt = 5;                   // Kpad 160

    GP ga{};  // reuse loadA4<3>
    ga.A1 = g.A1; ga.coords = g.coords; ga.maskB = g.maskB; ga.K = 131;

    for (int t = 0; t < nt; t++) {
        const int b = t & (NSTAGE - 1);
        if (t >= NSTAGE) mbar_wait(sb + 8 + b * 8, ((t >> 1) - 1) & 1);

        char* base = smem + CPL_HDR + b * CPL_STAGE;
#pragma unroll
        for (int it = 0; it < 24; it++) {
            int idx = tid + it * 128;            // 0..3071
            int sec = idx >> 10;                 // 0=A 1=Ws 2=Wh
            int w   = idx & 1023;
            int r   = w >> 3;
            int c4  = w & 7;
            int k   = t * 32 + c4 * 4;
            float4 v;
            if (sec == 0)
                v = (k < 131) ? loadA4<3>(ga, block_row + r, k)
                              : make_float4(0.f, 0.f, 0.f, 0.f);
            else if (sec == 1)
                v = *(const float4*)(g.Wse + (size_t)r * 160 + k);
            else
                v = *(const float4*)(g.Whe + (size_t)r * 160 + k);
            uint32_t off = SW128((uint32_t)(r * 128 + c4 * 16));
            *(float4*)(base + sec * 16384 + off) = v;
        }
        __syncthreads();

        if (tid == 0) {
            asm volatile("fence.proxy.async.shared::cta;" ::: "memory");
            uint32_t stage = sb + CPL_HDR + b * CPL_STAGE;
            uint64_t ad = mk_desc(stage);
            uint64_t sd = mk_desc(stage + 16384);
            uint64_t hd = mk_desc(stage + 32768);
            uint32_t en0 = (t > 0) ? 1u : 0u;
#pragma unroll
            for (int j = 0; j < 4; j++) {
                uint32_t en = (j > 0) ? 1u : en0;
                mma_tf32_ss(tmem,       ad + j * 2, sd + j * 2, en);
                mma_tf32_ss(tmem + 128, ad + j * 2, hd + j * 2, en);
            }
            tc_commit(sb + 8 + b * 8);
        }
    }

    mbar_wait(sb + 8 + ((nt - 1) & (NSTAGE - 1)) * 8, ((nt - 1) >> 1) & 1);
    asm volatile("tcgen05.fence::after_thread_sync;" ::: "memory");

    const int m = block_row + wid * 32 + lid;
    float raw[3] = {0.f, 0.f, 0.f};
    float shf[3] = {0.f, 0.f, 0.f};
#pragma unroll
    for (int cb = 0; cb < 128; cb += 32) {
        uint32_t rs[32], rh[32];
        TC_LD_X32(rs, tmem + cb);
        TC_LD_X32(rh, tmem + 128 + cb);
        asm volatile("tcgen05.wait::ld.sync.aligned;" ::: "memory");
#pragma unroll
        for (int k = 0; k < 32; k++) {
            int col = cb + k;
            float sv = fmaxf(__uint_as_float(rs[k]) + smf[784 + col], 0.f);
            float hv = fmaxf(__uint_as_float(rh[k]) + smf[912 + col], 0.f);
#pragma unroll
            for (int c = 0; c < 3; c++) {
                raw[c] = fmaf(sv, smf[16 + col * 3 + c],  raw[c]);
                shf[c] = fmaf(hv, smf[400 + col * 3 + c], shf[c]);
            }
        }
    }

    bool cm = ((m & 1) == 0) && (g.maskB[m] == 0);   // PHASE = 0
    float ld = 0.f;
#pragma unroll
    for (int c = 0; c < 3; c++) {
        float r = raw[c] + g.bs2[c];
        float s = shf[c] + g.bh2[c];
        float ls = cm ? tanhf(r) * 2.f : 0.f;
        ld += ls;
        float coord = g.coords[m * 3 + c];
        g.out[m * 3 + c] = cm ? (expf(ls) * coord + s) : coord;
    }
#pragma unroll
    for (int o = 16; o > 0; o >>= 1)
        ld += __shfl_xor_sync(0xFFFFFFFFu, ld, o);
    if (lid == 0) atomicAdd(&g.logdet[m >> 13], ld);

    __syncthreads();
    if (wid == 0) {
        asm volatile("tcgen05.dealloc.cta_group::1.sync.aligned.b32 %0, %1;"
                     :: "r"(tmem), "r"(256u));
    }
#else
    // Scalar fallback (never runs on GB300).
    const int m = blockIdx.x * 128 + threadIdx.x;
    bool cm = ((m & 1) == 0) && (g.maskB[m] == 0);
    float raw[3], shf[3];
#pragma unroll
    for (int c = 0; c < 3; c++) { raw[c] = g.bs2[c]; shf[c] = g.bh2[c]; }
    for (int n = 0; n < 128; n++) {
        float accs = g.bse[n], acch = g.bhe[n];
        for (int k = 0; k < 128; k++) {
            float a = g.A1[(size_t)m * 128 + k];
            accs = fmaf(a, g.Wse[n * 160 + k], accs);
            acch = fmaf(a, g.Whe[n * 160 + k], acch);
        }
        for (int k = 128; k < 131; k++) {
            float a = cm ? 0.f : g.coords[m * 3 + (k - 128)];
            accs = fmaf(a, g.Wse[n * 160 + k], accs);
            acch = fmaf(a, g.Whe[n * 160 + k], acch);
        }
        accs = fmaxf(accs, 0.f); acch = fmaxf(acch, 0.f);
#pragma unroll
        for (int c = 0; c < 3; c++) {
            raw[c] = fmaf(accs, g.Ws2[n * 3 + c], raw[c]);
            shf[c] = fmaf(acch, g.Wh2[n * 3 + c], shf[c]);
        }
    }
    float ld = 0.f;
#pragma unroll
    for (int c = 0; c < 3; c++) {
        float ls = cm ? tanhf(raw[c]) * 2.f : 0.f;
        ld += ls;
        float coord = g.coords[m * 3 + c];
        g.out[m * 3 + c] = cm ? (expf(ls) * coord + shf[c]) : coord;
    }
    atomicAdd(&g.logdet[m >> 13], ld);
#endif
}

// ---------------------------------------------------------------------------
// Host launcher
// ---------------------------------------------------------------------------
extern "C" void kernel_launch(void* const* d_in, const int* in_sizes, int n_in,
                              void* d_out, int out_size) {
    const float*         coords = (const float*)d_in[0];
    const int*           types  = (const int*)  d_in[1];
    const int*           adj    = (const int*)  d_in[2];
    const int*           ebi    = (const int*)  d_in[3];
    const unsigned char* maskB  = (const unsigned char*)d_in[4];
    const float* emb   = (const float*)d_in[5];
    const float* W_in  = (const float*)d_in[6];
    const float* b_in  = (const float*)d_in[7];
    const float* msg_W = (const float*)d_in[8];
    const float* msg_b = (const float*)d_in[9];
    const float* upd_W = (const float*)d_in[10];
    const float* upd_b = (const float*)d_in[11];
    const float* W_out = (const float*)d_in[12];
    const float* b_out = (const float*)d_in[13];
    const float* Ws1   = (const float*)d_in[14];
    const float* bs1   = (const float*)d_in[15];
    const float* Ws2   = (const float*)d_in[16];
    const float* bs2   = (const float*)d_in[17];
    const float* Wh1   = (const float*)d_in[18];
    const float* bh1   = (const float*)d_in[19];
    const float* Wh2   = (const float*)d_in[20];
    const float* bh2   = (const float*)d_in[21];

    float* out    = (float*)d_out;
    float* logdet = out + (size_t)BN_ * 3;

    float *h, *b1, *b2, *wt;
    int *off, *part, *cur, *srcl;
    cudaGetSymbolAddress((void**)&h,    g_h);
    cudaGetSymbolAddress((void**)&b1,   g_b1);
    cudaGetSymbolAddress((void**)&b2,   g_b2);
    cudaGetSymbolAddress((void**)&wt,   g_wt);
    cudaGetSymbolAddress((void**)&off,  g_off);
    cudaGetSymbolAddress((void**)&part, g_part);
    cudaGetSymbolAddress((void**)&cur,  g_cur);
    cudaGetSymbolAddress((void**)&srcl, g_srcl);

    cudaFuncSetAttribute(k_gemm_tc<0>, cudaFuncAttributeMaxDynamicSharedMemorySize, SMEM_GEMM);
    cudaFuncSetAttribute(k_gemm_tc<1>, cudaFuncAttributeMaxDynamicSharedMemorySize, SMEM_GEMM);
    cudaFuncSetAttribute(k_gemm_tc<2>, cudaFuncAttributeMaxDynamicSharedMemorySize, SMEM_GEMM);
    cudaFuncSetAttribute(k_gemm_cpl,   cudaFuncAttributeMaxDynamicSharedMemorySize, SMEM_CPL);

    const int BT = 256;
    const int GB = BN_ / 128;   // 2048 CTAs per GEMM

    // 0: prep (weights + fused coupling weights + zero deg/logdet)
    k_prep<<<512, BT>>>(W_in, msg_W, upd_W, W_out, Ws1, Wh1, bs1, bh1, b_out,
                        wt, off, logdet);
    // 1-4: CSR build (reused by both layers)
    k_hist <<<E_ / BT, BT>>>(adj, ebi, off);
    k_scanA<<<512, 512>>>(off, part);
    k_scanB<<<512, 512>>>(off, part, cur);
    k_place<<<E_ / BT, BT>>>(adj, ebi, cur, srcl);

    GP g{};
    g.emb = emb; g.types = types; g.coords = coords; g.maskB = maskB;

    // 5: input layer  (ncu -s 5 captures this GEMM)
    g.A1 = 0; g.A2 = 0; g.Wt = wt + O_WIN; g.bias = b_in; g.C = h;
    g.K = 67; g.Kpad = 96; g.relu = 1; g.use_mask = 1;
    k_gemm_tc<2><<<GB, 128, SMEM_GEMM>>>(g);

    const float* mWt[2] = {wt + O_MSG0, wt + O_MSG1};
    const float* uWt[2] = {wt + O_UPD0, wt + O_UPD1};
    for (int l = 0; l < L_; l++) {
        // msg_all = relu(h @ msg_W + msg_b)
        g.A1 = h; g.A2 = 0; g.Wt = mWt[l]; g.bias = msg_b + l * 128; g.C = b1;
        g.K = 128; g.Kpad = 128; g.relu = 1; g.use_mask = 0;
        k_gemm_tc<0><<<GB, 128, SMEM_GEMM>>>(g);
        // agg = segment_sum via CSR gather (no zero, no atomics on data)
        k_gather<<<BN_ / 8, BT>>>(b1, off, srcl, b2);
        // h = relu([h|agg] @ upd_W + upd_b) * vf
        g.A1 = h; g.A2 = b2; g.Wt = uWt[l]; g.bias = upd_b + l * 128; g.C = h;
        g.K = 256; g.Kpad = 256; g.relu = 1; g.use_mask = 1;
        k_gemm_tc<1><<<GB, 128, SMEM_GEMM>>>(g);
    }

    // 12: fused coupling (dual GEMM + final epilogue)
    CP c{};
    c.A1 = h; c.coords = coords;
    c.Wse = wt + O_WSE; c.Whe = wt + O_WHE;
    c.bse = wt + O_BSE; c.bhe = wt + O_BHE;
    c.Ws2 = Ws2; c.bs2 = bs2; c.Wh2 = Wh2; c.bh2 = bh2;
    c.maskB = maskB; c.out = out; c.logdet = logdet;
    k_gemm_cpl<<<GB, 128, SMEM_CPL>>>(c);
}

// round 9
// speedup vs baseline: 3.6502x; 1.1781x over previous
#include <cuda_runtime.h>
#include <cstdint>
#include <math.h>
#include <stddef.h>

// Problem constants
#define B_   32
#define N_   8192
#define E_   1048576
#define BN_  (B_ * N_)          // 262144
#define L_   2

// ---------------------------------------------------------------------------
// Arch-feature gate (tcgen05 only exists on sm_100a/sm_103a passes)
// ---------------------------------------------------------------------------
#if defined(__CUDA_ARCH_FEAT_SM103_ALL) || defined(__CUDA_ARCH_FEAT_SM100_ALL)
#  define TC_AVAIL 1
#endif
#ifndef TC_AVAIL
#  ifdef __CUDA_ARCH_HAS_FEATURE__
#    if __CUDA_ARCH_HAS_FEATURE__(SM103_ALL) || __CUDA_ARCH_HAS_FEATURE__(SM100_ALL)
#      define TC_AVAIL 1
#    endif
#  endif
#endif
#ifndef TC_AVAIL
#  define TC_AVAIL 0
#endif

// ---------------------------------------------------------------------------
// Scratch (static device globals)
// ---------------------------------------------------------------------------
static __device__ float g_h   [(size_t)BN_ * 128];
static __device__ float g_b1  [(size_t)BN_ * 128];   // msg_all
static __device__ float g_b2  [(size_t)BN_ * 128];   // agg
static __device__ float g_wt  [167936];              // packed weights
static __device__ int   g_off [BN_ + 1];             // CSR offsets (also deg)
static __device__ int   g_part[512];                 // scan partials
static __device__ int   g_cur [BN_];                 // placement cursors
static __device__ int   g_srcl[E_];                  // CSR src list

// g_wt float offsets
#define O_WIN   0        // Kpad 96
#define O_MSG0  12288    // 128x128
#define O_MSG1  28672
#define O_UPD0  45056    // 128x256
#define O_UPD1  77824
#define O_WSE   110592   // 128x160 fused coupling (scale)
#define O_WHE   131072   // 128x160 fused coupling (shift)
#define O_BSE   151552   // 128
#define O_BHE   151680   // 128

// ---------------------------------------------------------------------------
// Helpers
// ---------------------------------------------------------------------------
__device__ __forceinline__ uint32_t smem_u32(const void* p) {
    uint32_t a;
    asm("{ .reg .u64 t; cvta.to.shared.u64 t, %1; cvt.u32.u64 %0, t; }"
        : "=r"(a) : "l"(p));
    return a;
}

#define SW128(o) ((o) ^ (((o) >> 3) & 0x70))

#if TC_AVAIL
__device__ __forceinline__ uint64_t mk_desc(uint32_t addr) {
    // SW128, version=1 (Blackwell), LBO=1, SBO=64 (K-major)
    const uint64_t BASE = (2ULL << 61) | (1ULL << 46) | (64ULL << 32) | (1ULL << 16);
    return BASE | ((uint64_t)(addr >> 4) & 0x3FFF);
}

// idesc: acc=F32(1<<4), atype=TF32(2<<7), btype=TF32(2<<10), N=128, M=128
#define IDESC_TF32 ((1u << 4) | (2u << 7) | (2u << 10) | ((128u/8u) << 17) | ((128u/16u) << 24))

__device__ __forceinline__ void mma_tf32_ss(uint32_t d, uint64_t a, uint64_t b,
                                            uint32_t en) {
    asm volatile(
        "{\n\t.reg .pred p;\n\t"
        "setp.ne.u32 p, %4, 0;\n\t"
        "tcgen05.mma.cta_group::1.kind::tf32 [%0], %1, %2, %3, p;\n\t}"
        :: "r"(d), "l"(a), "l"(b), "r"(IDESC_TF32), "r"(en) : "memory");
}

__device__ __forceinline__ void tc_commit(uint32_t mbar) {
    asm volatile(
        "tcgen05.commit.cta_group::1.mbarrier::arrive::one.shared::cluster.b64 [%0];"
        :: "r"(mbar) : "memory");
}

#define TC_LD_X32(r, addr)                                                     \
    asm volatile(                                                              \
        "tcgen05.ld.sync.aligned.32x32b.x32.b32 "                              \
        "{%0, %1, %2, %3, %4, %5, %6, %7, "                                    \
        " %8, %9, %10, %11, %12, %13, %14, %15, "                              \
        " %16, %17, %18, %19, %20, %21, %22, %23, "                            \
        " %24, %25, %26, %27, %28, %29, %30, %31}, [%32];"                     \
        : "=r"((r)[0]),  "=r"((r)[1]),  "=r"((r)[2]),  "=r"((r)[3]),           \
          "=r"((r)[4]),  "=r"((r)[5]),  "=r"((r)[6]),  "=r"((r)[7]),           \
          "=r"((r)[8]),  "=r"((r)[9]),  "=r"((r)[10]), "=r"((r)[11]),          \
          "=r"((r)[12]), "=r"((r)[13]), "=r"((r)[14]), "=r"((r)[15]),          \
          "=r"((r)[16]), "=r"((r)[17]), "=r"((r)[18]), "=r"((r)[19]),          \
          "=r"((r)[20]), "=r"((r)[21]), "=r"((r)[22]), "=r"((r)[23]),          \
          "=r"((r)[24]), "=r"((r)[25]), "=r"((r)[26]), "=r"((r)[27]),          \
          "=r"((r)[28]), "=r"((r)[29]), "=r"((r)[30]), "=r"((r)[31])           \
        : "r"(addr))
#endif  // TC_AVAIL

__device__ __forceinline__ void mbar_init(uint32_t a, uint32_t cnt) {
    asm volatile("mbarrier.init.shared.b64 [%0], %1;" :: "r"(a), "r"(cnt) : "memory");
}
__device__ __forceinline__ void mbar_wait(uint32_t a, uint32_t parity) {
    asm volatile(
        "{\n\t.reg .pred P;\n"
        "WL%=:\n\t"
        "mbarrier.try_wait.parity.acquire.cta.shared::cta.b64 P, [%0], %1, 0x989680;\n\t"
        "@P bra WD%=;\n\t"
        "bra WL%=;\n"
        "WD%=:\n\t}"
        :: "r"(a), "r"(parity) : "memory");
}

// ---------------------------------------------------------------------------
// k_prep: weight transposes, fused coupling weight products, zeros.
// ---------------------------------------------------------------------------
__global__ void k_prep(const float* __restrict__ W_in,
                       const float* __restrict__ msg_W,
                       const float* __restrict__ upd_W,
                       const float* __restrict__ W_out,
                       const float* __restrict__ Ws1,
                       const float* __restrict__ Wh1,
                       const float* __restrict__ bs1,
                       const float* __restrict__ bh1,
                       const float* __restrict__ b_out,
                       float* __restrict__ wt,
                       int* __restrict__ off,
                       float* __restrict__ logdet) {
    const int TOTAL = 151808 + (BN_ + 1) + 32;
    for (int idx = blockIdx.x * blockDim.x + threadIdx.x; idx < TOTAL;
         idx += gridDim.x * blockDim.x) {
        if (idx < 12288) {                       // W_in^T, K=67 pad 96
            int n = idx / 96, k = idx - n * 96;
            wt[idx] = (k < 67) ? W_in[k * 128 + n] : 0.f;
        } else if (idx < 45056) {                // msg_W^T x2
            int j = idx - 12288;
            int l = j >> 14, r = j & 16383;
            int n = r >> 7, k = r & 127;
            wt[idx] = msg_W[l * 16384 + k * 128 + n];
        } else if (idx < 110592) {               // upd_W^T x2 (K=256)
            int j = idx - 45056;
            int l = j >> 15, r = j & 32767;
            int n = r >> 8, k = r & 255;
            wt[idx] = upd_W[l * 32768 + k * 128 + n];
        } else if (idx < 131072) {               // Wse_t
            int j = idx - 110592;
            int n = j / 160, k = j - n * 160;
            float v = 0.f;
            if (k < 128) {
                for (int q = 0; q < 128; q++)
                    v = fmaf(W_out[k * 128 + q], Ws1[q * 128 + n], v);
            } else if (k < 131) {
                v = Ws1[k * 128 + n];
            }
            wt[idx] = v;
        } else if (idx < 151552) {               // Whe_t
            int j = idx - 131072;
            int n = j / 160, k = j - n * 160;
            float v = 0.f;
            if (k < 128) {
                for (int q = 0; q < 128; q++)
                    v = fmaf(W_out[k * 128 + q], Wh1[q * 128 + n], v);
            } else if (k < 131) {
                v = Wh1[k * 128 + n];
            }
            wt[idx] = v;
        } else if (idx < 151680) {               // bse
            int n = idx - 151552;
            float v = bs1[n];
            for (int q = 0; q < 128; q++)
                v = fmaf(b_out[q], Ws1[q * 128 + n], v);
            wt[idx] = v;
        } else if (idx < 151808) {               // bhe
            int n = idx - 151680;
            float v = bh1[n];
            for (int q = 0; q < 128; q++)
                v = fmaf(b_out[q], Wh1[q * 128 + n], v);
            wt[idx] = v;
        } else if (idx < 151808 + BN_ + 1) {     // zero deg/offsets
            off[idx - 151808] = 0;
        } else {                                 // zero logdet
            logdet[idx - (151808 + BN_ + 1)] = 0.f;
        }
    }
}

// ---------------------------------------------------------------------------
// CSR build: hist -> scanA -> scanB -> place
// ---------------------------------------------------------------------------
__global__ void k_hist(const int* __restrict__ adj, const int* __restrict__ ebi,
                       int* __restrict__ deg) {
    int e = blockIdx.x * blockDim.x + threadIdx.x;
    if (e >= E_) return;
    int dst = ebi[e] * N_ + adj[2 * e + 1];
    atomicAdd(&deg[dst], 1);
}

__global__ void k_scanA(int* __restrict__ off, int* __restrict__ part) {
    __shared__ int s[512];
    int t = threadIdx.x;
    int i = blockIdx.x * 512 + t;
    int v = off[i];
    s[t] = v; __syncthreads();
    for (int d = 1; d < 512; d <<= 1) {
        int x = (t >= d) ? s[t - d] : 0;
        __syncthreads();
        s[t] += x;
        __syncthreads();
    }
    off[i] = s[t] - v;                 // exclusive within chunk
    if (t == 511) part[blockIdx.x] = s[t];
}

__global__ void k_scanB(int* __restrict__ off, const int* __restrict__ part,
                        int* __restrict__ cur) {
    __shared__ int s[512];
    int t = threadIdx.x, b = blockIdx.x;
    s[t] = part[t]; __syncthreads();
    for (int d = 1; d < 512; d <<= 1) {
        int x = (t >= d) ? s[t - d] : 0;
        __syncthreads();
        s[t] += x;
        __syncthreads();
    }
    int prefix = (b == 0) ? 0 : s[b - 1];
    int i = b * 512 + t;
    int v = off[i] + prefix;
    off[i] = v;
    cur[i] = v;
    if (b == 0 && t == 0) off[BN_] = E_;
}

__global__ void k_place(const int* __restrict__ adj, const int* __restrict__ ebi,
                        int* __restrict__ cur, int* __restrict__ srcl) {
    int e = blockIdx.x * blockDim.x + threadIdx.x;
    if (e >= E_) return;
    int b = ebi[e];
    int src = b * N_ + adj[2 * e];
    int dst = b * N_ + adj[2 * e + 1];
    int pos = atomicAdd(&cur[dst], 1);
    srcl[pos] = src;
}

// ---------------------------------------------------------------------------
// Gather: agg[d] = sum over incident edges of msg[src]. One warp per node.
// ---------------------------------------------------------------------------
__global__ void k_gather(const float* __restrict__ msg,
                         const int* __restrict__ off,
                         const int* __restrict__ srcl,
                         float* __restrict__ agg) {
    int warp = (blockIdx.x * blockDim.x + threadIdx.x) >> 5;
    int lane = threadIdx.x & 31;
    int s0 = off[warp], s1 = off[warp + 1];
    float4 acc = make_float4(0.f, 0.f, 0.f, 0.f);
    for (int j = s0; j < s1; j++) {
        int s = srcl[j];
        float4 v = *((const float4*)(msg + (size_t)s * 128) + lane);
        acc.x += v.x; acc.y += v.y; acc.z += v.z; acc.w += v.w;
    }
    *((float4*)(agg + (size_t)warp * 128) + lane) = acc;
}

// ---------------------------------------------------------------------------
// GEMM core. 256 threads/CTA, M-tile 128, N=128, 2-stage ring, K chunks of 32.
// MODE: 0=direct(lda128) 1=concat(h|agg) 2=embed-gather 3=feat(h|masked coords)
// ---------------------------------------------------------------------------
#define NSTAGE       2
#define STAGE_BYTES  32768            // 16KB A + 16KB W
#define SMEM_GEMM    (1024 + NSTAGE * STAGE_BYTES)

struct GP {
    const float* A1; const float* A2;
    const float* emb; const int* types; const float* coords;
    const float* Wt; const float* bias;
    const unsigned char* maskB;
    float* C;
    int K; int Kpad; int relu; int use_mask;
};

template<int MODE>
__device__ __forceinline__ float4 loadA4(const GP& g, int gr, int k) {
    if (MODE == 0) {                       // direct, K = 128
        return *(const float4*)(g.A1 + (size_t)gr * 128 + k);
    } else if (MODE == 1) {                // concat [h | agg], K = 256
        if (k < 128) return *(const float4*)(g.A1 + (size_t)gr * 128 + k);
        return *(const float4*)(g.A2 + (size_t)gr * 128 + (k - 128));
    } else if (MODE == 2) {                // [embed[types] | coords], K = 67
        int t = g.types[gr];
        if (k + 3 < 64) return *(const float4*)(g.emb + t * 64 + k);
        float4 v; float* vp = &v.x;
#pragma unroll
        for (int i = 0; i < 4; i++) {
            int kk = k + i; float x;
            if (kk < 64)      x = g.emb[t * 64 + kk];
            else if (kk < 67) x = g.coords[gr * 3 + (kk - 64)];
            else              x = 0.f;
            vp[i] = x;
        }
        return v;
    } else {                               // [h | cond_coords], K = 131
        if (k + 3 < 128) return *(const float4*)(g.A1 + (size_t)gr * 128 + k);
        bool cm = ((gr & 1) == 0) && (g.maskB[gr] == 0);   // PHASE=0
        float4 v; float* vp = &v.x;
#pragma unroll
        for (int i = 0; i < 4; i++) {
            int kk = k + i; float x;
            if (kk < 128)      x = g.A1[(size_t)gr * 128 + kk];
            else if (kk < 131) x = cm ? 0.f : g.coords[gr * 3 + (kk - 128)];
            else               x = 0.f;
            vp[i] = x;
        }
        return v;
    }
}

template<int MODE>
__global__ void __launch_bounds__(256) k_gemm_tc(GP g) {
#if TC_AVAIL
    extern __shared__ __align__(1024) char smem[];
    const uint32_t sb = smem_u32(smem);
    const int tid = threadIdx.x;
    const int wid = tid >> 5;
    const int lid = tid & 31;
    const int block_row = blockIdx.x * 128;

    if (wid == 0) {
        asm volatile(
            "tcgen05.alloc.cta_group::1.sync.aligned.shared::cta.b32 [%0], %1;"
            :: "r"(sb), "r"(128u) : "memory");
        asm volatile("tcgen05.relinquish_alloc_permit.cta_group::1.sync.aligned;");
    }
    if (tid == 0) {
#pragma unroll
        for (int s = 0; s < NSTAGE; s++) mbar_init(sb + 8 + s * 8, 1);
    }
    __syncthreads();
    uint32_t tmem;
    asm volatile("ld.shared.b32 %0, [%1];" : "=r"(tmem) : "r"(sb));

    const int nt = g.Kpad / 32;

    for (int t = 0; t < nt; t++) {
        const int b = t & (NSTAGE - 1);
        if (t >= NSTAGE) mbar_wait(sb + 8 + b * 8, ((t >> 1) - 1) & 1);

        char* bufA = smem + 1024 + b * STAGE_BYTES;
        char* bufW = bufA + 16384;
        // 256 threads: 4 A-float4 + 4 W-float4 each
#pragma unroll
        for (int it = 0; it < 4; it++) {
            int idx = tid + it * 256;         // 0..1023
            int r   = idx >> 3;
            int c4  = idx & 7;
            int k   = t * 32 + c4 * 4;
            float4 av = (k < g.K) ? loadA4<MODE>(g, block_row + r, k)
                                  : make_float4(0.f, 0.f, 0.f, 0.f);
            float4 wv = *(const float4*)(g.Wt + (size_t)r * g.Kpad + k);
            uint32_t off = SW128((uint32_t)(r * 128 + c4 * 16));
            *(float4*)(bufA + off) = av;
            *(float4*)(bufW + off) = wv;
        }
        __syncthreads();

        if (tid == 0) {
            asm volatile("fence.proxy.async.shared::cta;" ::: "memory");
            uint64_t ad = mk_desc(sb + 1024 + b * STAGE_BYTES);
            uint64_t bd = mk_desc(sb + 1024 + b * STAGE_BYTES + 16384);
#pragma unroll
            for (int j = 0; j < 4; j++)
                mma_tf32_ss(tmem, ad + j * 2, bd + j * 2,
                            (t > 0 || j > 0) ? 1u : 0u);
            tc_commit(sb + 8 + b * 8);
        }
    }

    mbar_wait(sb + 8 + ((nt - 1) & (NSTAGE - 1)) * 8, ((nt - 1) >> 1) & 1);
    asm volatile("tcgen05.fence::after_thread_sync;" ::: "memory");

    // epilogue: 8 warps. warp w -> TMEM subpartition (w&3) [rows], col half w>>2.
    const int rg = wid & 3;
    const int ch = wid >> 2;
    const int m  = block_row + rg * 32 + lid;
    const bool masked = g.use_mask && (g.maskB[m] != 0);
#pragma unroll
    for (int half = 0; half < 2; half++) {
        int cb = ch * 64 + half * 32;
        uint32_t r32[32];
        TC_LD_X32(r32, tmem + cb);
        asm volatile("tcgen05.wait::ld.sync.aligned;" ::: "memory");
#pragma unroll
        for (int j = 0; j < 32; j += 4) {
            float4 o;
            float* op = &o.x;
#pragma unroll
            for (int i = 0; i < 4; i++) {
                float v = __uint_as_float(r32[j + i]) + g.bias[cb + j + i];
                if (g.relu) v = fmaxf(v, 0.f);
                if (masked) v = 0.f;
                op[i] = v;
            }
            *(float4*)(g.C + (size_t)m * 128 + cb + j) = o;
        }
    }

    __syncthreads();
    if (wid == 0) {
        asm volatile("tcgen05.dealloc.cta_group::1.sync.aligned.b32 %0, %1;"
                     :: "r"(tmem), "r"(128u));
    }
#else
    // Scalar fallback for non-sm_103a passes (never runs on GB300).
    if (threadIdx.x >= 128) return;
    const int row = blockIdx.x * 128 + threadIdx.x;
    const bool masked = g.use_mask && (g.maskB[row] != 0);
#pragma unroll 1
    for (int cb = 0; cb < 128; cb += 4) {
        float acc[4] = {0.f, 0.f, 0.f, 0.f};
        for (int k = 0; k < g.K; k += 4) {
            float4 a = loadA4<MODE>(g, row, k);
            const float* ap = &a.x;
#pragma unroll
            for (int c = 0; c < 4; c++) {
                const float* wr = g.Wt + (size_t)(cb + c) * g.Kpad + k;
#pragma unroll
                for (int i = 0; i < 4; i++)
                    acc[c] = fmaf(ap[i], wr[i], acc[c]);
            }
        }
#pragma unroll
        for (int c = 0; c < 4; c++) {
            float v = acc[c] + g.bias[cb + c];
            if (g.relu) v = fmaxf(v, 0.f);
            if (masked) v = 0.f;
            g.C[(size_t)row * 128 + cb + c] = v;
        }
    }
#endif
}

// ---------------------------------------------------------------------------
// Coupling dual GEMM + fused final epilogue (128 threads; one launch).
// ---------------------------------------------------------------------------
#define CPL_HDR      8192
#define CPL_STAGE    49152           // 16KB A + 16KB Ws + 16KB Wh
#define SMEM_CPL     (CPL_HDR + NSTAGE * CPL_STAGE)

struct CP {
    const float* A1; const float* coords;
    const float* Wse; const float* Whe;
    const float* bse; const float* bhe;
    const float* Ws2; const float* bs2;
    const float* Wh2; const float* bh2;
    const unsigned char* maskB;
    float* out; float* logdet;
};

__global__ void __launch_bounds__(128) k_gemm_cpl(CP g) {
#if TC_AVAIL
    extern __shared__ __align__(1024) char smem[];
    const uint32_t sb = smem_u32(smem);
    float* smf = (float*)smem;
    const int tid = threadIdx.x;
    const int wid = tid >> 5;
    const int lid = tid & 31;
    const int block_row = blockIdx.x * 128;

    if (wid == 0) {
        asm volatile(
            "tcgen05.alloc.cta_group::1.sync.aligned.shared::cta.b32 [%0], %1;"
            :: "r"(sb), "r"(256u) : "memory");
        asm volatile("tcgen05.relinquish_alloc_permit.cta_group::1.sync.aligned;");
    }
    if (tid == 0) {
#pragma unroll
        for (int s = 0; s < NSTAGE; s++) mbar_init(sb + 8 + s * 8, 1);
    }
    for (int i = tid; i < 384; i += 128) {
        smf[16 + i]  = g.Ws2[i];
        smf[400 + i] = g.Wh2[i];
    }
    smf[784 + tid] = g.bse[tid];
    smf[912 + tid] = g.bhe[tid];
    __syncthreads();
    uint32_t tmem;
    asm volatile("ld.shared.b32 %0, [%1];" : "=r"(tmem) : "r"(sb));

    const int nt = 5;                   // Kpad 160

    GP ga{};
    ga.A1 = g.A1; ga.coords = g.coords; ga.maskB = g.maskB; ga.K = 131;

    for (int t = 0; t < nt; t++) {
        const int b = t & (NSTAGE - 1);
        if (t >= NSTAGE) mbar_wait(sb + 8 + b * 8, ((t >> 1) - 1) & 1);

        char* base = smem + CPL_HDR + b * CPL_STAGE;
#pragma unroll
        for (int it = 0; it < 24; it++) {
            int idx = tid + it * 128;            // 0..3071
            int sec = idx >> 10;                 // 0=A 1=Ws 2=Wh
            int w   = idx & 1023;
            int r   = w >> 3;
            int c4  = w & 7;
            int k   = t * 32 + c4 * 4;
            float4 v;
            if (sec == 0)
                v = (k < 131) ? loadA4<3>(ga, block_row + r, k)
                              : make_float4(0.f, 0.f, 0.f, 0.f);
            else if (sec == 1)
                v = *(const float4*)(g.Wse + (size_t)r * 160 + k);
            else
                v = *(const float4*)(g.Whe + (size_t)r * 160 + k);
            uint32_t off = SW128((uint32_t)(r * 128 + c4 * 16));
            *(float4*)(base + sec * 16384 + off) = v;
        }
        __syncthreads();

        if (tid == 0) {
            asm volatile("fence.proxy.async.shared::cta;" ::: "memory");
            uint32_t stage = sb + CPL_HDR + b * CPL_STAGE;
            uint64_t ad = mk_desc(stage);
            uint64_t sd = mk_desc(stage + 16384);
            uint64_t hd = mk_desc(stage + 32768);
            uint32_t en0 = (t > 0) ? 1u : 0u;
#pragma unroll
            for (int j = 0; j < 4; j++) {
                uint32_t en = (j > 0) ? 1u : en0;
                mma_tf32_ss(tmem,       ad + j * 2, sd + j * 2, en);
                mma_tf32_ss(tmem + 128, ad + j * 2, hd + j * 2, en);
            }
            tc_commit(sb + 8 + b * 8);
        }
    }

    mbar_wait(sb + 8 + ((nt - 1) & (NSTAGE - 1)) * 8, ((nt - 1) >> 1) & 1);
    asm volatile("tcgen05.fence::after_thread_sync;" ::: "memory");

    const int m = block_row + wid * 32 + lid;
    float raw[3] = {0.f, 0.f, 0.f};
    float shf[3] = {0.f, 0.f, 0.f};
#pragma unroll
    for (int cb = 0; cb < 128; cb += 32) {
        uint32_t rs[32], rh[32];
        TC_LD_X32(rs, tmem + cb);
        TC_LD_X32(rh, tmem + 128 + cb);
        asm volatile("tcgen05.wait::ld.sync.aligned;" ::: "memory");
#pragma unroll
        for (int k = 0; k < 32; k++) {
            int col = cb + k;
            float sv = fmaxf(__uint_as_float(rs[k]) + smf[784 + col], 0.f);
            float hv = fmaxf(__uint_as_float(rh[k]) + smf[912 + col], 0.f);
#pragma unroll
            for (int c = 0; c < 3; c++) {
                raw[c] = fmaf(sv, smf[16 + col * 3 + c],  raw[c]);
                shf[c] = fmaf(hv, smf[400 + col * 3 + c], shf[c]);
            }
        }
    }

    bool cm = ((m & 1) == 0) && (g.maskB[m] == 0);   // PHASE = 0
    float ld = 0.f;
#pragma unroll
    for (int c = 0; c < 3; c++) {
        float r = raw[c] + g.bs2[c];
        float s = shf[c] + g.bh2[c];
        float ls = cm ? tanhf(r) * 2.f : 0.f;
        ld += ls;
        float coord = g.coords[m * 3 + c];
        g.out[m * 3 + c] = cm ? (expf(ls) * coord + s) : coord;
    }
#pragma unroll
    for (int o = 16; o > 0; o >>= 1)
        ld += __shfl_xor_sync(0xFFFFFFFFu, ld, o);
    if (lid == 0) atomicAdd(&g.logdet[m >> 13], ld);

    __syncthreads();
    if (wid == 0) {
        asm volatile("tcgen05.dealloc.cta_group::1.sync.aligned.b32 %0, %1;"
                     :: "r"(tmem), "r"(256u));
    }
#else
    // Scalar fallback (never runs on GB300).
    const int m = blockIdx.x * 128 + threadIdx.x;
    bool cm = ((m & 1) == 0) && (g.maskB[m] == 0);
    float raw[3], shf[3];
#pragma unroll
    for (int c = 0; c < 3; c++) { raw[c] = g.bs2[c]; shf[c] = g.bh2[c]; }
    for (int n = 0; n < 128; n++) {
        float accs = g.bse[n], acch = g.bhe[n];
        for (int k = 0; k < 128; k++) {
            float a = g.A1[(size_t)m * 128 + k];
            accs = fmaf(a, g.Wse[n * 160 + k], accs);
            acch = fmaf(a, g.Whe[n * 160 + k], acch);
        }
        for (int k = 128; k < 131; k++) {
            float a = cm ? 0.f : g.coords[m * 3 + (k - 128)];
            accs = fmaf(a, g.Wse[n * 160 + k], accs);
            acch = fmaf(a, g.Whe[n * 160 + k], acch);
        }
        accs = fmaxf(accs, 0.f); acch = fmaxf(acch, 0.f);
#pragma unroll
        for (int c = 0; c < 3; c++) {
            raw[c] = fmaf(accs, g.Ws2[n * 3 + c], raw[c]);
            shf[c] = fmaf(acch, g.Wh2[n * 3 + c], shf[c]);
        }
    }
    float ld = 0.f;
#pragma unroll
    for (int c = 0; c < 3; c++) {
        float ls = cm ? tanhf(raw[c]) * 2.f : 0.f;
        ld += ls;
        float coord = g.coords[m * 3 + c];
        g.out[m * 3 + c] = cm ? (expf(ls) * coord + shf[c]) : coord;
    }
    atomicAdd(&g.logdet[m >> 13], ld);
#endif
}

// ---------------------------------------------------------------------------
// Host launcher. Launch order tuned so ncu (-s 5 -c 1, empirical offset:
// profiled = 4th launch) captures the K=128 msg GEMM at index 3.
// ---------------------------------------------------------------------------
extern "C" void kernel_launch(void* const* d_in, const int* in_sizes, int n_in,
                              void* d_out, int out_size) {
    const float*         coords = (const float*)d_in[0];
    const int*           types  = (const int*)  d_in[1];
    const int*           adj    = (const int*)  d_in[2];
    const int*           ebi    = (const int*)  d_in[3];
    const unsigned char* maskB  = (const unsigned char*)d_in[4];
    const float* emb   = (const float*)d_in[5];
    const float* W_in  = (const float*)d_in[6];
    const float* b_in  = (const float*)d_in[7];
    const float* msg_W = (const float*)d_in[8];
    const float* msg_b = (const float*)d_in[9];
    const float* upd_W = (const float*)d_in[10];
    const float* upd_b = (const float*)d_in[11];
    const float* W_out = (const float*)d_in[12];
    const float* b_out = (const float*)d_in[13];
    const float* Ws1   = (const float*)d_in[14];
    const float* bs1   = (const float*)d_in[15];
    const float* Ws2   = (const float*)d_in[16];
    const float* bs2   = (const float*)d_in[17];
    const float* Wh1   = (const float*)d_in[18];
    const float* bh1   = (const float*)d_in[19];
    const float* Wh2   = (const float*)d_in[20];
    const float* bh2   = (const float*)d_in[21];

    float* out    = (float*)d_out;
    float* logdet = out + (size_t)BN_ * 3;

    float *h, *b1, *b2, *wt;
    int *off, *part, *cur, *srcl;
    cudaGetSymbolAddress((void**)&h,    g_h);
    cudaGetSymbolAddress((void**)&b1,   g_b1);
    cudaGetSymbolAddress((void**)&b2,   g_b2);
    cudaGetSymbolAddress((void**)&wt,   g_wt);
    cudaGetSymbolAddress((void**)&off,  g_off);
    cudaGetSymbolAddress((void**)&part, g_part);
    cudaGetSymbolAddress((void**)&cur,  g_cur);
    cudaGetSymbolAddress((void**)&srcl, g_srcl);

    cudaFuncSetAttribute(k_gemm_tc<0>, cudaFuncAttributeMaxDynamicSharedMemorySize, SMEM_GEMM);
    cudaFuncSetAttribute(k_gemm_tc<1>, cudaFuncAttributeMaxDynamicSharedMemorySize, SMEM_GEMM);
    cudaFuncSetAttribute(k_gemm_tc<2>, cudaFuncAttributeMaxDynamicSharedMemorySize, SMEM_GEMM);
    cudaFuncSetAttribute(k_gemm_cpl,   cudaFuncAttributeMaxDynamicSharedMemorySize, SMEM_CPL);

    const int BT = 256;
    const int GB = BN_ / 128;   // 2048 CTAs per GEMM

    GP g{};
    g.emb = emb; g.types = types; g.coords = coords; g.maskB = maskB;

    // 0: prep
    k_prep<<<512, BT>>>(W_in, msg_W, upd_W, W_out, Ws1, Wh1, bs1, bh1, b_out,
                        wt, off, logdet);
    // 1: hist (CSR step 1)
    k_hist <<<E_ / BT, BT>>>(adj, ebi, off);
    // 2: input layer
    g.A1 = 0; g.A2 = 0; g.Wt = wt + O_WIN; g.bias = b_in; g.C = h;
    g.K = 67; g.Kpad = 96; g.relu = 1; g.use_mask = 1;
    k_gemm_tc<2><<<GB, 256, SMEM_GEMM>>>(g);
    // 3: msg GEMM layer 0  <-- ncu profile target
    g.A1 = h; g.A2 = 0; g.Wt = wt + O_MSG0; g.bias = msg_b; g.C = b1;
    g.K = 128; g.Kpad = 128; g.relu = 1; g.use_mask = 0;
    k_gemm_tc<0><<<GB, 256, SMEM_GEMM>>>(g);
    // 4-6: finish CSR
    k_scanA<<<512, 512>>>(off, part);
    k_scanB<<<512, 512>>>(off, part, cur);
    k_place<<<E_ / BT, BT>>>(adj, ebi, cur, srcl);
    // 7: gather layer 0
    k_gather<<<BN_ / 8, BT>>>(b1, off, srcl, b2);
    // 8: upd layer 0
    g.A1 = h; g.A2 = b2; g.Wt = wt + O_UPD0; g.bias = upd_b; g.C = h;
    g.K = 256; g.Kpad = 256; g.relu = 1; g.use_mask = 1;
    k_gemm_tc<1><<<GB, 256, SMEM_GEMM>>>(g);
    // 9: msg GEMM layer 1
    g.A1 = h; g.A2 = 0; g.Wt = wt + O_MSG1; g.bias = msg_b + 128; g.C = b1;
    g.K = 128; g.Kpad = 128; g.relu = 1; g.use_mask = 0;
    k_gemm_tc<0><<<GB, 256, SMEM_GEMM>>>(g);
    // 10: gather layer 1
    k_gather<<<BN_ / 8, BT>>>(b1, off, srcl, b2);
    // 11: upd layer 1
    g.A1 = h; g.A2 = b2; g.Wt = wt + O_UPD1; g.bias = upd_b + 128; g.C = h;
    g.K = 256; g.Kpad = 256; g.relu = 1; g.use_mask = 1;
    k_gemm_tc<1><<<GB, 256, SMEM_GEMM>>>(g);

    // 12: fused coupling (dual GEMM + final epilogue)
    CP c{};
    c.A1 = h; c.coords = coords;
    c.Wse = wt + O_WSE; c.Whe = wt + O_WHE;
    c.bse = wt + O_BSE; c.bhe = wt + O_BHE;
    c.Ws2 = Ws2; c.bs2 = bs2; c.Wh2 = Wh2; c.bh2 = bh2;
    c.maskB = maskB; c.out = out; c.logdet = logdet;
    k_gemm_cpl<<<GB, 128, SMEM_CPL>>>(c);
}

// round 10
// speedup vs baseline: 4.2531x; 1.1652x over previous
#include <cuda_runtime.h>
#include <cstdint>
#include <math.h>
#include <stddef.h>

// Problem constants
#define B_   32
#define N_   8192
#define E_   1048576
#define BN_  (B_ * N_)          // 262144
#define L_   2

// ---------------------------------------------------------------------------
// Arch-feature gate (tcgen05 only exists on sm_100a/sm_103a passes)
// ---------------------------------------------------------------------------
#if defined(__CUDA_ARCH_FEAT_SM103_ALL) || defined(__CUDA_ARCH_FEAT_SM100_ALL)
#  define TC_AVAIL 1
#endif
#ifndef TC_AVAIL
#  ifdef __CUDA_ARCH_HAS_FEATURE__
#    if __CUDA_ARCH_HAS_FEATURE__(SM103_ALL) || __CUDA_ARCH_HAS_FEATURE__(SM100_ALL)
#      define TC_AVAIL 1
#    endif
#  endif
#endif
#ifndef TC_AVAIL
#  define TC_AVAIL 0
#endif

// ---------------------------------------------------------------------------
// Scratch (static device globals)
// ---------------------------------------------------------------------------
static __device__ float g_h   [(size_t)BN_ * 128];
static __device__ float g_b1  [(size_t)BN_ * 128];   // msg_all
static __device__ float g_b2  [(size_t)BN_ * 128];   // agg
static __device__ float g_wt  [167936];              // packed weights
static __device__ int   g_off [BN_ + 1];             // CSR offsets (also deg)
static __device__ int   g_part[512];                 // scan partials
static __device__ int   g_cur [BN_];                 // placement cursors
static __device__ int   g_srcl[E_];                  // CSR src list

// g_wt float offsets
#define O_WIN   0        // Kpad 96
#define O_MSG0  12288    // 128x128
#define O_MSG1  28672
#define O_UPD0  45056    // 128x256
#define O_UPD1  77824
#define O_WSE   110592   // 128x160 fused coupling (scale)
#define O_WHE   131072   // 128x160 fused coupling (shift)
#define O_BSE   151552   // 128
#define O_BHE   151680   // 128

// ---------------------------------------------------------------------------
// Helpers
// ---------------------------------------------------------------------------
__device__ __forceinline__ uint32_t smem_u32(const void* p) {
    uint32_t a;
    asm("{ .reg .u64 t; cvta.to.shared.u64 t, %1; cvt.u32.u64 %0, t; }"
        : "=r"(a) : "l"(p));
    return a;
}

#define SW128(o) ((o) ^ (((o) >> 3) & 0x70))

__device__ __forceinline__ void cp16(uint32_t dst, const void* src) {
    asm volatile("cp.async.cg.shared.global [%0], [%1], 16;"
                 :: "r"(dst), "l"(src) : "memory");
}
__device__ __forceinline__ void cp_commit() {
    asm volatile("cp.async.commit_group;" ::: "memory");
}
__device__ __forceinline__ void cp_wait1() {
    asm volatile("cp.async.wait_group 1;" ::: "memory");
}
__device__ __forceinline__ void cp_wait0() {
    asm volatile("cp.async.wait_group 0;" ::: "memory");
}
__device__ __forceinline__ void sts4(uint32_t dst, float4 v) {
    asm volatile("st.shared.v4.f32 [%0], {%1, %2, %3, %4};"
                 :: "r"(dst), "f"(v.x), "f"(v.y), "f"(v.z), "f"(v.w) : "memory");
}

#if TC_AVAIL
__device__ __forceinline__ uint64_t mk_desc(uint32_t addr) {
    // SW128, version=1 (Blackwell), LBO=1, SBO=64 (K-major)
    const uint64_t BASE = (2ULL << 61) | (1ULL << 46) | (64ULL << 32) | (1ULL << 16);
    return BASE | ((uint64_t)(addr >> 4) & 0x3FFF);
}

// idesc: acc=F32(1<<4), atype=TF32(2<<7), btype=TF32(2<<10), N=128, M=128
#define IDESC_TF32 ((1u << 4) | (2u << 7) | (2u << 10) | ((128u/8u) << 17) | ((128u/16u) << 24))

__device__ __forceinline__ void mma_tf32_ss(uint32_t d, uint64_t a, uint64_t b,
                                            uint32_t en) {
    asm volatile(
        "{\n\t.reg .pred p;\n\t"
        "setp.ne.u32 p, %4, 0;\n\t"
        "tcgen05.mma.cta_group::1.kind::tf32 [%0], %1, %2, %3, p;\n\t}"
        :: "r"(d), "l"(a), "l"(b), "r"(IDESC_TF32), "r"(en) : "memory");
}

__device__ __forceinline__ void tc_commit(uint32_t mbar) {
    asm volatile(
        "tcgen05.commit.cta_group::1.mbarrier::arrive::one.shared::cluster.b64 [%0];"
        :: "r"(mbar) : "memory");
}

#define TC_LD_X32(r, addr)                                                     \
    asm volatile(                                                              \
        "tcgen05.ld.sync.aligned.32x32b.x32.b32 "                              \
        "{%0, %1, %2, %3, %4, %5, %6, %7, "                                    \
        " %8, %9, %10, %11, %12, %13, %14, %15, "                              \
        " %16, %17, %18, %19, %20, %21, %22, %23, "                            \
        " %24, %25, %26, %27, %28, %29, %30, %31}, [%32];"                     \
        : "=r"((r)[0]),  "=r"((r)[1]),  "=r"((r)[2]),  "=r"((r)[3]),           \
          "=r"((r)[4]),  "=r"((r)[5]),  "=r"((r)[6]),  "=r"((r)[7]),           \
          "=r"((r)[8]),  "=r"((r)[9]),  "=r"((r)[10]), "=r"((r)[11]),          \
          "=r"((r)[12]), "=r"((r)[13]), "=r"((r)[14]), "=r"((r)[15]),          \
          "=r"((r)[16]), "=r"((r)[17]), "=r"((r)[18]), "=r"((r)[19]),          \
          "=r"((r)[20]), "=r"((r)[21]), "=r"((r)[22]), "=r"((r)[23]),          \
          "=r"((r)[24]), "=r"((r)[25]), "=r"((r)[26]), "=r"((r)[27]),          \
          "=r"((r)[28]), "=r"((r)[29]), "=r"((r)[30]), "=r"((r)[31])           \
        : "r"(addr))
#endif  // TC_AVAIL

__device__ __forceinline__ void mbar_init(uint32_t a, uint32_t cnt) {
    asm volatile("mbarrier.init.shared.b64 [%0], %1;" :: "r"(a), "r"(cnt) : "memory");
}
__device__ __forceinline__ void mbar_wait(uint32_t a, uint32_t parity) {
    asm volatile(
        "{\n\t.reg .pred P;\n"
        "WL%=:\n\t"
        "mbarrier.try_wait.parity.acquire.cta.shared::cta.b64 P, [%0], %1, 0x989680;\n\t"
        "@P bra WD%=;\n\t"
        "bra WL%=;\n"
        "WD%=:\n\t}"
        :: "r"(a), "r"(parity) : "memory");
}

// ---------------------------------------------------------------------------
// k_prep: weight transposes, fused coupling weight products, zeros.
// ---------------------------------------------------------------------------
__global__ void k_prep(const float* __restrict__ W_in,
                       const float* __restrict__ msg_W,
                       const float* __restrict__ upd_W,
                       const float* __restrict__ W_out,
                       const float* __restrict__ Ws1,
                       const float* __restrict__ Wh1,
                       const float* __restrict__ bs1,
                       const float* __restrict__ bh1,
                       const float* __restrict__ b_out,
                       float* __restrict__ wt,
                       int* __restrict__ off,
                       float* __restrict__ logdet) {
    const int TOTAL = 151808 + (BN_ + 1) + 32;
    for (int idx = blockIdx.x * blockDim.x + threadIdx.x; idx < TOTAL;
         idx += gridDim.x * blockDim.x) {
        if (idx < 12288) {                       // W_in^T, K=67 pad 96
            int n = idx / 96, k = idx - n * 96;
            wt[idx] = (k < 67) ? W_in[k * 128 + n] : 0.f;
        } else if (idx < 45056) {                // msg_W^T x2
            int j = idx - 12288;
            int l = j >> 14, r = j & 16383;
            int n = r >> 7, k = r & 127;
            wt[idx] = msg_W[l * 16384 + k * 128 + n];
        } else if (idx < 110592) {               // upd_W^T x2 (K=256)
            int j = idx - 45056;
            int l = j >> 15, r = j & 32767;
            int n = r >> 8, k = r & 255;
            wt[idx] = upd_W[l * 32768 + k * 128 + n];
        } else if (idx < 131072) {               // Wse_t
            int j = idx - 110592;
            int n = j / 160, k = j - n * 160;
            float v = 0.f;
            if (k < 128) {
                for (int q = 0; q < 128; q++)
                    v = fmaf(W_out[k * 128 + q], Ws1[q * 128 + n], v);
            } else if (k < 131) {
                v = Ws1[k * 128 + n];
            }
            wt[idx] = v;
        } else if (idx < 151552) {               // Whe_t
            int j = idx - 131072;
            int n = j / 160, k = j - n * 160;
            float v = 0.f;
            if (k < 128) {
                for (int q = 0; q < 128; q++)
                    v = fmaf(W_out[k * 128 + q], Wh1[q * 128 + n], v);
            } else if (k < 131) {
                v = Wh1[k * 128 + n];
            }
            wt[idx] = v;
        } else if (idx < 151680) {               // bse
            int n = idx - 151552;
            float v = bs1[n];
            for (int q = 0; q < 128; q++)
                v = fmaf(b_out[q], Ws1[q * 128 + n], v);
            wt[idx] = v;
        } else if (idx < 151808) {               // bhe
            int n = idx - 151680;
            float v = bh1[n];
            for (int q = 0; q < 128; q++)
                v = fmaf(b_out[q], Wh1[q * 128 + n], v);
            wt[idx] = v;
        } else if (idx < 151808 + BN_ + 1) {     // zero deg/offsets
            off[idx - 151808] = 0;
        } else {                                 // zero logdet
            logdet[idx - (151808 + BN_ + 1)] = 0.f;
        }
    }
}

// ---------------------------------------------------------------------------
// CSR build: hist -> scanA -> scanB -> place
// ---------------------------------------------------------------------------
__global__ void k_hist(const int* __restrict__ adj, const int* __restrict__ ebi,
                       int* __restrict__ deg) {
    int e = blockIdx.x * blockDim.x + threadIdx.x;
    if (e >= E_) return;
    int dst = ebi[e] * N_ + adj[2 * e + 1];
    atomicAdd(&deg[dst], 1);
}

__global__ void k_scanA(int* __restrict__ off, int* __restrict__ part) {
    __shared__ int s[512];
    int t = threadIdx.x;
    int i = blockIdx.x * 512 + t;
    int v = off[i];
    s[t] = v; __syncthreads();
    for (int d = 1; d < 512; d <<= 1) {
        int x = (t >= d) ? s[t - d] : 0;
        __syncthreads();
        s[t] += x;
        __syncthreads();
    }
    off[i] = s[t] - v;                 // exclusive within chunk
    if (t == 511) part[blockIdx.x] = s[t];
}

__global__ void k_scanB(int* __restrict__ off, const int* __restrict__ part,
                        int* __restrict__ cur) {
    __shared__ int s[512];
    int t = threadIdx.x, b = blockIdx.x;
    s[t] = part[t]; __syncthreads();
    for (int d = 1; d < 512; d <<= 1) {
        int x = (t >= d) ? s[t - d] : 0;
        __syncthreads();
        s[t] += x;
        __syncthreads();
    }
    int prefix = (b == 0) ? 0 : s[b - 1];
    int i = b * 512 + t;
    int v = off[i] + prefix;
    off[i] = v;
    cur[i] = v;
    if (b == 0 && t == 0) off[BN_] = E_;
}

__global__ void k_place(const int* __restrict__ adj, const int* __restrict__ ebi,
                        int* __restrict__ cur, int* __restrict__ srcl) {
    int e = blockIdx.x * blockDim.x + threadIdx.x;
    if (e >= E_) return;
    int b = ebi[e];
    int src = b * N_ + adj[2 * e];
    int dst = b * N_ + adj[2 * e + 1];
    int pos = atomicAdd(&cur[dst], 1);
    srcl[pos] = src;
}

// ---------------------------------------------------------------------------
// Gather: agg[d] = sum of msg[src] over incident edges. One warp per node,
// 2-way unrolled for MLP.
// ---------------------------------------------------------------------------
__global__ void k_gather(const float* __restrict__ msg,
                         const int* __restrict__ off,
                         const int* __restrict__ srcl,
                         float* __restrict__ agg) {
    int warp = (blockIdx.x * blockDim.x + threadIdx.x) >> 5;
    int lane = threadIdx.x & 31;
    int s0 = off[warp], s1 = off[warp + 1];
    float4 acc0 = make_float4(0.f, 0.f, 0.f, 0.f);
    float4 acc1 = make_float4(0.f, 0.f, 0.f, 0.f);
    int j = s0;
    for (; j + 2 <= s1; j += 2) {
        int sA = srcl[j], sB = srcl[j + 1];
        float4 va = *((const float4*)(msg + (size_t)sA * 128) + lane);
        float4 vb = *((const float4*)(msg + (size_t)sB * 128) + lane);
        acc0.x += va.x; acc0.y += va.y; acc0.z += va.z; acc0.w += va.w;
        acc1.x += vb.x; acc1.y += vb.y; acc1.z += vb.z; acc1.w += vb.w;
    }
    if (j < s1) {
        int sA = srcl[j];
        float4 va = *((const float4*)(msg + (size_t)sA * 128) + lane);
        acc0.x += va.x; acc0.y += va.y; acc0.z += va.z; acc0.w += va.w;
    }
    acc0.x += acc1.x; acc0.y += acc1.y; acc0.z += acc1.z; acc0.w += acc1.w;
    *((float4*)(agg + (size_t)warp * 128) + lane) = acc0;
}

// ---------------------------------------------------------------------------
// GEMM core. 256 threads/CTA, M-tile 256, N=128, cp.async 2-stage ring,
// K chunks of 32. Two TMEM accumulator blocks (cols 0..127, 128..255).
// MODE: 0=direct(lda128) 1=concat(h|agg) 2=embed-gather 3=feat(h|masked coords)
// ---------------------------------------------------------------------------
#define NSTAGE       2
#define STAGE_BYTES  49152            // 32KB A (256 rows) + 16KB W
#define SMEM_GEMM    (1024 + NSTAGE * STAGE_BYTES)

struct GP {
    const float* A1; const float* A2;
    const float* emb; const int* types; const float* coords;
    const float* Wt; const float* bias;
    const unsigned char* maskB;
    float* C;
    int K; int Kpad; int relu; int use_mask;
};

template<int MODE>
__device__ __forceinline__ float4 loadA4(const GP& g, int gr, int k) {
    if (MODE == 0) {
        return *(const float4*)(g.A1 + (size_t)gr * 128 + k);
    } else if (MODE == 1) {
        if (k < 128) return *(const float4*)(g.A1 + (size_t)gr * 128 + k);
        return *(const float4*)(g.A2 + (size_t)gr * 128 + (k - 128));
    } else if (MODE == 2) {
        int t = g.types[gr];
        if (k + 3 < 64) return *(const float4*)(g.emb + t * 64 + k);
        float4 v; float* vp = &v.x;
#pragma unroll
        for (int i = 0; i < 4; i++) {
            int kk = k + i; float x;
            if (kk < 64)      x = g.emb[t * 64 + kk];
            else if (kk < 67) x = g.coords[gr * 3 + (kk - 64)];
            else              x = 0.f;
            vp[i] = x;
        }
        return v;
    } else {
        if (k + 3 < 128) return *(const float4*)(g.A1 + (size_t)gr * 128 + k);
        bool cm = ((gr & 1) == 0) && (g.maskB[gr] == 0);   // PHASE=0
        float4 v; float* vp = &v.x;
#pragma unroll
        for (int i = 0; i < 4; i++) {
            int kk = k + i; float x;
            if (kk < 128)      x = g.A1[(size_t)gr * 128 + kk];
            else if (kk < 131) x = cm ? 0.f : g.coords[gr * 3 + (kk - 128)];
            else               x = 0.f;
            vp[i] = x;
        }
        return v;
    }
}

#if TC_AVAIL
// Stage one 32-K chunk: A [256 rows] + W [128 n-rows] into buffer, SW128.
// cp.async for 16B-aligned bulk, sync STS for tails/padding.
template<int MODE>
__device__ __forceinline__ void stage_chunk(const GP& g, uint32_t bufA,
                                            uint32_t bufW, int block_row,
                                            int t, int tid) {
    // W: 1024 float4 -> 4 per thread
#pragma unroll
    for (int it = 0; it < 4; it++) {
        int idx = tid + it * 256;
        int r = idx >> 3, c4 = idx & 7;
        int k = t * 32 + c4 * 4;
        uint32_t dst = bufW + SW128((uint32_t)(r * 128 + c4 * 16));
        cp16(dst, g.Wt + (size_t)r * g.Kpad + k);
    }
    // A: 2048 float4 (256 rows) -> 8 per thread
#pragma unroll
    for (int it = 0; it < 8; it++) {
        int idx = tid + it * 256;             // 0..2047
        int r = idx >> 3, c4 = idx & 7;
        int gr = block_row + r;
        int k = t * 32 + c4 * 4;
        uint32_t dst = bufA + SW128((uint32_t)(r * 128 + c4 * 16));
        if (MODE == 0) {
            cp16(dst, g.A1 + (size_t)gr * 128 + k);
        } else if (MODE == 1) {
            const float* src = (k < 128) ? g.A1 + (size_t)gr * 128 + k
                                         : g.A2 + (size_t)gr * 128 + (k - 128);
            cp16(dst, src);
        } else if (MODE == 2) {
            if (k + 3 < 64) {
                cp16(dst, g.emb + (size_t)g.types[gr] * 64 + k);
            } else {
                sts4(dst, loadA4<2>(g, gr, k));   // coords tail / padding
            }
        } else {
            if (k + 3 < 128) {
                cp16(dst, g.A1 + (size_t)gr * 128 + k);
            } else {
                sts4(dst, loadA4<3>(g, gr, k));   // coords tail / padding
            }
        }
    }
    cp_commit();
}
#endif

template<int MODE>
__global__ void __launch_bounds__(256) k_gemm_tc(GP g) {
#if TC_AVAIL
    extern __shared__ __align__(1024) char smem[];
    const uint32_t sb = smem_u32(smem);
    const int tid = threadIdx.x;
    const int wid = tid >> 5;
    const int lid = tid & 31;
    const int block_row = blockIdx.x * 256;

    if (wid == 0) {
        asm volatile(
            "tcgen05.alloc.cta_group::1.sync.aligned.shared::cta.b32 [%0], %1;"
            :: "r"(sb), "r"(256u) : "memory");
        asm volatile("tcgen05.relinquish_alloc_permit.cta_group::1.sync.aligned;");
    }
    if (tid == 0) {
#pragma unroll
        for (int s = 0; s < NSTAGE; s++) mbar_init(sb + 8 + s * 8, 1);
    }
    __syncthreads();
    uint32_t tmem;
    asm volatile("ld.shared.b32 %0, [%1];" : "=r"(tmem) : "r"(sb));

    const int nt = g.Kpad / 32;
    const uint32_t bufA0 = sb + 1024;
    const uint32_t bufW0 = bufA0 + 32768;

    // prologue: stage chunks 0 and 1 (nt >= 3 always)
    stage_chunk<MODE>(g, bufA0, bufW0, block_row, 0, tid);
    stage_chunk<MODE>(g, bufA0 + STAGE_BYTES, bufW0 + STAGE_BYTES, block_row, 1, tid);

    for (int t = 0; t < nt; t++) {
        const int b = t & 1;
        if (t < nt - 1) cp_wait1(); else cp_wait0();
        __syncthreads();

        if (tid == 0) {
            asm volatile("fence.proxy.async.shared::cta;" ::: "memory");
            uint64_t ad0 = mk_desc(bufA0 + b * STAGE_BYTES);
            uint64_t ad1 = mk_desc(bufA0 + b * STAGE_BYTES + 16384);
            uint64_t bd  = mk_desc(bufW0 + b * STAGE_BYTES);
#pragma unroll
            for (int j = 0; j < 4; j++) {
                uint32_t en = (t > 0 || j > 0) ? 1u : 0u;
                mma_tf32_ss(tmem,       ad0 + j * 2, bd + j * 2, en);
                mma_tf32_ss(tmem + 128, ad1 + j * 2, bd + j * 2, en);
            }
            tc_commit(sb + 8 + b * 8);
        }

        if (t + 2 < nt) {
            // buffer b reused by chunk t+2: wait chunk t's MMA group
            mbar_wait(sb + 8 + b * 8, (t >> 1) & 1);
            stage_chunk<MODE>(g, bufA0 + b * STAGE_BYTES,
                              bufW0 + b * STAGE_BYTES, block_row, t + 2, tid);
        }
    }

    mbar_wait(sb + 8 + ((nt - 1) & 1) * 8, ((nt - 1) >> 1) & 1);
    asm volatile("tcgen05.fence::after_thread_sync;" ::: "memory");

    // epilogue: warp w -> M-block (w>>2), subpartition (w&3)
    const int blk = wid >> 2;
    const int sp  = wid & 3;
    const int m   = block_row + blk * 128 + sp * 32 + lid;
    const bool masked = g.use_mask && (g.maskB[m] != 0);
#pragma unroll
    for (int cb = 0; cb < 128; cb += 32) {
        uint32_t r32[32];
        TC_LD_X32(r32, tmem + blk * 128 + cb);
        asm volatile("tcgen05.wait::ld.sync.aligned;" ::: "memory");
#pragma unroll
        for (int j = 0; j < 32; j += 4) {
            float4 o;
            float* op = &o.x;
#pragma unroll
            for (int i = 0; i < 4; i++) {
                float v = __uint_as_float(r32[j + i]) + g.bias[cb + j + i];
                if (g.relu) v = fmaxf(v, 0.f);
                if (masked) v = 0.f;
                op[i] = v;
            }
            *(float4*)(g.C + (size_t)m * 128 + cb + j) = o;
        }
    }

    __syncthreads();
    if (wid == 0) {
        asm volatile("tcgen05.dealloc.cta_group::1.sync.aligned.b32 %0, %1;"
                     :: "r"(tmem), "r"(256u));
    }
#else
    // Scalar fallback for non-sm_103a passes (never runs on GB300).
    const int row = blockIdx.x * 256 + threadIdx.x;
    const bool masked = g.use_mask && (g.maskB[row] != 0);
#pragma unroll 1
    for (int cb = 0; cb < 128; cb += 4) {
        float acc[4] = {0.f, 0.f, 0.f, 0.f};
        for (int k = 0; k < g.K; k += 4) {
            float4 a = loadA4<MODE>(g, row, k);
            const float* ap = &a.x;
#pragma unroll
            for (int c = 0; c < 4; c++) {
                const float* wr = g.Wt + (size_t)(cb + c) * g.Kpad + k;
#pragma unroll
                for (int i = 0; i < 4; i++)
                    acc[c] = fmaf(ap[i], wr[i], acc[c]);
            }
        }
#pragma unroll
        for (int c = 0; c < 4; c++) {
            float v = acc[c] + g.bias[cb + c];
            if (g.relu) v = fmaxf(v, 0.f);
            if (masked) v = 0.f;
            g.C[(size_t)row * 128 + cb + c] = v;
        }
    }
#endif
}

// ---------------------------------------------------------------------------
// Coupling dual GEMM + fused final epilogue (unchanged; M=128, 128 threads)
// ---------------------------------------------------------------------------
#define CPL_HDR      8192
#define CPL_STAGE    49152           // 16KB A + 16KB Ws + 16KB Wh
#define SMEM_CPL     (CPL_HDR + NSTAGE * CPL_STAGE)

struct CP {
    const float* A1; const float* coords;
    const float* Wse; const float* Whe;
    const float* bse; const float* bhe;
    const float* Ws2; const float* bs2;
    const float* Wh2; const float* bh2;
    const unsigned char* maskB;
    float* out; float* logdet;
};

__global__ void __launch_bounds__(128) k_gemm_cpl(CP g) {
#if TC_AVAIL
    extern __shared__ __align__(1024) char smem[];
    const uint32_t sb = smem_u32(smem);
    float* smf = (float*)smem;
    const int tid = threadIdx.x;
    const int wid = tid >> 5;
    const int lid = tid & 31;
    const int block_row = blockIdx.x * 128;

    if (wid == 0) {
        asm volatile(
            "tcgen05.alloc.cta_group::1.sync.aligned.shared::cta.b32 [%0], %1;"
            :: "r"(sb), "r"(256u) : "memory");
        asm volatile("tcgen05.relinquish_alloc_permit.cta_group::1.sync.aligned;");
    }
    if (tid == 0) {
#pragma unroll
        for (int s = 0; s < NSTAGE; s++) mbar_init(sb + 8 + s * 8, 1);
    }
    for (int i = tid; i < 384; i += 128) {
        smf[16 + i]  = g.Ws2[i];
        smf[400 + i] = g.Wh2[i];
    }
    smf[784 + tid] = g.bse[tid];
    smf[912 + tid] = g.bhe[tid];
    __syncthreads();
    uint32_t tmem;
    asm volatile("ld.shared.b32 %0, [%1];" : "=r"(tmem) : "r"(sb));

    const int nt = 5;                   // Kpad 160

    GP ga{};
    ga.A1 = g.A1; ga.coords = g.coords; ga.maskB = g.maskB; ga.K = 131;

    for (int t = 0; t < nt; t++) {
        const int b = t & 1;
        if (t >= NSTAGE) mbar_wait(sb + 8 + b * 8, ((t >> 1) - 1) & 1);

        char* base = smem + CPL_HDR + b * CPL_STAGE;
#pragma unroll
        for (int it = 0; it < 24; it++) {
            int idx = tid + it * 128;            // 0..3071
            int sec = idx >> 10;                 // 0=A 1=Ws 2=Wh
            int w   = idx & 1023;
            int r   = w >> 3;
            int c4  = w & 7;
            int k   = t * 32 + c4 * 4;
            float4 v;
            if (sec == 0)
                v = (k < 131) ? loadA4<3>(ga, block_row + r, k)
                              : make_float4(0.f, 0.f, 0.f, 0.f);
            else if (sec == 1)
                v = *(const float4*)(g.Wse + (size_t)r * 160 + k);
            else
                v = *(const float4*)(g.Whe + (size_t)r * 160 + k);
            uint32_t off = SW128((uint32_t)(r * 128 + c4 * 16));
            *(float4*)(base + sec * 16384 + off) = v;
        }
        __syncthreads();

        if (tid == 0) {
            asm volatile("fence.proxy.async.shared::cta;" ::: "memory");
            uint32_t stage = sb + CPL_HDR + b * CPL_STAGE;
            uint64_t ad = mk_desc(stage);
            uint64_t sd = mk_desc(stage + 16384);
            uint64_t hd = mk_desc(stage + 32768);
            uint32_t en0 = (t > 0) ? 1u : 0u;
#pragma unroll
            for (int j = 0; j < 4; j++) {
                uint32_t en = (j > 0) ? 1u : en0;
                mma_tf32_ss(tmem,       ad + j * 2, sd + j * 2, en);
                mma_tf32_ss(tmem + 128, ad + j * 2, hd + j * 2, en);
            }
            tc_commit(sb + 8 + b * 8);
        }
    }

    mbar_wait(sb + 8 + ((nt - 1) & 1) * 8, ((nt - 1) >> 1) & 1);
    asm volatile("tcgen05.fence::after_thread_sync;" ::: "memory");

    const int m = block_row + wid * 32 + lid;
    float raw[3] = {0.f, 0.f, 0.f};
    float shf[3] = {0.f, 0.f, 0.f};
#pragma unroll
    for (int cb = 0; cb < 128; cb += 32) {
        uint32_t rs[32], rh[32];
        TC_LD_X32(rs, tmem + cb);
        TC_LD_X32(rh, tmem + 128 + cb);
        asm volatile("tcgen05.wait::ld.sync.aligned;" ::: "memory");
#pragma unroll
        for (int k = 0; k < 32; k++) {
            int col = cb + k;
            float sv = fmaxf(__uint_as_float(rs[k]) + smf[784 + col], 0.f);
            float hv = fmaxf(__uint_as_float(rh[k]) + smf[912 + col], 0.f);
#pragma unroll
            for (int c = 0; c < 3; c++) {
                raw[c] = fmaf(sv, smf[16 + col * 3 + c],  raw[c]);
                shf[c] = fmaf(hv, smf[400 + col * 3 + c], shf[c]);
            }
        }
    }

    bool cm = ((m & 1) == 0) && (g.maskB[m] == 0);   // PHASE = 0
    float ld = 0.f;
#pragma unroll
    for (int c = 0; c < 3; c++) {
        float r = raw[c] + g.bs2[c];
        float s = shf[c] + g.bh2[c];
        float ls = cm ? tanhf(r) * 2.f : 0.f;
        ld += ls;
        float coord = g.coords[m * 3 + c];
        g.out[m * 3 + c] = cm ? (expf(ls) * coord + s) : coord;
    }
#pragma unroll
    for (int o = 16; o > 0; o >>= 1)
        ld += __shfl_xor_sync(0xFFFFFFFFu, ld, o);
    if (lid == 0) atomicAdd(&g.logdet[m >> 13], ld);

    __syncthreads();
    if (wid == 0) {
        asm volatile("tcgen05.dealloc.cta_group::1.sync.aligned.b32 %0, %1;"
                     :: "r"(tmem), "r"(256u));
    }
#else
    // Scalar fallback (never runs on GB300).
    const int m = blockIdx.x * 128 + threadIdx.x;
    bool cm = ((m & 1) == 0) && (g.maskB[m] == 0);
    float raw[3], shf[3];
#pragma unroll
    for (int c = 0; c < 3; c++) { raw[c] = g.bs2[c]; shf[c] = g.bh2[c]; }
    for (int n = 0; n < 128; n++) {
        float accs = g.bse[n], acch = g.bhe[n];
        for (int k = 0; k < 128; k++) {
            float a = g.A1[(size_t)m * 128 + k];
            accs = fmaf(a, g.Wse[n * 160 + k], accs);
            acch = fmaf(a, g.Whe[n * 160 + k], acch);
        }
        for (int k = 128; k < 131; k++) {
            float a = cm ? 0.f : g.coords[m * 3 + (k - 128)];
            accs = fmaf(a, g.Wse[n * 160 + k], accs);
            acch = fmaf(a, g.Whe[n * 160 + k], acch);
        }
        accs = fmaxf(accs, 0.f); acch = fmaxf(acch, 0.f);
#pragma unroll
        for (int c = 0; c < 3; c++) {
            raw[c] = fmaf(accs, g.Ws2[n * 3 + c], raw[c]);
            shf[c] = fmaf(acch, g.Wh2[n * 3 + c], shf[c]);
        }
    }
    float ld = 0.f;
#pragma unroll
    for (int c = 0; c < 3; c++) {
        float ls = cm ? tanhf(raw[c]) * 2.f : 0.f;
        ld += ls;
        float coord = g.coords[m * 3 + c];
        g.out[m * 3 + c] = cm ? (expf(ls) * coord + shf[c]) : coord;
    }
    atomicAdd(&g.logdet[m >> 13], ld);
#endif
}

// ---------------------------------------------------------------------------
// Host launcher. Index 3 = msg GEMM layer 0 (ncu profile target).
// ---------------------------------------------------------------------------
extern "C" void kernel_launch(void* const* d_in, const int* in_sizes, int n_in,
                              void* d_out, int out_size) {
    const float*         coords = (const float*)d_in[0];
    const int*           types  = (const int*)  d_in[1];
    const int*           adj    = (const int*)  d_in[2];
    const int*           ebi    = (const int*)  d_in[3];
    const unsigned char* maskB  = (const unsigned char*)d_in[4];
    const float* emb   = (const float*)d_in[5];
    const float* W_in  = (const float*)d_in[6];
    const float* b_in  = (const float*)d_in[7];
    const float* msg_W = (const float*)d_in[8];
    const float* msg_b = (const float*)d_in[9];
    const float* upd_W = (const float*)d_in[10];
    const float* upd_b = (const float*)d_in[11];
    const float* W_out = (const float*)d_in[12];
    const float* b_out = (const float*)d_in[13];
    const float* Ws1   = (const float*)d_in[14];
    const float* bs1   = (const float*)d_in[15];
    const float* Ws2   = (const float*)d_in[16];
    const float* bs2   = (const float*)d_in[17];
    const float* Wh1   = (const float*)d_in[18];
    const float* bh1   = (const float*)d_in[19];
    const float* Wh2   = (const float*)d_in[20];
    const float* bh2   = (const float*)d_in[21];

    float* out    = (float*)d_out;
    float* logdet = out + (size_t)BN_ * 3;

    float *h, *b1, *b2, *wt;
    int *off, *part, *cur, *srcl;
    cudaGetSymbolAddress((void**)&h,    g_h);
    cudaGetSymbolAddress((void**)&b1,   g_b1);
    cudaGetSymbolAddress((void**)&b2,   g_b2);
    cudaGetSymbolAddress((void**)&wt,   g_wt);
    cudaGetSymbolAddress((void**)&off,  g_off);
    cudaGetSymbolAddress((void**)&part, g_part);
    cudaGetSymbolAddress((void**)&cur,  g_cur);
    cudaGetSymbolAddress((void**)&srcl, g_srcl);

    cudaFuncSetAttribute(k_gemm_tc<0>, cudaFuncAttributeMaxDynamicSharedMemorySize, SMEM_GEMM);
    cudaFuncSetAttribute(k_gemm_tc<1>, cudaFuncAttributeMaxDynamicSharedMemorySize, SMEM_GEMM);
    cudaFuncSetAttribute(k_gemm_tc<2>, cudaFuncAttributeMaxDynamicSharedMemorySize, SMEM_GEMM);
    cudaFuncSetAttribute(k_gemm_cpl,   cudaFuncAttributeMaxDynamicSharedMemorySize, SMEM_CPL);

    const int BT = 256;
    const int GB = BN_ / 256;   // 1024 CTAs per GEMM

    GP g{};
    g.emb = emb; g.types = types; g.coords = coords; g.maskB = maskB;

    // 0: prep
    k_prep<<<512, BT>>>(W_in, msg_W, upd_W, W_out, Ws1, Wh1, bs1, bh1, b_out,
                        wt, off, logdet);
    // 1: hist (CSR step 1)
    k_hist <<<E_ / BT, BT>>>(adj, ebi, off);
    // 2: input layer
    g.A1 = 0; g.A2 = 0; g.Wt = wt + O_WIN; g.bias = b_in; g.C = h;
    g.K = 67; g.Kpad = 96; g.relu = 1; g.use_mask = 1;
    k_gemm_tc<2><<<GB, 256, SMEM_GEMM>>>(g);
    // 3: msg GEMM layer 0  <-- ncu profile target
    g.A1 = h; g.A2 = 0; g.Wt = wt + O_MSG0; g.bias = msg_b; g.C = b1;
    g.K = 128; g.Kpad = 128; g.relu = 1; g.use_mask = 0;
    k_gemm_tc<0><<<GB, 256, SMEM_GEMM>>>(g);
    // 4-6: finish CSR
    k_scanA<<<512, 512>>>(off, part);
    k_scanB<<<512, 512>>>(off, part, cur);
    k_place<<<E_ / BT, BT>>>(adj, ebi, cur, srcl);
    // 7: gather layer 0
    k_gather<<<BN_ / 8, BT>>>(b1, off, srcl, b2);
    // 8: upd layer 0
    g.A1 = h; g.A2 = b2; g.Wt = wt + O_UPD0; g.bias = upd_b; g.C = h;
    g.K = 256; g.Kpad = 256; g.relu = 1; g.use_mask = 1;
    k_gemm_tc<1><<<GB, 256, SMEM_GEMM>>>(g);
    // 9: msg GEMM layer 1
    g.A1 = h; g.A2 = 0; g.Wt = wt + O_MSG1; g.bias = msg_b + 128; g.C = b1;
    g.K = 128; g.Kpad = 128; g.relu = 1; g.use_mask = 0;
    k_gemm_tc<0><<<GB, 256, SMEM_GEMM>>>(g);
    // 10: gather layer 1
    k_gather<<<BN_ / 8, BT>>>(b1, off, srcl, b2);
    // 11: upd layer 1
    g.A1 = h; g.A2 = b2; g.Wt = wt + O_UPD1; g.bias = upd_b + 128; g.C = h;
    g.K = 256; g.Kpad = 256; g.relu = 1; g.use_mask = 1;
    k_gemm_tc<1><<<GB, 256, SMEM_GEMM>>>(g);

    // 12: fused coupling (dual GEMM + final epilogue)
    CP c{};
    c.A1 = h; c.coords = coords;
    c.Wse = wt + O_WSE; c.Whe = wt + O_WHE;
    c.bse = wt + O_BSE; c.bhe = wt + O_BHE;
    c.Ws2 = Ws2; c.bs2 = bs2; c.Wh2 = Wh2; c.bh2 = bh2;
    c.maskB = maskB; c.out = out; c.logdet = logdet;
    k_gemm_cpl<<<GB * 2, 128, SMEM_CPL>>>(c);
}

// round 11
// speedup vs baseline: 7.0911x; 1.6673x over previous
#include <cuda_runtime.h>
#include <cuda_fp16.h>
#include <cstdint>
#include <math.h>
#include <stddef.h>

// Problem constants
#define B_   32
#define N_   8192
#define E_   1048576
#define BN_  (B_ * N_)          // 262144
#define L_   2

// ---------------------------------------------------------------------------
// Arch-feature gate (tcgen05 only exists on sm_100a/sm_103a passes)
// ---------------------------------------------------------------------------
#if defined(__CUDA_ARCH_FEAT_SM103_ALL) || defined(__CUDA_ARCH_FEAT_SM100_ALL)
#  define TC_AVAIL 1
#endif
#ifndef TC_AVAIL
#  ifdef __CUDA_ARCH_HAS_FEATURE__
#    if __CUDA_ARCH_HAS_FEATURE__(SM103_ALL) || __CUDA_ARCH_HAS_FEATURE__(SM100_ALL)
#      define TC_AVAIL 1
#    endif
#  endif
#endif
#ifndef TC_AVAIL
#  define TC_AVAIL 0
#endif

// ---------------------------------------------------------------------------
// Scratch (static device globals)
// ---------------------------------------------------------------------------
static __device__ __align__(16) __half g_h [(size_t)BN_ * 128];
static __device__ __align__(16) __half g_b1[(size_t)BN_ * 128];   // msg_all
static __device__ __align__(16) __half g_b2[(size_t)BN_ * 128];   // agg
static __device__ __align__(16) float  g_wt [12544];              // fp32: W_in^T + bse/bhe
static __device__ __align__(16) __half g_wth[147456];             // fp16 weights
static __device__ int g_off [BN_ + 1];
static __device__ int g_part[512];
static __device__ int g_cur [BN_];
static __device__ int g_srcl[E_];

// g_wt fp32 offsets
#define O_WIN   0        // 128 x 96 (K=67 pad)
#define O_BSE   12288
#define O_BHE   12416
// g_wth half offsets
#define H_MSG0  0        // 128x128
#define H_MSG1  16384
#define H_UPD0  32768    // 128x256
#define H_UPD1  65536
#define H_WSE   98304    // 128x192 (K=131 pad)
#define H_WHE   122880

// ---------------------------------------------------------------------------
// Helpers
// ---------------------------------------------------------------------------
__device__ __forceinline__ uint32_t smem_u32(const void* p) {
    uint32_t a;
    asm("{ .reg .u64 t; cvta.to.shared.u64 t, %1; cvt.u32.u64 %0, t; }"
        : "=r"(a) : "l"(p));
    return a;
}

#define SW128(o) ((o) ^ (((o) >> 3) & 0x70))

__device__ __forceinline__ void cp16(uint32_t dst, const void* src) {
    asm volatile("cp.async.cg.shared.global [%0], [%1], 16;"
                 :: "r"(dst), "l"(src) : "memory");
}
__device__ __forceinline__ void cp_commit() {
    asm volatile("cp.async.commit_group;" ::: "memory");
}
__device__ __forceinline__ void cp_wait1() {
    asm volatile("cp.async.wait_group 1;" ::: "memory");
}
__device__ __forceinline__ void cp_wait0() {
    asm volatile("cp.async.wait_group 0;" ::: "memory");
}
__device__ __forceinline__ void sts4(uint32_t dst, float4 v) {
    asm volatile("st.shared.v4.f32 [%0], {%1, %2, %3, %4};"
                 :: "r"(dst), "f"(v.x), "f"(v.y), "f"(v.z), "f"(v.w) : "memory");
}
__device__ __forceinline__ void sts4u(uint32_t dst, uint4 v) {
    asm volatile("st.shared.v4.u32 [%0], {%1, %2, %3, %4};"
                 :: "r"(dst), "r"(v.x), "r"(v.y), "r"(v.z), "r"(v.w) : "memory");
}
__device__ __forceinline__ uint32_t pack2(float a, float b) {
    __half2 h = __floats2half2_rn(a, b);
    return *reinterpret_cast<uint32_t*>(&h);
}

#if TC_AVAIL
__device__ __forceinline__ uint64_t mk_desc(uint32_t addr) {
    // SW128, version=1 (Blackwell), LBO=1, SBO=64 (K-major)
    const uint64_t BASE = (2ULL << 61) | (1ULL << 46) | (64ULL << 32) | (1ULL << 16);
    return BASE | ((uint64_t)(addr >> 4) & 0x3FFF);
}

// tf32: acc=F32, atype=btype=TF32(2), N=128, M=128
#define IDESC_TF32 ((1u << 4) | (2u << 7) | (2u << 10) | (16u << 17) | (8u << 24))
// fp16: acc=F32, atype=btype=FP16(0), N=128, M=128
#define IDESC_F16  ((1u << 4) | (16u << 17) | (8u << 24))

__device__ __forceinline__ void mma_tf32_ss(uint32_t d, uint64_t a, uint64_t b,
                                            uint32_t en) {
    asm volatile(
        "{\n\t.reg .pred p;\n\t"
        "setp.ne.u32 p, %4, 0;\n\t"
        "tcgen05.mma.cta_group::1.kind::tf32 [%0], %1, %2, %3, p;\n\t}"
        :: "r"(d), "l"(a), "l"(b), "r"(IDESC_TF32), "r"(en) : "memory");
}
__device__ __forceinline__ void mma_f16_ss(uint32_t d, uint64_t a, uint64_t b,
                                           uint32_t en) {
    asm volatile(
        "{\n\t.reg .pred p;\n\t"
        "setp.ne.u32 p, %4, 0;\n\t"
        "tcgen05.mma.cta_group::1.kind::f16 [%0], %1, %2, %3, p;\n\t}"
        :: "r"(d), "l"(a), "l"(b), "r"(IDESC_F16), "r"(en) : "memory");
}

__device__ __forceinline__ void tc_commit(uint32_t mbar) {
    asm volatile(
        "tcgen05.commit.cta_group::1.mbarrier::arrive::one.shared::cluster.b64 [%0];"
        :: "r"(mbar) : "memory");
}

#define TC_LD_X32(r, addr)                                                     \
    asm volatile(                                                              \
        "tcgen05.ld.sync.aligned.32x32b.x32.b32 "                              \
        "{%0, %1, %2, %3, %4, %5, %6, %7, "                                    \
        " %8, %9, %10, %11, %12, %13, %14, %15, "                              \
        " %16, %17, %18, %19, %20, %21, %22, %23, "                            \
        " %24, %25, %26, %27, %28, %29, %30, %31}, [%32];"                     \
        : "=r"((r)[0]),  "=r"((r)[1]),  "=r"((r)[2]),  "=r"((r)[3]),           \
          "=r"((r)[4]),  "=r"((r)[5]),  "=r"((r)[6]),  "=r"((r)[7]),           \
          "=r"((r)[8]),  "=r"((r)[9]),  "=r"((r)[10]), "=r"((r)[11]),          \
          "=r"((r)[12]), "=r"((r)[13]), "=r"((r)[14]), "=r"((r)[15]),          \
          "=r"((r)[16]), "=r"((r)[17]), "=r"((r)[18]), "=r"((r)[19]),          \
          "=r"((r)[20]), "=r"((r)[21]), "=r"((r)[22]), "=r"((r)[23]),          \
          "=r"((r)[24]), "=r"((r)[25]), "=r"((r)[26]), "=r"((r)[27]),          \
          "=r"((r)[28]), "=r"((r)[29]), "=r"((r)[30]), "=r"((r)[31])           \
        : "r"(addr))
#endif  // TC_AVAIL

__device__ __forceinline__ void mbar_init(uint32_t a, uint32_t cnt) {
    asm volatile("mbarrier.init.shared.b64 [%0], %1;" :: "r"(a), "r"(cnt) : "memory");
}
__device__ __forceinline__ void mbar_wait(uint32_t a, uint32_t parity) {
    asm volatile(
        "{\n\t.reg .pred P;\n"
        "WL%=:\n\t"
        "mbarrier.try_wait.parity.acquire.cta.shared::cta.b64 P, [%0], %1, 0x989680;\n\t"
        "@P bra WD%=;\n\t"
        "bra WL%=;\n"
        "WD%=:\n\t}"
        :: "r"(a), "r"(parity) : "memory");
}

// ---------------------------------------------------------------------------
// k_prep: fp32 W_in^T + fused bse/bhe; fp16 weight transposes; zeros.
// ---------------------------------------------------------------------------
__global__ void k_prep(const float* __restrict__ W_in,
                       const float* __restrict__ msg_W,
                       const float* __restrict__ upd_W,
                       const float* __restrict__ W_out,
                       const float* __restrict__ Ws1,
                       const float* __restrict__ Wh1,
                       const float* __restrict__ bs1,
                       const float* __restrict__ bh1,
                       const float* __restrict__ b_out,
                       float* __restrict__ wt,
                       __half* __restrict__ wth,
                       int* __restrict__ off,
                       float* __restrict__ logdet) {
    const int TOTAL = 12544 + 147456 + (BN_ + 1) + 32;
    for (int idx = blockIdx.x * blockDim.x + threadIdx.x; idx < TOTAL;
         idx += gridDim.x * blockDim.x) {
        if (idx < 12288) {                       // W_in^T, K=67 pad 96
            int n = idx / 96, k = idx - n * 96;
            wt[idx] = (k < 67) ? W_in[k * 128 + n] : 0.f;
        } else if (idx < 12416) {                // bse
            int n = idx - 12288;
            float v = bs1[n];
            for (int q = 0; q < 128; q++)
                v = fmaf(b_out[q], Ws1[q * 128 + n], v);
            wt[idx] = v;
        } else if (idx < 12544) {                // bhe
            int n = idx - 12416;
            float v = bh1[n];
            for (int q = 0; q < 128; q++)
                v = fmaf(b_out[q], Wh1[q * 128 + n], v);
            wt[idx] = v;
        } else {
            int j = idx - 12544;
            if (j < 32768) {                     // msg_W^T x2
                int l = j >> 14, r = j & 16383;
                int n = r >> 7, k = r & 127;
                wth[j] = __float2half(msg_W[l * 16384 + k * 128 + n]);
            } else if (j < 98304) {              // upd_W^T x2 (K=256)
                int j2 = j - 32768;
                int l = j2 >> 15, r = j2 & 32767;
                int n = r >> 8, k = r & 255;
                wth[j] = __float2half(upd_W[l * 32768 + k * 128 + n]);
            } else if (j < 122880) {             // Wse^T fused, Kpad 192
                int j2 = j - 98304;
                int n = j2 / 192, k = j2 - n * 192;
                float v = 0.f;
                if (k < 128) {
                    for (int q = 0; q < 128; q++)
                        v = fmaf(W_out[k * 128 + q], Ws1[q * 128 + n], v);
                } else if (k < 131) {
                    v = Ws1[k * 128 + n];
                }
                wth[j] = __float2half(v);
            } else if (j < 147456) {             // Whe^T fused, Kpad 192
                int j2 = j - 122880;
                int n = j2 / 192, k = j2 - n * 192;
                float v = 0.f;
                if (k < 128) {
                    for (int q = 0; q < 128; q++)
                        v = fmaf(W_out[k * 128 + q], Wh1[q * 128 + n], v);
                } else if (k < 131) {
                    v = Wh1[k * 128 + n];
                }
                wth[j] = __float2half(v);
            } else if (j < 147456 + BN_ + 1) {
                off[j - 147456] = 0;
            } else {
                logdet[j - (147456 + BN_ + 1)] = 0.f;
            }
        }
    }
}

// ---------------------------------------------------------------------------
// CSR build: hist -> scanA -> scanB -> place
// ---------------------------------------------------------------------------
__global__ void k_hist(const int* __restrict__ adj, const int* __restrict__ ebi,
                       int* __restrict__ deg) {
    int e = blockIdx.x * blockDim.x + threadIdx.x;
    if (e >= E_) return;
    int dst = ebi[e] * N_ + adj[2 * e + 1];
    atomicAdd(&deg[dst], 1);
}

__global__ void k_scanA(int* __restrict__ off, int* __restrict__ part) {
    __shared__ int s[512];
    int t = threadIdx.x;
    int i = blockIdx.x * 512 + t;
    int v = off[i];
    s[t] = v; __syncthreads();
    for (int d = 1; d < 512; d <<= 1) {
        int x = (t >= d) ? s[t - d] : 0;
        __syncthreads();
        s[t] += x;
        __syncthreads();
    }
    off[i] = s[t] - v;
    if (t == 511) part[blockIdx.x] = s[t];
}

__global__ void k_scanB(int* __restrict__ off, const int* __restrict__ part,
                        int* __restrict__ cur) {
    __shared__ int s[512];
    int t = threadIdx.x, b = blockIdx.x;
    s[t] = part[t]; __syncthreads();
    for (int d = 1; d < 512; d <<= 1) {
        int x = (t >= d) ? s[t - d] : 0;
        __syncthreads();
        s[t] += x;
        __syncthreads();
    }
    int prefix = (b == 0) ? 0 : s[b - 1];
    int i = b * 512 + t;
    int v = off[i] + prefix;
    off[i] = v;
    cur[i] = v;
    if (b == 0 && t == 0) off[BN_] = E_;
}

__global__ void k_place(const int* __restrict__ adj, const int* __restrict__ ebi,
                        int* __restrict__ cur, int* __restrict__ srcl) {
    int e = blockIdx.x * blockDim.x + threadIdx.x;
    if (e >= E_) return;
    int b = ebi[e];
    int src = b * N_ + adj[2 * e];
    int dst = b * N_ + adj[2 * e + 1];
    int pos = atomicAdd(&cur[dst], 1);
    srcl[pos] = src;
}

// ---------------------------------------------------------------------------
// Gather (fp16): agg[d] = sum msg[src]. One warp/node, lane = 4 halves (8B).
// ---------------------------------------------------------------------------
__global__ void k_gather(const __half* __restrict__ msg,
                         const int* __restrict__ off,
                         const int* __restrict__ srcl,
                         __half* __restrict__ agg) {
    int warp = (blockIdx.x * blockDim.x + threadIdx.x) >> 5;
    int lane = threadIdx.x & 31;
    int s0 = off[warp], s1 = off[warp + 1];
    float a0 = 0.f, a1 = 0.f, a2 = 0.f, a3 = 0.f;
    float b0 = 0.f, b1 = 0.f, b2 = 0.f, b3 = 0.f;
    int j = s0;
    for (; j + 2 <= s1; j += 2) {
        uint2 va = *((const uint2*)(msg + (size_t)srcl[j] * 128) + lane);
        uint2 vb = *((const uint2*)(msg + (size_t)srcl[j + 1] * 128) + lane);
        float2 fa0 = __half22float2(*(__half2*)&va.x);
        float2 fa1 = __half22float2(*(__half2*)&va.y);
        float2 fb0 = __half22float2(*(__half2*)&vb.x);
        float2 fb1 = __half22float2(*(__half2*)&vb.y);
        a0 += fa0.x; a1 += fa0.y; a2 += fa1.x; a3 += fa1.y;
        b0 += fb0.x; b1 += fb0.y; b2 += fb1.x; b3 += fb1.y;
    }
    if (j < s1) {
        uint2 va = *((const uint2*)(msg + (size_t)srcl[j] * 128) + lane);
        float2 fa0 = __half22float2(*(__half2*)&va.x);
        float2 fa1 = __half22float2(*(__half2*)&va.y);
        a0 += fa0.x; a1 += fa0.y; a2 += fa1.x; a3 += fa1.y;
    }
    a0 += b0; a1 += b1; a2 += b2; a3 += b3;
    uint2 o;
    o.x = pack2(a0, a1);
    o.y = pack2(a2, a3);
    *((uint2*)(agg + (size_t)warp * 128) + lane) = o;
}

// ---------------------------------------------------------------------------
// fp16 GEMM. 256 threads, M=256, N=128, K chunks of 64 elems (128B rows),
// cp.async 2-stage ring, fp32 accumulate, fp16 C.
// MODE 0: direct K=128 (nt=2). MODE 1: concat [h|agg] K=256 (nt=4).
// ---------------------------------------------------------------------------
#define STAGE_F16    49152            // 32KB A (256 rows) + 16KB W
#define SMEM_F16     (1024 + 2 * STAGE_F16)

struct GH {
    const __half* A1; const __half* A2;
    const __half* Wt; const float* bias;
    const unsigned char* maskB;
    __half* C;
};

#if TC_AVAIL
template<int MODE>
__device__ __forceinline__ void stage_f16(const GH& g, uint32_t bufA,
                                          uint32_t bufW, int block_row,
                                          int t, int tid, int Kpad) {
#pragma unroll
    for (int it = 0; it < 4; it++) {               // W: 1024 slots
        int idx = tid + it * 256;
        int r = idx >> 3, c4 = idx & 7;
        uint32_t dst = bufW + SW128((uint32_t)(r * 128 + c4 * 16));
        cp16(dst, g.Wt + (size_t)r * Kpad + t * 64 + c4 * 8);
    }
#pragma unroll
    for (int it = 0; it < 8; it++) {               // A: 2048 slots
        int idx = tid + it * 256;
        int r = idx >> 3, c4 = idx & 7;
        int gr = block_row + r;
        uint32_t dst = bufA + SW128((uint32_t)(r * 128 + c4 * 16));
        const __half* src;
        if (MODE == 0) src = g.A1 + (size_t)gr * 128 + t * 64 + c4 * 8;
        else src = (t < 2) ? g.A1 + (size_t)gr * 128 + t * 64 + c4 * 8
                           : g.A2 + (size_t)gr * 128 + (t - 2) * 64 + c4 * 8;
        cp16(dst, src);
    }
    cp_commit();
}
#endif

template<int MODE>
__global__ void __launch_bounds__(256) k_gemm_f16(GH g) {
    const int Kpad = (MODE == 0) ? 128 : 256;
    const int nt   = (MODE == 0) ? 2 : 4;
#if TC_AVAIL
    extern __shared__ __align__(1024) char smem[];
    const uint32_t sb = smem_u32(smem);
    const int tid = threadIdx.x;
    const int wid = tid >> 5;
    const int lid = tid & 31;
    const int block_row = blockIdx.x * 256;

    if (wid == 0) {
        asm volatile(
            "tcgen05.alloc.cta_group::1.sync.aligned.shared::cta.b32 [%0], %1;"
            :: "r"(sb), "r"(256u) : "memory");
        asm volatile("tcgen05.relinquish_alloc_permit.cta_group::1.sync.aligned;");
    }
    if (tid == 0) {
        mbar_init(sb + 8, 1);
        mbar_init(sb + 16, 1);
    }
    __syncthreads();
    uint32_t tmem;
    asm volatile("ld.shared.b32 %0, [%1];" : "=r"(tmem) : "r"(sb));

    const uint32_t bufA0 = sb + 1024;
    const uint32_t bufW0 = bufA0 + 32768;

    stage_f16<MODE>(g, bufA0, bufW0, block_row, 0, tid, Kpad);
    stage_f16<MODE>(g, bufA0 + STAGE_F16, bufW0 + STAGE_F16, block_row, 1, tid, Kpad);

    for (int t = 0; t < nt; t++) {
        const int b = t & 1;
        if (t < nt - 1) cp_wait1(); else cp_wait0();
        __syncthreads();

        if (tid == 0) {
            asm volatile("fence.proxy.async.shared::cta;" ::: "memory");
            uint64_t ad0 = mk_desc(bufA0 + b * STAGE_F16);
            uint64_t ad1 = mk_desc(bufA0 + b * STAGE_F16 + 16384);
            uint64_t bd  = mk_desc(bufW0 + b * STAGE_F16);
#pragma unroll
            for (int j = 0; j < 4; j++) {          // 4 x K=16 fp16 steps = K 64
                uint32_t en = (t > 0 || j > 0) ? 1u : 0u;
                mma_f16_ss(tmem,       ad0 + j * 2, bd + j * 2, en);
                mma_f16_ss(tmem + 128, ad1 + j * 2, bd + j * 2, en);
            }
            tc_commit(sb + 8 + b * 8);
        }

        if (t + 2 < nt) {
            mbar_wait(sb + 8 + b * 8, (t >> 1) & 1);
            stage_f16<MODE>(g, bufA0 + b * STAGE_F16, bufW0 + b * STAGE_F16,
                            block_row, t + 2, tid, Kpad);
        }
    }

    mbar_wait(sb + 8 + ((nt - 1) & 1) * 8, ((nt - 1) >> 1) & 1);
    asm volatile("tcgen05.fence::after_thread_sync;" ::: "memory");

    const int blk = wid >> 2;
    const int sp  = wid & 3;
    const int m   = block_row + blk * 128 + sp * 32 + lid;
    const bool masked = g.maskB && (g.maskB[m] != 0);
#pragma unroll
    for (int cb = 0; cb < 128; cb += 32) {
        uint32_t r32[32];
        TC_LD_X32(r32, tmem + blk * 128 + cb);
        asm volatile("tcgen05.wait::ld.sync.aligned;" ::: "memory");
#pragma unroll
        for (int j = 0; j < 32; j += 8) {
            float f[8];
#pragma unroll
            for (int i = 0; i < 8; i++) {
                float v = __uint_as_float(r32[j + i]) + g.bias[cb + j + i];
                v = fmaxf(v, 0.f);                 // all f16 GEMMs have relu
                if (masked) v = 0.f;
                f[i] = v;
            }
            uint4 o;
            o.x = pack2(f[0], f[1]); o.y = pack2(f[2], f[3]);
            o.z = pack2(f[4], f[5]); o.w = pack2(f[6], f[7]);
            *(uint4*)(g.C + (size_t)m * 128 + cb + j) = o;
        }
    }

    __syncthreads();
    if (wid == 0) {
        asm volatile("tcgen05.dealloc.cta_group::1.sync.aligned.b32 %0, %1;"
                     :: "r"(tmem), "r"(256u));
    }
#else
    const int row = blockIdx.x * 256 + threadIdx.x;  // fallback: 1 row/thread
    const int K = (MODE == 0) ? 128 : 256;
    const bool masked = g.maskB && (g.maskB[row] != 0);
#pragma unroll 1
    for (int cb = 0; cb < 128; cb++) {
        float acc = 0.f;
        for (int k = 0; k < K; k++) {
            float a = (MODE == 0 || k < 128)
                ? __half2float(g.A1[(size_t)row * 128 + (k & 127)])
                : __half2float(g.A2[(size_t)row * 128 + (k - 128)]);
            acc = fmaf(a, __half2float(g.Wt[(size_t)cb * Kpad + k]), acc);
        }
        float v = fmaxf(acc + g.bias[cb], 0.f);
        if (masked) v = 0.f;
        g.C[(size_t)row * 128 + cb] = __float2half(v);
    }
#endif
}

// ---------------------------------------------------------------------------
// Input GEMM (tf32, K=67 pad 96, fp32 A built from emb/coords, fp16 C).
// M=256, 256 threads, 2-stage cp.async ring, chunks of 32 fp32.
// ---------------------------------------------------------------------------
#define STAGE_IN     49152            // 32KB A + 16KB W (fp32, 32-float rows)
#define SMEM_IN      (1024 + 2 * STAGE_IN)

struct GI {
    const float* emb; const int* types; const float* coords;
    const float* Wt; const float* bias;
    const unsigned char* maskB;
    __half* C;
};

#if TC_AVAIL
__device__ __forceinline__ void stage_in(const GI& g, uint32_t bufA,
                                         uint32_t bufW, int block_row,
                                         int t, int tid) {
#pragma unroll
    for (int it = 0; it < 4; it++) {               // W: 1024 slots
        int idx = tid + it * 256;
        int r = idx >> 3, c4 = idx & 7;
        uint32_t dst = bufW + SW128((uint32_t)(r * 128 + c4 * 16));
        cp16(dst, g.Wt + (size_t)r * 96 + t * 32 + c4 * 4);
    }
#pragma unroll
    for (int it = 0; it < 8; it++) {               // A: 2048 slots
        int idx = tid + it * 256;
        int r = idx >> 3, c4 = idx & 7;
        int gr = block_row + r;
        uint32_t dst = bufA + SW128((uint32_t)(r * 128 + c4 * 16));
        if (t < 2) {
            cp16(dst, g.emb + (size_t)g.types[gr] * 64 + t * 32 + c4 * 4);
        } else {
            float4 v = make_float4(0.f, 0.f, 0.f, 0.f);
            if (c4 == 0) {
                v.x = g.coords[gr * 3];
                v.y = g.coords[gr * 3 + 1];
                v.z = g.coords[gr * 3 + 2];
            }
            sts4(dst, v);
        }
    }
    cp_commit();
}
#endif

__global__ void __launch_bounds__(256) k_gemm_in(GI g) {
#if TC_AVAIL
    extern __shared__ __align__(1024) char smem[];
    const uint32_t sb = smem_u32(smem);
    const int tid = threadIdx.x;
    const int wid = tid >> 5;
    const int lid = tid & 31;
    const int block_row = blockIdx.x * 256;

    if (wid == 0) {
        asm volatile(
            "tcgen05.alloc.cta_group::1.sync.aligned.shared::cta.b32 [%0], %1;"
            :: "r"(sb), "r"(256u) : "memory");
        asm volatile("tcgen05.relinquish_alloc_permit.cta_group::1.sync.aligned;");
    }
    if (tid == 0) { mbar_init(sb + 8, 1); mbar_init(sb + 16, 1); }
    __syncthreads();
    uint32_t tmem;
    asm volatile("ld.shared.b32 %0, [%1];" : "=r"(tmem) : "r"(sb));

    const int nt = 3;                              // Kpad 96 fp32
    const uint32_t bufA0 = sb + 1024;
    const uint32_t bufW0 = bufA0 + 32768;

    stage_in(g, bufA0, bufW0, block_row, 0, tid);
    stage_in(g, bufA0 + STAGE_IN, bufW0 + STAGE_IN, block_row, 1, tid);

    for (int t = 0; t < nt; t++) {
        const int b = t & 1;
        if (t < nt - 1) cp_wait1(); else cp_wait0();
        __syncthreads();

        if (tid == 0) {
            asm volatile("fence.proxy.async.shared::cta;" ::: "memory");
            uint64_t ad0 = mk_desc(bufA0 + b * STAGE_IN);
            uint64_t ad1 = mk_desc(bufA0 + b * STAGE_IN + 16384);
            uint64_t bd  = mk_desc(bufW0 + b * STAGE_IN);
#pragma unroll
            for (int j = 0; j < 4; j++) {          // 4 x K=8 tf32 steps = K 32
                uint32_t en = (t > 0 || j > 0) ? 1u : 0u;
                mma_tf32_ss(tmem,       ad0 + j * 2, bd + j * 2, en);
                mma_tf32_ss(tmem + 128, ad1 + j * 2, bd + j * 2, en);
            }
            tc_commit(sb + 8 + b * 8);
        }

        if (t + 2 < nt) {
            mbar_wait(sb + 8 + b * 8, (t >> 1) & 1);
            stage_in(g, bufA0 + b * STAGE_IN, bufW0 + b * STAGE_IN,
                     block_row, t + 2, tid);
        }
    }

    mbar_wait(sb + 8 + ((nt - 1) & 1) * 8, ((nt - 1) >> 1) & 1);
    asm volatile("tcgen05.fence::after_thread_sync;" ::: "memory");

    const int blk = wid >> 2;
    const int sp  = wid & 3;
    const int m   = block_row + blk * 128 + sp * 32 + lid;
    const bool masked = (g.maskB[m] != 0);
#pragma unroll
    for (int cb = 0; cb < 128; cb += 32) {
        uint32_t r32[32];
        TC_LD_X32(r32, tmem + blk * 128 + cb);
        asm volatile("tcgen05.wait::ld.sync.aligned;" ::: "memory");
#pragma unroll
        for (int j = 0; j < 32; j += 8) {
            float f[8];
#pragma unroll
            for (int i = 0; i < 8; i++) {
                float v = __uint_as_float(r32[j + i]) + g.bias[cb + j + i];
                v = fmaxf(v, 0.f);
                if (masked) v = 0.f;
                f[i] = v;
            }
            uint4 o;
            o.x = pack2(f[0], f[1]); o.y = pack2(f[2], f[3]);
            o.z = pack2(f[4], f[5]); o.w = pack2(f[6], f[7]);
            *(uint4*)(g.C + (size_t)m * 128 + cb + j) = o;
        }
    }

    __syncthreads();
    if (wid == 0) {
        asm volatile("tcgen05.dealloc.cta_group::1.sync.aligned.b32 %0, %1;"
                     :: "r"(tmem), "r"(256u));
    }
#else
    const int row = blockIdx.x * 256 + threadIdx.x;
    const bool masked = (g.maskB[row] != 0);
    int ty = g.types[row];
#pragma unroll 1
    for (int cb = 0; cb < 128; cb++) {
        float acc = 0.f;
        for (int k = 0; k < 64; k++)
            acc = fmaf(g.emb[(size_t)ty * 64 + k], g.Wt[(size_t)cb * 96 + k], acc);
        for (int k = 64; k < 67; k++)
            acc = fmaf(g.coords[row * 3 + (k - 64)], g.Wt[(size_t)cb * 96 + k], acc);
        float v = fmaxf(acc + g.bias[cb], 0.f);
        if (masked) v = 0.f;
        g.C[(size_t)row * 128 + cb] = __float2half(v);
    }
#endif
}

// ---------------------------------------------------------------------------
// Coupling dual fp16 GEMM + fused final epilogue. M=128, 128 threads.
// A = [h | cond_coords] fp16, Kpad 192 (3 chunks of 64).
// ---------------------------------------------------------------------------
#define CPL_HDR      8192
#define CPL_STAGE    49152           // 16KB A + 16KB Ws + 16KB Wh
#define SMEM_CPL     (CPL_HDR + 2 * CPL_STAGE)

struct CPH {
    const __half* A1; const float* coords;
    const __half* Wse; const __half* Whe;
    const float* bse; const float* bhe;
    const float* Ws2; const float* bs2;
    const float* Wh2; const float* bh2;
    const unsigned char* maskB;
    float* out; float* logdet;
};

__global__ void __launch_bounds__(128) k_gemm_cpl(CPH g) {
#if TC_AVAIL
    extern __shared__ __align__(1024) char smem[];
    const uint32_t sb = smem_u32(smem);
    float* smf = (float*)smem;
    const int tid = threadIdx.x;
    const int wid = tid >> 5;
    const int lid = tid & 31;
    const int block_row = blockIdx.x * 128;

    if (wid == 0) {
        asm volatile(
            "tcgen05.alloc.cta_group::1.sync.aligned.shared::cta.b32 [%0], %1;"
            :: "r"(sb), "r"(256u) : "memory");
        asm volatile("tcgen05.relinquish_alloc_permit.cta_group::1.sync.aligned;");
    }
    if (tid == 0) { mbar_init(sb + 8, 1); mbar_init(sb + 16, 1); }
    for (int i = tid; i < 384; i += 128) {
        smf[16 + i]  = g.Ws2[i];
        smf[400 + i] = g.Wh2[i];
    }
    smf[784 + tid] = g.bse[tid];
    smf[912 + tid] = g.bhe[tid];
    __syncthreads();
    uint32_t tmem;
    asm volatile("ld.shared.b32 %0, [%1];" : "=r"(tmem) : "r"(sb));

    const int nt = 3;                   // Kpad 192 fp16

    // stage helper (inline): chunk t into buffer b
    auto stage = [&](int t, int b) {
        uint32_t base = sb + CPL_HDR + b * CPL_STAGE;
#pragma unroll
        for (int it = 0; it < 24; it++) {
            int idx = tid + it * 128;            // 0..3071
            int sec = idx >> 10;                 // 0=A 1=Ws 2=Wh
            int w   = idx & 1023;
            int r   = w >> 3;
            int c4  = w & 7;
            uint32_t dst = base + sec * 16384 + SW128((uint32_t)(r * 128 + c4 * 16));
            if (sec == 0) {
                if (t < 2) {
                    cp16(dst, g.A1 + (size_t)(block_row + r) * 128 + t * 64 + c4 * 8);
                } else {
                    uint4 o = make_uint4(0u, 0u, 0u, 0u);
                    if (c4 == 0) {
                        int gr = block_row + r;
                        bool cm = ((gr & 1) == 0) && (g.maskB[gr] == 0);
                        float c0 = cm ? 0.f : g.coords[gr * 3];
                        float c1 = cm ? 0.f : g.coords[gr * 3 + 1];
                        float c2 = cm ? 0.f : g.coords[gr * 3 + 2];
                        o.x = pack2(c0, c1);
                        o.y = pack2(c2, 0.f);
                    }
                    sts4u(dst, o);
                }
            } else if (sec == 1) {
                cp16(dst, g.Wse + (size_t)r * 192 + t * 64 + c4 * 8);
            } else {
                cp16(dst, g.Whe + (size_t)r * 192 + t * 64 + c4 * 8);
            }
        }
        cp_commit();
    };

    stage(0, 0);
    stage(1, 1);

    for (int t = 0; t < nt; t++) {
        const int b = t & 1;
        if (t < nt - 1) cp_wait1(); else cp_wait0();
        __syncthreads();

        if (tid == 0) {
            asm volatile("fence.proxy.async.shared::cta;" ::: "memory");
            uint32_t base = sb + CPL_HDR + b * CPL_STAGE;
            uint64_t ad = mk_desc(base);
            uint64_t sd = mk_desc(base + 16384);
            uint64_t hd = mk_desc(base + 32768);
#pragma unroll
            for (int j = 0; j < 4; j++) {
                uint32_t en = (t > 0 || j > 0) ? 1u : 0u;
                mma_f16_ss(tmem,       ad + j * 2, sd + j * 2, en);
                mma_f16_ss(tmem + 128, ad + j * 2, hd + j * 2, en);
            }
            tc_commit(sb + 8 + b * 8);
        }

        if (t + 2 < nt) {
            mbar_wait(sb + 8 + b * 8, (t >> 1) & 1);
            stage(t + 2, b);
        }
    }

    mbar_wait(sb + 8 + ((nt - 1) & 1) * 8, ((nt - 1) >> 1) & 1);
    asm volatile("tcgen05.fence::after_thread_sync;" ::: "memory");

    const int m = block_row + wid * 32 + lid;
    float raw[3] = {0.f, 0.f, 0.f};
    float shf[3] = {0.f, 0.f, 0.f};
#pragma unroll
    for (int cb = 0; cb < 128; cb += 32) {
        uint32_t rs[32], rh[32];
        TC_LD_X32(rs, tmem + cb);
        TC_LD_X32(rh, tmem + 128 + cb);
        asm volatile("tcgen05.wait::ld.sync.aligned;" ::: "memory");
#pragma unroll
        for (int k = 0; k < 32; k++) {
            int col = cb + k;
            float sv = fmaxf(__uint_as_float(rs[k]) + smf[784 + col], 0.f);
            float hv = fmaxf(__uint_as_float(rh[k]) + smf[912 + col], 0.f);
#pragma unroll
            for (int c = 0; c < 3; c++) {
                raw[c] = fmaf(sv, smf[16 + col * 3 + c],  raw[c]);
                shf[c] = fmaf(hv, smf[400 + col * 3 + c], shf[c]);
            }
        }
    }

    bool cm = ((m & 1) == 0) && (g.maskB[m] == 0);   // PHASE = 0
    float ld = 0.f;
#pragma unroll
    for (int c = 0; c < 3; c++) {
        float r = raw[c] + g.bs2[c];
        float s = shf[c] + g.bh2[c];
        float ls = cm ? tanhf(r) * 2.f : 0.f;
        ld += ls;
        float coord = g.coords[m * 3 + c];
        g.out[m * 3 + c] = cm ? (expf(ls) * coord + s) : coord;
    }
#pragma unroll
    for (int o = 16; o > 0; o >>= 1)
        ld += __shfl_xor_sync(0xFFFFFFFFu, ld, o);
    if (lid == 0) atomicAdd(&g.logdet[m >> 13], ld);

    __syncthreads();
    if (wid == 0) {
        asm volatile("tcgen05.dealloc.cta_group::1.sync.aligned.b32 %0, %1;"
                     :: "r"(tmem), "r"(256u));
    }
#else
    const int m = blockIdx.x * 128 + threadIdx.x;
    bool cm = ((m & 1) == 0) && (g.maskB[m] == 0);
    float raw[3], shf[3];
#pragma unroll
    for (int c = 0; c < 3; c++) { raw[c] = g.bs2[c]; shf[c] = g.bh2[c]; }
    for (int n = 0; n < 128; n++) {
        float accs = g.bse[n], acch = g.bhe[n];
        for (int k = 0; k < 128; k++) {
            float a = __half2float(g.A1[(size_t)m * 128 + k]);
            accs = fmaf(a, __half2float(g.Wse[n * 192 + k]), accs);
            acch = fmaf(a, __half2float(g.Whe[n * 192 + k]), acch);
        }
        for (int k = 128; k < 131; k++) {
            float a = cm ? 0.f : g.coords[m * 3 + (k - 128)];
            accs = fmaf(a, __half2float(g.Wse[n * 192 + k]), accs);
            acch = fmaf(a, __half2float(g.Whe[n * 192 + k]), acch);
        }
        accs = fmaxf(accs, 0.f); acch = fmaxf(acch, 0.f);
#pragma unroll
        for (int c = 0; c < 3; c++) {
            raw[c] = fmaf(accs, g.Ws2[n * 3 + c], raw[c]);
            shf[c] = fmaf(acch, g.Wh2[n * 3 + c], shf[c]);
        }
    }
    float ld = 0.f;
#pragma unroll
    for (int c = 0; c < 3; c++) {
        float ls = cm ? tanhf(raw[c]) * 2.f : 0.f;
        ld += ls;
        float coord = g.coords[m * 3 + c];
        g.out[m * 3 + c] = cm ? (expf(ls) * coord + shf[c]) : coord;
    }
    atomicAdd(&g.logdet[m >> 13], ld);
#endif
}

// ---------------------------------------------------------------------------
// Host launcher. Index 3 = fp16 msg GEMM layer 0 (ncu profile target).
// ---------------------------------------------------------------------------
extern "C" void kernel_launch(void* const* d_in, const int* in_sizes, int n_in,
                              void* d_out, int out_size) {
    const float*         coords = (const float*)d_in[0];
    const int*           types  = (const int*)  d_in[1];
    const int*           adj    = (const int*)  d_in[2];
    const int*           ebi    = (const int*)  d_in[3];
    const unsigned char* maskB  = (const unsigned char*)d_in[4];
    const float* emb   = (const float*)d_in[5];
    const float* W_in  = (const float*)d_in[6];
    const float* b_in  = (const float*)d_in[7];
    const float* msg_W = (const float*)d_in[8];
    const float* msg_b = (const float*)d_in[9];
    const float* upd_W = (const float*)d_in[10];
    const float* upd_b = (const float*)d_in[11];
    const float* W_out = (const float*)d_in[12];
    const float* b_out = (const float*)d_in[13];
    const float* Ws1   = (const float*)d_in[14];
    const float* bs1   = (const float*)d_in[15];
    const float* Ws2   = (const float*)d_in[16];
    const float* bs2   = (const float*)d_in[17];
    const float* Wh1   = (const float*)d_in[18];
    const float* bh1   = (const float*)d_in[19];
    const float* Wh2   = (const float*)d_in[20];
    const float* bh2   = (const float*)d_in[21];

    float* out    = (float*)d_out;
    float* logdet = out + (size_t)BN_ * 3;

    __half *h, *b1, *b2, *wth;
    float *wt;
    int *off, *part, *cur, *srcl;
    cudaGetSymbolAddress((void**)&h,    g_h);
    cudaGetSymbolAddress((void**)&b1,   g_b1);
    cudaGetSymbolAddress((void**)&b2,   g_b2);
    cudaGetSymbolAddress((void**)&wt,   g_wt);
    cudaGetSymbolAddress((void**)&wth,  g_wth);
    cudaGetSymbolAddress((void**)&off,  g_off);
    cudaGetSymbolAddress((void**)&part, g_part);
    cudaGetSymbolAddress((void**)&cur,  g_cur);
    cudaGetSymbolAddress((void**)&srcl, g_srcl);

    cudaFuncSetAttribute(k_gemm_f16<0>, cudaFuncAttributeMaxDynamicSharedMemorySize, SMEM_F16);
    cudaFuncSetAttribute(k_gemm_f16<1>, cudaFuncAttributeMaxDynamicSharedMemorySize, SMEM_F16);
    cudaFuncSetAttribute(k_gemm_in,     cudaFuncAttributeMaxDynamicSharedMemorySize, SMEM_IN);
    cudaFuncSetAttribute(k_gemm_cpl,    cudaFuncAttributeMaxDynamicSharedMemorySize, SMEM_CPL);

    const int BT = 256;
    const int GB = BN_ / 256;   // 1024 CTAs per GEMM

    // 0: prep
    k_prep<<<1024, BT>>>(W_in, msg_W, upd_W, W_out, Ws1, Wh1, bs1, bh1, b_out,
                         wt, wth, off, logdet);
    // 1: hist
    k_hist<<<E_ / BT, BT>>>(adj, ebi, off);
    // 2: input layer (tf32, fp16 out)
    GI gi{emb, types, coords, wt + O_WIN, b_in, maskB, h};
    k_gemm_in<<<GB, 256, SMEM_IN>>>(gi);
    // 3: msg GEMM layer 0  <-- ncu profile target
    GH gm0{h, 0, wth + H_MSG0, msg_b, 0, b1};
    k_gemm_f16<0><<<GB, 256, SMEM_F16>>>(gm0);
    // 4-6: finish CSR
    k_scanA<<<512, 512>>>(off, part);
    k_scanB<<<512, 512>>>(off, part, cur);
    k_place<<<E_ / BT, BT>>>(adj, ebi, cur, srcl);
    // 7: gather layer 0
    k_gather<<<BN_ / 8, BT>>>(b1, off, srcl, b2);
    // 8: upd layer 0
    GH gu0{h, b2, wth + H_UPD0, upd_b, maskB, h};
    k_gemm_f16<1><<<GB, 256, SMEM_F16>>>(gu0);
    // 9: msg GEMM layer 1
    GH gm1{h, 0, wth + H_MSG1, msg_b + 128, 0, b1};
    k_gemm_f16<0><<<GB, 256, SMEM_F16>>>(gm1);
    // 10: gather layer 1
    k_gather<<<BN_ / 8, BT>>>(b1, off, srcl, b2);
    // 11: upd layer 1
    GH gu1{h, b2, wth + H_UPD1, upd_b + 128, maskB, h};
    k_gemm_f16<1><<<GB, 256, SMEM_F16>>>(gu1);

    // 12: fused coupling (dual fp16 GEMM + final epilogue)
    CPH c{h, coords, wth + H_WSE, wth + H_WHE, wt + O_BSE, wt + O_BHE,
          Ws2, bs2, Wh2, bh2, maskB, out, logdet};
    k_gemm_cpl<<<BN_ / 128, 128, SMEM_CPL>>>(c);
}

// round 12
// speedup vs baseline: 7.8953x; 1.1134x over previous
#include <cuda_runtime.h>
#include <cuda_fp16.h>
#include <cstdint>
#include <math.h>
#include <stddef.h>

// Problem constants
#define B_   32
#define N_   8192
#define E_   1048576
#define BN_  (B_ * N_)          // 262144
#define L_   2

// ---------------------------------------------------------------------------
// Arch-feature gate (tcgen05 only exists on sm_100a/sm_103a passes)
// ---------------------------------------------------------------------------
#if defined(__CUDA_ARCH_FEAT_SM103_ALL) || defined(__CUDA_ARCH_FEAT_SM100_ALL)
#  define TC_AVAIL 1
#endif
#ifndef TC_AVAIL
#  ifdef __CUDA_ARCH_HAS_FEATURE__
#    if __CUDA_ARCH_HAS_FEATURE__(SM103_ALL) || __CUDA_ARCH_HAS_FEATURE__(SM100_ALL)
#      define TC_AVAIL 1
#    endif
#  endif
#endif
#ifndef TC_AVAIL
#  define TC_AVAIL 0
#endif

// ---------------------------------------------------------------------------
// Scratch (static device globals)
// ---------------------------------------------------------------------------
static __device__ __align__(16) __half g_h [(size_t)BN_ * 128];
static __device__ __align__(16) __half g_b1[(size_t)BN_ * 128];   // msg_all
static __device__ __align__(16) __half g_b2[(size_t)BN_ * 128];   // agg
static __device__ __align__(16) float  g_wt [12544];              // fp32 W_in^T + bse/bhe
static __device__ __align__(16) __half g_wth[147456];             // fp16 weights
static __device__ int g_off [BN_ + 1];
static __device__ int g_part[512];
static __device__ int g_cur [BN_];
static __device__ int g_srcl[E_];

// g_wt fp32 offsets
#define O_WIN   0        // 128 x 96 (K=67 pad)
#define O_BSE   12288
#define O_BHE   12416
// g_wth half offsets
#define H_MSG0  0        // 128x128
#define H_MSG1  16384
#define H_UPD0  32768    // 128x256
#define H_UPD1  65536
#define H_WSE   98304    // 128x192 (K=131 pad)
#define H_WHE   122880

// ---------------------------------------------------------------------------
// Helpers
// ---------------------------------------------------------------------------
__device__ __forceinline__ uint32_t smem_u32(const void* p) {
    uint32_t a;
    asm("{ .reg .u64 t; cvta.to.shared.u64 t, %1; cvt.u32.u64 %0, t; }"
        : "=r"(a) : "l"(p));
    return a;
}

#define SW128(o) ((o) ^ (((o) >> 3) & 0x70))

__device__ __forceinline__ void cp16(uint32_t dst, const void* src) {
    asm volatile("cp.async.cg.shared.global [%0], [%1], 16;"
                 :: "r"(dst), "l"(src) : "memory");
}
__device__ __forceinline__ void cp_commit() {
    asm volatile("cp.async.commit_group;" ::: "memory");
}
__device__ __forceinline__ void cp_wait1() {
    asm volatile("cp.async.wait_group 1;" ::: "memory");
}
__device__ __forceinline__ void cp_wait0() {
    asm volatile("cp.async.wait_group 0;" ::: "memory");
}
__device__ __forceinline__ void sts4(uint32_t dst, float4 v) {
    asm volatile("st.shared.v4.f32 [%0], {%1, %2, %3, %4};"
                 :: "r"(dst), "f"(v.x), "f"(v.y), "f"(v.z), "f"(v.w) : "memory");
}
__device__ __forceinline__ void sts4u(uint32_t dst, uint4 v) {
    asm volatile("st.shared.v4.u32 [%0], {%1, %2, %3, %4};"
                 :: "r"(dst), "r"(v.x), "r"(v.y), "r"(v.z), "r"(v.w) : "memory");
}
__device__ __forceinline__ uint32_t pack2(float a, float b) {
    __half2 h = __floats2half2_rn(a, b);
    return *reinterpret_cast<uint32_t*>(&h);
}

#if TC_AVAIL
__device__ __forceinline__ uint64_t mk_desc(uint32_t addr) {
    // SW128, version=1 (Blackwell), LBO=1, SBO=64 (K-major)
    const uint64_t BASE = (2ULL << 61) | (1ULL << 46) | (64ULL << 32) | (1ULL << 16);
    return BASE | ((uint64_t)(addr >> 4) & 0x3FFF);
}

// tf32: acc=F32, atype=btype=TF32(2), N=128, M=128
#define IDESC_TF32 ((1u << 4) | (2u << 7) | (2u << 10) | (16u << 17) | (8u << 24))
// fp16: acc=F32, atype=btype=FP16(0), N=128, M=128
#define IDESC_F16  ((1u << 4) | (16u << 17) | (8u << 24))

__device__ __forceinline__ void mma_tf32_ss(uint32_t d, uint64_t a, uint64_t b,
                                            uint32_t en) {
    asm volatile(
        "{\n\t.reg .pred p;\n\t"
        "setp.ne.u32 p, %4, 0;\n\t"
        "tcgen05.mma.cta_group::1.kind::tf32 [%0], %1, %2, %3, p;\n\t}"
        :: "r"(d), "l"(a), "l"(b), "r"(IDESC_TF32), "r"(en) : "memory");
}
__device__ __forceinline__ void mma_f16_ss(uint32_t d, uint64_t a, uint64_t b,
                                           uint32_t en) {
    asm volatile(
        "{\n\t.reg .pred p;\n\t"
        "setp.ne.u32 p, %4, 0;\n\t"
        "tcgen05.mma.cta_group::1.kind::f16 [%0], %1, %2, %3, p;\n\t}"
        :: "r"(d), "l"(a), "l"(b), "r"(IDESC_F16), "r"(en) : "memory");
}

__device__ __forceinline__ void tc_commit(uint32_t mbar) {
    asm volatile(
        "tcgen05.commit.cta_group::1.mbarrier::arrive::one.shared::cluster.b64 [%0];"
        :: "r"(mbar) : "memory");
}

#define TC_LD_X32(r, addr)                                                     \
    asm volatile(                                                              \
        "tcgen05.ld.sync.aligned.32x32b.x32.b32 "                              \
        "{%0, %1, %2, %3, %4, %5, %6, %7, "                                    \
        " %8, %9, %10, %11, %12, %13, %14, %15, "                              \
        " %16, %17, %18, %19, %20, %21, %22, %23, "                            \
        " %24, %25, %26, %27, %28, %29, %30, %31}, [%32];"                     \
        : "=r"((r)[0]),  "=r"((r)[1]),  "=r"((r)[2]),  "=r"((r)[3]),           \
          "=r"((r)[4]),  "=r"((r)[5]),  "=r"((r)[6]),  "=r"((r)[7]),           \
          "=r"((r)[8]),  "=r"((r)[9]),  "=r"((r)[10]), "=r"((r)[11]),          \
          "=r"((r)[12]), "=r"((r)[13]), "=r"((r)[14]), "=r"((r)[15]),          \
          "=r"((r)[16]), "=r"((r)[17]), "=r"((r)[18]), "=r"((r)[19]),          \
          "=r"((r)[20]), "=r"((r)[21]), "=r"((r)[22]), "=r"((r)[23]),          \
          "=r"((r)[24]), "=r"((r)[25]), "=r"((r)[26]), "=r"((r)[27]),          \
          "=r"((r)[28]), "=r"((r)[29]), "=r"((r)[30]), "=r"((r)[31])           \
        : "r"(addr))
#endif  // TC_AVAIL

__device__ __forceinline__ void mbar_init(uint32_t a, uint32_t cnt) {
    asm volatile("mbarrier.init.shared.b64 [%0], %1;" :: "r"(a), "r"(cnt) : "memory");
}
__device__ __forceinline__ void mbar_wait(uint32_t a, uint32_t parity) {
    asm volatile(
        "{\n\t.reg .pred P;\n"
        "WL%=:\n\t"
        "mbarrier.try_wait.parity.acquire.cta.shared::cta.b64 P, [%0], %1, 0x989680;\n\t"
        "@P bra WD%=;\n\t"
        "bra WL%=;\n"
        "WD%=:\n\t}"
        :: "r"(a), "r"(parity) : "memory");
}

// ---------------------------------------------------------------------------
// k_prep: fp32 W_in^T + fused bse/bhe; fp16 weight transposes; zeros.
// ---------------------------------------------------------------------------
__global__ void k_prep(const float* __restrict__ W_in,
                       const float* __restrict__ msg_W,
                       const float* __restrict__ upd_W,
                       const float* __restrict__ W_out,
                       const float* __restrict__ Ws1,
                       const float* __restrict__ Wh1,
                       const float* __restrict__ bs1,
                       const float* __restrict__ bh1,
                       const float* __restrict__ b_out,
                       float* __restrict__ wt,
                       __half* __restrict__ wth,
                       int* __restrict__ off,
                       float* __restrict__ logdet) {
    const int TOTAL = 12544 + 147456 + (BN_ + 1) + 32;
    for (int idx = blockIdx.x * blockDim.x + threadIdx.x; idx < TOTAL;
         idx += gridDim.x * blockDim.x) {
        if (idx < 12288) {                       // W_in^T, K=67 pad 96
            int n = idx / 96, k = idx - n * 96;
            wt[idx] = (k < 67) ? W_in[k * 128 + n] : 0.f;
        } else if (idx < 12416) {                // bse
            int n = idx - 12288;
            float v = bs1[n];
            for (int q = 0; q < 128; q++)
                v = fmaf(b_out[q], Ws1[q * 128 + n], v);
            wt[idx] = v;
        } else if (idx < 12544) {                // bhe
            int n = idx - 12416;
            float v = bh1[n];
            for (int q = 0; q < 128; q++)
                v = fmaf(b_out[q], Wh1[q * 128 + n], v);
            wt[idx] = v;
        } else {
            int j = idx - 12544;
            if (j < 32768) {                     // msg_W^T x2
                int l = j >> 14, r = j & 16383;
                int n = r >> 7, k = r & 127;
                wth[j] = __float2half(msg_W[l * 16384 + k * 128 + n]);
            } else if (j < 98304) {              // upd_W^T x2 (K=256)
                int j2 = j - 32768;
                int l = j2 >> 15, r = j2 & 32767;
                int n = r >> 8, k = r & 255;
                wth[j] = __float2half(upd_W[l * 32768 + k * 128 + n]);
            } else if (j < 122880) {             // Wse^T fused, Kpad 192
                int j2 = j - 98304;
                int n = j2 / 192, k = j2 - n * 192;
                float v = 0.f;
                if (k < 128) {
                    for (int q = 0; q < 128; q++)
                        v = fmaf(W_out[k * 128 + q], Ws1[q * 128 + n], v);
                } else if (k < 131) {
                    v = Ws1[k * 128 + n];
                }
                wth[j] = __float2half(v);
            } else if (j < 147456) {             // Whe^T fused, Kpad 192
                int j2 = j - 122880;
                int n = j2 / 192, k = j2 - n * 192;
                float v = 0.f;
                if (k < 128) {
                    for (int q = 0; q < 128; q++)
                        v = fmaf(W_out[k * 128 + q], Wh1[q * 128 + n], v);
                } else if (k < 131) {
                    v = Wh1[k * 128 + n];
                }
                wth[j] = __float2half(v);
            } else if (j < 147456 + BN_ + 1) {
                off[j - 147456] = 0;
            } else {
                logdet[j - (147456 + BN_ + 1)] = 0.f;
            }
        }
    }
}

// ---------------------------------------------------------------------------
// CSR build: hist -> scanA -> scanB -> place
// ---------------------------------------------------------------------------
__global__ void k_hist(const int* __restrict__ adj, const int* __restrict__ ebi,
                       int* __restrict__ deg) {
    int e = blockIdx.x * blockDim.x + threadIdx.x;
    if (e >= E_) return;
    int dst = ebi[e] * N_ + adj[2 * e + 1];
    atomicAdd(&deg[dst], 1);
}

__global__ void k_scanA(int* __restrict__ off, int* __restrict__ part) {
    __shared__ int s[512];
    int t = threadIdx.x;
    int i = blockIdx.x * 512 + t;
    int v = off[i];
    s[t] = v; __syncthreads();
    for (int d = 1; d < 512; d <<= 1) {
        int x = (t >= d) ? s[t - d] : 0;
        __syncthreads();
        s[t] += x;
        __syncthreads();
    }
    off[i] = s[t] - v;
    if (t == 511) part[blockIdx.x] = s[t];
}

__global__ void k_scanB(int* __restrict__ off, const int* __restrict__ part,
                        int* __restrict__ cur) {
    __shared__ int s[512];
    int t = threadIdx.x, b = blockIdx.x;
    s[t] = part[t]; __syncthreads();
    for (int d = 1; d < 512; d <<= 1) {
        int x = (t >= d) ? s[t - d] : 0;
        __syncthreads();
        s[t] += x;
        __syncthreads();
    }
    int prefix = (b == 0) ? 0 : s[b - 1];
    int i = b * 512 + t;
    int v = off[i] + prefix;
    off[i] = v;
    cur[i] = v;
    if (b == 0 && t == 0) off[BN_] = E_;
}

__global__ void k_place(const int* __restrict__ adj, const int* __restrict__ ebi,
                        int* __restrict__ cur, int* __restrict__ srcl) {
    int e = blockIdx.x * blockDim.x + threadIdx.x;
    if (e >= E_) return;
    int b = ebi[e];
    int src = b * N_ + adj[2 * e];
    int dst = b * N_ + adj[2 * e + 1];
    int pos = atomicAdd(&cur[dst], 1);
    srcl[pos] = src;
}

// ---------------------------------------------------------------------------
// Gather (fp16): agg[d] = sum msg[src]. One warp/node, 4-way edge unroll.
// ---------------------------------------------------------------------------
__global__ void k_gather(const __half* __restrict__ msg,
                         const int* __restrict__ off,
                         const int* __restrict__ srcl,
                         __half* __restrict__ agg) {
    int warp = (blockIdx.x * blockDim.x + threadIdx.x) >> 5;
    int lane = threadIdx.x & 31;
    int s0 = off[warp], s1 = off[warp + 1];
    float a0 = 0.f, a1 = 0.f, a2 = 0.f, a3 = 0.f;
    int j = s0;
    for (; j + 4 <= s1; j += 4) {
        uint2 v0 = *((const uint2*)(msg + (size_t)srcl[j]     * 128) + lane);
        uint2 v1 = *((const uint2*)(msg + (size_t)srcl[j + 1] * 128) + lane);
        uint2 v2 = *((const uint2*)(msg + (size_t)srcl[j + 2] * 128) + lane);
        uint2 v3 = *((const uint2*)(msg + (size_t)srcl[j + 3] * 128) + lane);
        float2 f;
        f = __half22float2(*(__half2*)&v0.x); a0 += f.x; a1 += f.y;
        f = __half22float2(*(__half2*)&v0.y); a2 += f.x; a3 += f.y;
        f = __half22float2(*(__half2*)&v1.x); a0 += f.x; a1 += f.y;
        f = __half22float2(*(__half2*)&v1.y); a2 += f.x; a3 += f.y;
        f = __half22float2(*(__half2*)&v2.x); a0 += f.x; a1 += f.y;
        f = __half22float2(*(__half2*)&v2.y); a2 += f.x; a3 += f.y;
        f = __half22float2(*(__half2*)&v3.x); a0 += f.x; a1 += f.y;
        f = __half22float2(*(__half2*)&v3.y); a2 += f.x; a3 += f.y;
    }
    for (; j < s1; j++) {
        uint2 v = *((const uint2*)(msg + (size_t)srcl[j] * 128) + lane);
        float2 f;
        f = __half22float2(*(__half2*)&v.x); a0 += f.x; a1 += f.y;
        f = __half22float2(*(__half2*)&v.y); a2 += f.x; a3 += f.y;
    }
    uint2 o;
    o.x = pack2(a0, a1);
    o.y = pack2(a2, a3);
    *((uint2*)(agg + (size_t)warp * 128) + lane) = o;
}

// ===========================================================================
// FUSED GEMM kernels: phase1 produces h-tile (M=128) -> gmem + smem (fp16,
// MMA A-layout); phase2 computes msg = relu(h @ msgW + b2) -> gmem. TMEM:
// cols 0..127 = h accumulator, 128..255 = msg accumulator. smem: 1KB header
// + 64KB (phase1: 2-stage ring of A16K+W16K; phase2 reuse: hTile 32K @+0,
// msgW 32K @+32K).
// ===========================================================================
#define SMEM_FUSED   (1024 + 65536)

#if TC_AVAIL
// stage msgW (128n x 128k fp16, 2 chunks of 16KB) into sb+1024+32768
__device__ __forceinline__ void stage_msgW(uint32_t sb, int tid,
                                           const __half* msgW) {
#pragma unroll
    for (int it = 0; it < 8; it++) {
        int idx = tid + it * 256;              // 0..2047
        int chunk = idx >> 10, w = idx & 1023;
        int r = w >> 3, c4 = w & 7;
        uint32_t dst = sb + 1024 + 32768 + chunk * 16384
                     + SW128((uint32_t)(r * 128 + c4 * 16));
        cp16(dst, msgW + (size_t)r * 128 + chunk * 64 + c4 * 8);
    }
    cp_commit();
}

// epilogue1: read h accumulator (tmem cols 0..127), bias/relu/mask, write
// fp16 to gmem Ch AND smem hTile (sb+1024, 2 chunks).
__device__ __forceinline__ void epi1_store(uint32_t sb, uint32_t tmem,
                                           int wid, int lid, int block_row,
                                           const float* bias, int use_mask,
                                           const unsigned char* maskB,
                                           __half* Ch) {
    const int sp = wid & 3;
    const int ch = wid >> 2;
    const int row = sp * 32 + lid;
    const int m = block_row + row;
    const bool masked = use_mask && (maskB[m] != 0);
#pragma unroll
    for (int half = 0; half < 2; half++) {
        int cb = ch * 64 + half * 32;
        uint32_t r32[32];
        TC_LD_X32(r32, tmem + cb);
        asm volatile("tcgen05.wait::ld.sync.aligned;" ::: "memory");
#pragma unroll
        for (int j = 0; j < 32; j += 8) {
            float f[8];
#pragma unroll
            for (int i = 0; i < 8; i++) {
                float v = __uint_as_float(r32[j + i]) + bias[cb + j + i];
                v = fmaxf(v, 0.f);
                if (masked) v = 0.f;
                f[i] = v;
            }
            uint4 o;
            o.x = pack2(f[0], f[1]); o.y = pack2(f[2], f[3]);
            o.z = pack2(f[4], f[5]); o.w = pack2(f[6], f[7]);
            *(uint4*)(Ch + (size_t)m * 128 + cb + j) = o;
            uint32_t boff = (uint32_t)(((cb & 63) + j) * 2);
            sts4u(sb + 1024 + ch * 16384 + SW128((uint32_t)(row * 128) + boff), o);
        }
    }
}

// phase2: MMA msg = hTile @ msgW -> tmem+128, then epilogue to Cm.
__device__ __forceinline__ void phase2_run(uint32_t sb, uint32_t tmem,
                                           int tid, int wid, int lid,
                                           int block_row, const float* bias2,
                                           __half* Cm) {
    cp_wait0();
    __syncthreads();
    if (tid == 0) {
        asm volatile("fence.proxy.async.shared::cta;" ::: "memory");
#pragma unroll
        for (int c = 0; c < 2; c++) {
            uint64_t hd = mk_desc(sb + 1024 + c * 16384);
            uint64_t wd = mk_desc(sb + 1024 + 32768 + c * 16384);
#pragma unroll
            for (int j = 0; j < 4; j++)
                mma_f16_ss(tmem + 128, hd + j * 2, wd + j * 2,
                           (c > 0 || j > 0) ? 1u : 0u);
        }
        tc_commit(sb + 24);
    }
    mbar_wait(sb + 24, 0);
    asm volatile("tcgen05.fence::after_thread_sync;" ::: "memory");

    const int sp = wid & 3;
    const int ch = wid >> 2;
    const int m = block_row + sp * 32 + lid;
#pragma unroll
    for (int half = 0; half < 2; half++) {
        int cb = ch * 64 + half * 32;
        uint32_t r32[32];
        TC_LD_X32(r32, tmem + 128 + cb);
        asm volatile("tcgen05.wait::ld.sync.aligned;" ::: "memory");
#pragma unroll
        for (int j = 0; j < 32; j += 8) {
            float f[8];
#pragma unroll
            for (int i = 0; i < 8; i++)
                f[i] = fmaxf(__uint_as_float(r32[j + i]) + bias2[cb + j + i], 0.f);
            uint4 o;
            o.x = pack2(f[0], f[1]); o.y = pack2(f[2], f[3]);
            o.z = pack2(f[4], f[5]); o.w = pack2(f[6], f[7]);
            *(uint4*)(Cm + (size_t)m * 128 + cb + j) = o;
        }
    }
}
#endif  // TC_AVAIL

// ----- fused input layer (tf32 phase1, K=67 pad 96) + msg0 -----
struct FIN {
    const float* emb; const int* types; const float* coords;
    const float* Wt; const float* bias;
    const unsigned char* maskB;
    __half* Ch;
    const __half* msgW; const float* bias2; __half* Cm;
};

__global__ void __launch_bounds__(256) k_fused_in(FIN g) {
#if TC_AVAIL
    extern __shared__ __align__(1024) char smem[];
    const uint32_t sb = smem_u32(smem);
    const int tid = threadIdx.x;
    const int wid = tid >> 5;
    const int lid = tid & 31;
    const int block_row = blockIdx.x * 128;

    if (wid == 0) {
        asm volatile(
            "tcgen05.alloc.cta_group::1.sync.aligned.shared::cta.b32 [%0], %1;"
            :: "r"(sb), "r"(256u) : "memory");
        asm volatile("tcgen05.relinquish_alloc_permit.cta_group::1.sync.aligned;");
    }
    if (tid == 0) {
        mbar_init(sb + 8, 1); mbar_init(sb + 16, 1); mbar_init(sb + 24, 1);
    }
    __syncthreads();
    uint32_t tmem;
    asm volatile("ld.shared.b32 %0, [%1];" : "=r"(tmem) : "r"(sb));

    // phase1 staging: A 128 rows x 32 fp32 (16KB) + W 128n x 32 fp32 (16KB)
    auto stage1 = [&](int t, int s) {
        uint32_t bufA = sb + 1024 + s * 32768;
        uint32_t bufW = bufA + 16384;
#pragma unroll
        for (int it = 0; it < 4; it++) {           // W 1024 slots
            int idx = tid + it * 256;
            int r = idx >> 3, c4 = idx & 7;
            cp16(bufW + SW128((uint32_t)(r * 128 + c4 * 16)),
                 g.Wt + (size_t)r * 96 + t * 32 + c4 * 4);
        }
#pragma unroll
        for (int it = 0; it < 4; it++) {           // A 1024 slots
            int idx = tid + it * 256;
            int r = idx >> 3, c4 = idx & 7;
            int gr = block_row + r;
            uint32_t dst = bufA + SW128((uint32_t)(r * 128 + c4 * 16));
            if (t < 2) {
                cp16(dst, g.emb + (size_t)g.types[gr] * 64 + t * 32 + c4 * 4);
            } else {
                float4 v = make_float4(0.f, 0.f, 0.f, 0.f);
                if (c4 == 0) {
                    v.x = g.coords[gr * 3];
                    v.y = g.coords[gr * 3 + 1];
                    v.z = g.coords[gr * 3 + 2];
                }
                sts4(dst, v);
            }
        }
        cp_commit();
    };

    const int nt = 3;
    stage1(0, 0);
    stage1(1, 1);

    for (int t = 0; t < nt; t++) {
        const int s = t & 1;
        if (t < nt - 1) cp_wait1(); else cp_wait0();
        __syncthreads();
        if (tid == 0) {
            asm volatile("fence.proxy.async.shared::cta;" ::: "memory");
            uint64_t ad = mk_desc(sb + 1024 + s * 32768);
            uint64_t bd = mk_desc(sb + 1024 + s * 32768 + 16384);
#pragma unroll
            for (int j = 0; j < 4; j++)
                mma_tf32_ss(tmem, ad + j * 2, bd + j * 2,
                            (t > 0 || j > 0) ? 1u : 0u);
            tc_commit(sb + 8 + s * 8);
        }
        if (t + 2 < nt) {
            mbar_wait(sb + 8 + s * 8, (t >> 1) & 1);
            stage1(t + 2, s);
        }
    }

    mbar_wait(sb + 8 + ((nt - 1) & 1) * 8, ((nt - 1) >> 1) & 1);
    asm volatile("tcgen05.fence::after_thread_sync;" ::: "memory");

    // overlap msgW staging with epilogue1
    stage_msgW(sb, tid, g.msgW);
    epi1_store(sb, tmem, wid, lid, block_row, g.bias, 1, g.maskB, g.Ch);
    phase2_run(sb, tmem, tid, wid, lid, block_row, g.bias2, g.Cm);

    __syncthreads();
    if (wid == 0) {
        asm volatile("tcgen05.dealloc.cta_group::1.sync.aligned.b32 %0, %1;"
                     :: "r"(tmem), "r"(256u));
    }
#else
    // Scalar fallback (never runs on GB300).
    const int m = blockIdx.x * 128 + threadIdx.x % 128;
    if (threadIdx.x >= 128) return;
    const bool masked = (g.maskB[m] != 0);
    int ty = g.types[m];
    for (int cb = 0; cb < 128; cb++) {
        float acc = 0.f;
        for (int k = 0; k < 64; k++)
            acc = fmaf(g.emb[(size_t)ty * 64 + k], g.Wt[(size_t)cb * 96 + k], acc);
        for (int k = 64; k < 67; k++)
            acc = fmaf(g.coords[m * 3 + (k - 64)], g.Wt[(size_t)cb * 96 + k], acc);
        float v = fmaxf(acc + g.bias[cb], 0.f);
        if (masked) v = 0.f;
        g.Ch[(size_t)m * 128 + cb] = __float2half(v);
    }
    for (int cb = 0; cb < 128; cb++) {
        float acc = 0.f;
        for (int k = 0; k < 128; k++)
            acc = fmaf(__half2float(g.Ch[(size_t)m * 128 + k]),
                       __half2float(g.msgW[(size_t)cb * 128 + k]), acc);
        g.Cm[(size_t)m * 128 + cb] = __float2half(fmaxf(acc + g.bias2[cb], 0.f));
    }
#endif
}

// ----- fused upd layer (f16 phase1, K=256 concat [h|agg]) + next msg -----
struct FUP {
    const __half* A1; const __half* A2;
    const __half* Wt; const float* bias;
    const unsigned char* maskB;
    __half* Ch;
    const __half* msgW; const float* bias2; __half* Cm;
};

__global__ void __launch_bounds__(256) k_fused_upd(FUP g) {
#if TC_AVAIL
    extern __shared__ __align__(1024) char smem[];
    const uint32_t sb = smem_u32(smem);
    const int tid = threadIdx.x;
    const int wid = tid >> 5;
    const int lid = tid & 31;
    const int block_row = blockIdx.x * 128;

    if (wid == 0) {
        asm volatile(
            "tcgen05.alloc.cta_group::1.sync.aligned.shared::cta.b32 [%0], %1;"
            :: "r"(sb), "r"(256u) : "memory");
        asm volatile("tcgen05.relinquish_alloc_permit.cta_group::1.sync.aligned;");
    }
    if (tid == 0) {
        mbar_init(sb + 8, 1); mbar_init(sb + 16, 1); mbar_init(sb + 24, 1);
    }
    __syncthreads();
    uint32_t tmem;
    asm volatile("ld.shared.b32 %0, [%1];" : "=r"(tmem) : "r"(sb));

    // phase1 staging: A 128 rows x 64 halves (16KB) + W 128n x 64 halves (16KB)
    auto stage1 = [&](int t, int s) {
        uint32_t bufA = sb + 1024 + s * 32768;
        uint32_t bufW = bufA + 16384;
#pragma unroll
        for (int it = 0; it < 4; it++) {           // W
            int idx = tid + it * 256;
            int r = idx >> 3, c4 = idx & 7;
            cp16(bufW + SW128((uint32_t)(r * 128 + c4 * 16)),
                 g.Wt + (size_t)r * 256 + t * 64 + c4 * 8);
        }
#pragma unroll
        for (int it = 0; it < 4; it++) {           // A
            int idx = tid + it * 256;
            int r = idx >> 3, c4 = idx & 7;
            int gr = block_row + r;
            const __half* src = (t < 2)
                ? g.A1 + (size_t)gr * 128 + t * 64 + c4 * 8
                : g.A2 + (size_t)gr * 128 + (t - 2) * 64 + c4 * 8;
            cp16(bufA + SW128((uint32_t)(r * 128 + c4 * 16)), src);
        }
        cp_commit();
    };

    const int nt = 4;
    stage1(0, 0);
    stage1(1, 1);

    for (int t = 0; t < nt; t++) {
        const int s = t & 1;
        if (t < nt - 1) cp_wait1(); else cp_wait0();
        __syncthreads();
        if (tid == 0) {
            asm volatile("fence.proxy.async.shared::cta;" ::: "memory");
            uint64_t ad = mk_desc(sb + 1024 + s * 32768);
            uint64_t bd = mk_desc(sb + 1024 + s * 32768 + 16384);
#pragma unroll
            for (int j = 0; j < 4; j++)
                mma_f16_ss(tmem, ad + j * 2, bd + j * 2,
                           (t > 0 || j > 0) ? 1u : 0u);
            tc_commit(sb + 8 + s * 8);
        }
        if (t + 2 < nt) {
            mbar_wait(sb + 8 + s * 8, (t >> 1) & 1);
            stage1(t + 2, s);
        }
    }

    mbar_wait(sb + 8 + ((nt - 1) & 1) * 8, ((nt - 1) >> 1) & 1);
    asm volatile("tcgen05.fence::after_thread_sync;" ::: "memory");

    stage_msgW(sb, tid, g.msgW);
    epi1_store(sb, tmem, wid, lid, block_row, g.bias, 1, g.maskB, g.Ch);
    phase2_run(sb, tmem, tid, wid, lid, block_row, g.bias2, g.Cm);

    __syncthreads();
    if (wid == 0) {
        asm volatile("tcgen05.dealloc.cta_group::1.sync.aligned.b32 %0, %1;"
                     :: "r"(tmem), "r"(256u));
    }
#else
    const int m = blockIdx.x * 128 + threadIdx.x % 128;
    if (threadIdx.x >= 128) return;
    const bool masked = (g.maskB[m] != 0);
    for (int cb = 0; cb < 128; cb++) {
        float acc = 0.f;
        for (int k = 0; k < 128; k++)
            acc = fmaf(__half2float(g.A1[(size_t)m * 128 + k]),
                       __half2float(g.Wt[(size_t)cb * 256 + k]), acc);
        for (int k = 0; k < 128; k++)
            acc = fmaf(__half2float(g.A2[(size_t)m * 128 + k]),
                       __half2float(g.Wt[(size_t)cb * 256 + 128 + k]), acc);
        float v = fmaxf(acc + g.bias[cb], 0.f);
        if (masked) v = 0.f;
        g.Ch[(size_t)m * 128 + cb] = __float2half(v);
    }
    for (int cb = 0; cb < 128; cb++) {
        float acc = 0.f;
        for (int k = 0; k < 128; k++)
            acc = fmaf(__half2float(g.Ch[(size_t)m * 128 + k]),
                       __half2float(g.msgW[(size_t)cb * 128 + k]), acc);
        g.Cm[(size_t)m * 128 + cb] = __float2half(fmaxf(acc + g.bias2[cb], 0.f));
    }
#endif
}

// ---------------------------------------------------------------------------
// Standalone fp16 GEMM (upd1). 256 threads, M=256, 2-stage cp.async ring.
// MODE 1: concat [h|agg], K=256 (nt=4).
// ---------------------------------------------------------------------------
#define STAGE_F16    49152            // 32KB A (256 rows) + 16KB W
#define SMEM_F16     (1024 + 2 * STAGE_F16)

struct GH {
    const __half* A1; const __half* A2;
    const __half* Wt; const float* bias;
    const unsigned char* maskB;
    __half* C;
};

#if TC_AVAIL
__device__ __forceinline__ void stage_f16u(const GH& g, uint32_t bufA,
                                           uint32_t bufW, int block_row,
                                           int t, int tid) {
#pragma unroll
    for (int it = 0; it < 4; it++) {               // W: 1024 slots
        int idx = tid + it * 256;
        int r = idx >> 3, c4 = idx & 7;
        cp16(bufW + SW128((uint32_t)(r * 128 + c4 * 16)),
             g.Wt + (size_t)r * 256 + t * 64 + c4 * 8);
    }
#pragma unroll
    for (int it = 0; it < 8; it++) {               // A: 2048 slots (256 rows)
        int idx = tid + it * 256;
        int r = idx >> 3, c4 = idx & 7;
        int gr = block_row + r;
        const __half* src = (t < 2)
            ? g.A1 + (size_t)gr * 128 + t * 64 + c4 * 8
            : g.A2 + (size_t)gr * 128 + (t - 2) * 64 + c4 * 8;
        cp16(bufA + SW128((uint32_t)(r * 128 + c4 * 16)), src);
    }
    cp_commit();
}
#endif

__global__ void __launch_bounds__(256) k_gemm_upd(GH g) {
#if TC_AVAIL
    extern __shared__ __align__(1024) char smem[];
    const uint32_t sb = smem_u32(smem);
    const int tid = threadIdx.x;
    const int wid = tid >> 5;
    const int lid = tid & 31;
    const int block_row = blockIdx.x * 256;

    if (wid == 0) {
        asm volatile(
            "tcgen05.alloc.cta_group::1.sync.aligned.shared::cta.b32 [%0], %1;"
            :: "r"(sb), "r"(256u) : "memory");
        asm volatile("tcgen05.relinquish_alloc_permit.cta_group::1.sync.aligned;");
    }
    if (tid == 0) { mbar_init(sb + 8, 1); mbar_init(sb + 16, 1); }
    __syncthreads();
    uint32_t tmem;
    asm volatile("ld.shared.b32 %0, [%1];" : "=r"(tmem) : "r"(sb));

    const int nt = 4;
    const uint32_t bufA0 = sb + 1024;
    const uint32_t bufW0 = bufA0 + 32768;

    stage_f16u(g, bufA0, bufW0, block_row, 0, tid);
    stage_f16u(g, bufA0 + STAGE_F16, bufW0 + STAGE_F16, block_row, 1, tid);

    for (int t = 0; t < nt; t++) {
        const int b = t & 1;
        if (t < nt - 1) cp_wait1(); else cp_wait0();
        __syncthreads();
        if (tid == 0) {
            asm volatile("fence.proxy.async.shared::cta;" ::: "memory");
            uint64_t ad0 = mk_desc(bufA0 + b * STAGE_F16);
            uint64_t ad1 = mk_desc(bufA0 + b * STAGE_F16 + 16384);
            uint64_t bd  = mk_desc(bufW0 + b * STAGE_F16);
#pragma unroll
            for (int j = 0; j < 4; j++) {
                uint32_t en = (t > 0 || j > 0) ? 1u : 0u;
                mma_f16_ss(tmem,       ad0 + j * 2, bd + j * 2, en);
                mma_f16_ss(tmem + 128, ad1 + j * 2, bd + j * 2, en);
            }
            tc_commit(sb + 8 + b * 8);
        }
        if (t + 2 < nt) {
            mbar_wait(sb + 8 + b * 8, (t >> 1) & 1);
            stage_f16u(g, bufA0 + b * STAGE_F16, bufW0 + b * STAGE_F16,
                       block_row, t + 2, tid);
        }
    }

    mbar_wait(sb + 8 + ((nt - 1) & 1) * 8, ((nt - 1) >> 1) & 1);
    asm volatile("tcgen05.fence::after_thread_sync;" ::: "memory");

    const int blk = wid >> 2;
    const int sp  = wid & 3;
    const int m   = block_row + blk * 128 + sp * 32 + lid;
    const bool masked = (g.maskB[m] != 0);
#pragma unroll
    for (int cb = 0; cb < 128; cb += 32) {
        uint32_t r32[32];
        TC_LD_X32(r32, tmem + blk * 128 + cb);
        asm volatile("tcgen05.wait::ld.sync.aligned;" ::: "memory");
#pragma unroll
        for (int j = 0; j < 32; j += 8) {
            float f[8];
#pragma unroll
            for (int i = 0; i < 8; i++) {
                float v = __uint_as_float(r32[j + i]) + g.bias[cb + j + i];
                v = fmaxf(v, 0.f);
                if (masked) v = 0.f;
                f[i] = v;
            }
            uint4 o;
            o.x = pack2(f[0], f[1]); o.y = pack2(f[2], f[3]);
            o.z = pack2(f[4], f[5]); o.w = pack2(f[6], f[7]);
            *(uint4*)(g.C + (size_t)m * 128 + cb + j) = o;
        }
    }

    __syncthreads();
    if (wid == 0) {
        asm volatile("tcgen05.dealloc.cta_group::1.sync.aligned.b32 %0, %1;"
                     :: "r"(tmem), "r"(256u));
    }
#else
    const int row = blockIdx.x * 256 + threadIdx.x;
    const bool masked = (g.maskB[row] != 0);
#pragma unroll 1
    for (int cb = 0; cb < 128; cb++) {
        float acc = 0.f;
        for (int k = 0; k < 128; k++)
            acc = fmaf(__half2float(g.A1[(size_t)row * 128 + k]),
                       __half2float(g.Wt[(size_t)cb * 256 + k]), acc);
        for (int k = 0; k < 128; k++)
            acc = fmaf(__half2float(g.A2[(size_t)row * 128 + k]),
                       __half2float(g.Wt[(size_t)cb * 256 + 128 + k]), acc);
        float v = fmaxf(acc + g.bias[cb], 0.f);
        if (masked) v = 0.f;
        g.C[(size_t)row * 128 + cb] = __float2half(v);
    }
#endif
}

// ---------------------------------------------------------------------------
// Coupling dual fp16 GEMM + fused final epilogue. M=128, 128 threads.
// ---------------------------------------------------------------------------
#define CPL_HDR      8192
#define CPL_STAGE    49152           // 16KB A + 16KB Ws + 16KB Wh
#define SMEM_CPL     (CPL_HDR + 2 * CPL_STAGE)

struct CPH {
    const __half* A1; const float* coords;
    const __half* Wse; const __half* Whe;
    const float* bse; const float* bhe;
    const float* Ws2; const float* bs2;
    const float* Wh2; const float* bh2;
    const unsigned char* maskB;
    float* out; float* logdet;
};

__global__ void __launch_bounds__(128) k_gemm_cpl(CPH g) {
#if TC_AVAIL
    extern __shared__ __align__(1024) char smem[];
    const uint32_t sb = smem_u32(smem);
    float* smf = (float*)smem;
    const int tid = threadIdx.x;
    const int wid = tid >> 5;
    const int lid = tid & 31;
    const int block_row = blockIdx.x * 128;

    if (wid == 0) {
        asm volatile(
            "tcgen05.alloc.cta_group::1.sync.aligned.shared::cta.b32 [%0], %1;"
            :: "r"(sb), "r"(256u) : "memory");
        asm volatile("tcgen05.relinquish_alloc_permit.cta_group::1.sync.aligned;");
    }
    if (tid == 0) { mbar_init(sb + 8, 1); mbar_init(sb + 16, 1); }
    for (int i = tid; i < 384; i += 128) {
        smf[16 + i]  = g.Ws2[i];
        smf[400 + i] = g.Wh2[i];
    }
    smf[784 + tid] = g.bse[tid];
    smf[912 + tid] = g.bhe[tid];
    __syncthreads();
    uint32_t tmem;
    asm volatile("ld.shared.b32 %0, [%1];" : "=r"(tmem) : "r"(sb));

    const int nt = 3;                   // Kpad 192 fp16

    auto stage = [&](int t, int b) {
        uint32_t base = sb + CPL_HDR + b * CPL_STAGE;
#pragma unroll
        for (int it = 0; it < 24; it++) {
            int idx = tid + it * 128;            // 0..3071
            int sec = idx >> 10;
            int w   = idx & 1023;
            int r   = w >> 3;
            int c4  = w & 7;
            uint32_t dst = base + sec * 16384 + SW128((uint32_t)(r * 128 + c4 * 16));
            if (sec == 0) {
                if (t < 2) {
                    cp16(dst, g.A1 + (size_t)(block_row + r) * 128 + t * 64 + c4 * 8);
                } else {
                    uint4 o = make_uint4(0u, 0u, 0u, 0u);
                    if (c4 == 0) {
                        int gr = block_row + r;
                        bool cm = ((gr & 1) == 0) && (g.maskB[gr] == 0);
                        float c0 = cm ? 0.f : g.coords[gr * 3];
                        float c1 = cm ? 0.f : g.coords[gr * 3 + 1];
                        float c2 = cm ? 0.f : g.coords[gr * 3 + 2];
                        o.x = pack2(c0, c1);
                        o.y = pack2(c2, 0.f);
                    }
                    sts4u(dst, o);
                }
            } else if (sec == 1) {
                cp16(dst, g.Wse + (size_t)r * 192 + t * 64 + c4 * 8);
            } else {
                cp16(dst, g.Whe + (size_t)r * 192 + t * 64 + c4 * 8);
            }
        }
        cp_commit();
    };

    stage(0, 0);
    stage(1, 1);

    for (int t = 0; t < nt; t++) {
        const int b = t & 1;
        if (t < nt - 1) cp_wait1(); else cp_wait0();
        __syncthreads();
        if (tid == 0) {
            asm volatile("fence.proxy.async.shared::cta;" ::: "memory");
            uint32_t base = sb + CPL_HDR + b * CPL_STAGE;
            uint64_t ad = mk_desc(base);
            uint64_t sd = mk_desc(base + 16384);
            uint64_t hd = mk_desc(base + 32768);
#pragma unroll
            for (int j = 0; j < 4; j++) {
                uint32_t en = (t > 0 || j > 0) ? 1u : 0u;
                mma_f16_ss(tmem,       ad + j * 2, sd + j * 2, en);
                mma_f16_ss(tmem + 128, ad + j * 2, hd + j * 2, en);
            }
            tc_commit(sb + 8 + b * 8);
        }
        if (t + 2 < nt) {
            mbar_wait(sb + 8 + b * 8, (t >> 1) & 1);
            stage(t + 2, b);
        }
    }

    mbar_wait(sb + 8 + ((nt - 1) & 1) * 8, ((nt - 1) >> 1) & 1);
    asm volatile("tcgen05.fence::after_thread_sync;" ::: "memory");

    const int m = block_row + wid * 32 + lid;
    float raw[3] = {0.f, 0.f, 0.f};
    float shf[3] = {0.f, 0.f, 0.f};
#pragma unroll
    for (int cb = 0; cb < 128; cb += 32) {
        uint32_t rs[32], rh[32];
        TC_LD_X32(rs, tmem + cb);
        TC_LD_X32(rh, tmem + 128 + cb);
        asm volatile("tcgen05.wait::ld.sync.aligned;" ::: "memory");
#pragma unroll
        for (int k = 0; k < 32; k++) {
            int col = cb + k;
            float sv = fmaxf(__uint_as_float(rs[k]) + smf[784 + col], 0.f);
            float hv = fmaxf(__uint_as_float(rh[k]) + smf[912 + col], 0.f);
#pragma unroll
            for (int c = 0; c < 3; c++) {
                raw[c] = fmaf(sv, smf[16 + col * 3 + c],  raw[c]);
                shf[c] = fmaf(hv, smf[400 + col * 3 + c], shf[c]);
            }
        }
    }

    bool cm = ((m & 1) == 0) && (g.maskB[m] == 0);   // PHASE = 0
    float ld = 0.f;
#pragma unroll
    for (int c = 0; c < 3; c++) {
        float r = raw[c] + g.bs2[c];
        float s = shf[c] + g.bh2[c];
        float ls = cm ? tanhf(r) * 2.f : 0.f;
        ld += ls;
        float coord = g.coords[m * 3 + c];
        g.out[m * 3 + c] = cm ? (expf(ls) * coord + s) : coord;
    }
#pragma unroll
    for (int o = 16; o > 0; o >>= 1)
        ld += __shfl_xor_sync(0xFFFFFFFFu, ld, o);
    if (lid == 0) atomicAdd(&g.logdet[m >> 13], ld);

    __syncthreads();
    if (wid == 0) {
        asm volatile("tcgen05.dealloc.cta_group::1.sync.aligned.b32 %0, %1;"
                     :: "r"(tmem), "r"(256u));
    }
#else
    const int m = blockIdx.x * 128 + threadIdx.x;
    bool cm = ((m & 1) == 0) && (g.maskB[m] == 0);
    float raw[3], shf[3];
#pragma unroll
    for (int c = 0; c < 3; c++) { raw[c] = g.bs2[c]; shf[c] = g.bh2[c]; }
    for (int n = 0; n < 128; n++) {
        float accs = g.bse[n], acch = g.bhe[n];
        for (int k = 0; k < 128; k++) {
            float a = __half2float(g.A1[(size_t)m * 128 + k]);
            accs = fmaf(a, __half2float(g.Wse[n * 192 + k]), accs);
            acch = fmaf(a, __half2float(g.Whe[n * 192 + k]), acch);
        }
        for (int k = 128; k < 131; k++) {
            float a = cm ? 0.f : g.coords[m * 3 + (k - 128)];
            accs = fmaf(a, __half2float(g.Wse[n * 192 + k]), accs);
            acch = fmaf(a, __half2float(g.Whe[n * 192 + k]), acch);
        }
        accs = fmaxf(accs, 0.f); acch = fmaxf(acch, 0.f);
#pragma unroll
        for (int c = 0; c < 3; c++) {
            raw[c] = fmaf(accs, g.Ws2[n * 3 + c], raw[c]);
            shf[c] = fmaf(acch, g.Wh2[n * 3 + c], shf[c]);
        }
    }
    float ld = 0.f;
#pragma unroll
    for (int c = 0; c < 3; c++) {
        float ls = cm ? tanhf(raw[c]) * 2.f : 0.f;
        ld += ls;
        float coord = g.coords[m * 3 + c];
        g.out[m * 3 + c] = cm ? (expf(ls) * coord + shf[c]) : coord;
    }
    atomicAdd(&g.logdet[m >> 13], ld);
#endif
}

// ---------------------------------------------------------------------------
// Host launcher. Index 3 = k_fused_in (ncu profile target).
// ---------------------------------------------------------------------------
extern "C" void kernel_launch(void* const* d_in, const int* in_sizes, int n_in,
                              void* d_out, int out_size) {
    const float*         coords = (const float*)d_in[0];
    const int*           types  = (const int*)  d_in[1];
    const int*           adj    = (const int*)  d_in[2];
    const int*           ebi    = (const int*)  d_in[3];
    const unsigned char* maskB  = (const unsigned char*)d_in[4];
    const float* emb   = (const float*)d_in[5];
    const float* W_in  = (const float*)d_in[6];
    const float* b_in  = (const float*)d_in[7];
    const float* msg_W = (const float*)d_in[8];
    const float* msg_b = (const float*)d_in[9];
    const float* upd_W = (const float*)d_in[10];
    const float* upd_b = (const float*)d_in[11];
    const float* W_out = (const float*)d_in[12];
    const float* b_out = (const float*)d_in[13];
    const float* Ws1   = (const float*)d_in[14];
    const float* bs1   = (const float*)d_in[15];
    const float* Ws2   = (const float*)d_in[16];
    const float* bs2   = (const float*)d_in[17];
    const float* Wh1   = (const float*)d_in[18];
    const float* bh1   = (const float*)d_in[19];
    const float* Wh2   = (const float*)d_in[20];
    const float* bh2   = (const float*)d_in[21];

    float* out    = (float*)d_out;
    float* logdet = out + (size_t)BN_ * 3;

    __half *h, *b1, *b2, *wth;
    float *wt;
    int *off, *part, *cur, *srcl;
    cudaGetSymbolAddress((void**)&h,    g_h);
    cudaGetSymbolAddress((void**)&b1,   g_b1);
    cudaGetSymbolAddress((void**)&b2,   g_b2);
    cudaGetSymbolAddress((void**)&wt,   g_wt);
    cudaGetSymbolAddress((void**)&wth,  g_wth);
    cudaGetSymbolAddress((void**)&off,  g_off);
    cudaGetSymbolAddress((void**)&part, g_part);
    cudaGetSymbolAddress((void**)&cur,  g_cur);
    cudaGetSymbolAddress((void**)&srcl, g_srcl);

    cudaFuncSetAttribute(k_fused_in,  cudaFuncAttributeMaxDynamicSharedMemorySize, SMEM_FUSED);
    cudaFuncSetAttribute(k_fused_upd, cudaFuncAttributeMaxDynamicSharedMemorySize, SMEM_FUSED);
    cudaFuncSetAttribute(k_gemm_upd,  cudaFuncAttributeMaxDynamicSharedMemorySize, SMEM_F16);
    cudaFuncSetAttribute(k_gemm_cpl,  cudaFuncAttributeMaxDynamicSharedMemorySize, SMEM_CPL);

    const int BT = 256;

    // 0: prep
    k_prep<<<1024, BT>>>(W_in, msg_W, upd_W, W_out, Ws1, Wh1, bs1, bh1, b_out,
                         wt, wth, off, logdet);
    // 1: hist
    k_hist<<<E_ / BT, BT>>>(adj, ebi, off);
    // 2: scanA (no dependency on fused_in)
    k_scanA<<<512, 512>>>(off, part);
    // 3: fused input + msg0  <-- ncu profile target
    FIN fi{emb, types, coords, wt + O_WIN, b_in, maskB, h,
           wth + H_MSG0, msg_b, b1};
    k_fused_in<<<BN_ / 128, 256, SMEM_FUSED>>>(fi);
    // 4-5: finish CSR
    k_scanB<<<512, 512>>>(off, part, cur);
    k_place<<<E_ / BT, BT>>>(adj, ebi, cur, srcl);
    // 6: gather layer 0
    k_gather<<<BN_ / 8, BT>>>(b1, off, srcl, b2);
    // 7: fused upd0 + msg1
    FUP fu{h, b2, wth + H_UPD0, upd_b, maskB, h, wth + H_MSG1, msg_b + 128, b1};
    k_fused_upd<<<BN_ / 128, 256, SMEM_FUSED>>>(fu);
    // 8: gather layer 1
    k_gather<<<BN_ / 8, BT>>>(b1, off, srcl, b2);
    // 9: upd layer 1 (standalone)
    GH gu1{h, b2, wth + H_UPD1, upd_b + 128, maskB, h};
    k_gemm_upd<<<BN_ / 256, 256, SMEM_F16>>>(gu1);
    // 10: fused coupling (dual fp16 GEMM + final epilogue)
    CPH c{h, coords, wth + H_WSE, wth + H_WHE, wt + O_BSE, wt + O_BHE,
          Ws2, bs2, Wh2, bh2, maskB, out, logdet};
    k_gemm_cpl<<<BN_ / 128, 128, SMEM_CPL>>>(c);
}

// round 13
// speedup vs baseline: 8.5042x; 1.0771x over previous
#include <cuda_runtime.h>
#include <cuda_fp16.h>
#include <cstdint>
#include <math.h>
#include <stddef.h>

// Problem constants
#define B_   32
#define N_   8192
#define E_   1048576
#define BN_  (B_ * N_)          // 262144
#define L_   2

// ---------------------------------------------------------------------------
// Arch-feature gate (tcgen05 only exists on sm_100a/sm_103a passes)
// ---------------------------------------------------------------------------
#if defined(__CUDA_ARCH_FEAT_SM103_ALL) || defined(__CUDA_ARCH_FEAT_SM100_ALL)
#  define TC_AVAIL 1
#endif
#ifndef TC_AVAIL
#  ifdef __CUDA_ARCH_HAS_FEATURE__
#    if __CUDA_ARCH_HAS_FEATURE__(SM103_ALL) || __CUDA_ARCH_HAS_FEATURE__(SM100_ALL)
#      define TC_AVAIL 1
#    endif
#  endif
#endif
#ifndef TC_AVAIL
#  define TC_AVAIL 0
#endif

// ---------------------------------------------------------------------------
// Scratch (static device globals)
// ---------------------------------------------------------------------------
static __device__ __align__(16) __half g_h [(size_t)BN_ * 128];
static __device__ __align__(16) __half g_b1[(size_t)BN_ * 128];   // msg_all
static __device__ __align__(16) __half g_b2[(size_t)BN_ * 128];   // agg
static __device__ __align__(16) float  g_wt [12544];              // fp32 W_in^T + bse/bhe
static __device__ __align__(16) __half g_wth[147456];             // fp16 weights
static __device__ int g_off [BN_ + 1];
static __device__ int g_part[512];
static __device__ int g_cur [BN_];
static __device__ int g_srcl[E_];

// g_wt fp32 offsets
#define O_WIN   0        // 128 x 96 (K=67 pad)
#define O_BSE   12288
#define O_BHE   12416
// g_wth half offsets
#define H_MSG0  0        // 128x128
#define H_MSG1  16384
#define H_UPD0  32768    // 128x256
#define H_UPD1  65536
#define H_WSE   98304    // 128x192 (K=131 pad)
#define H_WHE   122880

// ---------------------------------------------------------------------------
// Helpers
// ---------------------------------------------------------------------------
__device__ __forceinline__ uint32_t smem_u32(const void* p) {
    uint32_t a;
    asm("{ .reg .u64 t; cvta.to.shared.u64 t, %1; cvt.u32.u64 %0, t; }"
        : "=r"(a) : "l"(p));
    return a;
}

#define SW128(o) ((o) ^ (((o) >> 3) & 0x70))

__device__ __forceinline__ void cp16(uint32_t dst, const void* src) {
    asm volatile("cp.async.cg.shared.global [%0], [%1], 16;"
                 :: "r"(dst), "l"(src) : "memory");
}
__device__ __forceinline__ void cp_commit() {
    asm volatile("cp.async.commit_group;" ::: "memory");
}
__device__ __forceinline__ void cp_wait1() {
    asm volatile("cp.async.wait_group 1;" ::: "memory");
}
__device__ __forceinline__ void cp_wait0() {
    asm volatile("cp.async.wait_group 0;" ::: "memory");
}
__device__ __forceinline__ void sts4(uint32_t dst, float4 v) {
    asm volatile("st.shared.v4.f32 [%0], {%1, %2, %3, %4};"
                 :: "r"(dst), "f"(v.x), "f"(v.y), "f"(v.z), "f"(v.w) : "memory");
}
__device__ __forceinline__ void sts4u(uint32_t dst, uint4 v) {
    asm volatile("st.shared.v4.u32 [%0], {%1, %2, %3, %4};"
                 :: "r"(dst), "r"(v.x), "r"(v.y), "r"(v.z), "r"(v.w) : "memory");
}
__device__ __forceinline__ uint32_t pack2(float a, float b) {
    __half2 h = __floats2half2_rn(a, b);
    return *reinterpret_cast<uint32_t*>(&h);
}

#if TC_AVAIL
__device__ __forceinline__ uint64_t mk_desc(uint32_t addr) {
    // SW128, version=1 (Blackwell), LBO=1, SBO=64 (K-major)
    const uint64_t BASE = (2ULL << 61) | (1ULL << 46) | (64ULL << 32) | (1ULL << 16);
    return BASE | ((uint64_t)(addr >> 4) & 0x3FFF);
}

// tf32: acc=F32, atype=btype=TF32(2), N=128, M=128
#define IDESC_TF32 ((1u << 4) | (2u << 7) | (2u << 10) | (16u << 17) | (8u << 24))
// fp16: acc=F32, atype=btype=FP16(0), N=128, M=128
#define IDESC_F16  ((1u << 4) | (16u << 17) | (8u << 24))

__device__ __forceinline__ void mma_tf32_ss(uint32_t d, uint64_t a, uint64_t b,
                                            uint32_t en) {
    asm volatile(
        "{\n\t.reg .pred p;\n\t"
        "setp.ne.u32 p, %4, 0;\n\t"
        "tcgen05.mma.cta_group::1.kind::tf32 [%0], %1, %2, %3, p;\n\t}"
        :: "r"(d), "l"(a), "l"(b), "r"(IDESC_TF32), "r"(en) : "memory");
}
__device__ __forceinline__ void mma_f16_ss(uint32_t d, uint64_t a, uint64_t b,
                                           uint32_t en) {
    asm volatile(
        "{\n\t.reg .pred p;\n\t"
        "setp.ne.u32 p, %4, 0;\n\t"
        "tcgen05.mma.cta_group::1.kind::f16 [%0], %1, %2, %3, p;\n\t}"
        :: "r"(d), "l"(a), "l"(b), "r"(IDESC_F16), "r"(en) : "memory");
}

__device__ __forceinline__ void tc_commit(uint32_t mbar) {
    asm volatile(
        "tcgen05.commit.cta_group::1.mbarrier::arrive::one.shared::cluster.b64 [%0];"
        :: "r"(mbar) : "memory");
}

#define TC_LD_X32(r, addr)                                                     \
    asm volatile(                                                              \
        "tcgen05.ld.sync.aligned.32x32b.x32.b32 "                              \
        "{%0, %1, %2, %3, %4, %5, %6, %7, "                                    \
        " %8, %9, %10, %11, %12, %13, %14, %15, "                              \
        " %16, %17, %18, %19, %20, %21, %22, %23, "                            \
        " %24, %25, %26, %27, %28, %29, %30, %31}, [%32];"                     \
        : "=r"((r)[0]),  "=r"((r)[1]),  "=r"((r)[2]),  "=r"((r)[3]),           \
          "=r"((r)[4]),  "=r"((r)[5]),  "=r"((r)[6]),  "=r"((r)[7]),           \
          "=r"((r)[8]),  "=r"((r)[9]),  "=r"((r)[10]), "=r"((r)[11]),          \
          "=r"((r)[12]), "=r"((r)[13]), "=r"((r)[14]), "=r"((r)[15]),          \
          "=r"((r)[16]), "=r"((r)[17]), "=r"((r)[18]), "=r"((r)[19]),          \
          "=r"((r)[20]), "=r"((r)[21]), "=r"((r)[22]), "=r"((r)[23]),          \
          "=r"((r)[24]), "=r"((r)[25]), "=r"((r)[26]), "=r"((r)[27]),          \
          "=r"((r)[28]), "=r"((r)[29]), "=r"((r)[30]), "=r"((r)[31])           \
        : "r"(addr))
#endif  // TC_AVAIL

__device__ __forceinline__ void mbar_init(uint32_t a, uint32_t cnt) {
    asm volatile("mbarrier.init.shared.b64 [%0], %1;" :: "r"(a), "r"(cnt) : "memory");
}
__device__ __forceinline__ void mbar_wait(uint32_t a, uint32_t parity) {
    asm volatile(
        "{\n\t.reg .pred P;\n"
        "WL%=:\n\t"
        "mbarrier.try_wait.parity.acquire.cta.shared::cta.b64 P, [%0], %1, 0x989680;\n\t"
        "@P bra WD%=;\n\t"
        "bra WL%=;\n"
        "WD%=:\n\t}"
        :: "r"(a), "r"(parity) : "memory");
}

// ---------------------------------------------------------------------------
// k_prep: fp32 W_in^T + fused bse/bhe; fp16 weight transposes; zeros.
// ---------------------------------------------------------------------------
__global__ void k_prep(const float* __restrict__ W_in,
                       const float* __restrict__ msg_W,
                       const float* __restrict__ upd_W,
                       const float* __restrict__ W_out,
                       const float* __restrict__ Ws1,
                       const float* __restrict__ Wh1,
                       const float* __restrict__ bs1,
                       const float* __restrict__ bh1,
                       const float* __restrict__ b_out,
                       float* __restrict__ wt,
                       __half* __restrict__ wth,
                       int* __restrict__ off,
                       float* __restrict__ logdet) {
    const int TOTAL = 12544 + 147456 + (BN_ + 1) + 32;
    for (int idx = blockIdx.x * blockDim.x + threadIdx.x; idx < TOTAL;
         idx += gridDim.x * blockDim.x) {
        if (idx < 12288) {                       // W_in^T, K=67 pad 96
            int n = idx / 96, k = idx - n * 96;
            wt[idx] = (k < 67) ? W_in[k * 128 + n] : 0.f;
        } else if (idx < 12416) {                // bse
            int n = idx - 12288;
            float v = bs1[n];
            for (int q = 0; q < 128; q++)
                v = fmaf(b_out[q], Ws1[q * 128 + n], v);
            wt[idx] = v;
        } else if (idx < 12544) {                // bhe
            int n = idx - 12416;
            float v = bh1[n];
            for (int q = 0; q < 128; q++)
                v = fmaf(b_out[q], Wh1[q * 128 + n], v);
            wt[idx] = v;
        } else {
            int j = idx - 12544;
            if (j < 32768) {                     // msg_W^T x2
                int l = j >> 14, r = j & 16383;
                int n = r >> 7, k = r & 127;
                wth[j] = __float2half(msg_W[l * 16384 + k * 128 + n]);
            } else if (j < 98304) {              // upd_W^T x2 (K=256)
                int j2 = j - 32768;
                int l = j2 >> 15, r = j2 & 32767;
                int n = r >> 8, k = r & 255;
                wth[j] = __float2half(upd_W[l * 32768 + k * 128 + n]);
            } else if (j < 122880) {             // Wse^T fused, Kpad 192
                int j2 = j - 98304;
                int n = j2 / 192, k = j2 - n * 192;
                float v = 0.f;
                if (k < 128) {
                    for (int q = 0; q < 128; q++)
                        v = fmaf(W_out[k * 128 + q], Ws1[q * 128 + n], v);
                } else if (k < 131) {
                    v = Ws1[k * 128 + n];
                }
                wth[j] = __float2half(v);
            } else if (j < 147456) {             // Whe^T fused, Kpad 192
                int j2 = j - 122880;
                int n = j2 / 192, k = j2 - n * 192;
                float v = 0.f;
                if (k < 128) {
                    for (int q = 0; q < 128; q++)
                        v = fmaf(W_out[k * 128 + q], Wh1[q * 128 + n], v);
                } else if (k < 131) {
                    v = Wh1[k * 128 + n];
                }
                wth[j] = __float2half(v);
            } else if (j < 147456 + BN_ + 1) {
                off[j - 147456] = 0;
            } else {
                logdet[j - (147456 + BN_ + 1)] = 0.f;
            }
        }
    }
}

// ---------------------------------------------------------------------------
// CSR build: hist -> scanA -> scanB -> place
// ---------------------------------------------------------------------------
__global__ void k_hist(const int* __restrict__ adj, const int* __restrict__ ebi,
                       int* __restrict__ deg) {
    int e = blockIdx.x * blockDim.x + threadIdx.x;
    if (e >= E_) return;
    int dst = ebi[e] * N_ + adj[2 * e + 1];
    atomicAdd(&deg[dst], 1);
}

__global__ void k_scanA(int* __restrict__ off, int* __restrict__ part) {
    __shared__ int s[512];
    int t = threadIdx.x;
    int i = blockIdx.x * 512 + t;
    int v = off[i];
    s[t] = v; __syncthreads();
    for (int d = 1; d < 512; d <<= 1) {
        int x = (t >= d) ? s[t - d] : 0;
        __syncthreads();
        s[t] += x;
        __syncthreads();
    }
    off[i] = s[t] - v;
    if (t == 511) part[blockIdx.x] = s[t];
}

__global__ void k_scanB(int* __restrict__ off, const int* __restrict__ part,
                        int* __restrict__ cur) {
    __shared__ int s[512];
    int t = threadIdx.x, b = blockIdx.x;
    s[t] = part[t]; __syncthreads();
    for (int d = 1; d < 512; d <<= 1) {
        int x = (t >= d) ? s[t - d] : 0;
        __syncthreads();
        s[t] += x;
        __syncthreads();
    }
    int prefix = (b == 0) ? 0 : s[b - 1];
    int i = b * 512 + t;
    int v = off[i] + prefix;
    off[i] = v;
    cur[i] = v;
    if (b == 0 && t == 0) off[BN_] = E_;
}

__global__ void k_place(const int* __restrict__ adj, const int* __restrict__ ebi,
                        int* __restrict__ cur, int* __restrict__ srcl) {
    int e = blockIdx.x * blockDim.x + threadIdx.x;
    if (e >= E_) return;
    int b = ebi[e];
    int src = b * N_ + adj[2 * e];
    int dst = b * N_ + adj[2 * e + 1];
    int pos = atomicAdd(&cur[dst], 1);
    srcl[pos] = src;
}

// ---------------------------------------------------------------------------
// Gather (fp16): agg[d] = sum msg[src]. HALF-warp per node; 16 lanes x 16B
// cover the 256B msg row. 4-way edge unroll. 2 nodes per warp.
// ---------------------------------------------------------------------------
__global__ void k_gather(const __half* __restrict__ msg,
                         const int* __restrict__ off,
                         const int* __restrict__ srcl,
                         __half* __restrict__ agg) {
    int gwarp = (blockIdx.x * blockDim.x + threadIdx.x) >> 5;
    int lane  = threadIdx.x & 31;
    int half_ = lane >> 4;                 // 0 or 1
    int l16   = lane & 15;
    int node  = gwarp * 2 + half_;
    int s0 = off[node], s1 = off[node + 1];

    float a[8] = {0.f, 0.f, 0.f, 0.f, 0.f, 0.f, 0.f, 0.f};
    int j = s0;
    for (; j + 4 <= s1; j += 4) {
        uint4 v0 = *((const uint4*)(msg + (size_t)srcl[j]     * 128) + l16);
        uint4 v1 = *((const uint4*)(msg + (size_t)srcl[j + 1] * 128) + l16);
        uint4 v2 = *((const uint4*)(msg + (size_t)srcl[j + 2] * 128) + l16);
        uint4 v3 = *((const uint4*)(msg + (size_t)srcl[j + 3] * 128) + l16);
        const uint32_t* ws[4] = {&v0.x, &v1.x, &v2.x, &v3.x};
#pragma unroll
        for (int e = 0; e < 4; e++)
#pragma unroll
            for (int q = 0; q < 4; q++) {
                float2 f = __half22float2(*(const __half2*)&ws[e][q]);
                a[q * 2] += f.x; a[q * 2 + 1] += f.y;
            }
    }
    for (; j < s1; j++) {
        uint4 v = *((const uint4*)(msg + (size_t)srcl[j] * 128) + l16);
        const uint32_t* w = &v.x;
#pragma unroll
        for (int q = 0; q < 4; q++) {
            float2 f = __half22float2(*(const __half2*)&w[q]);
            a[q * 2] += f.x; a[q * 2 + 1] += f.y;
        }
    }
    uint4 o;
    o.x = pack2(a[0], a[1]); o.y = pack2(a[2], a[3]);
    o.z = pack2(a[4], a[5]); o.w = pack2(a[6], a[7]);
    *((uint4*)(agg + (size_t)node * 128) + l16) = o;
}

// ===========================================================================
// FUSED GEMM kernels: phase1 produces h-tile (M=128) -> gmem + smem (fp16,
// MMA A-layout); phase2 computes msg = relu(h @ msgW + b2) -> gmem.
// TMEM: only 128 cols allocated — phase2 REUSES cols 0..127 after epilogue1
// fully drains the h accumulator (wait::ld + fence). 3 CTAs/SM.
// smem: 1KB header + 64KB (ring / hTile+msgW).
// ===========================================================================
#define SMEM_FUSED   (1024 + 65536)

#if TC_AVAIL
// stage msgW (128n x 128k fp16, 2 chunks of 16KB) into sb+1024+32768
__device__ __forceinline__ void stage_msgW(uint32_t sb, int tid,
                                           const __half* msgW) {
#pragma unroll
    for (int it = 0; it < 8; it++) {
        int idx = tid + it * 256;              // 0..2047
        int chunk = idx >> 10, w = idx & 1023;
        int r = w >> 3, c4 = w & 7;
        uint32_t dst = sb + 1024 + 32768 + chunk * 16384
                     + SW128((uint32_t)(r * 128 + c4 * 16));
        cp16(dst, msgW + (size_t)r * 128 + chunk * 64 + c4 * 8);
    }
    cp_commit();
}

// epilogue1: read h accumulator (tmem cols 0..127), bias/relu/mask, write
// fp16 to gmem Ch AND smem hTile (sb+1024, 2 chunks). Fully drains TMEM.
__device__ __forceinline__ void epi1_store(uint32_t sb, uint32_t tmem,
                                           int wid, int lid, int block_row,
                                           const float* bias, int use_mask,
                                           const unsigned char* maskB,
                                           __half* Ch) {
    const int sp = wid & 3;
    const int ch = wid >> 2;
    const int row = sp * 32 + lid;
    const int m = block_row + row;
    const bool masked = use_mask && (maskB[m] != 0);
#pragma unroll
    for (int half = 0; half < 2; half++) {
        int cb = ch * 64 + half * 32;
        uint32_t r32[32];
        TC_LD_X32(r32, tmem + cb);
        asm volatile("tcgen05.wait::ld.sync.aligned;" ::: "memory");
#pragma unroll
        for (int j = 0; j < 32; j += 8) {
            float f[8];
#pragma unroll
            for (int i = 0; i < 8; i++) {
                float v = __uint_as_float(r32[j + i]) + bias[cb + j + i];
                v = fmaxf(v, 0.f);
                if (masked) v = 0.f;
                f[i] = v;
            }
            uint4 o;
            o.x = pack2(f[0], f[1]); o.y = pack2(f[2], f[3]);
            o.z = pack2(f[4], f[5]); o.w = pack2(f[6], f[7]);
            *(uint4*)(Ch + (size_t)m * 128 + cb + j) = o;
            uint32_t boff = (uint32_t)(((cb & 63) + j) * 2);
            sts4u(sb + 1024 + ch * 16384 + SW128((uint32_t)(row * 128) + boff), o);
        }
    }
    // order TMEM reads before the upcoming __syncthreads + phase2 MMA write
    asm volatile("tcgen05.fence::before_thread_sync;" ::: "memory");
}

// phase2: MMA msg = hTile @ msgW -> REUSE tmem cols 0..127, epilogue to Cm.
__device__ __forceinline__ void phase2_run(uint32_t sb, uint32_t tmem,
                                           int tid, int wid, int lid,
                                           int block_row, const float* bias2,
                                           __half* Cm) {
    cp_wait0();
    __syncthreads();       // all TMEM reads of phase1 complete (fenced) here
    if (tid == 0) {
        asm volatile("tcgen05.fence::after_thread_sync;" ::: "memory");
        asm volatile("fence.proxy.async.shared::cta;" ::: "memory");
#pragma unroll
        for (int c = 0; c < 2; c++) {
            uint64_t hd = mk_desc(sb + 1024 + c * 16384);
            uint64_t wd = mk_desc(sb + 1024 + 32768 + c * 16384);
#pragma unroll
            for (int j = 0; j < 4; j++)
                mma_f16_ss(tmem, hd + j * 2, wd + j * 2,
                           (c > 0 || j > 0) ? 1u : 0u);   // en=0 first: overwrite
        }
        tc_commit(sb + 24);
    }
    mbar_wait(sb + 24, 0);
    asm volatile("tcgen05.fence::after_thread_sync;" ::: "memory");

    const int sp = wid & 3;
    const int ch = wid >> 2;
    const int m = block_row + sp * 32 + lid;
#pragma unroll
    for (int half = 0; half < 2; half++) {
        int cb = ch * 64 + half * 32;
        uint32_t r32[32];
        TC_LD_X32(r32, tmem + cb);
        asm volatile("tcgen05.wait::ld.sync.aligned;" ::: "memory");
#pragma unroll
        for (int j = 0; j < 32; j += 8) {
            float f[8];
#pragma unroll
            for (int i = 0; i < 8; i++)
                f[i] = fmaxf(__uint_as_float(r32[j + i]) + bias2[cb + j + i], 0.f);
            uint4 o;
            o.x = pack2(f[0], f[1]); o.y = pack2(f[2], f[3]);
            o.z = pack2(f[4], f[5]); o.w = pack2(f[6], f[7]);
            *(uint4*)(Cm + (size_t)m * 128 + cb + j) = o;
        }
    }
}
#endif  // TC_AVAIL

// ----- fused input layer (tf32 phase1, K=67 pad 96) + msg0 -----
struct FIN {
    const float* emb; const int* types; const float* coords;
    const float* Wt; const float* bias;
    const unsigned char* maskB;
    __half* Ch;
    const __half* msgW; const float* bias2; __half* Cm;
};

__global__ void __launch_bounds__(256) k_fused_in(FIN g) {
#if TC_AVAIL
    extern __shared__ __align__(1024) char smem[];
    const uint32_t sb = smem_u32(smem);
    const int tid = threadIdx.x;
    const int wid = tid >> 5;
    const int lid = tid & 31;
    const int block_row = blockIdx.x * 128;

    if (wid == 0) {
        asm volatile(
            "tcgen05.alloc.cta_group::1.sync.aligned.shared::cta.b32 [%0], %1;"
            :: "r"(sb), "r"(128u) : "memory");
        asm volatile("tcgen05.relinquish_alloc_permit.cta_group::1.sync.aligned;");
    }
    if (tid == 0) {
        mbar_init(sb + 8, 1); mbar_init(sb + 16, 1); mbar_init(sb + 24, 1);
    }
    __syncthreads();
    uint32_t tmem;
    asm volatile("ld.shared.b32 %0, [%1];" : "=r"(tmem) : "r"(sb));

    // phase1 staging: A 128 rows x 32 fp32 (16KB) + W 128n x 32 fp32 (16KB)
    auto stage1 = [&](int t, int s) {
        uint32_t bufA = sb + 1024 + s * 32768;
        uint32_t bufW = bufA + 16384;
#pragma unroll
        for (int it = 0; it < 4; it++) {           // W 1024 slots
            int idx = tid + it * 256;
            int r = idx >> 3, c4 = idx & 7;
            cp16(bufW + SW128((uint32_t)(r * 128 + c4 * 16)),
                 g.Wt + (size_t)r * 96 + t * 32 + c4 * 4);
        }
#pragma unroll
        for (int it = 0; it < 4; it++) {           // A 1024 slots
            int idx = tid + it * 256;
            int r = idx >> 3, c4 = idx & 7;
            int gr = block_row + r;
            uint32_t dst = bufA + SW128((uint32_t)(r * 128 + c4 * 16));
            if (t < 2) {
                cp16(dst, g.emb + (size_t)g.types[gr] * 64 + t * 32 + c4 * 4);
            } else {
                float4 v = make_float4(0.f, 0.f, 0.f, 0.f);
                if (c4 == 0) {
                    v.x = g.coords[gr * 3];
                    v.y = g.coords[gr * 3 + 1];
                    v.z = g.coords[gr * 3 + 2];
                }
                sts4(dst, v);
            }
        }
        cp_commit();
    };

    const int nt = 3;
    stage1(0, 0);
    stage1(1, 1);

    for (int t = 0; t < nt; t++) {
        const int s = t & 1;
        if (t < nt - 1) cp_wait1(); else cp_wait0();
        __syncthreads();
        if (tid == 0) {
            asm volatile("fence.proxy.async.shared::cta;" ::: "memory");
            uint64_t ad = mk_desc(sb + 1024 + s * 32768);
            uint64_t bd = mk_desc(sb + 1024 + s * 32768 + 16384);
#pragma unroll
            for (int j = 0; j < 4; j++)
                mma_tf32_ss(tmem, ad + j * 2, bd + j * 2,
                            (t > 0 || j > 0) ? 1u : 0u);
            tc_commit(sb + 8 + s * 8);
        }
        if (t + 2 < nt) {
            mbar_wait(sb + 8 + s * 8, (t >> 1) & 1);
            stage1(t + 2, s);
        }
    }

    mbar_wait(sb + 8 + ((nt - 1) & 1) * 8, ((nt - 1) >> 1) & 1);
    asm volatile("tcgen05.fence::after_thread_sync;" ::: "memory");

    // overlap msgW staging with epilogue1
    stage_msgW(sb, tid, g.msgW);
    epi1_store(sb, tmem, wid, lid, block_row, g.bias, 1, g.maskB, g.Ch);
    phase2_run(sb, tmem, tid, wid, lid, block_row, g.bias2, g.Cm);

    __syncthreads();
    if (wid == 0) {
        asm volatile("tcgen05.dealloc.cta_group::1.sync.aligned.b32 %0, %1;"
                     :: "r"(tmem), "r"(128u));
    }
#else
    // Scalar fallback (never runs on GB300).
    const int m = blockIdx.x * 128 + threadIdx.x % 128;
    if (threadIdx.x >= 128) return;
    const bool masked = (g.maskB[m] != 0);
    int ty = g.types[m];
    for (int cb = 0; cb < 128; cb++) {
        float acc = 0.f;
        for (int k = 0; k < 64; k++)
            acc = fmaf(g.emb[(size_t)ty * 64 + k], g.Wt[(size_t)cb * 96 + k], acc);
        for (int k = 64; k < 67; k++)
            acc = fmaf(g.coords[m * 3 + (k - 64)], g.Wt[(size_t)cb * 96 + k], acc);
        float v = fmaxf(acc + g.bias[cb], 0.f);
        if (masked) v = 0.f;
        g.Ch[(size_t)m * 128 + cb] = __float2half(v);
    }
    for (int cb = 0; cb < 128; cb++) {
        float acc = 0.f;
        for (int k = 0; k < 128; k++)
            acc = fmaf(__half2float(g.Ch[(size_t)m * 128 + k]),
                       __half2float(g.msgW[(size_t)cb * 128 + k]), acc);
        g.Cm[(size_t)m * 128 + cb] = __float2half(fmaxf(acc + g.bias2[cb], 0.f));
    }
#endif
}

// ----- fused upd layer (f16 phase1, K=256 concat [h|agg]) + next msg -----
struct FUP {
    const __half* A1; const __half* A2;
    const __half* Wt; const float* bias;
    const unsigned char* maskB;
    __half* Ch;
    const __half* msgW; const float* bias2; __half* Cm;
};

__global__ void __launch_bounds__(256) k_fused_upd(FUP g) {
#if TC_AVAIL
    extern __shared__ __align__(1024) char smem[];
    const uint32_t sb = smem_u32(smem);
    const int tid = threadIdx.x;
    const int wid = tid >> 5;
    const int lid = tid & 31;
    const int block_row = blockIdx.x * 128;

    if (wid == 0) {
        asm volatile(
            "tcgen05.alloc.cta_group::1.sync.aligned.shared::cta.b32 [%0], %1;"
            :: "r"(sb), "r"(128u) : "memory");
        asm volatile("tcgen05.relinquish_alloc_permit.cta_group::1.sync.aligned;");
    }
    if (tid == 0) {
        mbar_init(sb + 8, 1); mbar_init(sb + 16, 1); mbar_init(sb + 24, 1);
    }
    __syncthreads();
    uint32_t tmem;
    asm volatile("ld.shared.b32 %0, [%1];" : "=r"(tmem) : "r"(sb));

    // phase1 staging: A 128 rows x 64 halves (16KB) + W 128n x 64 halves (16KB)
    auto stage1 = [&](int t, int s) {
        uint32_t bufA = sb + 1024 + s * 32768;
        uint32_t bufW = bufA + 16384;
#pragma unroll
        for (int it = 0; it < 4; it++) {           // W
            int idx = tid + it * 256;
            int r = idx >> 3, c4 = idx & 7;
            cp16(bufW + SW128((uint32_t)(r * 128 + c4 * 16)),
                 g.Wt + (size_t)r * 256 + t * 64 + c4 * 8);
        }
#pragma unroll
        for (int it = 0; it < 4; it++) {           // A
            int idx = tid + it * 256;
            int r = idx >> 3, c4 = idx & 7;
            int gr = block_row + r;
            const __half* src = (t < 2)
                ? g.A1 + (size_t)gr * 128 + t * 64 + c4 * 8
                : g.A2 + (size_t)gr * 128 + (t - 2) * 64 + c4 * 8;
            cp16(bufA + SW128((uint32_t)(r * 128 + c4 * 16)), src);
        }
        cp_commit();
    };

    const int nt = 4;
    stage1(0, 0);
    stage1(1, 1);

    for (int t = 0; t < nt; t++) {
        const int s = t & 1;
        if (t < nt - 1) cp_wait1(); else cp_wait0();
        __syncthreads();
        if (tid == 0) {
            asm volatile("fence.proxy.async.shared::cta;" ::: "memory");
            uint64_t ad = mk_desc(sb + 1024 + s * 32768);
            uint64_t bd = mk_desc(sb + 1024 + s * 32768 + 16384);
#pragma unroll
            for (int j = 0; j < 4; j++)
                mma_f16_ss(tmem, ad + j * 2, bd + j * 2,
                           (t > 0 || j > 0) ? 1u : 0u);
            tc_commit(sb + 8 + s * 8);
        }
        if (t + 2 < nt) {
            mbar_wait(sb + 8 + s * 8, (t >> 1) & 1);
            stage1(t + 2, s);
        }
    }

    mbar_wait(sb + 8 + ((nt - 1) & 1) * 8, ((nt - 1) >> 1) & 1);
    asm volatile("tcgen05.fence::after_thread_sync;" ::: "memory");

    stage_msgW(sb, tid, g.msgW);
    epi1_store(sb, tmem, wid, lid, block_row, g.bias, 1, g.maskB, g.Ch);
    phase2_run(sb, tmem, tid, wid, lid, block_row, g.bias2, g.Cm);

    __syncthreads();
    if (wid == 0) {
        asm volatile("tcgen05.dealloc.cta_group::1.sync.aligned.b32 %0, %1;"
                     :: "r"(tmem), "r"(128u));
    }
#else
    const int m = blockIdx.x * 128 + threadIdx.x % 128;
    if (threadIdx.x >= 128) return;
    const bool masked = (g.maskB[m] != 0);
    for (int cb = 0; cb < 128; cb++) {
        float acc = 0.f;
        for (int k = 0; k < 128; k++)
            acc = fmaf(__half2float(g.A1[(size_t)m * 128 + k]),
                       __half2float(g.Wt[(size_t)cb * 256 + k]), acc);
        for (int k = 0; k < 128; k++)
            acc = fmaf(__half2float(g.A2[(size_t)m * 128 + k]),
                       __half2float(g.Wt[(size_t)cb * 256 + 128 + k]), acc);
        float v = fmaxf(acc + g.bias[cb], 0.f);
        if (masked) v = 0.f;
        g.Ch[(size_t)m * 128 + cb] = __float2half(v);
    }
    for (int cb = 0; cb < 128; cb++) {
        float acc = 0.f;
        for (int k = 0; k < 128; k++)
            acc = fmaf(__half2float(g.Ch[(size_t)m * 128 + k]),
                       __half2float(g.msgW[(size_t)cb * 128 + k]), acc);
        g.Cm[(size_t)m * 128 + cb] = __float2half(fmaxf(acc + g.bias2[cb], 0.f));
    }
#endif
}

// ---------------------------------------------------------------------------
// Standalone fp16 GEMM (upd1). 256 threads, M=256, 2-stage cp.async ring.
// ---------------------------------------------------------------------------
#define STAGE_F16    49152            // 32KB A (256 rows) + 16KB W
#define SMEM_F16     (1024 + 2 * STAGE_F16)

struct GH {
    const __half* A1; const __half* A2;
    const __half* Wt; const float* bias;
    const unsigned char* maskB;
    __half* C;
};

#if TC_AVAIL
__device__ __forceinline__ void stage_f16u(const GH& g, uint32_t bufA,
                                           uint32_t bufW, int block_row,
                                           int t, int tid) {
#pragma unroll
    for (int it = 0; it < 4; it++) {               // W: 1024 slots
        int idx = tid + it * 256;
        int r = idx >> 3, c4 = idx & 7;
        cp16(bufW + SW128((uint32_t)(r * 128 + c4 * 16)),
             g.Wt + (size_t)r * 256 + t * 64 + c4 * 8);
    }
#pragma unroll
    for (int it = 0; it < 8; it++) {               // A: 2048 slots (256 rows)
        int idx = tid + it * 256;
        int r = idx >> 3, c4 = idx & 7;
        int gr = block_row + r;
        const __half* src = (t < 2)
            ? g.A1 + (size_t)gr * 128 + t * 64 + c4 * 8
            : g.A2 + (size_t)gr * 128 + (t - 2) * 64 + c4 * 8;
        cp16(bufA + SW128((uint32_t)(r * 128 + c4 * 16)), src);
    }
    cp_commit();
}
#endif

__global__ void __launch_bounds__(256) k_gemm_upd(GH g) {
#if TC_AVAIL
    extern __shared__ __align__(1024) char smem[];
    const uint32_t sb = smem_u32(smem);
    const int tid = threadIdx.x;
    const int wid = tid >> 5;
    const int lid = tid & 31;
    const int block_row = blockIdx.x * 256;

    if (wid == 0) {
        asm volatile(
            "tcgen05.alloc.cta_group::1.sync.aligned.shared::cta.b32 [%0], %1;"
            :: "r"(sb), "r"(256u) : "memory");
        asm volatile("tcgen05.relinquish_alloc_permit.cta_group::1.sync.aligned;");
    }
    if (tid == 0) { mbar_init(sb + 8, 1); mbar_init(sb + 16, 1); }
    __syncthreads();
    uint32_t tmem;
    asm volatile("ld.shared.b32 %0, [%1];" : "=r"(tmem) : "r"(sb));

    const int nt = 4;
    const uint32_t bufA0 = sb + 1024;
    const uint32_t bufW0 = bufA0 + 32768;

    stage_f16u(g, bufA0, bufW0, block_row, 0, tid);
    stage_f16u(g, bufA0 + STAGE_F16, bufW0 + STAGE_F16, block_row, 1, tid);

    for (int t = 0; t < nt; t++) {
        const int b = t & 1;
        if (t < nt - 1) cp_wait1(); else cp_wait0();
        __syncthreads();
        if (tid == 0) {
            asm volatile("fence.proxy.async.shared::cta;" ::: "memory");
            uint64_t ad0 = mk_desc(bufA0 + b * STAGE_F16);
            uint64_t ad1 = mk_desc(bufA0 + b * STAGE_F16 + 16384);
            uint64_t bd  = mk_desc(bufW0 + b * STAGE_F16);
#pragma unroll
            for (int j = 0; j < 4; j++) {
                uint32_t en = (t > 0 || j > 0) ? 1u : 0u;
                mma_f16_ss(tmem,       ad0 + j * 2, bd + j * 2, en);
                mma_f16_ss(tmem + 128, ad1 + j * 2, bd + j * 2, en);
            }
            tc_commit(sb + 8 + b * 8);
        }
        if (t + 2 < nt) {
            mbar_wait(sb + 8 + b * 8, (t >> 1) & 1);
            stage_f16u(g, bufA0 + b * STAGE_F16, bufW0 + b * STAGE_F16,
                       block_row, t + 2, tid);
        }
    }

    mbar_wait(sb + 8 + ((nt - 1) & 1) * 8, ((nt - 1) >> 1) & 1);
    asm volatile("tcgen05.fence::after_thread_sync;" ::: "memory");

    const int blk = wid >> 2;
    const int sp  = wid & 3;
    const int m   = block_row + blk * 128 + sp * 32 + lid;
    const bool masked = (g.maskB[m] != 0);
#pragma unroll
    for (int cb = 0; cb < 128; cb += 32) {
        uint32_t r32[32];
        TC_LD_X32(r32, tmem + blk * 128 + cb);
        asm volatile("tcgen05.wait::ld.sync.aligned;" ::: "memory");
#pragma unroll
        for (int j = 0; j < 32; j += 8) {
            float f[8];
#pragma unroll
            for (int i = 0; i < 8; i++) {
                float v = __uint_as_float(r32[j + i]) + g.bias[cb + j + i];
                v = fmaxf(v, 0.f);
                if (masked) v = 0.f;
                f[i] = v;
            }
            uint4 o;
            o.x = pack2(f[0], f[1]); o.y = pack2(f[2], f[3]);
            o.z = pack2(f[4], f[5]); o.w = pack2(f[6], f[7]);
            *(uint4*)(g.C + (size_t)m * 128 + cb + j) = o;
        }
    }

    __syncthreads();
    if (wid == 0) {
        asm volatile("tcgen05.dealloc.cta_group::1.sync.aligned.b32 %0, %1;"
                     :: "r"(tmem), "r"(256u));
    }
#else
    const int row = blockIdx.x * 256 + threadIdx.x;
    const bool masked = (g.maskB[row] != 0);
#pragma unroll 1
    for (int cb = 0; cb < 128; cb++) {
        float acc = 0.f;
        for (int k = 0; k < 128; k++)
            acc = fmaf(__half2float(g.A1[(size_t)row * 128 + k]),
                       __half2float(g.Wt[(size_t)cb * 256 + k]), acc);
        for (int k = 0; k < 128; k++)
            acc = fmaf(__half2float(g.A2[(size_t)row * 128 + k]),
                       __half2float(g.Wt[(size_t)cb * 256 + 128 + k]), acc);
        float v = fmaxf(acc + g.bias[cb], 0.f);
        if (masked) v = 0.f;
        g.C[(size_t)row * 128 + cb] = __float2half(v);
    }
#endif
}

// ---------------------------------------------------------------------------
// Coupling dual fp16 GEMM + fused final epilogue. M=128, 128 threads.
// ---------------------------------------------------------------------------
#define CPL_HDR      8192
#define CPL_STAGE    49152           // 16KB A + 16KB Ws + 16KB Wh
#define SMEM_CPL     (CPL_HDR + 2 * CPL_STAGE)

struct CPH {
    const __half* A1; const float* coords;
    const __half* Wse; const __half* Whe;
    const float* bse; const float* bhe;
    const float* Ws2; const float* bs2;
    const float* Wh2; const float* bh2;
    const unsigned char* maskB;
    float* out; float* logdet;
};

__global__ void __launch_bounds__(128) k_gemm_cpl(CPH g) {
#if TC_AVAIL
    extern __shared__ __align__(1024) char smem[];
    const uint32_t sb = smem_u32(smem);
    float* smf = (float*)smem;
    const int tid = threadIdx.x;
    const int wid = tid >> 5;
    const int lid = tid & 31;
    const int block_row = blockIdx.x * 128;

    if (wid == 0) {
        asm volatile(
            "tcgen05.alloc.cta_group::1.sync.aligned.shared::cta.b32 [%0], %1;"
            :: "r"(sb), "r"(256u) : "memory");
        asm volatile("tcgen05.relinquish_alloc_permit.cta_group::1.sync.aligned;");
    }
    if (tid == 0) { mbar_init(sb + 8, 1); mbar_init(sb + 16, 1); }
    for (int i = tid; i < 384; i += 128) {
        smf[16 + i]  = g.Ws2[i];
        smf[400 + i] = g.Wh2[i];
    }
    smf[784 + tid] = g.bse[tid];
    smf[912 + tid] = g.bhe[tid];
    __syncthreads();
    uint32_t tmem;
    asm volatile("ld.shared.b32 %0, [%1];" : "=r"(tmem) : "r"(sb));

    const int nt = 3;                   // Kpad 192 fp16

    auto stage = [&](int t, int b) {
        uint32_t base = sb + CPL_HDR + b * CPL_STAGE;
#pragma unroll
        for (int it = 0; it < 24; it++) {
            int idx = tid + it * 128;            // 0..3071
            int sec = idx >> 10;
            int w   = idx & 1023;
            int r   = w >> 3;
            int c4  = w & 7;
            uint32_t dst = base + sec * 16384 + SW128((uint32_t)(r * 128 + c4 * 16));
            if (sec == 0) {
                if (t < 2) {
                    cp16(dst, g.A1 + (size_t)(block_row + r) * 128 + t * 64 + c4 * 8);
                } else {
                    uint4 o = make_uint4(0u, 0u, 0u, 0u);
                    if (c4 == 0) {
                        int gr = block_row + r;
                        bool cm = ((gr & 1) == 0) && (g.maskB[gr] == 0);
                        float c0 = cm ? 0.f : g.coords[gr * 3];
                        float c1 = cm ? 0.f : g.coords[gr * 3 + 1];
                        float c2 = cm ? 0.f : g.coords[gr * 3 + 2];
                        o.x = pack2(c0, c1);
                        o.y = pack2(c2, 0.f);
                    }
                    sts4u(dst, o);
                }
            } else if (sec == 1) {
                cp16(dst, g.Wse + (size_t)r * 192 + t * 64 + c4 * 8);
            } else {
                cp16(dst, g.Whe + (size_t)r * 192 + t * 64 + c4 * 8);
            }
        }
        cp_commit();
    };

    stage(0, 0);
    stage(1, 1);

    for (int t = 0; t < nt; t++) {
        const int b = t & 1;
        if (t < nt - 1) cp_wait1(); else cp_wait0();
        __syncthreads();
        if (tid == 0) {
            asm volatile("fence.proxy.async.shared::cta;" ::: "memory");
            uint32_t base = sb + CPL_HDR + b * CPL_STAGE;
            uint64_t ad = mk_desc(base);
            uint64_t sd = mk_desc(base + 16384);
            uint64_t hd = mk_desc(base + 32768);
#pragma unroll
            for (int j = 0; j < 4; j++) {
                uint32_t en = (t > 0 || j > 0) ? 1u : 0u;
                mma_f16_ss(tmem,       ad + j * 2, sd + j * 2, en);
                mma_f16_ss(tmem + 128, ad + j * 2, hd + j * 2, en);
            }
            tc_commit(sb + 8 + b * 8);
        }
        if (t + 2 < nt) {
            mbar_wait(sb + 8 + b * 8, (t >> 1) & 1);
            stage(t + 2, b);
        }
    }

    mbar_wait(sb + 8 + ((nt - 1) & 1) * 8, ((nt - 1) >> 1) & 1);
    asm volatile("tcgen05.fence::after_thread_sync;" ::: "memory");

    const int m = block_row + wid * 32 + lid;
    float raw[3] = {0.f, 0.f, 0.f};
    float shf[3] = {0.f, 0.f, 0.f};
#pragma unroll
    for (int cb = 0; cb < 128; cb += 32) {
        uint32_t rs[32], rh[32];
        TC_LD_X32(rs, tmem + cb);
        TC_LD_X32(rh, tmem + 128 + cb);
        asm volatile("tcgen05.wait::ld.sync.aligned;" ::: "memory");
#pragma unroll
        for (int k = 0; k < 32; k++) {
            int col = cb + k;
            float sv = fmaxf(__uint_as_float(rs[k]) + smf[784 + col], 0.f);
            float hv = fmaxf(__uint_as_float(rh[k]) + smf[912 + col], 0.f);
#pragma unroll
            for (int c = 0; c < 3; c++) {
                raw[c] = fmaf(sv, smf[16 + col * 3 + c],  raw[c]);
                shf[c] = fmaf(hv, smf[400 + col * 3 + c], shf[c]);
            }
        }
    }

    bool cm = ((m & 1) == 0) && (g.maskB[m] == 0);   // PHASE = 0
    float ld = 0.f;
#pragma unroll
    for (int c = 0; c < 3; c++) {
        float r = raw[c] + g.bs2[c];
        float s = shf[c] + g.bh2[c];
        float ls = cm ? tanhf(r) * 2.f : 0.f;
        ld += ls;
        float coord = g.coords[m * 3 + c];
        g.out[m * 3 + c] = cm ? (expf(ls) * coord + s) : coord;
    }
#pragma unroll
    for (int o = 16; o > 0; o >>= 1)
        ld += __shfl_xor_sync(0xFFFFFFFFu, ld, o);
    if (lid == 0) atomicAdd(&g.logdet[m >> 13], ld);

    __syncthreads();
    if (wid == 0) {
        asm volatile("tcgen05.dealloc.cta_group::1.sync.aligned.b32 %0, %1;"
                     :: "r"(tmem), "r"(256u));
    }
#else
    const int m = blockIdx.x * 128 + threadIdx.x;
    bool cm = ((m & 1) == 0) && (g.maskB[m] == 0);
    float raw[3], shf[3];
#pragma unroll
    for (int c = 0; c < 3; c++) { raw[c] = g.bs2[c]; shf[c] = g.bh2[c]; }
    for (int n = 0; n < 128; n++) {
        float accs = g.bse[n], acch = g.bhe[n];
        for (int k = 0; k < 128; k++) {
            float a = __half2float(g.A1[(size_t)m * 128 + k]);
            accs = fmaf(a, __half2float(g.Wse[n * 192 + k]), accs);
            acch = fmaf(a, __half2float(g.Whe[n * 192 + k]), acch);
        }
        for (int k = 128; k < 131; k++) {
            float a = cm ? 0.f : g.coords[m * 3 + (k - 128)];
            accs = fmaf(a, __half2float(g.Wse[n * 192 + k]), accs);
            acch = fmaf(a, __half2float(g.Whe[n * 192 + k]), acch);
        }
        accs = fmaxf(accs, 0.f); acch = fmaxf(acch, 0.f);
#pragma unroll
        for (int c = 0; c < 3; c++) {
            raw[c] = fmaf(accs, g.Ws2[n * 3 + c], raw[c]);
            shf[c] = fmaf(acch, g.Wh2[n * 3 + c], shf[c]);
        }
    }
    float ld = 0.f;
#pragma unroll
    for (int c = 0; c < 3; c++) {
        float ls = cm ? tanhf(raw[c]) * 2.f : 0.f;
        ld += ls;
        float coord = g.coords[m * 3 + c];
        g.out[m * 3 + c] = cm ? (expf(ls) * coord + shf[c]) : coord;
    }
    atomicAdd(&g.logdet[m >> 13], ld);
#endif
}

// ---------------------------------------------------------------------------
// Host launcher. Index 3 = k_fused_in (ncu profile target).
// ---------------------------------------------------------------------------
extern "C" void kernel_launch(void* const* d_in, const int* in_sizes, int n_in,
                              void* d_out, int out_size) {
    const float*         coords = (const float*)d_in[0];
    const int*           types  = (const int*)  d_in[1];
    const int*           adj    = (const int*)  d_in[2];
    const int*           ebi    = (const int*)  d_in[3];
    const unsigned char* maskB  = (const unsigned char*)d_in[4];
    const float* emb   = (const float*)d_in[5];
    const float* W_in  = (const float*)d_in[6];
    const float* b_in  = (const float*)d_in[7];
    const float* msg_W = (const float*)d_in[8];
    const float* msg_b = (const float*)d_in[9];
    const float* upd_W = (const float*)d_in[10];
    const float* upd_b = (const float*)d_in[11];
    const float* W_out = (const float*)d_in[12];
    const float* b_out = (const float*)d_in[13];
    const float* Ws1   = (const float*)d_in[14];
    const float* bs1   = (const float*)d_in[15];
    const float* Ws2   = (const float*)d_in[16];
    const float* bs2   = (const float*)d_in[17];
    const float* Wh1   = (const float*)d_in[18];
    const float* bh1   = (const float*)d_in[19];
    const float* Wh2   = (const float*)d_in[20];
    const float* bh2   = (const float*)d_in[21];

    float* out    = (float*)d_out;
    float* logdet = out + (size_t)BN_ * 3;

    __half *h, *b1, *b2, *wth;
    float *wt;
    int *off, *part, *cur, *srcl;
    cudaGetSymbolAddress((void**)&h,    g_h);
    cudaGetSymbolAddress((void**)&b1,   g_b1);
    cudaGetSymbolAddress((void**)&b2,   g_b2);
    cudaGetSymbolAddress((void**)&wt,   g_wt);
    cudaGetSymbolAddress((void**)&wth,  g_wth);
    cudaGetSymbolAddress((void**)&off,  g_off);
    cudaGetSymbolAddress((void**)&part, g_part);
    cudaGetSymbolAddress((void**)&cur,  g_cur);
    cudaGetSymbolAddress((void**)&srcl, g_srcl);

    cudaFuncSetAttribute(k_fused_in,  cudaFuncAttributeMaxDynamicSharedMemorySize, SMEM_FUSED);
    cudaFuncSetAttribute(k_fused_upd, cudaFuncAttributeMaxDynamicSharedMemorySize, SMEM_FUSED);
    cudaFuncSetAttribute(k_gemm_upd,  cudaFuncAttributeMaxDynamicSharedMemorySize, SMEM_F16);
    cudaFuncSetAttribute(k_gemm_cpl,  cudaFuncAttributeMaxDynamicSharedMemorySize, SMEM_CPL);

    const int BT = 256;

    // 0: prep
    k_prep<<<1024, BT>>>(W_in, msg_W, upd_W, W_out, Ws1, Wh1, bs1, bh1, b_out,
                         wt, wth, off, logdet);
    // 1: hist
    k_hist<<<E_ / BT, BT>>>(adj, ebi, off);
    // 2: scanA (no dependency on fused_in)
    k_scanA<<<512, 512>>>(off, part);
    // 3: fused input + msg0  <-- ncu profile target
    FIN fi{emb, types, coords, wt + O_WIN, b_in, maskB, h,
           wth + H_MSG0, msg_b, b1};
    k_fused_in<<<BN_ / 128, 256, SMEM_FUSED>>>(fi);
    // 4-5: finish CSR
    k_scanB<<<512, 512>>>(off, part, cur);
    k_place<<<E_ / BT, BT>>>(adj, ebi, cur, srcl);
    // 6: gather layer 0
    k_gather<<<BN_ / 16, BT>>>(b1, off, srcl, b2);
    // 7: fused upd0 + msg1
    FUP fu{h, b2, wth + H_UPD0, upd_b, maskB, h, wth + H_MSG1, msg_b + 128, b1};
    k_fused_upd<<<BN_ / 128, 256, SMEM_FUSED>>>(fu);
    // 8: gather layer 1
    k_gather<<<BN_ / 16, BT>>>(b1, off, srcl, b2);
    // 9: upd layer 1 (standalone)
    GH gu1{h, b2, wth + H_UPD1, upd_b + 128, maskB, h};
    k_gemm_upd<<<BN_ / 256, 256, SMEM_F16>>>(gu1);
    // 10: fused coupling (dual fp16 GEMM + final epilogue)
    CPH c{h, coords, wth + H_WSE, wth + H_WHE, wt + O_BSE, wt + O_BHE,
          Ws2, bs2, Wh2, bh2, maskB, out, logdet};
    k_gemm_cpl<<<BN_ / 128, 128, SMEM_CPL>>>(c);
}

// round 14
// speedup vs baseline: 8.8126x; 1.0363x over previous
#include <cuda_runtime.h>
#include <cuda_fp16.h>
#include <cstdint>
#include <math.h>
#include <stddef.h>

// Problem constants
#define B_   32
#define N_   8192
#define E_   1048576
#define BN_  (B_ * N_)          // 262144
#define L_   2

// ---------------------------------------------------------------------------
// Arch-feature gate (tcgen05 only exists on sm_100a/sm_103a passes)
// ---------------------------------------------------------------------------
#if defined(__CUDA_ARCH_FEAT_SM103_ALL) || defined(__CUDA_ARCH_FEAT_SM100_ALL)
#  define TC_AVAIL 1
#endif
#ifndef TC_AVAIL
#  ifdef __CUDA_ARCH_HAS_FEATURE__
#    if __CUDA_ARCH_HAS_FEATURE__(SM103_ALL) || __CUDA_ARCH_HAS_FEATURE__(SM100_ALL)
#      define TC_AVAIL 1
#    endif
#  endif
#endif
#ifndef TC_AVAIL
#  define TC_AVAIL 0
#endif

// ---------------------------------------------------------------------------
// Scratch (static device globals)
// ---------------------------------------------------------------------------
static __device__ __align__(16) __half g_h [(size_t)BN_ * 128];
static __device__ __align__(16) __half g_b1[(size_t)BN_ * 128];   // msg_all
static __device__ __align__(16) __half g_b2[(size_t)BN_ * 128];   // agg
static __device__ __align__(16) float  g_wt [12544];              // fp32 W_in^T + bse/bhe
static __device__ __align__(16) __half g_wth[147456];             // fp16 weights
static __device__ int g_off [BN_ + 1];
static __device__ int g_part[512];
static __device__ int g_cur [BN_];
static __device__ int g_srcl[E_];

// g_wt fp32 offsets
#define O_WIN   0        // 128 x 96 (K=67 pad)
#define O_BSE   12288
#define O_BHE   12416
// g_wth half offsets
#define H_MSG0  0        // 128x128
#define H_MSG1  16384
#define H_UPD0  32768    // 128x256
#define H_UPD1  65536
#define H_WSE   98304    // 128x192 (K=131 pad)
#define H_WHE   122880

// ---------------------------------------------------------------------------
// Helpers
// ---------------------------------------------------------------------------
__device__ __forceinline__ uint32_t smem_u32(const void* p) {
    uint32_t a;
    asm("{ .reg .u64 t; cvta.to.shared.u64 t, %1; cvt.u32.u64 %0, t; }"
        : "=r"(a) : "l"(p));
    return a;
}

#define SW128(o) ((o) ^ (((o) >> 3) & 0x70))

__device__ __forceinline__ void cp16(uint32_t dst, const void* src) {
    asm volatile("cp.async.cg.shared.global [%0], [%1], 16;"
                 :: "r"(dst), "l"(src) : "memory");
}
__device__ __forceinline__ void cp_commit() {
    asm volatile("cp.async.commit_group;" ::: "memory");
}
__device__ __forceinline__ void cp_wait1() {
    asm volatile("cp.async.wait_group 1;" ::: "memory");
}
__device__ __forceinline__ void cp_wait0() {
    asm volatile("cp.async.wait_group 0;" ::: "memory");
}
__device__ __forceinline__ void sts4(uint32_t dst, float4 v) {
    asm volatile("st.shared.v4.f32 [%0], {%1, %2, %3, %4};"
                 :: "r"(dst), "f"(v.x), "f"(v.y), "f"(v.z), "f"(v.w) : "memory");
}
__device__ __forceinline__ void sts4u(uint32_t dst, uint4 v) {
    asm volatile("st.shared.v4.u32 [%0], {%1, %2, %3, %4};"
                 :: "r"(dst), "r"(v.x), "r"(v.y), "r"(v.z), "r"(v.w) : "memory");
}
__device__ __forceinline__ uint32_t pack2(float a, float b) {
    __half2 h = __floats2half2_rn(a, b);
    return *reinterpret_cast<uint32_t*>(&h);
}

#if TC_AVAIL
__device__ __forceinline__ uint64_t mk_desc(uint32_t addr) {
    // SW128, version=1 (Blackwell), LBO=1, SBO=64 (K-major)
    const uint64_t BASE = (2ULL << 61) | (1ULL << 46) | (64ULL << 32) | (1ULL << 16);
    return BASE | ((uint64_t)(addr >> 4) & 0x3FFF);
}

// tf32: acc=F32, atype=btype=TF32(2), N=128, M=128
#define IDESC_TF32 ((1u << 4) | (2u << 7) | (2u << 10) | (16u << 17) | (8u << 24))
// fp16: acc=F32, atype=btype=FP16(0), N=128, M=128
#define IDESC_F16  ((1u << 4) | (16u << 17) | (8u << 24))

__device__ __forceinline__ void mma_tf32_ss(uint32_t d, uint64_t a, uint64_t b,
                                            uint32_t en) {
    asm volatile(
        "{\n\t.reg .pred p;\n\t"
        "setp.ne.u32 p, %4, 0;\n\t"
        "tcgen05.mma.cta_group::1.kind::tf32 [%0], %1, %2, %3, p;\n\t}"
        :: "r"(d), "l"(a), "l"(b), "r"(IDESC_TF32), "r"(en) : "memory");
}
__device__ __forceinline__ void mma_f16_ss(uint32_t d, uint64_t a, uint64_t b,
                                           uint32_t en) {
    asm volatile(
        "{\n\t.reg .pred p;\n\t"
        "setp.ne.u32 p, %4, 0;\n\t"
        "tcgen05.mma.cta_group::1.kind::f16 [%0], %1, %2, %3, p;\n\t}"
        :: "r"(d), "l"(a), "l"(b), "r"(IDESC_F16), "r"(en) : "memory");
}

__device__ __forceinline__ void tc_commit(uint32_t mbar) {
    asm volatile(
        "tcgen05.commit.cta_group::1.mbarrier::arrive::one.shared::cluster.b64 [%0];"
        :: "r"(mbar) : "memory");
}

#define TC_LD_X32(r, addr)                                                     \
    asm volatile(                                                              \
        "tcgen05.ld.sync.aligned.32x32b.x32.b32 "                              \
        "{%0, %1, %2, %3, %4, %5, %6, %7, "                                    \
        " %8, %9, %10, %11, %12, %13, %14, %15, "                              \
        " %16, %17, %18, %19, %20, %21, %22, %23, "                            \
        " %24, %25, %26, %27, %28, %29, %30, %31}, [%32];"                     \
        : "=r"((r)[0]),  "=r"((r)[1]),  "=r"((r)[2]),  "=r"((r)[3]),           \
          "=r"((r)[4]),  "=r"((r)[5]),  "=r"((r)[6]),  "=r"((r)[7]),           \
          "=r"((r)[8]),  "=r"((r)[9]),  "=r"((r)[10]), "=r"((r)[11]),          \
          "=r"((r)[12]), "=r"((r)[13]), "=r"((r)[14]), "=r"((r)[15]),          \
          "=r"((r)[16]), "=r"((r)[17]), "=r"((r)[18]), "=r"((r)[19]),          \
          "=r"((r)[20]), "=r"((r)[21]), "=r"((r)[22]), "=r"((r)[23]),          \
          "=r"((r)[24]), "=r"((r)[25]), "=r"((r)[26]), "=r"((r)[27]),          \
          "=r"((r)[28]), "=r"((r)[29]), "=r"((r)[30]), "=r"((r)[31])           \
        : "r"(addr))
#endif  // TC_AVAIL

__device__ __forceinline__ void mbar_init(uint32_t a, uint32_t cnt) {
    asm volatile("mbarrier.init.shared.b64 [%0], %1;" :: "r"(a), "r"(cnt) : "memory");
}
__device__ __forceinline__ void mbar_wait(uint32_t a, uint32_t parity) {
    asm volatile(
        "{\n\t.reg .pred P;\n"
        "WL%=:\n\t"
        "mbarrier.try_wait.parity.acquire.cta.shared::cta.b64 P, [%0], %1, 0x989680;\n\t"
        "@P bra WD%=;\n\t"
        "bra WL%=;\n"
        "WD%=:\n\t}"
        :: "r"(a), "r"(parity) : "memory");
}

// ---------------------------------------------------------------------------
// k_prep (unchanged)
// ---------------------------------------------------------------------------
__global__ void k_prep(const float* __restrict__ W_in,
                       const float* __restrict__ msg_W,
                       const float* __restrict__ upd_W,
                       const float* __restrict__ W_out,
                       const float* __restrict__ Ws1,
                       const float* __restrict__ Wh1,
                       const float* __restrict__ bs1,
                       const float* __restrict__ bh1,
                       const float* __restrict__ b_out,
                       float* __restrict__ wt,
                       __half* __restrict__ wth,
                       int* __restrict__ off,
                       float* __restrict__ logdet) {
    const int TOTAL = 12544 + 147456 + (BN_ + 1) + 32;
    for (int idx = blockIdx.x * blockDim.x + threadIdx.x; idx < TOTAL;
         idx += gridDim.x * blockDim.x) {
        if (idx < 12288) {
            int n = idx / 96, k = idx - n * 96;
            wt[idx] = (k < 67) ? W_in[k * 128 + n] : 0.f;
        } else if (idx < 12416) {
            int n = idx - 12288;
            float v = bs1[n];
            for (int q = 0; q < 128; q++)
                v = fmaf(b_out[q], Ws1[q * 128 + n], v);
            wt[idx] = v;
        } else if (idx < 12544) {
            int n = idx - 12416;
            float v = bh1[n];
            for (int q = 0; q < 128; q++)
                v = fmaf(b_out[q], Wh1[q * 128 + n], v);
            wt[idx] = v;
        } else {
            int j = idx - 12544;
            if (j < 32768) {
                int l = j >> 14, r = j & 16383;
                int n = r >> 7, k = r & 127;
                wth[j] = __float2half(msg_W[l * 16384 + k * 128 + n]);
            } else if (j < 98304) {
                int j2 = j - 32768;
                int l = j2 >> 15, r = j2 & 32767;
                int n = r >> 8, k = r & 255;
                wth[j] = __float2half(upd_W[l * 32768 + k * 128 + n]);
            } else if (j < 122880) {
                int j2 = j - 98304;
                int n = j2 / 192, k = j2 - n * 192;
                float v = 0.f;
                if (k < 128) {
                    for (int q = 0; q < 128; q++)
                        v = fmaf(W_out[k * 128 + q], Ws1[q * 128 + n], v);
                } else if (k < 131) {
                    v = Ws1[k * 128 + n];
                }
                wth[j] = __float2half(v);
            } else if (j < 147456) {
                int j2 = j - 122880;
                int n = j2 / 192, k = j2 - n * 192;
                float v = 0.f;
                if (k < 128) {
                    for (int q = 0; q < 128; q++)
                        v = fmaf(W_out[k * 128 + q], Wh1[q * 128 + n], v);
                } else if (k < 131) {
                    v = Wh1[k * 128 + n];
                }
                wth[j] = __float2half(v);
            } else if (j < 147456 + BN_ + 1) {
                off[j - 147456] = 0;
            } else {
                logdet[j - (147456 + BN_ + 1)] = 0.f;
            }
        }
    }
}

// ---------------------------------------------------------------------------
// CSR build (unchanged)
// ---------------------------------------------------------------------------
__global__ void k_hist(const int* __restrict__ adj, const int* __restrict__ ebi,
                       int* __restrict__ deg) {
    int e = blockIdx.x * blockDim.x + threadIdx.x;
    if (e >= E_) return;
    int dst = ebi[e] * N_ + adj[2 * e + 1];
    atomicAdd(&deg[dst], 1);
}

__global__ void k_scanA(int* __restrict__ off, int* __restrict__ part) {
    __shared__ int s[512];
    int t = threadIdx.x;
    int i = blockIdx.x * 512 + t;
    int v = off[i];
    s[t] = v; __syncthreads();
    for (int d = 1; d < 512; d <<= 1) {
        int x = (t >= d) ? s[t - d] : 0;
        __syncthreads();
        s[t] += x;
        __syncthreads();
    }
    off[i] = s[t] - v;
    if (t == 511) part[blockIdx.x] = s[t];
}

__global__ void k_scanB(int* __restrict__ off, const int* __restrict__ part,
                        int* __restrict__ cur) {
    __shared__ int s[512];
    int t = threadIdx.x, b = blockIdx.x;
    s[t] = part[t]; __syncthreads();
    for (int d = 1; d < 512; d <<= 1) {
        int x = (t >= d) ? s[t - d] : 0;
        __syncthreads();
        s[t] += x;
        __syncthreads();
    }
    int prefix = (b == 0) ? 0 : s[b - 1];
    int i = b * 512 + t;
    int v = off[i] + prefix;
    off[i] = v;
    cur[i] = v;
    if (b == 0 && t == 0) off[BN_] = E_;
}

__global__ void k_place(const int* __restrict__ adj, const int* __restrict__ ebi,
                        int* __restrict__ cur, int* __restrict__ srcl) {
    int e = blockIdx.x * blockDim.x + threadIdx.x;
    if (e >= E_) return;
    int b = ebi[e];
    int src = b * N_ + adj[2 * e];
    int dst = b * N_ + adj[2 * e + 1];
    int pos = atomicAdd(&cur[dst], 1);
    srcl[pos] = src;
}

// ---------------------------------------------------------------------------
// Gather (unchanged from R13): half-warp per node, uint4 lanes, 4-way unroll.
// ---------------------------------------------------------------------------
__global__ void k_gather(const __half* __restrict__ msg,
                         const int* __restrict__ off,
                         const int* __restrict__ srcl,
                         __half* __restrict__ agg) {
    int gwarp = (blockIdx.x * blockDim.x + threadIdx.x) >> 5;
    int lane  = threadIdx.x & 31;
    int half_ = lane >> 4;
    int l16   = lane & 15;
    int node  = gwarp * 2 + half_;
    int s0 = off[node], s1 = off[node + 1];

    float a[8] = {0.f, 0.f, 0.f, 0.f, 0.f, 0.f, 0.f, 0.f};
    int j = s0;
    for (; j + 4 <= s1; j += 4) {
        uint4 v0 = *((const uint4*)(msg + (size_t)srcl[j]     * 128) + l16);
        uint4 v1 = *((const uint4*)(msg + (size_t)srcl[j + 1] * 128) + l16);
        uint4 v2 = *((const uint4*)(msg + (size_t)srcl[j + 2] * 128) + l16);
        uint4 v3 = *((const uint4*)(msg + (size_t)srcl[j + 3] * 128) + l16);
        const uint32_t* ws[4] = {&v0.x, &v1.x, &v2.x, &v3.x};
#pragma unroll
        for (int e = 0; e < 4; e++)
#pragma unroll
            for (int q = 0; q < 4; q++) {
                float2 f = __half22float2(*(const __half2*)&ws[e][q]);
                a[q * 2] += f.x; a[q * 2 + 1] += f.y;
            }
    }
    for (; j < s1; j++) {
        uint4 v = *((const uint4*)(msg + (size_t)srcl[j] * 128) + l16);
        const uint32_t* w = &v.x;
#pragma unroll
        for (int q = 0; q < 4; q++) {
            float2 f = __half22float2(*(const __half2*)&w[q]);
            a[q * 2] += f.x; a[q * 2 + 1] += f.y;
        }
    }
    uint4 o;
    o.x = pack2(a[0], a[1]); o.y = pack2(a[2], a[3]);
    o.z = pack2(a[4], a[5]); o.w = pack2(a[6], a[7]);
    *((uint4*)(agg + (size_t)node * 128) + l16) = o;
}

// ===========================================================================
// FUSED GEMM kernels, explicit pipelines. TMEM 128 cols (phase2 reuses after
// drain+fence). smem: 1KB header + 64KB. Staging precedes alloc; msgW
// prefetched as soon as its region's last MMA completes.
// ===========================================================================
#define SMEM_FUSED   (1024 + 65536)

#if TC_AVAIL
// stage msgW (128n x 128k fp16, 2 chunks of 16KB) into sb+1024+dstoff
__device__ __forceinline__ void stage_msgW(uint32_t sb, int tid,
                                           const __half* msgW, uint32_t dstoff) {
#pragma unroll
    for (int it = 0; it < 8; it++) {
        int idx = tid + it * 256;
        int chunk = idx >> 10, w = idx & 1023;
        int r = w >> 3, c4 = w & 7;
        uint32_t dst = sb + 1024 + dstoff + chunk * 16384
                     + SW128((uint32_t)(r * 128 + c4 * 16));
        cp16(dst, msgW + (size_t)r * 128 + chunk * 64 + c4 * 8);
    }
    cp_commit();
}

// epilogue1: drain h accumulator -> gmem + smem hTile at sb+1024+hoff.
__device__ __forceinline__ void epi1_store(uint32_t sb, uint32_t tmem,
                                           int wid, int lid, int block_row,
                                           const float* bias,
                                           const unsigned char* maskB,
                                           __half* Ch, uint32_t hoff) {
    const int sp = wid & 3;
    const int ch = wid >> 2;
    const int row = sp * 32 + lid;
    const int m = block_row + row;
    const bool masked = (maskB[m] != 0);
#pragma unroll
    for (int half = 0; half < 2; half++) {
        int cb = ch * 64 + half * 32;
        uint32_t r32[32];
        TC_LD_X32(r32, tmem + cb);
        asm volatile("tcgen05.wait::ld.sync.aligned;" ::: "memory");
#pragma unroll
        for (int j = 0; j < 32; j += 8) {
            float f[8];
#pragma unroll
            for (int i = 0; i < 8; i++) {
                float v = __uint_as_float(r32[j + i]) + bias[cb + j + i];
                v = fmaxf(v, 0.f);
                if (masked) v = 0.f;
                f[i] = v;
            }
            uint4 o;
            o.x = pack2(f[0], f[1]); o.y = pack2(f[2], f[3]);
            o.z = pack2(f[4], f[5]); o.w = pack2(f[6], f[7]);
            *(uint4*)(Ch + (size_t)m * 128 + cb + j) = o;
            uint32_t boff = (uint32_t)(((cb & 63) + j) * 2);
            sts4u(sb + 1024 + hoff + ch * 16384
                  + SW128((uint32_t)(row * 128) + boff), o);
        }
    }
    asm volatile("tcgen05.fence::before_thread_sync;" ::: "memory");
}

// phase2: msg = hTile @ msgW -> reuse tmem cols 0..127, epilogue to Cm.
__device__ __forceinline__ void phase2_run(uint32_t sb, uint32_t tmem,
                                           int tid, int wid, int lid,
                                           int block_row, const float* bias2,
                                           __half* Cm, uint32_t hoff,
                                           uint32_t woff) {
    cp_wait0();
    __syncthreads();
    if (tid == 0) {
        asm volatile("tcgen05.fence::after_thread_sync;" ::: "memory");
        asm volatile("fence.proxy.async.shared::cta;" ::: "memory");
#pragma unroll
        for (int c = 0; c < 2; c++) {
            uint64_t hd = mk_desc(sb + 1024 + hoff + c * 16384);
            uint64_t wd = mk_desc(sb + 1024 + woff + c * 16384);
#pragma unroll
            for (int j = 0; j < 4; j++)
                mma_f16_ss(tmem, hd + j * 2, wd + j * 2,
                           (c > 0 || j > 0) ? 1u : 0u);
        }
        tc_commit(sb + 24);
    }
    mbar_wait(sb + 24, 0);
    asm volatile("tcgen05.fence::after_thread_sync;" ::: "memory");

    const int sp = wid & 3;
    const int ch = wid >> 2;
    const int m = block_row + sp * 32 + lid;
#pragma unroll
    for (int half = 0; half < 2; half++) {
        int cb = ch * 64 + half * 32;
        uint32_t r32[32];
        TC_LD_X32(r32, tmem + cb);
        asm volatile("tcgen05.wait::ld.sync.aligned;" ::: "memory");
#pragma unroll
        for (int j = 0; j < 32; j += 8) {
            float f[8];
#pragma unroll
            for (int i = 0; i < 8; i++)
                f[i] = fmaxf(__uint_as_float(r32[j + i]) + bias2[cb + j + i], 0.f);
            uint4 o;
            o.x = pack2(f[0], f[1]); o.y = pack2(f[2], f[3]);
            o.z = pack2(f[4], f[5]); o.w = pack2(f[6], f[7]);
            *(uint4*)(Cm + (size_t)m * 128 + cb + j) = o;
        }
    }
}
#endif  // TC_AVAIL

// ----- fused input layer (tf32 phase1, K=67 pad 96) + msg0 -----
struct FIN {
    const float* emb; const int* types; const float* coords;
    const float* Wt; const float* bias;
    const unsigned char* maskB;
    __half* Ch;
    const __half* msgW; const float* bias2; __half* Cm;
};

__global__ void __launch_bounds__(256) k_fused_in(FIN g) {
#if TC_AVAIL
    extern __shared__ __align__(1024) char smem[];
    const uint32_t sb = smem_u32(smem);
    const int tid = threadIdx.x;
    const int wid = tid >> 5;
    const int lid = tid & 31;
    const int block_row = blockIdx.x * 128;

    auto stage1 = [&](int t, int s) {
        uint32_t bufA = sb + 1024 + s * 32768;
        uint32_t bufW = bufA + 16384;
#pragma unroll
        for (int it = 0; it < 4; it++) {
            int idx = tid + it * 256;
            int r = idx >> 3, c4 = idx & 7;
            cp16(bufW + SW128((uint32_t)(r * 128 + c4 * 16)),
                 g.Wt + (size_t)r * 96 + t * 32 + c4 * 4);
        }
#pragma unroll
        for (int it = 0; it < 4; it++) {
            int idx = tid + it * 256;
            int r = idx >> 3, c4 = idx & 7;
            int gr = block_row + r;
            uint32_t dst = bufA + SW128((uint32_t)(r * 128 + c4 * 16));
            if (t < 2) {
                cp16(dst, g.emb + (size_t)g.types[gr] * 64 + t * 32 + c4 * 4);
            } else {
                float4 v = make_float4(0.f, 0.f, 0.f, 0.f);
                if (c4 == 0) {
                    v.x = g.coords[gr * 3];
                    v.y = g.coords[gr * 3 + 1];
                    v.z = g.coords[gr * 3 + 2];
                }
                sts4(dst, v);
            }
        }
        cp_commit();
    };

    // stage first (no TMEM dependency), then alloc overlaps the loads
    stage1(0, 0);                         // G0
    stage1(1, 1);                         // G1
    if (wid == 0) {
        asm volatile(
            "tcgen05.alloc.cta_group::1.sync.aligned.shared::cta.b32 [%0], %1;"
            :: "r"(sb), "r"(128u) : "memory");
        asm volatile("tcgen05.relinquish_alloc_permit.cta_group::1.sync.aligned;");
    }
    if (tid == 0) {
        mbar_init(sb + 8, 1); mbar_init(sb + 16, 1); mbar_init(sb + 24, 1);
    }
    __syncthreads();
    uint32_t tmem;
    asm volatile("ld.shared.b32 %0, [%1];" : "=r"(tmem) : "r"(sb));

    uint64_t d0A = mk_desc(sb + 1024);
    uint64_t d0W = mk_desc(sb + 1024 + 16384);
    uint64_t d1A = mk_desc(sb + 1024 + 32768);
    uint64_t d1W = mk_desc(sb + 1024 + 49152);

    // chunk0 (stage0)
    cp_wait1(); __syncthreads();
    if (tid == 0) {
        asm volatile("fence.proxy.async.shared::cta;" ::: "memory");
#pragma unroll
        for (int j = 0; j < 4; j++)
            mma_tf32_ss(tmem, d0A + j * 2, d0W + j * 2, (j > 0) ? 1u : 0u);
        tc_commit(sb + 8);
    }
    mbar_wait(sb + 8, 0);
    stage1(2, 0);                         // G2 -> stage0

    // chunk1 (stage1)
    cp_wait1(); __syncthreads();
    if (tid == 0) {
        asm volatile("fence.proxy.async.shared::cta;" ::: "memory");
#pragma unroll
        for (int j = 0; j < 4; j++)
            mma_tf32_ss(tmem, d1A + j * 2, d1W + j * 2, 1u);
        tc_commit(sb + 16);
    }
    mbar_wait(sb + 16, 0);
    stage_msgW(sb, tid, g.msgW, 32768);   // G3 -> stage1 region (early prefetch)

    // chunk2 (stage0)
    cp_wait1(); __syncthreads();
    if (tid == 0) {
        asm volatile("fence.proxy.async.shared::cta;" ::: "memory");
#pragma unroll
        for (int j = 0; j < 4; j++)
            mma_tf32_ss(tmem, d0A + j * 2, d0W + j * 2, 1u);
        tc_commit(sb + 8);
    }
    mbar_wait(sb + 8, 1);
    asm volatile("tcgen05.fence::after_thread_sync;" ::: "memory");

    // drain h (hTile into stage0 region), then phase2 (msgW in stage1 region)
    epi1_store(sb, tmem, wid, lid, block_row, g.bias, g.maskB, g.Ch, 0);
    phase2_run(sb, tmem, tid, wid, lid, block_row, g.bias2, g.Cm, 0, 32768);

    __syncthreads();
    if (wid == 0) {
        asm volatile("tcgen05.dealloc.cta_group::1.sync.aligned.b32 %0, %1;"
                     :: "r"(tmem), "r"(128u));
    }
#else
    const int m = blockIdx.x * 128 + threadIdx.x % 128;
    if (threadIdx.x >= 128) return;
    const bool masked = (g.maskB[m] != 0);
    int ty = g.types[m];
    for (int cb = 0; cb < 128; cb++) {
        float acc = 0.f;
        for (int k = 0; k < 64; k++)
            acc = fmaf(g.emb[(size_t)ty * 64 + k], g.Wt[(size_t)cb * 96 + k], acc);
        for (int k = 64; k < 67; k++)
            acc = fmaf(g.coords[m * 3 + (k - 64)], g.Wt[(size_t)cb * 96 + k], acc);
        float v = fmaxf(acc + g.bias[cb], 0.f);
        if (masked) v = 0.f;
        g.Ch[(size_t)m * 128 + cb] = __float2half(v);
    }
    for (int cb = 0; cb < 128; cb++) {
        float acc = 0.f;
        for (int k = 0; k < 128; k++)
            acc = fmaf(__half2float(g.Ch[(size_t)m * 128 + k]),
                       __half2float(g.msgW[(size_t)cb * 128 + k]), acc);
        g.Cm[(size_t)m * 128 + cb] = __float2half(fmaxf(acc + g.bias2[cb], 0.f));
    }
#endif
}

// ----- fused upd layer (f16 phase1, K=256 concat [h|agg]) + next msg -----
struct FUP {
    const __half* A1; const __half* A2;
    const __half* Wt; const float* bias;
    const unsigned char* maskB;
    __half* Ch;
    const __half* msgW; const float* bias2; __half* Cm;
};

__global__ void __launch_bounds__(256) k_fused_upd(FUP g) {
#if TC_AVAIL
    extern __shared__ __align__(1024) char smem[];
    const uint32_t sb = smem_u32(smem);
    const int tid = threadIdx.x;
    const int wid = tid >> 5;
    const int lid = tid & 31;
    const int block_row = blockIdx.x * 128;

    auto stage1 = [&](int t, int s) {
        uint32_t bufA = sb + 1024 + s * 32768;
        uint32_t bufW = bufA + 16384;
#pragma unroll
        for (int it = 0; it < 4; it++) {
            int idx = tid + it * 256;
            int r = idx >> 3, c4 = idx & 7;
            cp16(bufW + SW128((uint32_t)(r * 128 + c4 * 16)),
                 g.Wt + (size_t)r * 256 + t * 64 + c4 * 8);
        }
#pragma unroll
        for (int it = 0; it < 4; it++) {
            int idx = tid + it * 256;
            int r = idx >> 3, c4 = idx & 7;
            int gr = block_row + r;
            const __half* src = (t < 2)
                ? g.A1 + (size_t)gr * 128 + t * 64 + c4 * 8
                : g.A2 + (size_t)gr * 128 + (t - 2) * 64 + c4 * 8;
            cp16(bufA + SW128((uint32_t)(r * 128 + c4 * 16)), src);
        }
        cp_commit();
    };

    stage1(0, 0);                         // G0
    stage1(1, 1);                         // G1
    if (wid == 0) {
        asm volatile(
            "tcgen05.alloc.cta_group::1.sync.aligned.shared::cta.b32 [%0], %1;"
            :: "r"(sb), "r"(128u) : "memory");
        asm volatile("tcgen05.relinquish_alloc_permit.cta_group::1.sync.aligned;");
    }
    if (tid == 0) {
        mbar_init(sb + 8, 1); mbar_init(sb + 16, 1); mbar_init(sb + 24, 1);
    }
    __syncthreads();
    uint32_t tmem;
    asm volatile("ld.shared.b32 %0, [%1];" : "=r"(tmem) : "r"(sb));

    uint64_t d0A = mk_desc(sb + 1024);
    uint64_t d0W = mk_desc(sb + 1024 + 16384);
    uint64_t d1A = mk_desc(sb + 1024 + 32768);
    uint64_t d1W = mk_desc(sb + 1024 + 49152);

    // chunk0 (stage0)
    cp_wait1(); __syncthreads();
    if (tid == 0) {
        asm volatile("fence.proxy.async.shared::cta;" ::: "memory");
#pragma unroll
        for (int j = 0; j < 4; j++)
            mma_f16_ss(tmem, d0A + j * 2, d0W + j * 2, (j > 0) ? 1u : 0u);
        tc_commit(sb + 8);
    }
    mbar_wait(sb + 8, 0);
    stage1(2, 0);                         // G2

    // chunk1 (stage1)
    cp_wait1(); __syncthreads();
    if (tid == 0) {
        asm volatile("fence.proxy.async.shared::cta;" ::: "memory");
#pragma unroll
        for (int j = 0; j < 4; j++)
            mma_f16_ss(tmem, d1A + j * 2, d1W + j * 2, 1u);
        tc_commit(sb + 16);
    }
    mbar_wait(sb + 16, 0);
    stage1(3, 1);                         // G3

    // chunk2 (stage0)
    cp_wait1(); __syncthreads();
    if (tid == 0) {
        asm volatile("fence.proxy.async.shared::cta;" ::: "memory");
#pragma unroll
        for (int j = 0; j < 4; j++)
            mma_f16_ss(tmem, d0A + j * 2, d0W + j * 2, 1u);
        tc_commit(sb + 8);
    }
    mbar_wait(sb + 8, 1);
    stage_msgW(sb, tid, g.msgW, 0);       // G4 -> stage0 region (early prefetch)

    // chunk3 (stage1)
    cp_wait1(); __syncthreads();
    if (tid == 0) {
        asm volatile("fence.proxy.async.shared::cta;" ::: "memory");
#pragma unroll
        for (int j = 0; j < 4; j++)
            mma_f16_ss(tmem, d1A + j * 2, d1W + j * 2, 1u);
        tc_commit(sb + 16);
    }
    mbar_wait(sb + 16, 1);
    asm volatile("tcgen05.fence::after_thread_sync;" ::: "memory");

    // drain h (hTile into stage1 region), then phase2 (msgW in stage0 region)
    epi1_store(sb, tmem, wid, lid, block_row, g.bias, g.maskB, g.Ch, 32768);
    phase2_run(sb, tmem, tid, wid, lid, block_row, g.bias2, g.Cm, 32768, 0);

    __syncthreads();
    if (wid == 0) {
        asm volatile("tcgen05.dealloc.cta_group::1.sync.aligned.b32 %0, %1;"
                     :: "r"(tmem), "r"(128u));
    }
#else
    const int m = blockIdx.x * 128 + threadIdx.x % 128;
    if (threadIdx.x >= 128) return;
    const bool masked = (g.maskB[m] != 0);
    for (int cb = 0; cb < 128; cb++) {
        float acc = 0.f;
        for (int k = 0; k < 128; k++)
            acc = fmaf(__half2float(g.A1[(size_t)m * 128 + k]),
                       __half2float(g.Wt[(size_t)cb * 256 + k]), acc);
        for (int k = 0; k < 128; k++)
            acc = fmaf(__half2float(g.A2[(size_t)m * 128 + k]),
                       __half2float(g.Wt[(size_t)cb * 256 + 128 + k]), acc);
        float v = fmaxf(acc + g.bias[cb], 0.f);
        if (masked) v = 0.f;
        g.Ch[(size_t)m * 128 + cb] = __float2half(v);
    }
    for (int cb = 0; cb < 128; cb++) {
        float acc = 0.f;
        for (int k = 0; k < 128; k++)
            acc = fmaf(__half2float(g.Ch[(size_t)m * 128 + k]),
                       __half2float(g.msgW[(size_t)cb * 128 + k]), acc);
        g.Cm[(size_t)m * 128 + cb] = __float2half(fmaxf(acc + g.bias2[cb], 0.f));
    }
#endif
}

// ---------------------------------------------------------------------------
// Standalone fp16 GEMM (upd1). M=256, staging before alloc.
// ---------------------------------------------------------------------------
#define STAGE_F16    49152
#define SMEM_F16     (1024 + 2 * STAGE_F16)

struct GH {
    const __half* A1; const __half* A2;
    const __half* Wt; const float* bias;
    const unsigned char* maskB;
    __half* C;
};

#if TC_AVAIL
__device__ __forceinline__ void stage_f16u(const GH& g, uint32_t bufA,
                                           uint32_t bufW, int block_row,
                                           int t, int tid) {
#pragma unroll
    for (int it = 0; it < 4; it++) {
        int idx = tid + it * 256;
        int r = idx >> 3, c4 = idx & 7;
        cp16(bufW + SW128((uint32_t)(r * 128 + c4 * 16)),
             g.Wt + (size_t)r * 256 + t * 64 + c4 * 8);
    }
#pragma unroll
    for (int it = 0; it < 8; it++) {
        int idx = tid + it * 256;
        int r = idx >> 3, c4 = idx & 7;
        int gr = block_row + r;
        const __half* src = (t < 2)
            ? g.A1 + (size_t)gr * 128 + t * 64 + c4 * 8
            : g.A2 + (size_t)gr * 128 + (t - 2) * 64 + c4 * 8;
        cp16(bufA + SW128((uint32_t)(r * 128 + c4 * 16)), src);
    }
    cp_commit();
}
#endif

__global__ void __launch_bounds__(256) k_gemm_upd(GH g) {
#if TC_AVAIL
    extern __shared__ __align__(1024) char smem[];
    const uint32_t sb = smem_u32(smem);
    const int tid = threadIdx.x;
    const int wid = tid >> 5;
    const int lid = tid & 31;
    const int block_row = blockIdx.x * 256;

    const uint32_t bufA0 = sb + 1024;
    const uint32_t bufW0 = bufA0 + 32768;

    stage_f16u(g, bufA0, bufW0, block_row, 0, tid);
    stage_f16u(g, bufA0 + STAGE_F16, bufW0 + STAGE_F16, block_row, 1, tid);

    if (wid == 0) {
        asm volatile(
            "tcgen05.alloc.cta_group::1.sync.aligned.shared::cta.b32 [%0], %1;"
            :: "r"(sb), "r"(256u) : "memory");
        asm volatile("tcgen05.relinquish_alloc_permit.cta_group::1.sync.aligned;");
    }
    if (tid == 0) { mbar_init(sb + 8, 1); mbar_init(sb + 16, 1); }
    __syncthreads();
    uint32_t tmem;
    asm volatile("ld.shared.b32 %0, [%1];" : "=r"(tmem) : "r"(sb));

    const int nt = 4;
    for (int t = 0; t < nt; t++) {
        const int b = t & 1;
        if (t < nt - 1) cp_wait1(); else cp_wait0();
        __syncthreads();
        if (tid == 0) {
            asm volatile("fence.proxy.async.shared::cta;" ::: "memory");
            uint64_t ad0 = mk_desc(bufA0 + b * STAGE_F16);
            uint64_t ad1 = mk_desc(bufA0 + b * STAGE_F16 + 16384);
            uint64_t bd  = mk_desc(bufW0 + b * STAGE_F16);
#pragma unroll
            for (int j = 0; j < 4; j++) {
                uint32_t en = (t > 0 || j > 0) ? 1u : 0u;
                mma_f16_ss(tmem,       ad0 + j * 2, bd + j * 2, en);
                mma_f16_ss(tmem + 128, ad1 + j * 2, bd + j * 2, en);
            }
            tc_commit(sb + 8 + b * 8);
        }
        if (t + 2 < nt) {
            mbar_wait(sb + 8 + b * 8, (t >> 1) & 1);
            stage_f16u(g, bufA0 + b * STAGE_F16, bufW0 + b * STAGE_F16,
                       block_row, t + 2, tid);
        }
    }

    mbar_wait(sb + 8 + ((nt - 1) & 1) * 8, ((nt - 1) >> 1) & 1);
    asm volatile("tcgen05.fence::after_thread_sync;" ::: "memory");

    const int blk = wid >> 2;
    const int sp  = wid & 3;
    const int m   = block_row + blk * 128 + sp * 32 + lid;
    const bool masked = (g.maskB[m] != 0);
#pragma unroll
    for (int cb = 0; cb < 128; cb += 32) {
        uint32_t r32[32];
        TC_LD_X32(r32, tmem + blk * 128 + cb);
        asm volatile("tcgen05.wait::ld.sync.aligned;" ::: "memory");
#pragma unroll
        for (int j = 0; j < 32; j += 8) {
            float f[8];
#pragma unroll
            for (int i = 0; i < 8; i++) {
                float v = __uint_as_float(r32[j + i]) + g.bias[cb + j + i];
                v = fmaxf(v, 0.f);
                if (masked) v = 0.f;
                f[i] = v;
            }
            uint4 o;
            o.x = pack2(f[0], f[1]); o.y = pack2(f[2], f[3]);
            o.z = pack2(f[4], f[5]); o.w = pack2(f[6], f[7]);
            *(uint4*)(g.C + (size_t)m * 128 + cb + j) = o;
        }
    }

    __syncthreads();
    if (wid == 0) {
        asm volatile("tcgen05.dealloc.cta_group::1.sync.aligned.b32 %0, %1;"
                     :: "r"(tmem), "r"(256u));
    }
#else
    const int row = blockIdx.x * 256 + threadIdx.x;
    const bool masked = (g.maskB[row] != 0);
#pragma unroll 1
    for (int cb = 0; cb < 128; cb++) {
        float acc = 0.f;
        for (int k = 0; k < 128; k++)
            acc = fmaf(__half2float(g.A1[(size_t)row * 128 + k]),
                       __half2float(g.Wt[(size_t)cb * 256 + k]), acc);
        for (int k = 0; k < 128; k++)
            acc = fmaf(__half2float(g.A2[(size_t)row * 128 + k]),
                       __half2float(g.Wt[(size_t)cb * 256 + 128 + k]), acc);
        float v = fmaxf(acc + g.bias[cb], 0.f);
        if (masked) v = 0.f;
        g.C[(size_t)row * 128 + cb] = __float2half(v);
    }
#endif
}

// ---------------------------------------------------------------------------
// Coupling dual fp16 GEMM + fused final epilogue. 256 threads; epilogue split
// across 8 warps (warps 0-3: scale accumulator, warps 4-7: shift accumulator,
// partials exchanged via smem).
// ---------------------------------------------------------------------------
#define CPL_HDR      8192
#define CPL_STAGE    49152           // 16KB A + 16KB Ws + 16KB Wh
#define SMEM_CPL     (CPL_HDR + 2 * CPL_STAGE)

struct CPH {
    const __half* A1; const float* coords;
    const __half* Wse; const __half* Whe;
    const float* bse; const float* bhe;
    const float* Ws2; const float* bs2;
    const float* Wh2; const float* bh2;
    const unsigned char* maskB;
    float* out; float* logdet;
};

__global__ void __launch_bounds__(256) k_gemm_cpl(CPH g) {
#if TC_AVAIL
    extern __shared__ __align__(1024) char smem[];
    const uint32_t sb = smem_u32(smem);
    float* smf = (float*)smem;
    const int tid = threadIdx.x;
    const int wid = tid >> 5;
    const int lid = tid & 31;
    const int block_row = blockIdx.x * 128;

    auto stage = [&](int t, int b) {
        uint32_t base = sb + CPL_HDR + b * CPL_STAGE;
#pragma unroll
        for (int it = 0; it < 12; it++) {
            int idx = tid + it * 256;            // 0..3071
            int sec = idx >> 10;
            int w   = idx & 1023;
            int r   = w >> 3;
            int c4  = w & 7;
            uint32_t dst = base + sec * 16384 + SW128((uint32_t)(r * 128 + c4 * 16));
            if (sec == 0) {
                if (t < 2) {
                    cp16(dst, g.A1 + (size_t)(block_row + r) * 128 + t * 64 + c4 * 8);
                } else {
                    uint4 o = make_uint4(0u, 0u, 0u, 0u);
                    if (c4 == 0) {
                        int gr = block_row + r;
                        bool cm = ((gr & 1) == 0) && (g.maskB[gr] == 0);
                        float c0 = cm ? 0.f : g.coords[gr * 3];
                        float c1 = cm ? 0.f : g.coords[gr * 3 + 1];
                        float c2 = cm ? 0.f : g.coords[gr * 3 + 2];
                        o.x = pack2(c0, c1);
                        o.y = pack2(c2, 0.f);
                    }
                    sts4u(dst, o);
                }
            } else if (sec == 1) {
                cp16(dst, g.Wse + (size_t)r * 192 + t * 64 + c4 * 8);
            } else {
                cp16(dst, g.Whe + (size_t)r * 192 + t * 64 + c4 * 8);
            }
        }
        cp_commit();
    };

    stage(0, 0);
    stage(1, 1);

    if (wid == 0) {
        asm volatile(
            "tcgen05.alloc.cta_group::1.sync.aligned.shared::cta.b32 [%0], %1;"
            :: "r"(sb), "r"(256u) : "memory");
        asm volatile("tcgen05.relinquish_alloc_permit.cta_group::1.sync.aligned;");
    }
    if (tid == 0) { mbar_init(sb + 8, 1); mbar_init(sb + 16, 1); }
    for (int i = tid; i < 384; i += 256) {
        smf[16 + i]  = g.Ws2[i];
        smf[400 + i] = g.Wh2[i];
    }
    if (tid < 128) {
        smf[784 + tid] = g.bse[tid];
        smf[912 + tid] = g.bhe[tid];
    }
    __syncthreads();
    uint32_t tmem;
    asm volatile("ld.shared.b32 %0, [%1];" : "=r"(tmem) : "r"(sb));

    const int nt = 3;
    for (int t = 0; t < nt; t++) {
        const int b = t & 1;
        if (t < nt - 1) cp_wait1(); else cp_wait0();
        __syncthreads();
        if (tid == 0) {
            asm volatile("fence.proxy.async.shared::cta;" ::: "memory");
            uint32_t base = sb + CPL_HDR + b * CPL_STAGE;
            uint64_t ad = mk_desc(base);
            uint64_t sd = mk_desc(base + 16384);
            uint64_t hd = mk_desc(base + 32768);
#pragma unroll
            for (int j = 0; j < 4; j++) {
                uint32_t en = (t > 0 || j > 0) ? 1u : 0u;
                mma_f16_ss(tmem,       ad + j * 2, sd + j * 2, en);
                mma_f16_ss(tmem + 128, ad + j * 2, hd + j * 2, en);
            }
            tc_commit(sb + 8 + b * 8);
        }
        if (t + 2 < nt) {
            mbar_wait(sb + 8 + b * 8, (t >> 1) & 1);
            stage(t + 2, b);
        }
    }

    mbar_wait(sb + 8 + ((nt - 1) & 1) * 8, ((nt - 1) >> 1) & 1);
    asm volatile("tcgen05.fence::after_thread_sync;" ::: "memory");

    // split epilogue: grp 0 (warps 0-3) = scale acc, grp 1 (warps 4-7) = shift
    const int grp = wid >> 2;
    const int sp  = wid & 3;
    const int row = sp * 32 + lid;
    const int m   = block_row + row;
    const uint32_t tbase = tmem + grp * 128;
    const int tbl = grp ? 400 : 16;
    const int bb  = grp ? 912 : 784;

    float acc[3] = {0.f, 0.f, 0.f};
#pragma unroll
    for (int cb = 0; cb < 128; cb += 32) {
        uint32_t r32[32];
        TC_LD_X32(r32, tbase + cb);
        asm volatile("tcgen05.wait::ld.sync.aligned;" ::: "memory");
#pragma unroll
        for (int k = 0; k < 32; k++) {
            int col = cb + k;
            float v = fmaxf(__uint_as_float(r32[k]) + smf[bb + col], 0.f);
#pragma unroll
            for (int c = 0; c < 3; c++)
                acc[c] = fmaf(v, smf[tbl + col * 3 + c], acc[c]);
        }
    }

    if (grp == 1) {   // shift warps stash partials (smf[1152..1535], byte 4608)
#pragma unroll
        for (int c = 0; c < 3; c++) smf[1152 + row * 3 + c] = acc[c];
    }
    __syncthreads();

    if (grp == 0) {
        bool cm = ((m & 1) == 0) && (g.maskB[m] == 0);   // PHASE = 0
        float ld = 0.f;
#pragma unroll
        for (int c = 0; c < 3; c++) {
            float r = acc[c] + g.bs2[c];
            float s = smf[1152 + row * 3 + c] + g.bh2[c];
            float ls = cm ? tanhf(r) * 2.f : 0.f;
            ld += ls;
            float coord = g.coords[m * 3 + c];
            g.out[m * 3 + c] = cm ? (expf(ls) * coord + s) : coord;
        }
#pragma unroll
        for (int o = 16; o > 0; o >>= 1)
            ld += __shfl_xor_sync(0xFFFFFFFFu, ld, o);
        if (lid == 0) atomicAdd(&g.logdet[m >> 13], ld);
    }

    __syncthreads();
    if (wid == 0) {
        asm volatile("tcgen05.dealloc.cta_group::1.sync.aligned.b32 %0, %1;"
                     :: "r"(tmem), "r"(256u));
    }
#else
    if (threadIdx.x >= 128) return;
    const int m = blockIdx.x * 128 + threadIdx.x;
    bool cm = ((m & 1) == 0) && (g.maskB[m] == 0);
    float raw[3], shf[3];
#pragma unroll
    for (int c = 0; c < 3; c++) { raw[c] = g.bs2[c]; shf[c] = g.bh2[c]; }
    for (int n = 0; n < 128; n++) {
        float accs = g.bse[n], acch = g.bhe[n];
        for (int k = 0; k < 128; k++) {
            float a = __half2float(g.A1[(size_t)m * 128 + k]);
            accs = fmaf(a, __half2float(g.Wse[n * 192 + k]), accs);
            acch = fmaf(a, __half2float(g.Whe[n * 192 + k]), acch);
        }
        for (int k = 128; k < 131; k++) {
            float a = cm ? 0.f : g.coords[m * 3 + (k - 128)];
            accs = fmaf(a, __half2float(g.Wse[n * 192 + k]), accs);
            acch = fmaf(a, __half2float(g.Whe[n * 192 + k]), acch);
        }
        accs = fmaxf(accs, 0.f); acch = fmaxf(acch, 0.f);
#pragma unroll
        for (int c = 0; c < 3; c++) {
            raw[c] = fmaf(accs, g.Ws2[n * 3 + c], raw[c]);
            shf[c] = fmaf(acch, g.Wh2[n * 3 + c], shf[c]);
        }
    }
    float ld = 0.f;
#pragma unroll
    for (int c = 0; c < 3; c++) {
        float ls = cm ? tanhf(raw[c]) * 2.f : 0.f;
        ld += ls;
        float coord = g.coords[m * 3 + c];
        g.out[m * 3 + c] = cm ? (expf(ls) * coord + shf[c]) : coord;
    }
    atomicAdd(&g.logdet[m >> 13], ld);
#endif
}

// ---------------------------------------------------------------------------
// Host launcher. Index 3 = k_fused_in (ncu profile target).
// ---------------------------------------------------------------------------
extern "C" void kernel_launch(void* const* d_in, const int* in_sizes, int n_in,
                              void* d_out, int out_size) {
    const float*         coords = (const float*)d_in[0];
    const int*           types  = (const int*)  d_in[1];
    const int*           adj    = (const int*)  d_in[2];
    const int*           ebi    = (const int*)  d_in[3];
    const unsigned char* maskB  = (const unsigned char*)d_in[4];
    const float* emb   = (const float*)d_in[5];
    const float* W_in  = (const float*)d_in[6];
    const float* b_in  = (const float*)d_in[7];
    const float* msg_W = (const float*)d_in[8];
    const float* msg_b = (const float*)d_in[9];
    const float* upd_W = (const float*)d_in[10];
    const float* upd_b = (const float*)d_in[11];
    const float* W_out = (const float*)d_in[12];
    const float* b_out = (const float*)d_in[13];
    const float* Ws1   = (const float*)d_in[14];
    const float* bs1   = (const float*)d_in[15];
    const float* Ws2   = (const float*)d_in[16];
    const float* bs2   = (const float*)d_in[17];
    const float* Wh1   = (const float*)d_in[18];
    const float* bh1   = (const float*)d_in[19];
    const float* Wh2   = (const float*)d_in[20];
    const float* bh2   = (const float*)d_in[21];

    float* out    = (float*)d_out;
    float* logdet = out + (size_t)BN_ * 3;

    __half *h, *b1, *b2, *wth;
    float *wt;
    int *off, *part, *cur, *srcl;
    cudaGetSymbolAddress((void**)&h,    g_h);
    cudaGetSymbolAddress((void**)&b1,   g_b1);
    cudaGetSymbolAddress((void**)&b2,   g_b2);
    cudaGetSymbolAddress((void**)&wt,   g_wt);
    cudaGetSymbolAddress((void**)&wth,  g_wth);
    cudaGetSymbolAddress((void**)&off,  g_off);
    cudaGetSymbolAddress((void**)&part, g_part);
    cudaGetSymbolAddress((void**)&cur,  g_cur);
    cudaGetSymbolAddress((void**)&srcl, g_srcl);

    cudaFuncSetAttribute(k_fused_in,  cudaFuncAttributeMaxDynamicSharedMemorySize, SMEM_FUSED);
    cudaFuncSetAttribute(k_fused_upd, cudaFuncAttributeMaxDynamicSharedMemorySize, SMEM_FUSED);
    cudaFuncSetAttribute(k_gemm_upd,  cudaFuncAttributeMaxDynamicSharedMemorySize, SMEM_F16);
    cudaFuncSetAttribute(k_gemm_cpl,  cudaFuncAttributeMaxDynamicSharedMemorySize, SMEM_CPL);

    const int BT = 256;

    // 0: prep
    k_prep<<<1024, BT>>>(W_in, msg_W, upd_W, W_out, Ws1, Wh1, bs1, bh1, b_out,
                         wt, wth, off, logdet);
    // 1: hist
    k_hist<<<E_ / BT, BT>>>(adj, ebi, off);
    // 2: scanA
    k_scanA<<<512, 512>>>(off, part);
    // 3: fused input + msg0  <-- ncu profile target
    FIN fi{emb, types, coords, wt + O_WIN, b_in, maskB, h,
           wth + H_MSG0, msg_b, b1};
    k_fused_in<<<BN_ / 128, 256, SMEM_FUSED>>>(fi);
    // 4-5: finish CSR
    k_scanB<<<512, 512>>>(off, part, cur);
    k_place<<<E_ / BT, BT>>>(adj, ebi, cur, srcl);
    // 6: gather layer 0
    k_gather<<<BN_ / 16, BT>>>(b1, off, srcl, b2);
    // 7: fused upd0 + msg1
    FUP fu{h, b2, wth + H_UPD0, upd_b, maskB, h, wth + H_MSG1, msg_b + 128, b1};
    k_fused_upd<<<BN_ / 128, 256, SMEM_FUSED>>>(fu);
    // 8: gather layer 1
    k_gather<<<BN_ / 16, BT>>>(b1, off, srcl, b2);
    // 9: upd layer 1 (standalone)
    GH gu1{h, b2, wth + H_UPD1, upd_b + 128, maskB, h};
    k_gemm_upd<<<BN_ / 256, 256, SMEM_F16>>>(gu1);
    // 10: fused coupling (dual fp16 GEMM + final epilogue), 256 threads
    CPH c{h, coords, wth + H_WSE, wth + H_WHE, wt + O_BSE, wt + O_BHE,
          Ws2, bs2, Wh2, bh2, maskB, out, logdet};
    k_gemm_cpl<<<BN_ / 128, 256, SMEM_CPL>>>(c);
}

// round 15
// speedup vs baseline: 9.5735x; 1.0863x over previous
#include <cuda_runtime.h>
#include <cuda_fp16.h>
#include <cstdint>
#include <math.h>
#include <stddef.h>

// Problem constants
#define B_   32
#define N_   8192
#define E_   1048576
#define BN_  (B_ * N_)          // 262144
#define L_   2

// ---------------------------------------------------------------------------
// Arch-feature gate (tcgen05 only exists on sm_100a/sm_103a passes)
// ---------------------------------------------------------------------------
#if defined(__CUDA_ARCH_FEAT_SM103_ALL) || defined(__CUDA_ARCH_FEAT_SM100_ALL)
#  define TC_AVAIL 1
#endif
#ifndef TC_AVAIL
#  ifdef __CUDA_ARCH_HAS_FEATURE__
#    if __CUDA_ARCH_HAS_FEATURE__(SM103_ALL) || __CUDA_ARCH_HAS_FEATURE__(SM100_ALL)
#      define TC_AVAIL 1
#    endif
#  endif
#endif
#ifndef TC_AVAIL
#  define TC_AVAIL 0
#endif

// ---------------------------------------------------------------------------
// Scratch (static device globals)
// ---------------------------------------------------------------------------
static __device__ __align__(16) __half g_h [(size_t)BN_ * 128];
static __device__ __align__(16) __half g_b1[(size_t)BN_ * 128];   // msg_all
static __device__ __align__(16) __half g_b2[(size_t)BN_ * 128];   // agg
static __device__ __align__(16) float  g_wt [12544];              // fp32 W_in^T + bse/bhe
static __device__ __align__(16) __half g_wth[147456];             // fp16 weights
static __device__ int g_off [BN_ + 1];
static __device__ int g_part[512];
static __device__ int g_cur [BN_];
static __device__ int g_srcl[E_];

// g_wt fp32 offsets
#define O_WIN   0        // 128 x 96 (K=67 pad)
#define O_BSE   12288
#define O_BHE   12416
// g_wth half offsets
#define H_MSG0  0        // 128x128
#define H_MSG1  16384
#define H_UPD0  32768    // 128x256
#define H_UPD1  65536
#define H_WSE   98304    // 128x192 (K=131 pad)
#define H_WHE   122880

// ---------------------------------------------------------------------------
// Helpers
// ---------------------------------------------------------------------------
__device__ __forceinline__ uint32_t smem_u32(const void* p) {
    uint32_t a;
    asm("{ .reg .u64 t; cvta.to.shared.u64 t, %1; cvt.u32.u64 %0, t; }"
        : "=r"(a) : "l"(p));
    return a;
}

#define SW128(o) ((o) ^ (((o) >> 3) & 0x70))

__device__ __forceinline__ void cp16(uint32_t dst, const void* src) {
    asm volatile("cp.async.cg.shared.global [%0], [%1], 16;"
                 :: "r"(dst), "l"(src) : "memory");
}
__device__ __forceinline__ void cp_commit() {
    asm volatile("cp.async.commit_group;" ::: "memory");
}
__device__ __forceinline__ void cp_wait1() {
    asm volatile("cp.async.wait_group 1;" ::: "memory");
}
__device__ __forceinline__ void cp_wait0() {
    asm volatile("cp.async.wait_group 0;" ::: "memory");
}
__device__ __forceinline__ void sts4(uint32_t dst, float4 v) {
    asm volatile("st.shared.v4.f32 [%0], {%1, %2, %3, %4};"
                 :: "r"(dst), "f"(v.x), "f"(v.y), "f"(v.z), "f"(v.w) : "memory");
}
__device__ __forceinline__ void sts4u(uint32_t dst, uint4 v) {
    asm volatile("st.shared.v4.u32 [%0], {%1, %2, %3, %4};"
                 :: "r"(dst), "r"(v.x), "r"(v.y), "r"(v.z), "r"(v.w) : "memory");
}
__device__ __forceinline__ uint32_t pack2(float a, float b) {
    __half2 h = __floats2half2_rn(a, b);
    return *reinterpret_cast<uint32_t*>(&h);
}

#if TC_AVAIL
__device__ __forceinline__ uint64_t mk_desc(uint32_t addr) {
    // SW128, version=1 (Blackwell), LBO=1, SBO=64 (K-major)
    const uint64_t BASE = (2ULL << 61) | (1ULL << 46) | (64ULL << 32) | (1ULL << 16);
    return BASE | ((uint64_t)(addr >> 4) & 0x3FFF);
}

// tf32: acc=F32, atype=btype=TF32(2), N=128, M=128
#define IDESC_TF32 ((1u << 4) | (2u << 7) | (2u << 10) | (16u << 17) | (8u << 24))
// fp16: acc=F32, atype=btype=FP16(0), N=128, M=128
#define IDESC_F16  ((1u << 4) | (16u << 17) | (8u << 24))

__device__ __forceinline__ void mma_tf32_ss(uint32_t d, uint64_t a, uint64_t b,
                                            uint32_t en) {
    asm volatile(
        "{\n\t.reg .pred p;\n\t"
        "setp.ne.u32 p, %4, 0;\n\t"
        "tcgen05.mma.cta_group::1.kind::tf32 [%0], %1, %2, %3, p;\n\t}"
        :: "r"(d), "l"(a), "l"(b), "r"(IDESC_TF32), "r"(en) : "memory");
}
__device__ __forceinline__ void mma_f16_ss(uint32_t d, uint64_t a, uint64_t b,
                                           uint32_t en) {
    asm volatile(
        "{\n\t.reg .pred p;\n\t"
        "setp.ne.u32 p, %4, 0;\n\t"
        "tcgen05.mma.cta_group::1.kind::f16 [%0], %1, %2, %3, p;\n\t}"
        :: "r"(d), "l"(a), "l"(b), "r"(IDESC_F16), "r"(en) : "memory");
}
// TS-mode: A operand in TMEM (fp16x2 columns), B in SMEM.
__device__ __forceinline__ void mma_f16_ts(uint32_t d, uint32_t a, uint64_t b,
                                           uint32_t en) {
    asm volatile(
        "{\n\t.reg .pred p;\n\t"
        "setp.ne.u32 p, %4, 0;\n\t"
        "tcgen05.mma.cta_group::1.kind::f16 [%0], [%1], %2, %3, p;\n\t}"
        :: "r"(d), "r"(a), "l"(b), "r"(IDESC_F16), "r"(en) : "memory");
}

__device__ __forceinline__ void tc_commit(uint32_t mbar) {
    asm volatile(
        "tcgen05.commit.cta_group::1.mbarrier::arrive::one.shared::cluster.b64 [%0];"
        :: "r"(mbar) : "memory");
}

#define TC_LD_X32(r, addr)                                                     \
    asm volatile(                                                              \
        "tcgen05.ld.sync.aligned.32x32b.x32.b32 "                              \
        "{%0, %1, %2, %3, %4, %5, %6, %7, "                                    \
        " %8, %9, %10, %11, %12, %13, %14, %15, "                              \
        " %16, %17, %18, %19, %20, %21, %22, %23, "                            \
        " %24, %25, %26, %27, %28, %29, %30, %31}, [%32];"                     \
        : "=r"((r)[0]),  "=r"((r)[1]),  "=r"((r)[2]),  "=r"((r)[3]),           \
          "=r"((r)[4]),  "=r"((r)[5]),  "=r"((r)[6]),  "=r"((r)[7]),           \
          "=r"((r)[8]),  "=r"((r)[9]),  "=r"((r)[10]), "=r"((r)[11]),          \
          "=r"((r)[12]), "=r"((r)[13]), "=r"((r)[14]), "=r"((r)[15]),          \
          "=r"((r)[16]), "=r"((r)[17]), "=r"((r)[18]), "=r"((r)[19]),          \
          "=r"((r)[20]), "=r"((r)[21]), "=r"((r)[22]), "=r"((r)[23]),          \
          "=r"((r)[24]), "=r"((r)[25]), "=r"((r)[26]), "=r"((r)[27]),          \
          "=r"((r)[28]), "=r"((r)[29]), "=r"((r)[30]), "=r"((r)[31])           \
        : "r"(addr))

#define TC_ST_X32(addr, r)                                                     \
    asm volatile(                                                              \
        "tcgen05.st.sync.aligned.32x32b.x32.b32 [%0], "                        \
        "{%1, %2, %3, %4, %5, %6, %7, %8, "                                    \
        " %9, %10, %11, %12, %13, %14, %15, %16, "                             \
        " %17, %18, %19, %20, %21, %22, %23, %24, "                            \
        " %25, %26, %27, %28, %29, %30, %31, %32};"                            \
        :: "r"(addr),                                                          \
           "r"((r)[0]),  "r"((r)[1]),  "r"((r)[2]),  "r"((r)[3]),              \
           "r"((r)[4]),  "r"((r)[5]),  "r"((r)[6]),  "r"((r)[7]),              \
           "r"((r)[8]),  "r"((r)[9]),  "r"((r)[10]), "r"((r)[11]),             \
           "r"((r)[12]), "r"((r)[13]), "r"((r)[14]), "r"((r)[15]),             \
           "r"((r)[16]), "r"((r)[17]), "r"((r)[18]), "r"((r)[19]),             \
           "r"((r)[20]), "r"((r)[21]), "r"((r)[22]), "r"((r)[23]),             \
           "r"((r)[24]), "r"((r)[25]), "r"((r)[26]), "r"((r)[27]),             \
           "r"((r)[28]), "r"((r)[29]), "r"((r)[30]), "r"((r)[31])              \
        : "memory")
#endif  // TC_AVAIL

__device__ __forceinline__ void mbar_init(uint32_t a, uint32_t cnt) {
    asm volatile("mbarrier.init.shared.b64 [%0], %1;" :: "r"(a), "r"(cnt) : "memory");
}
__device__ __forceinline__ void mbar_wait(uint32_t a, uint32_t parity) {
    asm volatile(
        "{\n\t.reg .pred P;\n"
        "WL%=:\n\t"
        "mbarrier.try_wait.parity.acquire.cta.shared::cta.b64 P, [%0], %1, 0x989680;\n\t"
        "@P bra WD%=;\n\t"
        "bra WL%=;\n"
        "WD%=:\n\t}"
        :: "r"(a), "r"(parity) : "memory");
}

// ---------------------------------------------------------------------------
// k_prep (unchanged)
// ---------------------------------------------------------------------------
__global__ void k_prep(const float* __restrict__ W_in,
                       const float* __restrict__ msg_W,
                       const float* __restrict__ upd_W,
                       const float* __restrict__ W_out,
                       const float* __restrict__ Ws1,
                       const float* __restrict__ Wh1,
                       const float* __restrict__ bs1,
                       const float* __restrict__ bh1,
                       const float* __restrict__ b_out,
                       float* __restrict__ wt,
                       __half* __restrict__ wth,
                       int* __restrict__ off,
                       float* __restrict__ logdet) {
    const int TOTAL = 12544 + 147456 + (BN_ + 1) + 32;
    for (int idx = blockIdx.x * blockDim.x + threadIdx.x; idx < TOTAL;
         idx += gridDim.x * blockDim.x) {
        if (idx < 12288) {
            int n = idx / 96, k = idx - n * 96;
            wt[idx] = (k < 67) ? W_in[k * 128 + n] : 0.f;
        } else if (idx < 12416) {
            int n = idx - 12288;
            float v = bs1[n];
            for (int q = 0; q < 128; q++)
                v = fmaf(b_out[q], Ws1[q * 128 + n], v);
            wt[idx] = v;
        } else if (idx < 12544) {
            int n = idx - 12416;
            float v = bh1[n];
            for (int q = 0; q < 128; q++)
                v = fmaf(b_out[q], Wh1[q * 128 + n], v);
            wt[idx] = v;
        } else {
            int j = idx - 12544;
            if (j < 32768) {
                int l = j >> 14, r = j & 16383;
                int n = r >> 7, k = r & 127;
                wth[j] = __float2half(msg_W[l * 16384 + k * 128 + n]);
            } else if (j < 98304) {
                int j2 = j - 32768;
                int l = j2 >> 15, r = j2 & 32767;
                int n = r >> 8, k = r & 255;
                wth[j] = __float2half(upd_W[l * 32768 + k * 128 + n]);
            } else if (j < 122880) {
                int j2 = j - 98304;
                int n = j2 / 192, k = j2 - n * 192;
                float v = 0.f;
                if (k < 128) {
                    for (int q = 0; q < 128; q++)
                        v = fmaf(W_out[k * 128 + q], Ws1[q * 128 + n], v);
                } else if (k < 131) {
                    v = Ws1[k * 128 + n];
                }
                wth[j] = __float2half(v);
            } else if (j < 147456) {
                int j2 = j - 122880;
                int n = j2 / 192, k = j2 - n * 192;
                float v = 0.f;
                if (k < 128) {
                    for (int q = 0; q < 128; q++)
                        v = fmaf(W_out[k * 128 + q], Wh1[q * 128 + n], v);
                } else if (k < 131) {
                    v = Wh1[k * 128 + n];
                }
                wth[j] = __float2half(v);
            } else if (j < 147456 + BN_ + 1) {
                off[j - 147456] = 0;
            } else {
                logdet[j - (147456 + BN_ + 1)] = 0.f;
            }
        }
    }
}

// ---------------------------------------------------------------------------
// CSR build (unchanged)
// ---------------------------------------------------------------------------
__global__ void k_hist(const int* __restrict__ adj, const int* __restrict__ ebi,
                       int* __restrict__ deg) {
    int e = blockIdx.x * blockDim.x + threadIdx.x;
    if (e >= E_) return;
    int dst = ebi[e] * N_ + adj[2 * e + 1];
    atomicAdd(&deg[dst], 1);
}

__global__ void k_scanA(int* __restrict__ off, int* __restrict__ part) {
    __shared__ int s[512];
    int t = threadIdx.x;
    int i = blockIdx.x * 512 + t;
    int v = off[i];
    s[t] = v; __syncthreads();
    for (int d = 1; d < 512; d <<= 1) {
        int x = (t >= d) ? s[t - d] : 0;
        __syncthreads();
        s[t] += x;
        __syncthreads();
    }
    off[i] = s[t] - v;
    if (t == 511) part[blockIdx.x] = s[t];
}

__global__ void k_scanB(int* __restrict__ off, const int* __restrict__ part,
                        int* __restrict__ cur) {
    __shared__ int s[512];
    int t = threadIdx.x, b = blockIdx.x;
    s[t] = part[t]; __syncthreads();
    for (int d = 1; d < 512; d <<= 1) {
        int x = (t >= d) ? s[t - d] : 0;
        __syncthreads();
        s[t] += x;
        __syncthreads();
    }
    int prefix = (b == 0) ? 0 : s[b - 1];
    int i = b * 512 + t;
    int v = off[i] + prefix;
    off[i] = v;
    cur[i] = v;
    if (b == 0 && t == 0) off[BN_] = E_;
}

__global__ void k_place(const int* __restrict__ adj, const int* __restrict__ ebi,
                        int* __restrict__ cur, int* __restrict__ srcl) {
    int e = blockIdx.x * blockDim.x + threadIdx.x;
    if (e >= E_) return;
    int b = ebi[e];
    int src = b * N_ + adj[2 * e];
    int dst = b * N_ + adj[2 * e + 1];
    int pos = atomicAdd(&cur[dst], 1);
    srcl[pos] = src;
}

// ---------------------------------------------------------------------------
// Gather (unchanged): half-warp per node, uint4 lanes, 4-way unroll.
// ---------------------------------------------------------------------------
__global__ void k_gather(const __half* __restrict__ msg,
                         const int* __restrict__ off,
                         const int* __restrict__ srcl,
                         __half* __restrict__ agg) {
    int gwarp = (blockIdx.x * blockDim.x + threadIdx.x) >> 5;
    int lane  = threadIdx.x & 31;
    int half_ = lane >> 4;
    int l16   = lane & 15;
    int node  = gwarp * 2 + half_;
    int s0 = off[node], s1 = off[node + 1];

    float a[8] = {0.f, 0.f, 0.f, 0.f, 0.f, 0.f, 0.f, 0.f};
    int j = s0;
    for (; j + 4 <= s1; j += 4) {
        uint4 v0 = *((const uint4*)(msg + (size_t)srcl[j]     * 128) + l16);
        uint4 v1 = *((const uint4*)(msg + (size_t)srcl[j + 1] * 128) + l16);
        uint4 v2 = *((const uint4*)(msg + (size_t)srcl[j + 2] * 128) + l16);
        uint4 v3 = *((const uint4*)(msg + (size_t)srcl[j + 3] * 128) + l16);
        const uint32_t* ws[4] = {&v0.x, &v1.x, &v2.x, &v3.x};
#pragma unroll
        for (int e = 0; e < 4; e++)
#pragma unroll
            for (int q = 0; q < 4; q++) {
                float2 f = __half22float2(*(const __half2*)&ws[e][q]);
                a[q * 2] += f.x; a[q * 2 + 1] += f.y;
            }
    }
    for (; j < s1; j++) {
        uint4 v = *((const uint4*)(msg + (size_t)srcl[j] * 128) + l16);
        const uint32_t* w = &v.x;
#pragma unroll
        for (int q = 0; q < 4; q++) {
            float2 f = __half22float2(*(const __half2*)&w[q]);
            a[q * 2] += f.x; a[q * 2 + 1] += f.y;
        }
    }
    uint4 o;
    o.x = pack2(a[0], a[1]); o.y = pack2(a[2], a[3]);
    o.z = pack2(a[4], a[5]); o.w = pack2(a[6], a[7]);
    *((uint4*)(agg + (size_t)node * 128) + l16) = o;
}

// ===========================================================================
// FUSED in/upd kernels (unchanged from R14). TMEM 128 cols, phase2 reuse.
// ===========================================================================
#define SMEM_FUSED   (1024 + 65536)

#if TC_AVAIL
__device__ __forceinline__ void stage_msgW(uint32_t sb, int tid,
                                           const __half* msgW, uint32_t dstoff) {
#pragma unroll
    for (int it = 0; it < 8; it++) {
        int idx = tid + it * 256;
        int chunk = idx >> 10, w = idx & 1023;
        int r = w >> 3, c4 = w & 7;
        uint32_t dst = sb + 1024 + dstoff + chunk * 16384
                     + SW128((uint32_t)(r * 128 + c4 * 16));
        cp16(dst, msgW + (size_t)r * 128 + chunk * 64 + c4 * 8);
    }
    cp_commit();
}

__device__ __forceinline__ void epi1_store(uint32_t sb, uint32_t tmem,
                                           int wid, int lid, int block_row,
                                           const float* bias,
                                           const unsigned char* maskB,
                                           __half* Ch, uint32_t hoff) {
    const int sp = wid & 3;
    const int ch = wid >> 2;
    const int row = sp * 32 + lid;
    const int m = block_row + row;
    const bool masked = (maskB[m] != 0);
#pragma unroll
    for (int half = 0; half < 2; half++) {
        int cb = ch * 64 + half * 32;
        uint32_t r32[32];
        TC_LD_X32(r32, tmem + cb);
        asm volatile("tcgen05.wait::ld.sync.aligned;" ::: "memory");
#pragma unroll
        for (int j = 0; j < 32; j += 8) {
            float f[8];
#pragma unroll
            for (int i = 0; i < 8; i++) {
                float v = __uint_as_float(r32[j + i]) + bias[cb + j + i];
                v = fmaxf(v, 0.f);
                if (masked) v = 0.f;
                f[i] = v;
            }
            uint4 o;
            o.x = pack2(f[0], f[1]); o.y = pack2(f[2], f[3]);
            o.z = pack2(f[4], f[5]); o.w = pack2(f[6], f[7]);
            *(uint4*)(Ch + (size_t)m * 128 + cb + j) = o;
            uint32_t boff = (uint32_t)(((cb & 63) + j) * 2);
            sts4u(sb + 1024 + hoff + ch * 16384
                  + SW128((uint32_t)(row * 128) + boff), o);
        }
    }
    asm volatile("tcgen05.fence::before_thread_sync;" ::: "memory");
}

__device__ __forceinline__ void phase2_run(uint32_t sb, uint32_t tmem,
                                           int tid, int wid, int lid,
                                           int block_row, const float* bias2,
                                           __half* Cm, uint32_t hoff,
                                           uint32_t woff) {
    cp_wait0();
    __syncthreads();
    if (tid == 0) {
        asm volatile("tcgen05.fence::after_thread_sync;" ::: "memory");
        asm volatile("fence.proxy.async.shared::cta;" ::: "memory");
#pragma unroll
        for (int c = 0; c < 2; c++) {
            uint64_t hd = mk_desc(sb + 1024 + hoff + c * 16384);
            uint64_t wd = mk_desc(sb + 1024 + woff + c * 16384);
#pragma unroll
            for (int j = 0; j < 4; j++)
                mma_f16_ss(tmem, hd + j * 2, wd + j * 2,
                           (c > 0 || j > 0) ? 1u : 0u);
        }
        tc_commit(sb + 24);
    }
    mbar_wait(sb + 24, 0);
    asm volatile("tcgen05.fence::after_thread_sync;" ::: "memory");

    const int sp = wid & 3;
    const int ch = wid >> 2;
    const int m = block_row + sp * 32 + lid;
#pragma unroll
    for (int half = 0; half < 2; half++) {
        int cb = ch * 64 + half * 32;
        uint32_t r32[32];
        TC_LD_X32(r32, tmem + cb);
        asm volatile("tcgen05.wait::ld.sync.aligned;" ::: "memory");
#pragma unroll
        for (int j = 0; j < 32; j += 8) {
            float f[8];
#pragma unroll
            for (int i = 0; i < 8; i++)
                f[i] = fmaxf(__uint_as_float(r32[j + i]) + bias2[cb + j + i], 0.f);
            uint4 o;
            o.x = pack2(f[0], f[1]); o.y = pack2(f[2], f[3]);
            o.z = pack2(f[4], f[5]); o.w = pack2(f[6], f[7]);
            *(uint4*)(Cm + (size_t)m * 128 + cb + j) = o;
        }
    }
}
#endif  // TC_AVAIL

// ----- fused input layer (tf32 phase1, K=67 pad 96) + msg0 -----
struct FIN {
    const float* emb; const int* types; const float* coords;
    const float* Wt; const float* bias;
    const unsigned char* maskB;
    __half* Ch;
    const __half* msgW; const float* bias2; __half* Cm;
};

__global__ void __launch_bounds__(256) k_fused_in(FIN g) {
#if TC_AVAIL
    extern __shared__ __align__(1024) char smem[];
    const uint32_t sb = smem_u32(smem);
    const int tid = threadIdx.x;
    const int wid = tid >> 5;
    const int lid = tid & 31;
    const int block_row = blockIdx.x * 128;

    auto stage1 = [&](int t, int s) {
        uint32_t bufA = sb + 1024 + s * 32768;
        uint32_t bufW = bufA + 16384;
#pragma unroll
        for (int it = 0; it < 4; it++) {
            int idx = tid + it * 256;
            int r = idx >> 3, c4 = idx & 7;
            cp16(bufW + SW128((uint32_t)(r * 128 + c4 * 16)),
                 g.Wt + (size_t)r * 96 + t * 32 + c4 * 4);
        }
#pragma unroll
        for (int it = 0; it < 4; it++) {
            int idx = tid + it * 256;
            int r = idx >> 3, c4 = idx & 7;
            int gr = block_row + r;
            uint32_t dst = bufA + SW128((uint32_t)(r * 128 + c4 * 16));
            if (t < 2) {
                cp16(dst, g.emb + (size_t)g.types[gr] * 64 + t * 32 + c4 * 4);
            } else {
                float4 v = make_float4(0.f, 0.f, 0.f, 0.f);
                if (c4 == 0) {
                    v.x = g.coords[gr * 3];
                    v.y = g.coords[gr * 3 + 1];
                    v.z = g.coords[gr * 3 + 2];
                }
                sts4(dst, v);
            }
        }
        cp_commit();
    };

    stage1(0, 0);
    stage1(1, 1);
    if (wid == 0) {
        asm volatile(
            "tcgen05.alloc.cta_group::1.sync.aligned.shared::cta.b32 [%0], %1;"
            :: "r"(sb), "r"(128u) : "memory");
        asm volatile("tcgen05.relinquish_alloc_permit.cta_group::1.sync.aligned;");
    }
    if (tid == 0) {
        mbar_init(sb + 8, 1); mbar_init(sb + 16, 1); mbar_init(sb + 24, 1);
    }
    __syncthreads();
    uint32_t tmem;
    asm volatile("ld.shared.b32 %0, [%1];" : "=r"(tmem) : "r"(sb));

    uint64_t d0A = mk_desc(sb + 1024);
    uint64_t d0W = mk_desc(sb + 1024 + 16384);
    uint64_t d1A = mk_desc(sb + 1024 + 32768);
    uint64_t d1W = mk_desc(sb + 1024 + 49152);

    cp_wait1(); __syncthreads();
    if (tid == 0) {
        asm volatile("fence.proxy.async.shared::cta;" ::: "memory");
#pragma unroll
        for (int j = 0; j < 4; j++)
            mma_tf32_ss(tmem, d0A + j * 2, d0W + j * 2, (j > 0) ? 1u : 0u);
        tc_commit(sb + 8);
    }
    mbar_wait(sb + 8, 0);
    stage1(2, 0);

    cp_wait1(); __syncthreads();
    if (tid == 0) {
        asm volatile("fence.proxy.async.shared::cta;" ::: "memory");
#pragma unroll
        for (int j = 0; j < 4; j++)
            mma_tf32_ss(tmem, d1A + j * 2, d1W + j * 2, 1u);
        tc_commit(sb + 16);
    }
    mbar_wait(sb + 16, 0);
    stage_msgW(sb, tid, g.msgW, 32768);

    cp_wait1(); __syncthreads();
    if (tid == 0) {
        asm volatile("fence.proxy.async.shared::cta;" ::: "memory");
#pragma unroll
        for (int j = 0; j < 4; j++)
            mma_tf32_ss(tmem, d0A + j * 2, d0W + j * 2, 1u);
        tc_commit(sb + 8);
    }
    mbar_wait(sb + 8, 1);
    asm volatile("tcgen05.fence::after_thread_sync;" ::: "memory");

    epi1_store(sb, tmem, wid, lid, block_row, g.bias, g.maskB, g.Ch, 0);
    phase2_run(sb, tmem, tid, wid, lid, block_row, g.bias2, g.Cm, 0, 32768);

    __syncthreads();
    if (wid == 0) {
        asm volatile("tcgen05.dealloc.cta_group::1.sync.aligned.b32 %0, %1;"
                     :: "r"(tmem), "r"(128u));
    }
#else
    const int m = blockIdx.x * 128 + threadIdx.x % 128;
    if (threadIdx.x >= 128) return;
    const bool masked = (g.maskB[m] != 0);
    int ty = g.types[m];
    for (int cb = 0; cb < 128; cb++) {
        float acc = 0.f;
        for (int k = 0; k < 64; k++)
            acc = fmaf(g.emb[(size_t)ty * 64 + k], g.Wt[(size_t)cb * 96 + k], acc);
        for (int k = 64; k < 67; k++)
            acc = fmaf(g.coords[m * 3 + (k - 64)], g.Wt[(size_t)cb * 96 + k], acc);
        float v = fmaxf(acc + g.bias[cb], 0.f);
        if (masked) v = 0.f;
        g.Ch[(size_t)m * 128 + cb] = __float2half(v);
    }
    for (int cb = 0; cb < 128; cb++) {
        float acc = 0.f;
        for (int k = 0; k < 128; k++)
            acc = fmaf(__half2float(g.Ch[(size_t)m * 128 + k]),
                       __half2float(g.msgW[(size_t)cb * 128 + k]), acc);
        g.Cm[(size_t)m * 128 + cb] = __float2half(fmaxf(acc + g.bias2[cb], 0.f));
    }
#endif
}

// ----- fused upd layer (f16 phase1, K=256 concat [h|agg]) + next msg -----
struct FUP {
    const __half* A1; const __half* A2;
    const __half* Wt; const float* bias;
    const unsigned char* maskB;
    __half* Ch;
    const __half* msgW; const float* bias2; __half* Cm;
};

__global__ void __launch_bounds__(256) k_fused_upd(FUP g) {
#if TC_AVAIL
    extern __shared__ __align__(1024) char smem[];
    const uint32_t sb = smem_u32(smem);
    const int tid = threadIdx.x;
    const int wid = tid >> 5;
    const int lid = tid & 31;
    const int block_row = blockIdx.x * 128;

    auto stage1 = [&](int t, int s) {
        uint32_t bufA = sb + 1024 + s * 32768;
        uint32_t bufW = bufA + 16384;
#pragma unroll
        for (int it = 0; it < 4; it++) {
            int idx = tid + it * 256;
            int r = idx >> 3, c4 = idx & 7;
            cp16(bufW + SW128((uint32_t)(r * 128 + c4 * 16)),
                 g.Wt + (size_t)r * 256 + t * 64 + c4 * 8);
        }
#pragma unroll
        for (int it = 0; it < 4; it++) {
            int idx = tid + it * 256;
            int r = idx >> 3, c4 = idx & 7;
            int gr = block_row + r;
            const __half* src = (t < 2)
                ? g.A1 + (size_t)gr * 128 + t * 64 + c4 * 8
                : g.A2 + (size_t)gr * 128 + (t - 2) * 64 + c4 * 8;
            cp16(bufA + SW128((uint32_t)(r * 128 + c4 * 16)), src);
        }
        cp_commit();
    };

    stage1(0, 0);
    stage1(1, 1);
    if (wid == 0) {
        asm volatile(
            "tcgen05.alloc.cta_group::1.sync.aligned.shared::cta.b32 [%0], %1;"
            :: "r"(sb), "r"(128u) : "memory");
        asm volatile("tcgen05.relinquish_alloc_permit.cta_group::1.sync.aligned;");
    }
    if (tid == 0) {
        mbar_init(sb + 8, 1); mbar_init(sb + 16, 1); mbar_init(sb + 24, 1);
    }
    __syncthreads();
    uint32_t tmem;
    asm volatile("ld.shared.b32 %0, [%1];" : "=r"(tmem) : "r"(sb));

    uint64_t d0A = mk_desc(sb + 1024);
    uint64_t d0W = mk_desc(sb + 1024 + 16384);
    uint64_t d1A = mk_desc(sb + 1024 + 32768);
    uint64_t d1W = mk_desc(sb + 1024 + 49152);

    cp_wait1(); __syncthreads();
    if (tid == 0) {
        asm volatile("fence.proxy.async.shared::cta;" ::: "memory");
#pragma unroll
        for (int j = 0; j < 4; j++)
            mma_f16_ss(tmem, d0A + j * 2, d0W + j * 2, (j > 0) ? 1u : 0u);
        tc_commit(sb + 8);
    }
    mbar_wait(sb + 8, 0);
    stage1(2, 0);

    cp_wait1(); __syncthreads();
    if (tid == 0) {
        asm volatile("fence.proxy.async.shared::cta;" ::: "memory");
#pragma unroll
        for (int j = 0; j < 4; j++)
            mma_f16_ss(tmem, d1A + j * 2, d1W + j * 2, 1u);
        tc_commit(sb + 16);
    }
    mbar_wait(sb + 16, 0);
    stage1(3, 1);

    cp_wait1(); __syncthreads();
    if (tid == 0) {
        asm volatile("fence.proxy.async.shared::cta;" ::: "memory");
#pragma unroll
        for (int j = 0; j < 4; j++)
            mma_f16_ss(tmem, d0A + j * 2, d0W + j * 2, 1u);
        tc_commit(sb + 8);
    }
    mbar_wait(sb + 8, 1);
    stage_msgW(sb, tid, g.msgW, 0);

    cp_wait1(); __syncthreads();
    if (tid == 0) {
        asm volatile("fence.proxy.async.shared::cta;" ::: "memory");
#pragma unroll
        for (int j = 0; j < 4; j++)
            mma_f16_ss(tmem, d1A + j * 2, d1W + j * 2, 1u);
        tc_commit(sb + 16);
    }
    mbar_wait(sb + 16, 1);
    asm volatile("tcgen05.fence::after_thread_sync;" ::: "memory");

    epi1_store(sb, tmem, wid, lid, block_row, g.bias, g.maskB, g.Ch, 32768);
    phase2_run(sb, tmem, tid, wid, lid, block_row, g.bias2, g.Cm, 32768, 0);

    __syncthreads();
    if (wid == 0) {
        asm volatile("tcgen05.dealloc.cta_group::1.sync.aligned.b32 %0, %1;"
                     :: "r"(tmem), "r"(128u));
    }
#else
    const int m = blockIdx.x * 128 + threadIdx.x % 128;
    if (threadIdx.x >= 128) return;
    const bool masked = (g.maskB[m] != 0);
    for (int cb = 0; cb < 128; cb++) {
        float acc = 0.f;
        for (int k = 0; k < 128; k++)
            acc = fmaf(__half2float(g.A1[(size_t)m * 128 + k]),
                       __half2float(g.Wt[(size_t)cb * 256 + k]), acc);
        for (int k = 0; k < 128; k++)
            acc = fmaf(__half2float(g.A2[(size_t)m * 128 + k]),
                       __half2float(g.Wt[(size_t)cb * 256 + 128 + k]), acc);
        float v = fmaxf(acc + g.bias[cb], 0.f);
        if (masked) v = 0.f;
        g.Ch[(size_t)m * 128 + cb] = __float2half(v);
    }
    for (int cb = 0; cb < 128; cb++) {
        float acc = 0.f;
        for (int k = 0; k < 128; k++)
            acc = fmaf(__half2float(g.Ch[(size_t)m * 128 + k]),
                       __half2float(g.msgW[(size_t)cb * 128 + k]), acc);
        g.Cm[(size_t)m * 128 + cb] = __float2half(fmaxf(acc + g.bias2[cb], 0.f));
    }
#endif
}

// ===========================================================================
// k_fused_tail: upd1 + coupling in ONE kernel, h never touches gmem.
// phase1: upd acc -> TMEM cols 0..127 (fp32). epi1 (warps 0-3): read acc,
// bias/relu/mask, pack fp16x2 -> tcgen05.st to TMEM cols 128..191 (A operand).
// phase2-s: TS-mode MMA s = A @ Wse[:,0:128]^T -> cols 0..127 (reuse); drain
// with coords-correction + bse + relu, dot Ws2 -> raw[3]/row. phase2-h same
// with Whe/bhe/Wh2 -> shf[3]. Final: tanh/exp/out/logdet.
// Wse/Whe staged into freed phase1 ring stages during phase1 chunks 2/3.
// smem: 8KB header + 64KB ring = 72KB. TMEM alloc 256.
// ===========================================================================
#define TAIL_HDR   8192
#define SMEM_TAIL  (TAIL_HDR + 65536)
// header float idx: 16 Ws2[384]; 400 Wh2[384]; 784 bse[128]; 912 bhe[128];
//                   1040 WseK[384]; 1424 WheK[384]
struct FT {
    const __half* A1; const __half* A2;       // h, agg
    const __half* Wt; const float* bias;      // updW1^T (Kpad 256), upd_b1
    const __half* Wse; const __half* Whe;     // fused coupling weights (192-stride)
    const float* bse; const float* bhe;
    const float* Ws2; const float* bs2;
    const float* Wh2; const float* bh2;
    const float* coords;
    const unsigned char* maskB;
    float* out; float* logdet;
};

__global__ void __launch_bounds__(256) k_fused_tail(FT g) {
#if TC_AVAIL
    extern __shared__ __align__(1024) char smem[];
    const uint32_t sb = smem_u32(smem);
    float* smf = (float*)smem;
    const int tid = threadIdx.x;
    const int wid = tid >> 5;
    const int lid = tid & 31;
    const int block_row = blockIdx.x * 128;

    auto stage1 = [&](int t, int s) {
        uint32_t bufA = sb + TAIL_HDR + s * 32768;
        uint32_t bufW = bufA + 16384;
#pragma unroll
        for (int it = 0; it < 4; it++) {
            int idx = tid + it * 256;
            int r = idx >> 3, c4 = idx & 7;
            cp16(bufW + SW128((uint32_t)(r * 128 + c4 * 16)),
                 g.Wt + (size_t)r * 256 + t * 64 + c4 * 8);
        }
#pragma unroll
        for (int it = 0; it < 4; it++) {
            int idx = tid + it * 256;
            int r = idx >> 3, c4 = idx & 7;
            int gr = block_row + r;
            const __half* src = (t < 2)
                ? g.A1 + (size_t)gr * 128 + t * 64 + c4 * 8
                : g.A2 + (size_t)gr * 128 + (t - 2) * 64 + c4 * 8;
            cp16(bufA + SW128((uint32_t)(r * 128 + c4 * 16)), src);
        }
        cp_commit();
    };
    // stage coupling weight (192-stride src), 32KB (K=128 -> 2 chunks) into stage s
    auto stageCW = [&](const __half* W, int s) {
        uint32_t base = sb + TAIL_HDR + s * 32768;
#pragma unroll
        for (int it = 0; it < 8; it++) {
            int idx = tid + it * 256;              // 0..2047
            int chunk = idx >> 10, w = idx & 1023;
            int r = w >> 3, c4 = w & 7;
            cp16(base + chunk * 16384 + SW128((uint32_t)(r * 128 + c4 * 16)),
                 W + (size_t)r * 192 + chunk * 64 + c4 * 8);
        }
        cp_commit();
    };

    stage1(0, 0);                                 // G0
    stage1(1, 1);                                 // G1
    if (wid == 0) {
        asm volatile(
            "tcgen05.alloc.cta_group::1.sync.aligned.shared::cta.b32 [%0], %1;"
            :: "r"(sb), "r"(256u) : "memory");
        asm volatile("tcgen05.relinquish_alloc_permit.cta_group::1.sync.aligned;");
    }
    if (tid == 0) {
        mbar_init(sb + 8, 1); mbar_init(sb + 16, 1); mbar_init(sb + 24, 1);
    }
    // header tables
    for (int i = tid; i < 384; i += 256) {
        smf[16 + i]   = g.Ws2[i];
        smf[400 + i]  = g.Wh2[i];
        int n = i / 3, c = i - n * 3;
        smf[1040 + i] = __half2float(g.Wse[(size_t)n * 192 + 128 + c]);
        smf[1424 + i] = __half2float(g.Whe[(size_t)n * 192 + 128 + c]);
    }
    if (tid < 128) {
        smf[784 + tid] = g.bse[tid];
        smf[912 + tid] = g.bhe[tid];
    }
    __syncthreads();
    uint32_t tmem;
    asm volatile("ld.shared.b32 %0, [%1];" : "=r"(tmem) : "r"(sb));

    uint64_t d0A = mk_desc(sb + TAIL_HDR);
    uint64_t d0W = mk_desc(sb + TAIL_HDR + 16384);
    uint64_t d1A = mk_desc(sb + TAIL_HDR + 32768);
    uint64_t d1W = mk_desc(sb + TAIL_HDR + 49152);

    // ---- phase1: upd1, 4 chunks ----
    cp_wait1(); __syncthreads();
    if (tid == 0) {
        asm volatile("fence.proxy.async.shared::cta;" ::: "memory");
#pragma unroll
        for (int j = 0; j < 4; j++)
            mma_f16_ss(tmem, d0A + j * 2, d0W + j * 2, (j > 0) ? 1u : 0u);
        tc_commit(sb + 8);
    }
    mbar_wait(sb + 8, 0);
    stage1(2, 0);                                 // G2

    cp_wait1(); __syncthreads();
    if (tid == 0) {
        asm volatile("fence.proxy.async.shared::cta;" ::: "memory");
#pragma unroll
        for (int j = 0; j < 4; j++)
            mma_f16_ss(tmem, d1A + j * 2, d1W + j * 2, 1u);
        tc_commit(sb + 16);
    }
    mbar_wait(sb + 16, 0);
    stage1(3, 1);                                 // G3

    cp_wait1(); __syncthreads();
    if (tid == 0) {
        asm volatile("fence.proxy.async.shared::cta;" ::: "memory");
#pragma unroll
        for (int j = 0; j < 4; j++)
            mma_f16_ss(tmem, d0A + j * 2, d0W + j * 2, 1u);
        tc_commit(sb + 8);
    }
    mbar_wait(sb + 8, 1);
    stageCW(g.Wse, 0);                            // G4 -> stage0

    cp_wait1(); __syncthreads();
    if (tid == 0) {
        asm volatile("fence.proxy.async.shared::cta;" ::: "memory");
#pragma unroll
        for (int j = 0; j < 4; j++)
            mma_f16_ss(tmem, d1A + j * 2, d1W + j * 2, 1u);
        tc_commit(sb + 16);
    }
    mbar_wait(sb + 16, 1);
    stageCW(g.Whe, 1);                            // G5 -> stage1
    asm volatile("tcgen05.fence::after_thread_sync;" ::: "memory");

    // ---- epi1 (warps 0-3): acc -> fp16x2 A in TMEM cols 128..191 ----
    const int m = block_row + (wid & 3) * 32 + lid;
    if (wid < 4) {
        const bool masked = (g.maskB[m] != 0);
        uint32_t a2[64];
#pragma unroll
        for (int cb = 0; cb < 128; cb += 32) {
            uint32_t r32[32];
            TC_LD_X32(r32, tmem + cb);
            asm volatile("tcgen05.wait::ld.sync.aligned;" ::: "memory");
#pragma unroll
            for (int j = 0; j < 32; j += 2) {
                float v0 = fmaxf(__uint_as_float(r32[j])     + g.bias[cb + j],     0.f);
                float v1 = fmaxf(__uint_as_float(r32[j + 1]) + g.bias[cb + j + 1], 0.f);
                if (masked) { v0 = 0.f; v1 = 0.f; }
                a2[(cb + j) >> 1] = pack2(v0, v1);
            }
        }
        uint32_t woff = (uint32_t)wid << 21;
        TC_ST_X32(tmem + 128 + woff, a2);
        TC_ST_X32(tmem + 160 + woff, a2 + 32);
        asm volatile("tcgen05.wait::st.sync.aligned;" ::: "memory");
    }
    asm volatile("tcgen05.fence::before_thread_sync;" ::: "memory");

    // ---- phase2-s: TS MMA over Wse (stage0) ----
    cp_wait1();                                   // G4 done (G5 outstanding)
    __syncthreads();
    if (tid == 0) {
        asm volatile("tcgen05.fence::after_thread_sync;" ::: "memory");
        asm volatile("fence.proxy.async.shared::cta;" ::: "memory");
#pragma unroll
        for (int c = 0; c < 2; c++) {
            uint64_t wd = mk_desc(sb + TAIL_HDR + c * 16384);
#pragma unroll
            for (int j = 0; j < 4; j++)
                mma_f16_ts(tmem, tmem + 128 + c * 32 + j * 8, wd + j * 2,
                           (c > 0 || j > 0) ? 1u : 0u);
        }
        tc_commit(sb + 24);
    }
    mbar_wait(sb + 24, 0);
    asm volatile("tcgen05.fence::after_thread_sync;" ::: "memory");

    // drain s (warps 0-3): raw[3] with coords correction
    bool cm = ((m & 1) == 0) && (g.maskB[m] == 0);     // PHASE = 0
    float cc0 = 0.f, cc1 = 0.f, cc2 = 0.f;
    if (!cm) { cc0 = g.coords[m*3]; cc1 = g.coords[m*3+1]; cc2 = g.coords[m*3+2]; }
    float raw[3] = {0.f, 0.f, 0.f};
    if (wid < 4) {
#pragma unroll
        for (int cb = 0; cb < 128; cb += 32) {
            uint32_t r32[32];
            TC_LD_X32(r32, tmem + cb);
            asm volatile("tcgen05.wait::ld.sync.aligned;" ::: "memory");
#pragma unroll
            for (int k = 0; k < 32; k++) {
                int col = cb + k;
                float v = __uint_as_float(r32[k]) + smf[784 + col];
                v = fmaf(cc0, smf[1040 + col * 3],     v);
                v = fmaf(cc1, smf[1040 + col * 3 + 1], v);
                v = fmaf(cc2, smf[1040 + col * 3 + 2], v);
                v = fmaxf(v, 0.f);
#pragma unroll
                for (int c = 0; c < 3; c++)
                    raw[c] = fmaf(v, smf[16 + col * 3 + c], raw[c]);
            }
        }
    }
    asm volatile("tcgen05.fence::before_thread_sync;" ::: "memory");

    // ---- phase2-h: TS MMA over Whe (stage1), reuse cols 0..127 ----
    cp_wait0();                                   // G5 done
    __syncthreads();
    if (tid == 0) {
        asm volatile("tcgen05.fence::after_thread_sync;" ::: "memory");
        asm volatile("fence.proxy.async.shared::cta;" ::: "memory");
#pragma unroll
        for (int c = 0; c < 2; c++) {
            uint64_t wd = mk_desc(sb + TAIL_HDR + 32768 + c * 16384);
#pragma unroll
            for (int j = 0; j < 4; j++)
                mma_f16_ts(tmem, tmem + 128 + c * 32 + j * 8, wd + j * 2,
                           (c > 0 || j > 0) ? 1u : 0u);
        }
        tc_commit(sb + 24);
    }
    mbar_wait(sb + 24, 1);
    asm volatile("tcgen05.fence::after_thread_sync;" ::: "memory");

    if (wid < 4) {
        float shf[3] = {0.f, 0.f, 0.f};
#pragma unroll
        for (int cb = 0; cb < 128; cb += 32) {
            uint32_t r32[32];
            TC_LD_X32(r32, tmem + cb);
            asm volatile("tcgen05.wait::ld.sync.aligned;" ::: "memory");
#pragma unroll
            for (int k = 0; k < 32; k++) {
                int col = cb + k;
                float v = __uint_as_float(r32[k]) + smf[912 + col];
                v = fmaf(cc0, smf[1424 + col * 3],     v);
                v = fmaf(cc1, smf[1424 + col * 3 + 1], v);
                v = fmaf(cc2, smf[1424 + col * 3 + 2], v);
                v = fmaxf(v, 0.f);
#pragma unroll
                for (int c = 0; c < 3; c++)
                    shf[c] = fmaf(v, smf[400 + col * 3 + c], shf[c]);
            }
        }
        float ld = 0.f;
#pragma unroll
        for (int c = 0; c < 3; c++) {
            float r = raw[c] + g.bs2[c];
            float s = shf[c] + g.bh2[c];
            float ls = cm ? tanhf(r) * 2.f : 0.f;
            ld += ls;
            float coord = g.coords[m * 3 + c];
            g.out[m * 3 + c] = cm ? (expf(ls) * coord + s) : coord;
        }
#pragma unroll
        for (int o = 16; o > 0; o >>= 1)
            ld += __shfl_xor_sync(0xFFFFFFFFu, ld, o);
        if (lid == 0) atomicAdd(&g.logdet[m >> 13], ld);
    }

    __syncthreads();
    if (wid == 0) {
        asm volatile("tcgen05.dealloc.cta_group::1.sync.aligned.b32 %0, %1;"
                     :: "r"(tmem), "r"(256u));
    }
#else
    // Scalar fallback (never runs on GB300): upd1 row then coupling.
    if (threadIdx.x >= 128) return;
    const int m = blockIdx.x * 128 + threadIdx.x;
    const bool masked = (g.maskB[m] != 0);
    bool cm = ((m & 1) == 0) && !masked;
    float hrow[128];
    for (int cb = 0; cb < 128; cb++) {
        float acc = 0.f;
        for (int k = 0; k < 128; k++)
            acc = fmaf(__half2float(g.A1[(size_t)m * 128 + k]),
                       __half2float(g.Wt[(size_t)cb * 256 + k]), acc);
        for (int k = 0; k < 128; k++)
            acc = fmaf(__half2float(g.A2[(size_t)m * 128 + k]),
                       __half2float(g.Wt[(size_t)cb * 256 + 128 + k]), acc);
        float v = fmaxf(acc + g.bias[cb], 0.f);
        if (masked) v = 0.f;
        hrow[cb] = __half2float(__float2half(v));
    }
    float cc[3];
    for (int c = 0; c < 3; c++) cc[c] = cm ? 0.f : g.coords[m * 3 + c];
    float raw[3], shf[3];
    for (int c = 0; c < 3; c++) { raw[c] = g.bs2[c]; shf[c] = g.bh2[c]; }
    for (int n = 0; n < 128; n++) {
        float accs = g.bse[n], acch = g.bhe[n];
        for (int k = 0; k < 128; k++) {
            accs = fmaf(hrow[k], __half2float(g.Wse[(size_t)n * 192 + k]), accs);
            acch = fmaf(hrow[k], __half2float(g.Whe[(size_t)n * 192 + k]), acch);
        }
        for (int c = 0; c < 3; c++) {
            accs = fmaf(cc[c], __half2float(g.Wse[(size_t)n * 192 + 128 + c]), accs);
            acch = fmaf(cc[c], __half2float(g.Whe[(size_t)n * 192 + 128 + c]), acch);
        }
        accs = fmaxf(accs, 0.f); acch = fmaxf(acch, 0.f);
        for (int c = 0; c < 3; c++) {
            raw[c] = fmaf(accs, g.Ws2[n * 3 + c], raw[c]);
            shf[c] = fmaf(acch, g.Wh2[n * 3 + c], shf[c]);
        }
    }
    float ld = 0.f;
    for (int c = 0; c < 3; c++) {
        float ls = cm ? tanhf(raw[c]) * 2.f : 0.f;
        ld += ls;
        float coord = g.coords[m * 3 + c];
        g.out[m * 3 + c] = cm ? (expf(ls) * coord + shf[c]) : coord;
    }
    atomicAdd(&g.logdet[m >> 13], ld);
#endif
}

// ---------------------------------------------------------------------------
// Host launcher. Index 3 = k_fused_in (ncu profile target).
// ---------------------------------------------------------------------------
extern "C" void kernel_launch(void* const* d_in, const int* in_sizes, int n_in,
                              void* d_out, int out_size) {
    const float*         coords = (const float*)d_in[0];
    const int*           types  = (const int*)  d_in[1];
    const int*           adj    = (const int*)  d_in[2];
    const int*           ebi    = (const int*)  d_in[3];
    const unsigned char* maskB  = (const unsigned char*)d_in[4];
    const float* emb   = (const float*)d_in[5];
    const float* W_in  = (const float*)d_in[6];
    const float* b_in  = (const float*)d_in[7];
    const float* msg_W = (const float*)d_in[8];
    const float* msg_b = (const float*)d_in[9];
    const float* upd_W = (const float*)d_in[10];
    const float* upd_b = (const float*)d_in[11];
    const float* W_out = (const float*)d_in[12];
    const float* b_out = (const float*)d_in[13];
    const float* Ws1   = (const float*)d_in[14];
    const float* bs1   = (const float*)d_in[15];
    const float* Ws2   = (const float*)d_in[16];
    const float* bs2   = (const float*)d_in[17];
    const float* Wh1   = (const float*)d_in[18];
    const float* bh1   = (const float*)d_in[19];
    const float* Wh2   = (const float*)d_in[20];
    const float* bh2   = (const float*)d_in[21];

    float* out    = (float*)d_out;
    float* logdet = out + (size_t)BN_ * 3;

    __half *h, *b1, *b2, *wth;
    float *wt;
    int *off, *part, *cur, *srcl;
    cudaGetSymbolAddress((void**)&h,    g_h);
    cudaGetSymbolAddress((void**)&b1,   g_b1);
    cudaGetSymbolAddress((void**)&b2,   g_b2);
    cudaGetSymbolAddress((void**)&wt,   g_wt);
    cudaGetSymbolAddress((void**)&wth,  g_wth);
    cudaGetSymbolAddress((void**)&off,  g_off);
    cudaGetSymbolAddress((void**)&part, g_part);
    cudaGetSymbolAddress((void**)&cur,  g_cur);
    cudaGetSymbolAddress((void**)&srcl, g_srcl);

    cudaFuncSetAttribute(k_fused_in,   cudaFuncAttributeMaxDynamicSharedMemorySize, SMEM_FUSED);
    cudaFuncSetAttribute(k_fused_upd,  cudaFuncAttributeMaxDynamicSharedMemorySize, SMEM_FUSED);
    cudaFuncSetAttribute(k_fused_tail, cudaFuncAttributeMaxDynamicSharedMemorySize, SMEM_TAIL);

    const int BT = 256;

    // 0: prep
    k_prep<<<1024, BT>>>(W_in, msg_W, upd_W, W_out, Ws1, Wh1, bs1, bh1, b_out,
                         wt, wth, off, logdet);
    // 1: hist
    k_hist<<<E_ / BT, BT>>>(adj, ebi, off);
    // 2: scanA
    k_scanA<<<512, 512>>>(off, part);
    // 3: fused input + msg0  <-- ncu profile target
    FIN fi{emb, types, coords, wt + O_WIN, b_in, maskB, h,
           wth + H_MSG0, msg_b, b1};
    k_fused_in<<<BN_ / 128, 256, SMEM_FUSED>>>(fi);
    // 4-5: finish CSR
    k_scanB<<<512, 512>>>(off, part, cur);
    k_place<<<E_ / BT, BT>>>(adj, ebi, cur, srcl);
    // 6: gather layer 0
    k_gather<<<BN_ / 16, BT>>>(b1, off, srcl, b2);
    // 7: fused upd0 + msg1
    FUP fu{h, b2, wth + H_UPD0, upd_b, maskB, h, wth + H_MSG1, msg_b + 128, b1};
    k_fused_upd<<<BN_ / 128, 256, SMEM_FUSED>>>(fu);
    // 8: gather layer 1
    k_gather<<<BN_ / 16, BT>>>(b1, off, srcl, b2);
    // 9: fused tail = upd1 + coupling (h never written to gmem)
    FT ft{h, b2, wth + H_UPD1, upd_b + 128,
          wth + H_WSE, wth + H_WHE, wt + O_BSE, wt + O_BHE,
          Ws2, bs2, Wh2, bh2, coords, maskB, out, logdet};
    k_fused_tail<<<BN_ / 128, 256, SMEM_TAIL>>>(ft);
}

// round 16
// speedup vs baseline: 9.6493x; 1.0079x over previous
#include <cuda_runtime.h>
#include <cuda_fp16.h>
#include <cstdint>
#include <math.h>
#include <stddef.h>

// Problem constants
#define B_   32
#define N_   8192
#define E_   1048576
#define BN_  (B_ * N_)          // 262144
#define L_   2

// ---------------------------------------------------------------------------
// Arch-feature gate (tcgen05 only exists on sm_100a/sm_103a passes)
// ---------------------------------------------------------------------------
#if defined(__CUDA_ARCH_FEAT_SM103_ALL) || defined(__CUDA_ARCH_FEAT_SM100_ALL)
#  define TC_AVAIL 1
#endif
#ifndef TC_AVAIL
#  ifdef __CUDA_ARCH_HAS_FEATURE__
#    if __CUDA_ARCH_HAS_FEATURE__(SM103_ALL) || __CUDA_ARCH_HAS_FEATURE__(SM100_ALL)
#      define TC_AVAIL 1
#    endif
#  endif
#endif
#ifndef TC_AVAIL
#  define TC_AVAIL 0
#endif

// ---------------------------------------------------------------------------
// Scratch (static device globals)
// ---------------------------------------------------------------------------
static __device__ __align__(16) __half g_h [(size_t)BN_ * 128];
static __device__ __align__(16) __half g_b1[(size_t)BN_ * 128];   // msg_all
static __device__ __align__(16) __half g_b2[(size_t)BN_ * 128];   // agg
static __device__ __align__(16) float  g_wt [12544];              // fp32 W_in^T + bse/bhe
static __device__ __align__(16) __half g_wth[147456];             // fp16 weights
static __device__ int g_off [BN_ + 1];
static __device__ int g_part[512];
static __device__ int g_cur [BN_];
static __device__ int g_srcl[E_];

// g_wt fp32 offsets
#define O_WIN   0        // 128 x 96 (K=67 pad)
#define O_BSE   12288
#define O_BHE   12416
// g_wth half offsets
#define H_MSG0  0        // 128x128
#define H_MSG1  16384
#define H_UPD0  32768    // 128x256
#define H_UPD1  65536
#define H_WSE   98304    // 128x192 (K=131 pad)
#define H_WHE   122880

// ---------------------------------------------------------------------------
// Helpers
// ---------------------------------------------------------------------------
__device__ __forceinline__ uint32_t smem_u32(const void* p) {
    uint32_t a;
    asm("{ .reg .u64 t; cvta.to.shared.u64 t, %1; cvt.u32.u64 %0, t; }"
        : "=r"(a) : "l"(p));
    return a;
}

#define SW128(o) ((o) ^ (((o) >> 3) & 0x70))

__device__ __forceinline__ void cp16(uint32_t dst, const void* src) {
    asm volatile("cp.async.cg.shared.global [%0], [%1], 16;"
                 :: "r"(dst), "l"(src) : "memory");
}
__device__ __forceinline__ void cp_commit() {
    asm volatile("cp.async.commit_group;" ::: "memory");
}
__device__ __forceinline__ void cp_wait1() {
    asm volatile("cp.async.wait_group 1;" ::: "memory");
}
__device__ __forceinline__ void cp_wait0() {
    asm volatile("cp.async.wait_group 0;" ::: "memory");
}
__device__ __forceinline__ void sts4(uint32_t dst, float4 v) {
    asm volatile("st.shared.v4.f32 [%0], {%1, %2, %3, %4};"
                 :: "r"(dst), "f"(v.x), "f"(v.y), "f"(v.z), "f"(v.w) : "memory");
}
__device__ __forceinline__ void sts4u(uint32_t dst, uint4 v) {
    asm volatile("st.shared.v4.u32 [%0], {%1, %2, %3, %4};"
                 :: "r"(dst), "r"(v.x), "r"(v.y), "r"(v.z), "r"(v.w) : "memory");
}
__device__ __forceinline__ uint32_t pack2(float a, float b) {
    __half2 h = __floats2half2_rn(a, b);
    return *reinterpret_cast<uint32_t*>(&h);
}

#if TC_AVAIL
__device__ __forceinline__ uint64_t mk_desc(uint32_t addr) {
    // SW128, version=1 (Blackwell), LBO=1, SBO=64 (K-major)
    const uint64_t BASE = (2ULL << 61) | (1ULL << 46) | (64ULL << 32) | (1ULL << 16);
    return BASE | ((uint64_t)(addr >> 4) & 0x3FFF);
}

// tf32: acc=F32, atype=btype=TF32(2), N=128, M=128
#define IDESC_TF32 ((1u << 4) | (2u << 7) | (2u << 10) | (16u << 17) | (8u << 24))
// fp16: acc=F32, atype=btype=FP16(0), N=128, M=128
#define IDESC_F16  ((1u << 4) | (16u << 17) | (8u << 24))

__device__ __forceinline__ void mma_tf32_ss(uint32_t d, uint64_t a, uint64_t b,
                                            uint32_t en) {
    asm volatile(
        "{\n\t.reg .pred p;\n\t"
        "setp.ne.u32 p, %4, 0;\n\t"
        "tcgen05.mma.cta_group::1.kind::tf32 [%0], %1, %2, %3, p;\n\t}"
        :: "r"(d), "l"(a), "l"(b), "r"(IDESC_TF32), "r"(en) : "memory");
}
__device__ __forceinline__ void mma_f16_ss(uint32_t d, uint64_t a, uint64_t b,
                                           uint32_t en) {
    asm volatile(
        "{\n\t.reg .pred p;\n\t"
        "setp.ne.u32 p, %4, 0;\n\t"
        "tcgen05.mma.cta_group::1.kind::f16 [%0], %1, %2, %3, p;\n\t}"
        :: "r"(d), "l"(a), "l"(b), "r"(IDESC_F16), "r"(en) : "memory");
}
// TS-mode: A operand in TMEM (fp16x2 columns), B in SMEM.
__device__ __forceinline__ void mma_f16_ts(uint32_t d, uint32_t a, uint64_t b,
                                           uint32_t en) {
    asm volatile(
        "{\n\t.reg .pred p;\n\t"
        "setp.ne.u32 p, %4, 0;\n\t"
        "tcgen05.mma.cta_group::1.kind::f16 [%0], [%1], %2, %3, p;\n\t}"
        :: "r"(d), "r"(a), "l"(b), "r"(IDESC_F16), "r"(en) : "memory");
}

__device__ __forceinline__ void tc_commit(uint32_t mbar) {
    asm volatile(
        "tcgen05.commit.cta_group::1.mbarrier::arrive::one.shared::cluster.b64 [%0];"
        :: "r"(mbar) : "memory");
}

#define TC_LD_X32(r, addr)                                                     \
    asm volatile(                                                              \
        "tcgen05.ld.sync.aligned.32x32b.x32.b32 "                              \
        "{%0, %1, %2, %3, %4, %5, %6, %7, "                                    \
        " %8, %9, %10, %11, %12, %13, %14, %15, "                              \
        " %16, %17, %18, %19, %20, %21, %22, %23, "                            \
        " %24, %25, %26, %27, %28, %29, %30, %31}, [%32];"                     \
        : "=r"((r)[0]),  "=r"((r)[1]),  "=r"((r)[2]),  "=r"((r)[3]),           \
          "=r"((r)[4]),  "=r"((r)[5]),  "=r"((r)[6]),  "=r"((r)[7]),           \
          "=r"((r)[8]),  "=r"((r)[9]),  "=r"((r)[10]), "=r"((r)[11]),          \
          "=r"((r)[12]), "=r"((r)[13]), "=r"((r)[14]), "=r"((r)[15]),          \
          "=r"((r)[16]), "=r"((r)[17]), "=r"((r)[18]), "=r"((r)[19]),          \
          "=r"((r)[20]), "=r"((r)[21]), "=r"((r)[22]), "=r"((r)[23]),          \
          "=r"((r)[24]), "=r"((r)[25]), "=r"((r)[26]), "=r"((r)[27]),          \
          "=r"((r)[28]), "=r"((r)[29]), "=r"((r)[30]), "=r"((r)[31])           \
        : "r"(addr))

#define TC_ST_X32(addr, r)                                                     \
    asm volatile(                                                              \
        "tcgen05.st.sync.aligned.32x32b.x32.b32 [%0], "                        \
        "{%1, %2, %3, %4, %5, %6, %7, %8, "                                    \
        " %9, %10, %11, %12, %13, %14, %15, %16, "                             \
        " %17, %18, %19, %20, %21, %22, %23, %24, "                            \
        " %25, %26, %27, %28, %29, %30, %31, %32};"                            \
        :: "r"(addr),                                                          \
           "r"((r)[0]),  "r"((r)[1]),  "r"((r)[2]),  "r"((r)[3]),              \
           "r"((r)[4]),  "r"((r)[5]),  "r"((r)[6]),  "r"((r)[7]),              \
           "r"((r)[8]),  "r"((r)[9]),  "r"((r)[10]), "r"((r)[11]),             \
           "r"((r)[12]), "r"((r)[13]), "r"((r)[14]), "r"((r)[15]),             \
           "r"((r)[16]), "r"((r)[17]), "r"((r)[18]), "r"((r)[19]),             \
           "r"((r)[20]), "r"((r)[21]), "r"((r)[22]), "r"((r)[23]),             \
           "r"((r)[24]), "r"((r)[25]), "r"((r)[26]), "r"((r)[27]),             \
           "r"((r)[28]), "r"((r)[29]), "r"((r)[30]), "r"((r)[31])              \
        : "memory")
#endif  // TC_AVAIL

__device__ __forceinline__ void mbar_init(uint32_t a, uint32_t cnt) {
    asm volatile("mbarrier.init.shared.b64 [%0], %1;" :: "r"(a), "r"(cnt) : "memory");
}
__device__ __forceinline__ void mbar_wait(uint32_t a, uint32_t parity) {
    asm volatile(
        "{\n\t.reg .pred P;\n"
        "WL%=:\n\t"
        "mbarrier.try_wait.parity.acquire.cta.shared::cta.b64 P, [%0], %1, 0x989680;\n\t"
        "@P bra WD%=;\n\t"
        "bra WL%=;\n"
        "WD%=:\n\t}"
        :: "r"(a), "r"(parity) : "memory");
}

// ---------------------------------------------------------------------------
// k_prep (unchanged)
// ---------------------------------------------------------------------------
__global__ void k_prep(const float* __restrict__ W_in,
                       const float* __restrict__ msg_W,
                       const float* __restrict__ upd_W,
                       const float* __restrict__ W_out,
                       const float* __restrict__ Ws1,
                       const float* __restrict__ Wh1,
                       const float* __restrict__ bs1,
                       const float* __restrict__ bh1,
                       const float* __restrict__ b_out,
                       float* __restrict__ wt,
                       __half* __restrict__ wth,
                       int* __restrict__ off,
                       float* __restrict__ logdet) {
    const int TOTAL = 12544 + 147456 + (BN_ + 1) + 32;
    for (int idx = blockIdx.x * blockDim.x + threadIdx.x; idx < TOTAL;
         idx += gridDim.x * blockDim.x) {
        if (idx < 12288) {
            int n = idx / 96, k = idx - n * 96;
            wt[idx] = (k < 67) ? W_in[k * 128 + n] : 0.f;
        } else if (idx < 12416) {
            int n = idx - 12288;
            float v = bs1[n];
            for (int q = 0; q < 128; q++)
                v = fmaf(b_out[q], Ws1[q * 128 + n], v);
            wt[idx] = v;
        } else if (idx < 12544) {
            int n = idx - 12416;
            float v = bh1[n];
            for (int q = 0; q < 128; q++)
                v = fmaf(b_out[q], Wh1[q * 128 + n], v);
            wt[idx] = v;
        } else {
            int j = idx - 12544;
            if (j < 32768) {
                int l = j >> 14, r = j & 16383;
                int n = r >> 7, k = r & 127;
                wth[j] = __float2half(msg_W[l * 16384 + k * 128 + n]);
            } else if (j < 98304) {
                int j2 = j - 32768;
                int l = j2 >> 15, r = j2 & 32767;
                int n = r >> 8, k = r & 255;
                wth[j] = __float2half(upd_W[l * 32768 + k * 128 + n]);
            } else if (j < 122880) {
                int j2 = j - 98304;
                int n = j2 / 192, k = j2 - n * 192;
                float v = 0.f;
                if (k < 128) {
                    for (int q = 0; q < 128; q++)
                        v = fmaf(W_out[k * 128 + q], Ws1[q * 128 + n], v);
                } else if (k < 131) {
                    v = Ws1[k * 128 + n];
                }
                wth[j] = __float2half(v);
            } else if (j < 147456) {
                int j2 = j - 122880;
                int n = j2 / 192, k = j2 - n * 192;
                float v = 0.f;
                if (k < 128) {
                    for (int q = 0; q < 128; q++)
                        v = fmaf(W_out[k * 128 + q], Wh1[q * 128 + n], v);
                } else if (k < 131) {
                    v = Wh1[k * 128 + n];
                }
                wth[j] = __float2half(v);
            } else if (j < 147456 + BN_ + 1) {
                off[j - 147456] = 0;
            } else {
                logdet[j - (147456 + BN_ + 1)] = 0.f;
            }
        }
    }
}

// ---------------------------------------------------------------------------
// CSR build (unchanged)
// ---------------------------------------------------------------------------
__global__ void k_hist(const int* __restrict__ adj, const int* __restrict__ ebi,
                       int* __restrict__ deg) {
    int e = blockIdx.x * blockDim.x + threadIdx.x;
    if (e >= E_) return;
    int dst = ebi[e] * N_ + adj[2 * e + 1];
    atomicAdd(&deg[dst], 1);
}

__global__ void k_scanA(int* __restrict__ off, int* __restrict__ part) {
    __shared__ int s[512];
    int t = threadIdx.x;
    int i = blockIdx.x * 512 + t;
    int v = off[i];
    s[t] = v; __syncthreads();
    for (int d = 1; d < 512; d <<= 1) {
        int x = (t >= d) ? s[t - d] : 0;
        __syncthreads();
        s[t] += x;
        __syncthreads();
    }
    off[i] = s[t] - v;
    if (t == 511) part[blockIdx.x] = s[t];
}

__global__ void k_scanB(int* __restrict__ off, const int* __restrict__ part,
                        int* __restrict__ cur) {
    __shared__ int s[512];
    int t = threadIdx.x, b = blockIdx.x;
    s[t] = part[t]; __syncthreads();
    for (int d = 1; d < 512; d <<= 1) {
        int x = (t >= d) ? s[t - d] : 0;
        __syncthreads();
        s[t] += x;
        __syncthreads();
    }
    int prefix = (b == 0) ? 0 : s[b - 1];
    int i = b * 512 + t;
    int v = off[i] + prefix;
    off[i] = v;
    cur[i] = v;
    if (b == 0 && t == 0) off[BN_] = E_;
}

__global__ void k_place(const int* __restrict__ adj, const int* __restrict__ ebi,
                        int* __restrict__ cur, int* __restrict__ srcl) {
    int e = blockIdx.x * blockDim.x + threadIdx.x;
    if (e >= E_) return;
    int b = ebi[e];
    int src = b * N_ + adj[2 * e];
    int dst = b * N_ + adj[2 * e + 1];
    int pos = atomicAdd(&cur[dst], 1);
    srcl[pos] = src;
}

// ---------------------------------------------------------------------------
// Gather (unchanged): half-warp per node, uint4 lanes, 4-way unroll.
// ---------------------------------------------------------------------------
__global__ void k_gather(const __half* __restrict__ msg,
                         const int* __restrict__ off,
                         const int* __restrict__ srcl,
                         __half* __restrict__ agg) {
    int gwarp = (blockIdx.x * blockDim.x + threadIdx.x) >> 5;
    int lane  = threadIdx.x & 31;
    int half_ = lane >> 4;
    int l16   = lane & 15;
    int node  = gwarp * 2 + half_;
    int s0 = off[node], s1 = off[node + 1];

    float a[8] = {0.f, 0.f, 0.f, 0.f, 0.f, 0.f, 0.f, 0.f};
    int j = s0;
    for (; j + 4 <= s1; j += 4) {
        uint4 v0 = *((const uint4*)(msg + (size_t)srcl[j]     * 128) + l16);
        uint4 v1 = *((const uint4*)(msg + (size_t)srcl[j + 1] * 128) + l16);
        uint4 v2 = *((const uint4*)(msg + (size_t)srcl[j + 2] * 128) + l16);
        uint4 v3 = *((const uint4*)(msg + (size_t)srcl[j + 3] * 128) + l16);
        const uint32_t* ws[4] = {&v0.x, &v1.x, &v2.x, &v3.x};
#pragma unroll
        for (int e = 0; e < 4; e++)
#pragma unroll
            for (int q = 0; q < 4; q++) {
                float2 f = __half22float2(*(const __half2*)&ws[e][q]);
                a[q * 2] += f.x; a[q * 2 + 1] += f.y;
            }
    }
    for (; j < s1; j++) {
        uint4 v = *((const uint4*)(msg + (size_t)srcl[j] * 128) + l16);
        const uint32_t* w = &v.x;
#pragma unroll
        for (int q = 0; q < 4; q++) {
            float2 f = __half22float2(*(const __half2*)&w[q]);
            a[q * 2] += f.x; a[q * 2 + 1] += f.y;
        }
    }
    uint4 o;
    o.x = pack2(a[0], a[1]); o.y = pack2(a[2], a[3]);
    o.z = pack2(a[4], a[5]); o.w = pack2(a[6], a[7]);
    *((uint4*)(agg + (size_t)node * 128) + l16) = o;
}

// ===========================================================================
// FUSED in/upd kernels, M=256 per CTA (two 128-row tiles, TMEM cols 0..127 /
// 128..255; 2 CTAs/SM). Ring: 2 stages x 49152 (A 32K + W 16K). Phase2 SS with
// smem hTiles (4 x 16KB in freed ring regions) + msgW 32KB prefetched early.
// ===========================================================================
#define RING_OFF     1024
#define STG          49152
#define SMEM_FUSED   (1024 + 2 * STG)     // 99328

#if TC_AVAIL
// stage msgW (128n x 128k fp16 = 32KB, 2 chunks) at absolute ring offset dsto
__device__ __forceinline__ void stage_msgW(uint32_t sb, int tid,
                                           const __half* msgW, uint32_t dsto) {
#pragma unroll
    for (int it = 0; it < 8; it++) {
        int idx = tid + it * 256;
        int chunk = idx >> 10, w = idx & 1023;
        int r = w >> 3, c4 = w & 7;
        uint32_t dst = sb + RING_OFF + dsto + chunk * 16384
                     + SW128((uint32_t)(r * 128 + c4 * 16));
        cp16(dst, msgW + (size_t)r * 128 + chunk * 64 + c4 * 8);
    }
    cp_commit();
}

// epilogue1 M=256: warp w -> tile (w>>2), subpartition (w&3). Drains both
// tile accumulators, writes fp16 h to gmem + smem hTile chunks (hofs[4]).
__device__ __forceinline__ void epi1_256(uint32_t sb, uint32_t tmem,
                                         int wid, int lid, int block_row,
                                         const float* bias,
                                         const unsigned char* maskB,
                                         __half* Ch, const uint32_t* hofs) {
    const int tile = wid >> 2;
    const int sp   = wid & 3;
    const int row  = sp * 32 + lid;
    const int m    = block_row + tile * 128 + row;
    const bool masked = (maskB[m] != 0);
    const uint32_t tb = tmem + tile * 128;
#pragma unroll
    for (int half = 0; half < 2; half++) {
        int cb = half * 64;
#pragma unroll
        for (int q = 0; q < 2; q++) {
            int c0 = cb + q * 32;
            uint32_t r32[32];
            TC_LD_X32(r32, tb + c0);
            asm volatile("tcgen05.wait::ld.sync.aligned;" ::: "memory");
#pragma unroll
            for (int j = 0; j < 32; j += 8) {
                float f[8];
#pragma unroll
                for (int i = 0; i < 8; i++) {
                    float v = __uint_as_float(r32[j + i]) + bias[c0 + j + i];
                    v = fmaxf(v, 0.f);
                    if (masked) v = 0.f;
                    f[i] = v;
                }
                uint4 o;
                o.x = pack2(f[0], f[1]); o.y = pack2(f[2], f[3]);
                o.z = pack2(f[4], f[5]); o.w = pack2(f[6], f[7]);
                *(uint4*)(Ch + (size_t)m * 128 + c0 + j) = o;
                uint32_t boff = (uint32_t)(((c0 & 63) + j) * 2);
                sts4u(sb + RING_OFF + hofs[tile * 2 + half]
                      + SW128((uint32_t)(row * 128) + boff), o);
            }
        }
    }
    asm volatile("tcgen05.fence::before_thread_sync;" ::: "memory");
}

// phase2 M=256: two SS MMA chains (tiles reuse their acc cols), drain -> Cm.
__device__ __forceinline__ void phase2_256(uint32_t sb, uint32_t tmem,
                                           int tid, int wid, int lid,
                                           int block_row, const float* bias2,
                                           __half* Cm, const uint32_t* hofs,
                                           uint32_t woff) {
    cp_wait0();
    __syncthreads();
    if (tid == 0) {
        asm volatile("tcgen05.fence::after_thread_sync;" ::: "memory");
        asm volatile("fence.proxy.async.shared::cta;" ::: "memory");
#pragma unroll
        for (int tile = 0; tile < 2; tile++) {
#pragma unroll
            for (int c = 0; c < 2; c++) {
                uint64_t hd = mk_desc(sb + RING_OFF + hofs[tile * 2 + c]);
                uint64_t wd = mk_desc(sb + RING_OFF + woff + c * 16384);
#pragma unroll
                for (int j = 0; j < 4; j++)
                    mma_f16_ss(tmem + tile * 128, hd + j * 2, wd + j * 2,
                               (c > 0 || j > 0) ? 1u : 0u);
            }
        }
        tc_commit(sb + 24);
    }
    mbar_wait(sb + 24, 0);
    asm volatile("tcgen05.fence::after_thread_sync;" ::: "memory");

    const int tile = wid >> 2;
    const int sp   = wid & 3;
    const int m    = block_row + tile * 128 + sp * 32 + lid;
    const uint32_t tb = tmem + tile * 128;
#pragma unroll
    for (int cb = 0; cb < 128; cb += 32) {
        uint32_t r32[32];
        TC_LD_X32(r32, tb + cb);
        asm volatile("tcgen05.wait::ld.sync.aligned;" ::: "memory");
#pragma unroll
        for (int j = 0; j < 32; j += 8) {
            float f[8];
#pragma unroll
            for (int i = 0; i < 8; i++)
                f[i] = fmaxf(__uint_as_float(r32[j + i]) + bias2[cb + j + i], 0.f);
            uint4 o;
            o.x = pack2(f[0], f[1]); o.y = pack2(f[2], f[3]);
            o.z = pack2(f[4], f[5]); o.w = pack2(f[6], f[7]);
            *(uint4*)(Cm + (size_t)m * 128 + cb + j) = o;
        }
    }
}
#endif  // TC_AVAIL

// ----- fused input layer (tf32 phase1, K=67 pad 96, M=256) + msg0 -----
struct FIN {
    const float* emb; const int* types; const float* coords;
    const float* Wt; const float* bias;
    const unsigned char* maskB;
    __half* Ch;
    const __half* msgW; const float* bias2; __half* Cm;
};

__global__ void __launch_bounds__(256) k_fused_in(FIN g) {
#if TC_AVAIL
    extern __shared__ __align__(1024) char smem[];
    const uint32_t sb = smem_u32(smem);
    const int tid = threadIdx.x;
    const int wid = tid >> 5;
    const int lid = tid & 31;
    const int block_row = blockIdx.x * 256;

    auto stage1 = [&](int t, int s) {
        uint32_t bufA = sb + RING_OFF + s * STG;
        uint32_t bufW = bufA + 32768;
#pragma unroll
        for (int it = 0; it < 4; it++) {           // W: 1024 slots
            int idx = tid + it * 256;
            int r = idx >> 3, c4 = idx & 7;
            cp16(bufW + SW128((uint32_t)(r * 128 + c4 * 16)),
                 g.Wt + (size_t)r * 96 + t * 32 + c4 * 4);
        }
#pragma unroll
        for (int it = 0; it < 8; it++) {           // A: 2048 slots (256 rows)
            int idx = tid + it * 256;
            int r = idx >> 3, c4 = idx & 7;
            int gr = block_row + r;
            uint32_t dst = bufA + SW128((uint32_t)(r * 128 + c4 * 16));
            if (t < 2) {
                cp16(dst, g.emb + (size_t)g.types[gr] * 64 + t * 32 + c4 * 4);
            } else {
                float4 v = make_float4(0.f, 0.f, 0.f, 0.f);
                if (c4 == 0) {
                    v.x = g.coords[gr * 3];
                    v.y = g.coords[gr * 3 + 1];
                    v.z = g.coords[gr * 3 + 2];
                }
                sts4(dst, v);
            }
        }
        cp_commit();
    };

    stage1(0, 0);                          // G0
    stage1(1, 1);                          // G1
    if (wid == 0) {
        asm volatile(
            "tcgen05.alloc.cta_group::1.sync.aligned.shared::cta.b32 [%0], %1;"
            :: "r"(sb), "r"(256u) : "memory");
        asm volatile("tcgen05.relinquish_alloc_permit.cta_group::1.sync.aligned;");
    }
    if (tid == 0) {
        mbar_init(sb + 8, 1); mbar_init(sb + 16, 1); mbar_init(sb + 24, 1);
    }
    __syncthreads();
    uint32_t tmem;
    asm volatile("ld.shared.b32 %0, [%1];" : "=r"(tmem) : "r"(sb));

    uint64_t d0A0 = mk_desc(sb + RING_OFF);
    uint64_t d0A1 = mk_desc(sb + RING_OFF + 16384);
    uint64_t d0W  = mk_desc(sb + RING_OFF + 32768);
    uint64_t d1A0 = mk_desc(sb + RING_OFF + STG);
    uint64_t d1A1 = mk_desc(sb + RING_OFF + STG + 16384);
    uint64_t d1W  = mk_desc(sb + RING_OFF + STG + 32768);

    // chunk0 (stage0)
    cp_wait1(); __syncthreads();
    if (tid == 0) {
        asm volatile("fence.proxy.async.shared::cta;" ::: "memory");
#pragma unroll
        for (int j = 0; j < 4; j++) {
            uint32_t en = (j > 0) ? 1u : 0u;
            mma_tf32_ss(tmem,       d0A0 + j * 2, d0W + j * 2, en);
            mma_tf32_ss(tmem + 128, d0A1 + j * 2, d0W + j * 2, en);
        }
        tc_commit(sb + 8);
    }
    mbar_wait(sb + 8, 0);
    stage1(2, 0);                          // G2 -> stage0

    // chunk1 (stage1)
    cp_wait1(); __syncthreads();
    if (tid == 0) {
        asm volatile("fence.proxy.async.shared::cta;" ::: "memory");
#pragma unroll
        for (int j = 0; j < 4; j++) {
            mma_tf32_ss(tmem,       d1A0 + j * 2, d1W + j * 2, 1u);
            mma_tf32_ss(tmem + 128, d1A1 + j * 2, d1W + j * 2, 1u);
        }
        tc_commit(sb + 16);
    }
    mbar_wait(sb + 16, 0);
    stage_msgW(sb, tid, g.msgW, STG);      // G3: msgW @ stage1+0..32K

    // chunk2 (stage0)
    cp_wait1(); __syncthreads();
    if (tid == 0) {
        asm volatile("fence.proxy.async.shared::cta;" ::: "memory");
#pragma unroll
        for (int j = 0; j < 4; j++) {
            mma_tf32_ss(tmem,       d0A0 + j * 2, d0W + j * 2, 1u);
            mma_tf32_ss(tmem + 128, d0A1 + j * 2, d0W + j * 2, 1u);
        }
        tc_commit(sb + 8);
    }
    mbar_wait(sb + 8, 1);
    asm volatile("tcgen05.fence::after_thread_sync;" ::: "memory");

    // hTile chunks: stage0 0/16K/32K + stage1 tail 81920 (after msgW 49152..81920)
    const uint32_t hofs[4] = {0u, 16384u, 32768u, 81920u};
    epi1_256(sb, tmem, wid, lid, block_row, g.bias, g.maskB, g.Ch, hofs);
    phase2_256(sb, tmem, tid, wid, lid, block_row, g.bias2, g.Cm, hofs, STG);

    __syncthreads();
    if (wid == 0) {
        asm volatile("tcgen05.dealloc.cta_group::1.sync.aligned.b32 %0, %1;"
                     :: "r"(tmem), "r"(256u));
    }
#else
    const int m = blockIdx.x * 256 + threadIdx.x;
    const bool masked = (g.maskB[m] != 0);
    int ty = g.types[m];
    for (int cb = 0; cb < 128; cb++) {
        float acc = 0.f;
        for (int k = 0; k < 64; k++)
            acc = fmaf(g.emb[(size_t)ty * 64 + k], g.Wt[(size_t)cb * 96 + k], acc);
        for (int k = 64; k < 67; k++)
            acc = fmaf(g.coords[m * 3 + (k - 64)], g.Wt[(size_t)cb * 96 + k], acc);
        float v = fmaxf(acc + g.bias[cb], 0.f);
        if (masked) v = 0.f;
        g.Ch[(size_t)m * 128 + cb] = __float2half(v);
    }
    for (int cb = 0; cb < 128; cb++) {
        float acc = 0.f;
        for (int k = 0; k < 128; k++)
            acc = fmaf(__half2float(g.Ch[(size_t)m * 128 + k]),
                       __half2float(g.msgW[(size_t)cb * 128 + k]), acc);
        g.Cm[(size_t)m * 128 + cb] = __float2half(fmaxf(acc + g.bias2[cb], 0.f));
    }
#endif
}

// ----- fused upd layer (f16 phase1, K=256 concat [h|agg], M=256) + msg -----
struct FUP {
    const __half* A1; const __half* A2;
    const __half* Wt; const float* bias;
    const unsigned char* maskB;
    __half* Ch;
    const __half* msgW; const float* bias2; __half* Cm;
};

__global__ void __launch_bounds__(256) k_fused_upd(FUP g) {
#if TC_AVAIL
    extern __shared__ __align__(1024) char smem[];
    const uint32_t sb = smem_u32(smem);
    const int tid = threadIdx.x;
    const int wid = tid >> 5;
    const int lid = tid & 31;
    const int block_row = blockIdx.x * 256;

    auto stage1 = [&](int t, int s) {
        uint32_t bufA = sb + RING_OFF + s * STG;
        uint32_t bufW = bufA + 32768;
#pragma unroll
        for (int it = 0; it < 4; it++) {           // W: 1024 slots
            int idx = tid + it * 256;
            int r = idx >> 3, c4 = idx & 7;
            cp16(bufW + SW128((uint32_t)(r * 128 + c4 * 16)),
                 g.Wt + (size_t)r * 256 + t * 64 + c4 * 8);
        }
#pragma unroll
        for (int it = 0; it < 8; it++) {           // A: 2048 slots (256 rows)
            int idx = tid + it * 256;
            int r = idx >> 3, c4 = idx & 7;
            int gr = block_row + r;
            const __half* src = (t < 2)
                ? g.A1 + (size_t)gr * 128 + t * 64 + c4 * 8
                : g.A2 + (size_t)gr * 128 + (t - 2) * 64 + c4 * 8;
            cp16(bufA + SW128((uint32_t)(r * 128 + c4 * 16)), src);
        }
        cp_commit();
    };

    stage1(0, 0);                          // G0
    stage1(1, 1);                          // G1
    if (wid == 0) {
        asm volatile(
            "tcgen05.alloc.cta_group::1.sync.aligned.shared::cta.b32 [%0], %1;"
            :: "r"(sb), "r"(256u) : "memory");
        asm volatile("tcgen05.relinquish_alloc_permit.cta_group::1.sync.aligned;");
    }
    if (tid == 0) {
        mbar_init(sb + 8, 1); mbar_init(sb + 16, 1); mbar_init(sb + 24, 1);
    }
    __syncthreads();
    uint32_t tmem;
    asm volatile("ld.shared.b32 %0, [%1];" : "=r"(tmem) : "r"(sb));

    uint64_t d0A0 = mk_desc(sb + RING_OFF);
    uint64_t d0A1 = mk_desc(sb + RING_OFF + 16384);
    uint64_t d0W  = mk_desc(sb + RING_OFF + 32768);
    uint64_t d1A0 = mk_desc(sb + RING_OFF + STG);
    uint64_t d1A1 = mk_desc(sb + RING_OFF + STG + 16384);
    uint64_t d1W  = mk_desc(sb + RING_OFF + STG + 32768);

    // chunk0 (stage0)
    cp_wait1(); __syncthreads();
    if (tid == 0) {
        asm volatile("fence.proxy.async.shared::cta;" ::: "memory");
#pragma unroll
        for (int j = 0; j < 4; j++) {
            uint32_t en = (j > 0) ? 1u : 0u;
            mma_f16_ss(tmem,       d0A0 + j * 2, d0W + j * 2, en);
            mma_f16_ss(tmem + 128, d0A1 + j * 2, d0W + j * 2, en);
        }
        tc_commit(sb + 8);
    }
    mbar_wait(sb + 8, 0);
    stage1(2, 0);                          // G2

    // chunk1 (stage1)
    cp_wait1(); __syncthreads();
    if (tid == 0) {
        asm volatile("fence.proxy.async.shared::cta;" ::: "memory");
#pragma unroll
        for (int j = 0; j < 4; j++) {
            mma_f16_ss(tmem,       d1A0 + j * 2, d1W + j * 2, 1u);
            mma_f16_ss(tmem + 128, d1A1 + j * 2, d1W + j * 2, 1u);
        }
        tc_commit(sb + 16);
    }
    mbar_wait(sb + 16, 0);
    stage1(3, 1);                          // G3

    // chunk2 (stage0)
    cp_wait1(); __syncthreads();
    if (tid == 0) {
        asm volatile("fence.proxy.async.shared::cta;" ::: "memory");
#pragma unroll
        for (int j = 0; j < 4; j++) {
            mma_f16_ss(tmem,       d0A0 + j * 2, d0W + j * 2, 1u);
            mma_f16_ss(tmem + 128, d0A1 + j * 2, d0W + j * 2, 1u);
        }
        tc_commit(sb + 8);
    }
    mbar_wait(sb + 8, 1);
    stage_msgW(sb, tid, g.msgW, 0);        // G4: msgW @ stage0+0..32K

    // chunk3 (stage1)
    cp_wait1(); __syncthreads();
    if (tid == 0) {
        asm volatile("fence.proxy.async.shared::cta;" ::: "memory");
#pragma unroll
        for (int j = 0; j < 4; j++) {
            mma_f16_ss(tmem,       d1A0 + j * 2, d1W + j * 2, 1u);
            mma_f16_ss(tmem + 128, d1A1 + j * 2, d1W + j * 2, 1u);
        }
        tc_commit(sb + 16);
    }
    mbar_wait(sb + 16, 1);
    asm volatile("tcgen05.fence::after_thread_sync;" ::: "memory");

    // hTile chunks: stage0 tail 32768 + stage1 49152/65536/81920
    const uint32_t hofs[4] = {32768u, 49152u, 65536u, 81920u};
    epi1_256(sb, tmem, wid, lid, block_row, g.bias, g.maskB, g.Ch, hofs);
    phase2_256(sb, tmem, tid, wid, lid, block_row, g.bias2, g.Cm, hofs, 0);

    __syncthreads();
    if (wid == 0) {
        asm volatile("tcgen05.dealloc.cta_group::1.sync.aligned.b32 %0, %1;"
                     :: "r"(tmem), "r"(256u));
    }
#else
    const int m = blockIdx.x * 256 + threadIdx.x;
    const bool masked = (g.maskB[m] != 0);
    for (int cb = 0; cb < 128; cb++) {
        float acc = 0.f;
        for (int k = 0; k < 128; k++)
            acc = fmaf(__half2float(g.A1[(size_t)m * 128 + k]),
                       __half2float(g.Wt[(size_t)cb * 256 + k]), acc);
        for (int k = 0; k < 128; k++)
            acc = fmaf(__half2float(g.A2[(size_t)m * 128 + k]),
                       __half2float(g.Wt[(size_t)cb * 256 + 128 + k]), acc);
        float v = fmaxf(acc + g.bias[cb], 0.f);
        if (masked) v = 0.f;
        g.Ch[(size_t)m * 128 + cb] = __float2half(v);
    }
    for (int cb = 0; cb < 128; cb++) {
        float acc = 0.f;
        for (int k = 0; k < 128; k++)
            acc = fmaf(__half2float(g.Ch[(size_t)m * 128 + k]),
                       __half2float(g.msgW[(size_t)cb * 128 + k]), acc);
        g.Cm[(size_t)m * 128 + cb] = __float2half(fmaxf(acc + g.bias2[cb], 0.f));
    }
#endif
}

// ===========================================================================
// k_fused_tail: upd1 + coupling (unchanged from R15, passing).
// ===========================================================================
#define TAIL_HDR   8192
#define SMEM_TAIL  (TAIL_HDR + 65536)
struct FT {
    const __half* A1; const __half* A2;
    const __half* Wt; const float* bias;
    const __half* Wse; const __half* Whe;
    const float* bse; const float* bhe;
    const float* Ws2; const float* bs2;
    const float* Wh2; const float* bh2;
    const float* coords;
    const unsigned char* maskB;
    float* out; float* logdet;
};

__global__ void __launch_bounds__(256) k_fused_tail(FT g) {
#if TC_AVAIL
    extern __shared__ __align__(1024) char smem[];
    const uint32_t sb = smem_u32(smem);
    float* smf = (float*)smem;
    const int tid = threadIdx.x;
    const int wid = tid >> 5;
    const int lid = tid & 31;
    const int block_row = blockIdx.x * 128;

    auto stage1 = [&](int t, int s) {
        uint32_t bufA = sb + TAIL_HDR + s * 32768;
        uint32_t bufW = bufA + 16384;
#pragma unroll
        for (int it = 0; it < 4; it++) {
            int idx = tid + it * 256;
            int r = idx >> 3, c4 = idx & 7;
            cp16(bufW + SW128((uint32_t)(r * 128 + c4 * 16)),
                 g.Wt + (size_t)r * 256 + t * 64 + c4 * 8);
        }
#pragma unroll
        for (int it = 0; it < 4; it++) {
            int idx = tid + it * 256;
            int r = idx >> 3, c4 = idx & 7;
            int gr = block_row + r;
            const __half* src = (t < 2)
                ? g.A1 + (size_t)gr * 128 + t * 64 + c4 * 8
                : g.A2 + (size_t)gr * 128 + (t - 2) * 64 + c4 * 8;
            cp16(bufA + SW128((uint32_t)(r * 128 + c4 * 16)), src);
        }
        cp_commit();
    };
    auto stageCW = [&](const __half* W, int s) {
        uint32_t base = sb + TAIL_HDR + s * 32768;
#pragma unroll
        for (int it = 0; it < 8; it++) {
            int idx = tid + it * 256;
            int chunk = idx >> 10, w = idx & 1023;
            int r = w >> 3, c4 = w & 7;
            cp16(base + chunk * 16384 + SW128((uint32_t)(r * 128 + c4 * 16)),
                 W + (size_t)r * 192 + chunk * 64 + c4 * 8);
        }
        cp_commit();
    };

    stage1(0, 0);
    stage1(1, 1);
    if (wid == 0) {
        asm volatile(
            "tcgen05.alloc.cta_group::1.sync.aligned.shared::cta.b32 [%0], %1;"
            :: "r"(sb), "r"(256u) : "memory");
        asm volatile("tcgen05.relinquish_alloc_permit.cta_group::1.sync.aligned;");
    }
    if (tid == 0) {
        mbar_init(sb + 8, 1); mbar_init(sb + 16, 1); mbar_init(sb + 24, 1);
    }
    for (int i = tid; i < 384; i += 256) {
        smf[16 + i]   = g.Ws2[i];
        smf[400 + i]  = g.Wh2[i];
        int n = i / 3, c = i - n * 3;
        smf[1040 + i] = __half2float(g.Wse[(size_t)n * 192 + 128 + c]);
        smf[1424 + i] = __half2float(g.Whe[(size_t)n * 192 + 128 + c]);
    }
    if (tid < 128) {
        smf[784 + tid] = g.bse[tid];
        smf[912 + tid] = g.bhe[tid];
    }
    __syncthreads();
    uint32_t tmem;
    asm volatile("ld.shared.b32 %0, [%1];" : "=r"(tmem) : "r"(sb));

    uint64_t d0A = mk_desc(sb + TAIL_HDR);
    uint64_t d0W = mk_desc(sb + TAIL_HDR + 16384);
    uint64_t d1A = mk_desc(sb + TAIL_HDR + 32768);
    uint64_t d1W = mk_desc(sb + TAIL_HDR + 49152);

    cp_wait1(); __syncthreads();
    if (tid == 0) {
        asm volatile("fence.proxy.async.shared::cta;" ::: "memory");
#pragma unroll
        for (int j = 0; j < 4; j++)
            mma_f16_ss(tmem, d0A + j * 2, d0W + j * 2, (j > 0) ? 1u : 0u);
        tc_commit(sb + 8);
    }
    mbar_wait(sb + 8, 0);
    stage1(2, 0);

    cp_wait1(); __syncthreads();
    if (tid == 0) {
        asm volatile("fence.proxy.async.shared::cta;" ::: "memory");
#pragma unroll
        for (int j = 0; j < 4; j++)
            mma_f16_ss(tmem, d1A + j * 2, d1W + j * 2, 1u);
        tc_commit(sb + 16);
    }
    mbar_wait(sb + 16, 0);
    stage1(3, 1);

    cp_wait1(); __syncthreads();
    if (tid == 0) {
        asm volatile("fence.proxy.async.shared::cta;" ::: "memory");
#pragma unroll
        for (int j = 0; j < 4; j++)
            mma_f16_ss(tmem, d0A + j * 2, d0W + j * 2, 1u);
        tc_commit(sb + 8);
    }
    mbar_wait(sb + 8, 1);
    stageCW(g.Wse, 0);

    cp_wait1(); __syncthreads();
    if (tid == 0) {
        asm volatile("fence.proxy.async.shared::cta;" ::: "memory");
#pragma unroll
        for (int j = 0; j < 4; j++)
            mma_f16_ss(tmem, d1A + j * 2, d1W + j * 2, 1u);
        tc_commit(sb + 16);
    }
    mbar_wait(sb + 16, 1);
    stageCW(g.Whe, 1);
    asm volatile("tcgen05.fence::after_thread_sync;" ::: "memory");

    const int m = block_row + (wid & 3) * 32 + lid;
    if (wid < 4) {
        const bool masked = (g.maskB[m] != 0);
        uint32_t a2[64];
#pragma unroll
        for (int cb = 0; cb < 128; cb += 32) {
            uint32_t r32[32];
            TC_LD_X32(r32, tmem + cb);
            asm volatile("tcgen05.wait::ld.sync.aligned;" ::: "memory");
#pragma unroll
            for (int j = 0; j < 32; j += 2) {
                float v0 = fmaxf(__uint_as_float(r32[j])     + g.bias[cb + j],     0.f);
                float v1 = fmaxf(__uint_as_float(r32[j + 1]) + g.bias[cb + j + 1], 0.f);
                if (masked) { v0 = 0.f; v1 = 0.f; }
                a2[(cb + j) >> 1] = pack2(v0, v1);
            }
        }
        uint32_t woff = (uint32_t)wid << 21;
        TC_ST_X32(tmem + 128 + woff, a2);
        TC_ST_X32(tmem + 160 + woff, a2 + 32);
        asm volatile("tcgen05.wait::st.sync.aligned;" ::: "memory");
    }
    asm volatile("tcgen05.fence::before_thread_sync;" ::: "memory");

    cp_wait1();
    __syncthreads();
    if (tid == 0) {
        asm volatile("tcgen05.fence::after_thread_sync;" ::: "memory");
        asm volatile("fence.proxy.async.shared::cta;" ::: "memory");
#pragma unroll
        for (int c = 0; c < 2; c++) {
            uint64_t wd = mk_desc(sb + TAIL_HDR + c * 16384);
#pragma unroll
            for (int j = 0; j < 4; j++)
                mma_f16_ts(tmem, tmem + 128 + c * 32 + j * 8, wd + j * 2,
                           (c > 0 || j > 0) ? 1u : 0u);
        }
        tc_commit(sb + 24);
    }
    mbar_wait(sb + 24, 0);
    asm volatile("tcgen05.fence::after_thread_sync;" ::: "memory");

    bool cm = ((m & 1) == 0) && (g.maskB[m] == 0);     // PHASE = 0
    float cc0 = 0.f, cc1 = 0.f, cc2 = 0.f;
    if (!cm) { cc0 = g.coords[m*3]; cc1 = g.coords[m*3+1]; cc2 = g.coords[m*3+2]; }
    float raw[3] = {0.f, 0.f, 0.f};
    if (wid < 4) {
#pragma unroll
        for (int cb = 0; cb < 128; cb += 32) {
            uint32_t r32[32];
            TC_LD_X32(r32, tmem + cb);
            asm volatile("tcgen05.wait::ld.sync.aligned;" ::: "memory");
#pragma unroll
            for (int k = 0; k < 32; k++) {
                int col = cb + k;
                float v = __uint_as_float(r32[k]) + smf[784 + col];
                v = fmaf(cc0, smf[1040 + col * 3],     v);
                v = fmaf(cc1, smf[1040 + col * 3 + 1], v);
                v = fmaf(cc2, smf[1040 + col * 3 + 2], v);
                v = fmaxf(v, 0.f);
#pragma unroll
                for (int c = 0; c < 3; c++)
                    raw[c] = fmaf(v, smf[16 + col * 3 + c], raw[c]);
            }
        }
    }
    asm volatile("tcgen05.fence::before_thread_sync;" ::: "memory");

    cp_wait0();
    __syncthreads();
    if (tid == 0) {
        asm volatile("tcgen05.fence::after_thread_sync;" ::: "memory");
        asm volatile("fence.proxy.async.shared::cta;" ::: "memory");
#pragma unroll
        for (int c = 0; c < 2; c++) {
            uint64_t wd = mk_desc(sb + TAIL_HDR + 32768 + c * 16384);
#pragma unroll
            for (int j = 0; j < 4; j++)
                mma_f16_ts(tmem, tmem + 128 + c * 32 + j * 8, wd + j * 2,
                           (c > 0 || j > 0) ? 1u : 0u);
        }
        tc_commit(sb + 24);
    }
    mbar_wait(sb + 24, 1);
    asm volatile("tcgen05.fence::after_thread_sync;" ::: "memory");

    if (wid < 4) {
        float shf[3] = {0.f, 0.f, 0.f};
#pragma unroll
        for (int cb = 0; cb < 128; cb += 32) {
            uint32_t r32[32];
            TC_LD_X32(r32, tmem + cb);
            asm volatile("tcgen05.wait::ld.sync.aligned;" ::: "memory");
#pragma unroll
            for (int k = 0; k < 32; k++) {
                int col = cb + k;
                float v = __uint_as_float(r32[k]) + smf[912 + col];
                v = fmaf(cc0, smf[1424 + col * 3],     v);
                v = fmaf(cc1, smf[1424 + col * 3 + 1], v);
                v = fmaf(cc2, smf[1424 + col * 3 + 2], v);
                v = fmaxf(v, 0.f);
#pragma unroll
                for (int c = 0; c < 3; c++)
                    shf[c] = fmaf(v, smf[400 + col * 3 + c], shf[c]);
            }
        }
        float ld = 0.f;
#pragma unroll
        for (int c = 0; c < 3; c++) {
            float r = raw[c] + g.bs2[c];
            float s = shf[c] + g.bh2[c];
            float ls = cm ? tanhf(r) * 2.f : 0.f;
            ld += ls;
            float coord = g.coords[m * 3 + c];
            g.out[m * 3 + c] = cm ? (expf(ls) * coord + s) : coord;
        }
#pragma unroll
        for (int o = 16; o > 0; o >>= 1)
            ld += __shfl_xor_sync(0xFFFFFFFFu, ld, o);
        if (lid == 0) atomicAdd(&g.logdet[m >> 13], ld);
    }

    __syncthreads();
    if (wid == 0) {
        asm volatile("tcgen05.dealloc.cta_group::1.sync.aligned.b32 %0, %1;"
                     :: "r"(tmem), "r"(256u));
    }
#else
    if (threadIdx.x >= 128) return;
    const int m = blockIdx.x * 128 + threadIdx.x;
    const bool masked = (g.maskB[m] != 0);
    bool cm = ((m & 1) == 0) && !masked;
    float hrow[128];
    for (int cb = 0; cb < 128; cb++) {
        float acc = 0.f;
        for (int k = 0; k < 128; k++)
            acc = fmaf(__half2float(g.A1[(size_t)m * 128 + k]),
                       __half2float(g.Wt[(size_t)cb * 256 + k]), acc);
        for (int k = 0; k < 128; k++)
            acc = fmaf(__half2float(g.A2[(size_t)m * 128 + k]),
                       __half2float(g.Wt[(size_t)cb * 256 + 128 + k]), acc);
        float v = fmaxf(acc + g.bias[cb], 0.f);
        if (masked) v = 0.f;
        hrow[cb] = __half2float(__float2half(v));
    }
    float cc[3];
    for (int c = 0; c < 3; c++) cc[c] = cm ? 0.f : g.coords[m * 3 + c];
    float raw[3], shf[3];
    for (int c = 0; c < 3; c++) { raw[c] = g.bs2[c]; shf[c] = g.bh2[c]; }
    for (int n = 0; n < 128; n++) {
        float accs = g.bse[n], acch = g.bhe[n];
        for (int k = 0; k < 128; k++) {
            accs = fmaf(hrow[k], __half2float(g.Wse[(size_t)n * 192 + k]), accs);
            acch = fmaf(hrow[k], __half2float(g.Whe[(size_t)n * 192 + k]), acch);
        }
        for (int c = 0; c < 3; c++) {
            accs = fmaf(cc[c], __half2float(g.Wse[(size_t)n * 192 + 128 + c]), accs);
            acch = fmaf(cc[c], __half2float(g.Whe[(size_t)n * 192 + 128 + c]), acch);
        }
        accs = fmaxf(accs, 0.f); acch = fmaxf(acch, 0.f);
        for (int c = 0; c < 3; c++) {
            raw[c] = fmaf(accs, g.Ws2[n * 3 + c], raw[c]);
            shf[c] = fmaf(acch, g.Wh2[n * 3 + c], shf[c]);
        }
    }
    float ld = 0.f;
    for (int c = 0; c < 3; c++) {
        float ls = cm ? tanhf(raw[c]) * 2.f : 0.f;
        ld += ls;
        float coord = g.coords[m * 3 + c];
        g.out[m * 3 + c] = cm ? (expf(ls) * coord + shf[c]) : coord;
    }
    atomicAdd(&g.logdet[m >> 13], ld);
#endif
}

// ---------------------------------------------------------------------------
// Host launcher. Index 3 = k_fused_in (ncu profile target).
// ---------------------------------------------------------------------------
extern "C" void kernel_launch(void* const* d_in, const int* in_sizes, int n_in,
                              void* d_out, int out_size) {
    const float*         coords = (const float*)d_in[0];
    const int*           types  = (const int*)  d_in[1];
    const int*           adj    = (const int*)  d_in[2];
    const int*           ebi    = (const int*)  d_in[3];
    const unsigned char* maskB  = (const unsigned char*)d_in[4];
    const float* emb   = (const float*)d_in[5];
    const float* W_in  = (const float*)d_in[6];
    const float* b_in  = (const float*)d_in[7];
    const float* msg_W = (const float*)d_in[8];
    const float* msg_b = (const float*)d_in[9];
    const float* upd_W = (const float*)d_in[10];
    const float* upd_b = (const float*)d_in[11];
    const float* W_out = (const float*)d_in[12];
    const float* b_out = (const float*)d_in[13];
    const float* Ws1   = (const float*)d_in[14];
    const float* bs1   = (const float*)d_in[15];
    const float* Ws2   = (const float*)d_in[16];
    const float* bs2   = (const float*)d_in[17];
    const float* Wh1   = (const float*)d_in[18];
    const float* bh1   = (const float*)d_in[19];
    const float* Wh2   = (const float*)d_in[20];
    const float* bh2   = (const float*)d_in[21];

    float* out    = (float*)d_out;
    float* logdet = out + (size_t)BN_ * 3;

    __half *h, *b1, *b2, *wth;
    float *wt;
    int *off, *part, *cur, *srcl;
    cudaGetSymbolAddress((void**)&h,    g_h);
    cudaGetSymbolAddress((void**)&b1,   g_b1);
    cudaGetSymbolAddress((void**)&b2,   g_b2);
    cudaGetSymbolAddress((void**)&wt,   g_wt);
    cudaGetSymbolAddress((void**)&wth,  g_wth);
    cudaGetSymbolAddress((void**)&off,  g_off);
    cudaGetSymbolAddress((void**)&part, g_part);
    cudaGetSymbolAddress((void**)&cur,  g_cur);
    cudaGetSymbolAddress((void**)&srcl, g_srcl);

    cudaFuncSetAttribute(k_fused_in,   cudaFuncAttributeMaxDynamicSharedMemorySize, SMEM_FUSED);
    cudaFuncSetAttribute(k_fused_upd,  cudaFuncAttributeMaxDynamicSharedMemorySize, SMEM_FUSED);
    cudaFuncSetAttribute(k_fused_tail, cudaFuncAttributeMaxDynamicSharedMemorySize, SMEM_TAIL);

    const int BT = 256;

    // 0: prep
    k_prep<<<1024, BT>>>(W_in, msg_W, upd_W, W_out, Ws1, Wh1, bs1, bh1, b_out,
                         wt, wth, off, logdet);
    // 1: hist
    k_hist<<<E_ / BT, BT>>>(adj, ebi, off);
    // 2: scanA
    k_scanA<<<512, 512>>>(off, part);
    // 3: fused input + msg0 (M=256)  <-- ncu profile target
    FIN fi{emb, types, coords, wt + O_WIN, b_in, maskB, h,
           wth + H_MSG0, msg_b, b1};
    k_fused_in<<<BN_ / 256, 256, SMEM_FUSED>>>(fi);
    // 4-5: finish CSR
    k_scanB<<<512, 512>>>(off, part, cur);
    k_place<<<E_ / BT, BT>>>(adj, ebi, cur, srcl);
    // 6: gather layer 0
    k_gather<<<BN_ / 16, BT>>>(b1, off, srcl, b2);
    // 7: fused upd0 + msg1 (M=256)
    FUP fu{h, b2, wth + H_UPD0, upd_b, maskB, h, wth + H_MSG1, msg_b + 128, b1};
    k_fused_upd<<<BN_ / 256, 256, SMEM_FUSED>>>(fu);
    // 8: gather layer 1
    k_gather<<<BN_ / 16, BT>>>(b1, off, srcl, b2);
    // 9: fused tail = upd1 + coupling (M=128, unchanged)
    FT ft{h, b2, wth + H_UPD1, upd_b + 128,
          wth + H_WSE, wth + H_WHE, wt + O_BSE, wt + O_BHE,
          Ws2, bs2, Wh2, bh2, coords, maskB, out, logdet};
    k_fused_tail<<<BN_ / 128, 256, SMEM_TAIL>>>(ft);
}